// round 7
// baseline (speedup 1.0000x reference)
#include <cuda_runtime.h>
#include <cuda_bf16.h>
#include <math.h>
#include <stdint.h>

// ---------------- problem constants ----------------
#define Bx 8
#define Lx 1024
#define Hd 768
#define NHd 12
#define HDd 64
#define DI 3072
#define NLAYERS 2
#define NHID 1024
#define NOUT 5000
#define SCALE_ATT 0.125f
#define LEAKY 0.01f
#define ML (Bx*Lx)      // 8192

// ---------------- fp32 scratch ----------------
__device__ float g_x   [ML*Hd];
__device__ float g_qkv [ML*3*Hd];
__device__ float g_kv  [ML*2*Hd];
__device__ float g_ring[ML*Hd];
__device__ float g_relay[Bx*Hd];
__device__ float g_part[Bx*16*Hd];
__device__ float g_rk  [Bx*Hd];
__device__ float g_rv  [Bx*Hd];
__device__ float g_sq  [Bx*Hd];
__device__ float g_satt[Bx*Hd];
__device__ float g_ft  [Bx*2*Hd];
__device__ float g_hid [Bx*3*NHID];
__device__ int   g_mask[Bx*Lx];

// ---------------- bf16 2-plane scratch ----------------
__device__ __nv_bfloat16 g_x2  [ML*2*Hd];
__device__ __nv_bfloat16 g_h2  [ML*2*Hd];
__device__ __nv_bfloat16 g_att2[ML*2*Hd];
__device__ __nv_bfloat16 g_mid2[(size_t)ML*2*DI];
__device__ __nv_bfloat16 g_w1p [(size_t)NLAYERS*DI*2*Hd];
__device__ __nv_bfloat16 g_w2p [(size_t)NLAYERS*Hd*2*DI];
__device__ __nv_bfloat16 g_qkvp[(size_t)NLAYERS*3*Hd*2*Hd];
__device__ __nv_bfloat16 g_rop [(size_t)NLAYERS*Hd*2*Hd];
__device__ __nv_bfloat16 g_skvp[(size_t)NLAYERS*2*Hd*2*Hd];
__device__ float g_bqkv[NLAYERS*3*Hd];
__device__ float g_bskv[NLAYERS*2*Hd];

// ---------------- helpers ----------------
__device__ __forceinline__ uint32_t cvta_s(const void* p) {
    return (uint32_t)__cvta_generic_to_shared(p);
}
__device__ __forceinline__ void ldsm4(uint32_t* r, uint32_t addr) {
    asm volatile("ldmatrix.sync.aligned.m8n8.x4.shared.b16 {%0,%1,%2,%3}, [%4];\n"
                 : "=r"(r[0]), "=r"(r[1]), "=r"(r[2]), "=r"(r[3]) : "r"(addr));
}
__device__ __forceinline__ void mma16816(float* c, const uint32_t* a, const uint32_t* b) {
    asm volatile("mma.sync.aligned.m16n8k16.row.col.f32.bf16.bf16.f32 "
                 "{%0,%1,%2,%3},{%4,%5,%6,%7},{%8,%9},{%0,%1,%2,%3};\n"
                 : "+f"(c[0]), "+f"(c[1]), "+f"(c[2]), "+f"(c[3])
                 : "r"(a[0]), "r"(a[1]), "r"(a[2]), "r"(a[3]), "r"(b[0]), "r"(b[1]));
}
__device__ __forceinline__ void cp16(uint32_t s, const void* g) {
    asm volatile("cp.async.cg.shared.global [%0], [%1], 16;\n" :: "r"(s), "l"(g));
}
__device__ __forceinline__ void split_hl(float v, __nv_bfloat16& hi, __nv_bfloat16& lo) {
    hi = __float2bfloat16(v);
    lo = __float2bfloat16(v - __bfloat162float(hi));
}
__device__ __forceinline__ void plane_write1(__nv_bfloat16* base, size_t row, int C, int c, float v) {
    __nv_bfloat16 hi, lo; split_hl(v, hi, lo);
    __nv_bfloat16* p = base + row * (size_t)(2 * C) + 32 * (c >> 4) + (c & 15);
    p[0]  = hi;
    p[16] = lo;
}
__device__ __forceinline__ uint32_t sw128(uint32_t o) { return o ^ ((o >> 3) & 0x70); }

// =====================================================================
// Tensor-core GEMM, 128x256 CTA tile, warp tile 64x64 (2x4 warps),
// 3-stage cp.async pipeline. C[M,N] = act(A@W^T + bias), fp32-exact via
// 3 bf16 products (A/B hi/lo planes). M%128==0, N%256==0, K%32==0.
// =====================================================================
#define TA 16384                     // A bytes per buffer (128 rows x 128B)
#define TBB 32768                    // B bytes per buffer (256 rows x 128B)
#define BUFB (TA+TBB)                // 48 KB
#define SMEM_G (3*BUFB)              // 144 KB

__device__ __forceinline__ void fill_tile(uint32_t base, const __nv_bfloat16* A2,
                                          const __nv_bfloat16* W2, int lda2, int ldw2,
                                          int bm, int bn, int kc, int tid)
{
#pragma unroll
    for (int j = 0; j < 4; j++) {
        int idx = tid + j * 256;             // 0..1023 : A 128 rows x 8 chunks
        int row = idx >> 3, c16 = idx & 7;
        uint32_t off = sw128((uint32_t)(row * 128 + c16 * 16));
        cp16(base + off, A2 + (size_t)(bm + row) * lda2 + kc * 64 + c16 * 8);
    }
#pragma unroll
    for (int j = 0; j < 8; j++) {
        int idx = tid + j * 256;             // 0..2047 : B 256 rows x 8 chunks
        int row = idx >> 3, c16 = idx & 7;
        uint32_t off = sw128((uint32_t)(row * 128 + c16 * 16));
        cp16(base + TA + off, W2 + (size_t)(bn + row) * ldw2 + kc * 64 + c16 * 8);
    }
}

template<int ACT, int OUTP>
__global__ __launch_bounds__(256, 1)
void gemm_tc2(const __nv_bfloat16* __restrict__ A2, int lda2,
              const __nv_bfloat16* __restrict__ W2, int ldw2,
              const float* __restrict__ bias,
              float* __restrict__ C, int ldc,
              __nv_bfloat16* __restrict__ C2, int Nout,
              int T)
{
    extern __shared__ __align__(128) char smraw[];
    const uint32_t sb = cvta_s(smraw);

    const int tid  = threadIdx.x;
    const int lane = tid & 31;
    const int warp = tid >> 5;
    const int wm = warp >> 2;     // 0..1 -> 64 rows
    const int wn = warp & 3;      // 0..3 -> 64 cols
    const int bm = blockIdx.y * 128;
    const int bn = blockIdx.x * 256;

    float acc[4][8][4];
#pragma unroll
    for (int i = 0; i < 4; i++)
#pragma unroll
        for (int j = 0; j < 8; j++)
#pragma unroll
            for (int c = 0; c < 4; c++) acc[i][j][c] = 0.f;

    const int a_row = lane & 15;
    const int a_kb  = (lane >> 4) * 16;
    const int b_row = (lane & 7) + ((lane >> 4) << 3);
    const int b_kb  = ((lane >> 3) & 1) * 16;

    // prologue: chunks 0,1 into buffers 0,1
    fill_tile(sb, A2, W2, lda2, ldw2, bm, bn, 0, tid);
    asm volatile("cp.async.commit_group;\n");
    fill_tile(sb + BUFB, A2, W2, lda2, ldw2, bm, bn, 1, tid);
    asm volatile("cp.async.commit_group;\n");

    int bc = 0, bf = 2;
    for (int t = 0; t < T; t++) {
        if (t == T - 1) asm volatile("cp.async.wait_group 0;\n");
        else            asm volatile("cp.async.wait_group 1;\n");
        __syncthreads();

        if (t + 2 < T) {
            fill_tile(sb + bf * BUFB, A2, W2, lda2, ldw2, bm, bn, t + 2, tid);
            asm volatile("cp.async.commit_group;\n");
            bf = (bf == 2) ? 0 : bf + 1;
        }

        const uint32_t ab = sb + bc * BUFB;
        const uint32_t bb = ab + TA;
        bc = (bc == 2) ? 0 : bc + 1;

#pragma unroll
        for (int g = 0; g < 2; g++) {
            uint32_t af[4][4], bh[4][4];
            // A hi
#pragma unroll
            for (int mt = 0; mt < 4; mt++) {
                int row = wm * 64 + mt * 16 + a_row;
                ldsm4(af[mt], ab + sw128((uint32_t)(row * 128 + g * 64 + a_kb)));
            }
            // B hi (kept for phases 0 and 2)
#pragma unroll
            for (int p = 0; p < 4; p++) {
                int row = wn * 64 + p * 16 + b_row;
                ldsm4(bh[p], bb + sw128((uint32_t)(row * 128 + g * 64 + b_kb)));
            }
            // phase 0: A hi * B hi
#pragma unroll
            for (int mt = 0; mt < 4; mt++)
#pragma unroll
                for (int nt = 0; nt < 8; nt++)
                    mma16816(acc[mt][nt], af[mt], &bh[nt >> 1][(nt & 1) * 2]);
            // phase 1: A hi * B lo (B-lo streamed 1 p-tile at a time)
#pragma unroll
            for (int p = 0; p < 4; p++) {
                uint32_t bl[4];
                int row = wn * 64 + p * 16 + b_row;
                ldsm4(bl, bb + sw128((uint32_t)(row * 128 + g * 64 + 32 + b_kb)));
#pragma unroll
                for (int mt = 0; mt < 4; mt++) {
                    mma16816(acc[mt][2 * p],     af[mt], &bl[0]);
                    mma16816(acc[mt][2 * p + 1], af[mt], &bl[2]);
                }
            }
            // phase 2: A lo * B hi (A-lo overwrites af)
#pragma unroll
            for (int mt = 0; mt < 4; mt++) {
                int row = wm * 64 + mt * 16 + a_row;
                ldsm4(af[mt], ab + sw128((uint32_t)(row * 128 + g * 64 + 32 + a_kb)));
            }
#pragma unroll
            for (int mt = 0; mt < 4; mt++)
#pragma unroll
                for (int nt = 0; nt < 8; nt++)
                    mma16816(acc[mt][nt], af[mt], &bh[nt >> 1][(nt & 1) * 2]);
        }
    }

    // epilogue
#pragma unroll
    for (int mt = 0; mt < 4; mt++) {
#pragma unroll
        for (int nt = 0; nt < 8; nt++) {
            int row = bm + wm * 64 + mt * 16 + (lane >> 2);
            int col = bn + wn * 64 + nt * 8 + (lane & 3) * 2;
            float bi0 = bias[col], bi1 = bias[col + 1];
            float v0 = acc[mt][nt][0] + bi0;
            float v1 = acc[mt][nt][1] + bi1;
            float v2 = acc[mt][nt][2] + bi0;
            float v3 = acc[mt][nt][3] + bi1;
            if (ACT == 1) {
                v0 = fmaxf(v0, 0.f); v1 = fmaxf(v1, 0.f);
                v2 = fmaxf(v2, 0.f); v3 = fmaxf(v3, 0.f);
            }
            if (OUTP == 0) {
                *(float2*)(C + (size_t)row * ldc + col)       = make_float2(v0, v1);
                *(float2*)(C + (size_t)(row + 8) * ldc + col) = make_float2(v2, v3);
            } else {
                int gg = col >> 4, off = col & 15;
                __nv_bfloat16 h0, h1, h2, h3, l0, l1, l2, l3;
                split_hl(v0, h0, l0); split_hl(v1, h1, l1);
                split_hl(v2, h2, l2); split_hl(v3, h3, l3);
                __nv_bfloat16* p0 = C2 + (size_t)row * (2 * Nout) + 32 * gg + off;
                __nv_bfloat16* p1 = C2 + (size_t)(row + 8) * (2 * Nout) + 32 * gg + off;
                *(__nv_bfloat162*)(p0)      = __halves2bfloat162(h0, h1);
                *(__nv_bfloat162*)(p0 + 16) = __halves2bfloat162(l0, l1);
                *(__nv_bfloat162*)(p1)      = __halves2bfloat162(h2, h3);
                *(__nv_bfloat162*)(p1 + 16) = __halves2bfloat162(l2, l3);
            }
        }
    }
}

static void gemm_p(int act, int outp,
                   const __nv_bfloat16* A2, const __nv_bfloat16* W2,
                   const float* bias, float* C, int ldc, __nv_bfloat16* C2,
                   int M, int N, int K)
{
    dim3 grid(N / 256, M / 128);
    int T = K / 32;
    if (outp == 1)      gemm_tc2<1, 1><<<grid, 256, SMEM_G>>>(A2, 2 * K, W2, 2 * K, bias, nullptr, 0, C2, N, T);
    else if (act == 1)  gemm_tc2<1, 0><<<grid, 256, SMEM_G>>>(A2, 2 * K, W2, 2 * K, bias, C, ldc, nullptr, N, T);
    else                gemm_tc2<0, 0><<<grid, 256, SMEM_G>>>(A2, 2 * K, W2, 2 * K, bias, C, ldc, nullptr, N, T);
}

// =====================================================================
// fused weight plane conversion
// =====================================================================
#define S1 1179648
#define S2 2359296
#define S3 2654208
#define S4 2949120
#define S5 3244032
#define S6 3538944
#define S7 3833856
#define S8 4128768

__global__ void cvt_all(const float* w1, const float* w2, const float* rq, const float* rk,
                        const float* rv, const float* ro, const float* sk, const float* sv,
                        __nv_bfloat16* o1, __nv_bfloat16* o2, __nv_bfloat16* oqkv,
                        __nv_bfloat16* oro, __nv_bfloat16* oskv)
{
    int i = blockIdx.x * blockDim.x + threadIdx.x;
    if (i >= S8) return;
    const float* in; __nv_bfloat16* out; int C, base, extra;
    if      (i < S1) { in = w1; out = o1;   C = Hd; base = 0;  extra = 0; }
    else if (i < S2) { in = w2; out = o2;   C = DI; base = S1; extra = 0; }
    else if (i < S3) { in = rq; out = oqkv;                        C = Hd; base = S2; extra = 1536; }
    else if (i < S4) { in = rk; out = oqkv + (size_t)768 * 2 * Hd; C = Hd; base = S3; extra = 1536; }
    else if (i < S5) { in = rv; out = oqkv + (size_t)1536 * 2 * Hd;C = Hd; base = S4; extra = 1536; }
    else if (i < S6) { in = ro; out = oro;  C = Hd; base = S5; extra = 0; }
    else if (i < S7) { in = sk; out = oskv;                        C = Hd; base = S6; extra = 768; }
    else             { in = sv; out = oskv + (size_t)768 * 2 * Hd; C = Hd; base = S7; extra = 768; }
    int e = (i - base) * 4;
    int r = e / C, c = e % C;
    size_t ro_ = (size_t)r + (size_t)(r / Hd) * extra;
    if (extra == 0 && C == DI) ro_ = r;
    float4 f = *(const float4*)(in + e);
    __nv_bfloat16 h0, h1, h2, h3, l0, l1, l2, l3;
    split_hl(f.x, h0, l0); split_hl(f.y, h1, l1);
    split_hl(f.z, h2, l2); split_hl(f.w, h3, l3);
    __nv_bfloat16* p = out + ro_ * (2 * C) + 32 * (c >> 4) + (c & 15);
    *(__nv_bfloat162*)(p)      = __halves2bfloat162(h0, h1);
    *(__nv_bfloat162*)(p + 2)  = __halves2bfloat162(h2, h3);
    *(__nv_bfloat162*)(p + 16) = __halves2bfloat162(l0, l1);
    *(__nv_bfloat162*)(p + 18) = __halves2bfloat162(l2, l3);
}

__global__ void concat_bias(const float* bq, const float* bk, const float* bv,
                            const float* sk, const float* sv,
                            float* oqkv, float* oskv)
{
    int i = blockIdx.x * blockDim.x + threadIdx.x;
    int n1 = NLAYERS * 3 * Hd;
    if (i < n1) {
        int layer = i / (3 * Hd), c = i % (3 * Hd);
        const float* s = (c < Hd) ? bq : (c < 2 * Hd) ? bk : bv;
        oqkv[i] = s[layer * Hd + (c % Hd)];
    } else if (i < n1 + NLAYERS * 2 * Hd) {
        int j = i - n1;
        int layer = j / (2 * Hd), c = j % (2 * Hd);
        const float* s = (c < Hd) ? sk : sv;
        oskv[j] = s[layer * Hd + (c % Hd)];
    }
}

// =====================================================================
// Small-M GEMMs (M=8)
// =====================================================================
__device__ __forceinline__ void smalldot8(const float* __restrict__ A, int lda,
                                          const float* __restrict__ wrow, int K,
                                          int lane, float* s)
{
    const float4* w4 = (const float4*)wrow;
    int K4 = K >> 2;
#pragma unroll
    for (int m = 0; m < 8; m++) s[m] = 0.f;
    for (int k = lane; k < K4; k += 32) {
        float4 w = w4[k];
#pragma unroll
        for (int m = 0; m < 8; m++) {
            float4 a = ((const float4*)(A + (size_t)m * lda))[k];
            s[m] += a.x * w.x + a.y * w.y + a.z * w.z + a.w * w.w;
        }
    }
#pragma unroll
    for (int m = 0; m < 8; m++)
#pragma unroll
        for (int o = 16; o; o >>= 1) s[m] += __shfl_xor_sync(0xffffffffu, s[m], o);
}

__global__ __launch_bounds__(256)
void gemm_small8(const float* __restrict__ A, int lda,
                 const float* __restrict__ W, int ldw,
                 const float* __restrict__ bias,
                 float* __restrict__ C, int ldc,
                 int N, int K, int act)
{
    int n = (blockIdx.x * blockDim.x + threadIdx.x) >> 5;
    int lane = threadIdx.x & 31;
    if (n >= N) return;
    float s[8];
    smalldot8(A, lda, W + (size_t)n * ldw, K, lane, s);
    if (lane == 0) {
        float bv = bias[n];
#pragma unroll
        for (int m = 0; m < 8; m++) {
            float v = s[m] + bv;
            if (act == 1) v = fmaxf(v, 0.f);
            else if (act == 2) v = v > 0.f ? v : LEAKY * v;
            C[(size_t)m * ldc + n] = v;
        }
    }
}

__global__ __launch_bounds__(256)
void gemm_rel2(const float* __restrict__ relay,
               const float* __restrict__ wk, const float* __restrict__ bk,
               const float* __restrict__ wv, const float* __restrict__ bv,
               float* __restrict__ rk, float* __restrict__ rv)
{
    int n = (blockIdx.x * blockDim.x + threadIdx.x) >> 5;
    int lane = threadIdx.x & 31;
    if (n >= 2 * Hd) return;
    int seg = n >= Hd, c = n - seg * Hd;
    const float* W = seg ? wv : wk;
    const float* B = seg ? bv : bk;
    float* C = seg ? rv : rk;
    float s[8];
    smalldot8(relay, Hd, W + (size_t)c * Hd, Hd, lane, s);
    if (lane == 0) {
        float bb = B[c];
#pragma unroll
        for (int m = 0; m < 8; m++) C[(size_t)m * Hd + c] = s[m] + bb;
    }
}

__global__ __launch_bounds__(256)
void gemm_rel3(const float* __restrict__ relay,
               const float* __restrict__ wq, const float* __restrict__ bq,
               const float* __restrict__ wk, const float* __restrict__ bk,
               const float* __restrict__ wv, const float* __restrict__ bv,
               float* __restrict__ sq, float* __restrict__ rk, float* __restrict__ rv)
{
    int n = (blockIdx.x * blockDim.x + threadIdx.x) >> 5;
    int lane = threadIdx.x & 31;
    if (n >= 3 * Hd) return;
    int seg = n / Hd, c = n % Hd;
    const float* W = (seg == 0) ? wq : (seg == 1) ? wk : wv;
    const float* B = (seg == 0) ? bq : (seg == 1) ? bk : bv;
    float* C = (seg == 0) ? sq : (seg == 1) ? rk : rv;
    float s[8];
    smalldot8(relay, Hd, W + (size_t)c * Hd, Hd, lane, s);
    if (lane == 0) {
        float bb = B[c];
#pragma unroll
        for (int m = 0; m < 8; m++) C[(size_t)m * Hd + c] = s[m] + bb;
    }
}

__global__ __launch_bounds__(256)
void head2_kernel(const float* __restrict__ hid,
                  const float* __restrict__ w2,
                  const float* __restrict__ b2,
                  float* __restrict__ out)
{
    int n = (blockIdx.x * blockDim.x + threadIdx.x) >> 5;
    int lane = threadIdx.x & 31;
    if (n >= 3 * NOUT) return;
    int j = n / NOUT, c = n % NOUT;
    float s[8];
    smalldot8(hid + j * NHID, 3 * NHID, w2 + (size_t)n * NHID, NHID, lane, s);
    if (lane == 0) {
        float bb = b2[n];
#pragma unroll
        for (int m = 0; m < 8; m++)
            out[((size_t)m * 3 + j) * NOUT + c] = s[m] + bb;
    }
}

// ---------------- block reductions ----------------
__device__ __forceinline__ float2 block_reduce_sum2(float a, float b)
{
    static __shared__ float sa[8], sb2[8];
    __syncthreads();
    int lane = threadIdx.x & 31, w = threadIdx.x >> 5;
#pragma unroll
    for (int o = 16; o; o >>= 1) {
        a += __shfl_xor_sync(0xffffffffu, a, o);
        b += __shfl_xor_sync(0xffffffffu, b, o);
    }
    if (lane == 0) { sa[w] = a; sb2[w] = b; }
    __syncthreads();
    if (w == 0) {
        a = lane < 8 ? sa[lane] : 0.f;
        b = lane < 8 ? sb2[lane] : 0.f;
#pragma unroll
        for (int o = 4; o; o >>= 1) {
            a += __shfl_xor_sync(0xffffffffu, a, o);
            b += __shfl_xor_sync(0xffffffffu, b, o);
        }
        if (lane == 0) { sa[0] = a; sb2[0] = b; }
    }
    __syncthreads();
    return make_float2(sa[0], sb2[0]);
}
__device__ __forceinline__ float block_reduce_max(float a)
{
    static __shared__ float sm[8];
    __syncthreads();
    int lane = threadIdx.x & 31, w = threadIdx.x >> 5;
#pragma unroll
    for (int o = 16; o; o >>= 1) a = fmaxf(a, __shfl_xor_sync(0xffffffffu, a, o));
    if (lane == 0) sm[w] = a;
    __syncthreads();
    if (w == 0) {
        a = lane < 8 ? sm[lane] : -1e30f;
#pragma unroll
        for (int o = 4; o; o >>= 1) a = fmaxf(a, __shfl_xor_sync(0xffffffffu, a, o));
        if (lane == 0) sm[0] = a;
    }
    __syncthreads();
    return sm[0];
}
__device__ __forceinline__ float block_reduce_sum(float a)
{
    static __shared__ float ss[8];
    __syncthreads();
    int lane = threadIdx.x & 31, w = threadIdx.x >> 5;
#pragma unroll
    for (int o = 16; o; o >>= 1) a += __shfl_xor_sync(0xffffffffu, a, o);
    if (lane == 0) ss[w] = a;
    __syncthreads();
    if (w == 0) {
        a = lane < 8 ? ss[lane] : 0.f;
#pragma unroll
        for (int o = 4; o; o >>= 1) a += __shfl_xor_sync(0xffffffffu, a, o);
        if (lane == 0) ss[0] = a;
    }
    __syncthreads();
    return ss[0];
}

// ---------------- embed + mask + planes ----------------
__global__ void embed_kernel(const int* __restrict__ src, const float* __restrict__ emb,
                             const float* __restrict__ pos, float* __restrict__ x,
                             __nv_bfloat16* __restrict__ x2, int* __restrict__ mask)
{
    int idx = blockIdx.x * blockDim.x + threadIdx.x;
    if (idx >= ML * Hd) return;
    int h = idx % Hd;
    int bl = idx / Hd;
    int l = bl % Lx;
    int w = h >> 8;
    int dd = h & 255;
    int tok = src[bl * 3 + w];
    float v = emb[tok * 256 + dd] + pos[l * Hd + h];
    x[idx] = v;
    plane_write1(x2, bl, Hd, h, v);
    if (h == 0) mask[bl] = (src[bl * 3] == 0) ? 1 : 0;
}

// ---------------- relay mean: 2-stage ----------------
__global__ void relay_part_kernel(const float* __restrict__ x, float* __restrict__ part)
{
    int h = blockIdx.x * 128 + threadIdx.x;
    int ch = blockIdx.y;
    int b = blockIdx.z;
    const float* p = x + (size_t)b * Lx * Hd + (size_t)ch * 64 * Hd + h;
    float s = 0.f;
#pragma unroll 8
    for (int l = 0; l < 64; l++) s += p[(size_t)l * Hd];
    part[((size_t)b * 16 + ch) * Hd + h] = s;
}
__global__ void relay_fin_kernel(const float* __restrict__ part, float* __restrict__ relay)
{
    int h = blockIdx.x * 128 + threadIdx.x;
    int b = blockIdx.y;
    float s = 0.f;
#pragma unroll
    for (int ch = 0; ch < 16; ch++) s += part[((size_t)b * 16 + ch) * Hd + h];
    relay[b * Hd + h] = s * (1.0f / Lx);
}

// ---------------- layernorm ----------------
template<int RES, int ACT, int MODE, int MASKED>
__global__ __launch_bounds__(256)
void ln_kernel(const float* __restrict__ x, const float* __restrict__ res,
               const float* __restrict__ g, const float* __restrict__ b,
               float* __restrict__ out, __nv_bfloat16* __restrict__ out2,
               const int* __restrict__ mask)
{
    int row = blockIdx.x;
    const float* xr = x + (size_t)row * Hd;
    const float* rr = RES ? res + (size_t)row * Hd : nullptr;
    int mrow = MASKED ? mask[row] : 0;
    float t[3];
    float s = 0.f, ss = 0.f;
#pragma unroll
    for (int j = 0; j < 3; j++) {
        int i = threadIdx.x + j * 256;
        float v = xr[i];
        if (RES) v += rr[i];
        t[j] = v;
        s += v; ss += v * v;
    }
    float2 r = block_reduce_sum2(s, ss);
    float mu = r.x * (1.0f / Hd);
    float var = r.y * (1.0f / Hd) - mu * mu;
    float rstd = rsqrtf(var + 1e-5f);
#pragma unroll
    for (int j = 0; j < 3; j++) {
        int i = threadIdx.x + j * 256;
        float v = (t[j] - mu) * rstd * g[i] + b[i];
        if (ACT == 2) v = v > 0.f ? v : LEAKY * v;
        if (MASKED && mrow) v = 0.f;
        if (MODE != 1) out[(size_t)row * Hd + i] = v;
        if (MODE != 0) plane_write1(out2, row, Hd, i, v);
    }
}

// ---------------- ring attention ----------------
__global__ __launch_bounds__(256)
void ring_attn_kernel(const float* __restrict__ qkv, const float* __restrict__ rk,
                      const float* __restrict__ rv, __nv_bfloat16* __restrict__ out2)
{
    int gw = (blockIdx.x * blockDim.x + threadIdx.x) >> 5;
    int lane = threadIdx.x & 31;
    int n = gw % NHd;
    int bl = gw / NHd;
    int l = bl % Lx;
    int b = bl / Lx;

    const float* qp = qkv + (size_t)bl * (3 * Hd) + n * HDd;
    float q0 = qp[lane * 2], q1 = qp[lane * 2 + 1];

    float s[4];
#pragma unroll
    for (int w = 0; w < 3; w++) {
        int ll = l - 1 + w;
        float d = 0.f;
        if (ll >= 0 && ll < Lx) {
            const float* kp = qkv + ((size_t)(b * Lx + ll)) * (3 * Hd) + Hd + n * HDd;
            d = q0 * kp[lane * 2] + q1 * kp[lane * 2 + 1];
        }
#pragma unroll
        for (int o = 16; o; o >>= 1) d += __shfl_xor_sync(0xffffffffu, d, o);
        s[w] = d * SCALE_ATT;
    }
    {
        const float* kp = rk + b * Hd + n * HDd;
        float d = q0 * kp[lane * 2] + q1 * kp[lane * 2 + 1];
#pragma unroll
        for (int o = 16; o; o >>= 1) d += __shfl_xor_sync(0xffffffffu, d, o);
        s[3] = d * SCALE_ATT;
    }
    float m = fmaxf(fmaxf(s[0], s[1]), fmaxf(s[2], s[3]));
    float e[4], se = 0.f;
#pragma unroll
    for (int w = 0; w < 4; w++) { e[w] = expf(s[w] - m); se += e[w]; }
    float inv = 1.0f / se;

    float o0 = 0.f, o1 = 0.f;
#pragma unroll
    for (int w = 0; w < 3; w++) {
        int ll = l - 1 + w;
        if (ll >= 0 && ll < Lx) {
            const float* vp = qkv + ((size_t)(b * Lx + ll)) * (3 * Hd) + 2 * Hd + n * HDd;
            float p = e[w] * inv;
            o0 += p * vp[lane * 2];
            o1 += p * vp[lane * 2 + 1];
        }
    }
    {
        const float* vp = rv + b * Hd + n * HDd;
        float p = e[3] * inv;
        o0 += p * vp[lane * 2];
        o1 += p * vp[lane * 2 + 1];
    }
    int c0 = n * HDd + lane * 2;
    int gg = c0 >> 4, off = c0 & 15;
    __nv_bfloat16 h0, h1, l0b, l1b;
    split_hl(o0, h0, l0b); split_hl(o1, h1, l1b);
    __nv_bfloat16* p = out2 + (size_t)bl * (2 * Hd) + 32 * gg + off;
    *(__nv_bfloat162*)(p)      = __halves2bfloat162(h0, h1);
    *(__nv_bfloat162*)(p + 16) = __halves2bfloat162(l0b, l1b);
}

// ---------------- star attention ----------------
__global__ __launch_bounds__(256)
void star_attn_kernel(const float* __restrict__ sq, const float* __restrict__ kv,
                      const float* __restrict__ rk, const float* __restrict__ rv,
                      const int* __restrict__ mask, float* __restrict__ out)
{
    __shared__ float qs[HDd];
    __shared__ float sc[Lx + 1];
    __shared__ float red[4 * HDd];

    int b = blockIdx.x / NHd;
    int n = blockIdx.x % NHd;
    int tid = threadIdx.x;

    if (tid < HDd) qs[tid] = sq[b * Hd + n * HDd + tid];
    __syncthreads();

    float lmax = -1e30f;
    for (int s = tid; s < Lx + 1; s += 256) {
        const float* kp = (s == 0) ? rk + b * Hd + n * HDd
                                   : kv + ((size_t)(b * Lx + s - 1)) * (2 * Hd) + n * HDd;
        float d = 0.f;
#pragma unroll
        for (int i = 0; i < HDd; i++) d += qs[i] * kp[i];
        d *= SCALE_ATT;
        if (s > 0 && mask[b * Lx + s - 1]) d = -1e30f;
        sc[s] = d;
        lmax = fmaxf(lmax, d);
    }
    float bmax = block_reduce_max(lmax);

    float lsum = 0.f;
    for (int s = tid; s < Lx + 1; s += 256) {
        float ev = expf(sc[s] - bmax);
        sc[s] = ev;
        lsum += ev;
    }
    float bsum = block_reduce_sum(lsum);

    int gg = tid >> 6;
    int dd = tid & 63;
    float acc = 0.f;
    for (int s = gg; s < Lx + 1; s += 4) {
        const float* vp = (s == 0) ? rv + b * Hd + n * HDd
                                   : kv + ((size_t)(b * Lx + s - 1)) * (2 * Hd) + Hd + n * HDd;
        acc += sc[s] * vp[dd];
    }
    red[gg * HDd + dd] = acc;
    __syncthreads();
    if (tid < HDd) {
        float r = red[tid] + red[HDd + tid] + red[2 * HDd + tid] + red[3 * HDd + tid];
        out[b * Hd + n * HDd + tid] = r / bsum;
    }
}

// ---------------- gather ft ----------------
__global__ void gather_ft_kernel(const float* __restrict__ relay, const float* __restrict__ nodes,
                                 const int* __restrict__ positions, float* __restrict__ ft)
{
    int idx = blockIdx.x * blockDim.x + threadIdx.x;
    if (idx >= Bx * 2 * Hd) return;
    int b = idx / (2 * Hd);
    int i = idx % (2 * Hd);
    float v;
    if (i < Hd) v = relay[b * Hd + i];
    else        v = nodes[((size_t)b * Lx + positions[b]) * Hd + (i - Hd)];
    ft[idx] = v;
}

// ---------------- launch ----------------
extern "C" void kernel_launch(void* const* d_in, const int* in_sizes, int n_in,
                              void* d_out, int out_size)
{
    const int*   src       = (const int*)  d_in[0];
    const int*   positions = (const int*)  d_in[1];
    const float* emb       = (const float*)d_in[2];
    const float* pos_table = (const float*)d_in[3];
    const float* norm_g    = (const float*)d_in[4];
    const float* norm_b    = (const float*)d_in[5];
    const float* pw_w1     = (const float*)d_in[6];
    const float* pw_b1     = (const float*)d_in[7];
    const float* pw_w2     = (const float*)d_in[8];
    const float* pw_b2     = (const float*)d_in[9];
    const float* pw_g      = (const float*)d_in[10];
    const float* pw_bn     = (const float*)d_in[11];
    const float* ring_wq   = (const float*)d_in[12];
    const float* ring_bq   = (const float*)d_in[13];
    const float* ring_wk   = (const float*)d_in[14];
    const float* ring_bk   = (const float*)d_in[15];
    const float* ring_wv   = (const float*)d_in[16];
    const float* ring_bv   = (const float*)d_in[17];
    const float* ring_wo   = (const float*)d_in[18];
    const float* ring_bo   = (const float*)d_in[19];
    const float* star_wq   = (const float*)d_in[20];
    const float* star_bq   = (const float*)d_in[21];
    const float* star_wk   = (const float*)d_in[22];
    const float* star_bk   = (const float*)d_in[23];
    const float* star_wv   = (const float*)d_in[24];
    const float* star_bv   = (const float*)d_in[25];
    const float* star_wo   = (const float*)d_in[26];
    const float* star_bo   = (const float*)d_in[27];
    const float* head_w1   = (const float*)d_in[28];
    const float* head_b1   = (const float*)d_in[29];
    const float* head_w2   = (const float*)d_in[30];
    const float* head_b2   = (const float*)d_in[31];
    float* out = (float*)d_out;

    cudaFuncSetAttribute(gemm_tc2<0, 0>, cudaFuncAttributeMaxDynamicSharedMemorySize, SMEM_G);
    cudaFuncSetAttribute(gemm_tc2<1, 0>, cudaFuncAttributeMaxDynamicSharedMemorySize, SMEM_G);
    cudaFuncSetAttribute(gemm_tc2<1, 1>, cudaFuncAttributeMaxDynamicSharedMemorySize, SMEM_G);

    float *x, *qkv, *kv, *ring, *relay, *part, *rk, *rv, *sq, *satt, *ft, *hid, *bqkv, *bskv;
    int* mask;
    __nv_bfloat16 *x2, *h2, *att2, *mid2;
    __nv_bfloat16 *w1p, *w2p, *qkvp, *rop, *skvp;
    cudaGetSymbolAddress((void**)&x, g_x);
    cudaGetSymbolAddress((void**)&qkv, g_qkv);
    cudaGetSymbolAddress((void**)&kv, g_kv);
    cudaGetSymbolAddress((void**)&ring, g_ring);
    cudaGetSymbolAddress((void**)&relay, g_relay);
    cudaGetSymbolAddress((void**)&part, g_part);
    cudaGetSymbolAddress((void**)&rk, g_rk);
    cudaGetSymbolAddress((void**)&rv, g_rv);
    cudaGetSymbolAddress((void**)&sq, g_sq);
    cudaGetSymbolAddress((void**)&satt, g_satt);
    cudaGetSymbolAddress((void**)&ft, g_ft);
    cudaGetSymbolAddress((void**)&hid, g_hid);
    cudaGetSymbolAddress((void**)&mask, g_mask);
    cudaGetSymbolAddress((void**)&x2, g_x2);
    cudaGetSymbolAddress((void**)&h2, g_h2);
    cudaGetSymbolAddress((void**)&att2, g_att2);
    cudaGetSymbolAddress((void**)&mid2, g_mid2);
    cudaGetSymbolAddress((void**)&w1p, g_w1p);
    cudaGetSymbolAddress((void**)&w2p, g_w2p);
    cudaGetSymbolAddress((void**)&qkvp, g_qkvp);
    cudaGetSymbolAddress((void**)&rop, g_rop);
    cudaGetSymbolAddress((void**)&skvp, g_skvp);
    cudaGetSymbolAddress((void**)&bqkv, g_bqkv);
    cudaGetSymbolAddress((void**)&bskv, g_bskv);

    const int M = ML;

    cvt_all<<<(S8 + 255) / 256, 256>>>(pw_w1, pw_w2, ring_wq, ring_wk, ring_wv, ring_wo,
                                       star_wk, star_wv, w1p, w2p, qkvp, rop, skvp);
    concat_bias<<<(NLAYERS * 5 * Hd + 255) / 256, 256>>>(ring_bq, ring_bk, ring_bv,
                                                          star_bk, star_bv, bqkv, bskv);
    embed_kernel<<<(ML * Hd + 255) / 256, 256>>>(src, emb, pos_table, x, x2, mask);
    {
        dim3 gp(6, 16, Bx);
        relay_part_kernel<<<gp, 128>>>(x, part);
        dim3 gf(6, Bx);
        relay_fin_kernel<<<gf, 128>>>(part, relay);
    }

    for (int i = 0; i < NLAYERS; i++) {
        const float* b1 = pw_b1 + (size_t)i * DI;
        const float* b2 = pw_b2 + (size_t)i * Hd;
        const float* pg = pw_g + (size_t)i * Hd;
        const float* pb = pw_bn + (size_t)i * Hd;
        const float* rbk = ring_bk + (size_t)i * Hd;
        const float* rbv = ring_bv + (size_t)i * Hd;
        const float* rbo = ring_bo + (size_t)i * Hd;
        const float* ng = norm_g + (size_t)i * Hd;
        const float* nb = norm_b + (size_t)i * Hd;
        const float* rwk = ring_wk + (size_t)i * Hd * Hd;
        const float* rwv = ring_wv + (size_t)i * Hd * Hd;
        const __nv_bfloat16* w1i = w1p + (size_t)i * DI * 2 * Hd;
        const __nv_bfloat16* w2i = w2p + (size_t)i * Hd * 2 * DI;
        const __nv_bfloat16* qkvi = qkvp + (size_t)i * 3 * Hd * 2 * Hd;
        const __nv_bfloat16* roi = rop + (size_t)i * Hd * 2 * Hd;
        const __nv_bfloat16* skvi = skvp + (size_t)i * 2 * Hd * 2 * Hd;
        const float* bqkvi = bqkv + (size_t)i * 3 * Hd;
        const float* bskvi = bskv + (size_t)i * 2 * Hd;

        // PWFF
        gemm_p(1, 1, x2, w1i, b1, nullptr, 0, mid2, M, DI, Hd);
        gemm_p(0, 0, mid2, w2i, b2, ring, Hd, nullptr, M, Hd, DI);
        ln_kernel<1, 0, 1, 0><<<M, 256>>>(ring, x, pg, pb, nullptr, h2, nullptr);

        // Ring attention
        gemm_p(0, 0, h2, qkvi, bqkvi, qkv, 3 * Hd, nullptr, M, 3 * Hd, Hd);
        gemm_rel2<<<(2 * Hd * 32 + 255) / 256, 256>>>(relay, rwk, rbk, rwv, rbv, rk, rv);
        ring_attn_kernel<<<(M * NHd) / 8, 256>>>(qkv, rk, rv, att2);
        gemm_p(0, 0, att2, roi, rbo, ring, Hd, nullptr, M, Hd, Hd);
        ln_kernel<0, 2, 2, 1><<<M, 256>>>(ring, nullptr, ng, nb, x, x2, mask);

        // Star attention
        gemm_rel3<<<(3 * Hd * 32 + 255) / 256, 256>>>(relay,
            star_wq + (size_t)i * Hd * Hd, star_bq + (size_t)i * Hd,
            star_wk + (size_t)i * Hd * Hd, star_bk + (size_t)i * Hd,
            star_wv + (size_t)i * Hd * Hd, star_bv + (size_t)i * Hd,
            sq, rk, rv);
        gemm_p(0, 0, x2, skvi, bskvi, kv, 2 * Hd, nullptr, M, 2 * Hd, Hd);
        star_attn_kernel<<<Bx * NHd, 256>>>(sq, kv, rk, rv, mask, satt);
        gemm_small8<<<(Hd * 32 + 255) / 256, 256>>>(satt, Hd,
            star_wo + (size_t)i * Hd * Hd, Hd, star_bo + (size_t)i * Hd,
            relay, Hd, Hd, Hd, 2);
    }

    // heads
    gather_ft_kernel<<<(Bx * 2 * Hd + 255) / 256, 256>>>(relay, x, positions, ft);
    gemm_small8<<<(3 * NHID * 32 + 255) / 256, 256>>>(ft, 2 * Hd, head_w1, 2 * Hd,
                                                      head_b1, hid, 3 * NHID,
                                                      3 * NHID, 2 * Hd, 1);
    head2_kernel<<<(3 * NOUT * 32 + 255) / 256, 256>>>(hid, head_w2, head_b2, out);
}

// round 8
// speedup vs baseline: 1.1487x; 1.1487x over previous
#include <cuda_runtime.h>
#include <cuda_bf16.h>
#include <math.h>
#include <stdint.h>

// ---------------- problem constants ----------------
#define Bx 8
#define Lx 1024
#define Hd 768
#define NHd 12
#define HDd 64
#define DI 3072
#define NLAYERS 2
#define NHID 1024
#define NOUT 5000
#define SCALE_ATT 0.125f
#define LEAKY 0.01f
#define ML (Bx*Lx)      // 8192

// ---------------- fp32 scratch ----------------
__device__ float g_x   [ML*Hd];
__device__ float g_qkv [ML*3*Hd];
__device__ float g_kv  [ML*2*Hd];
__device__ float g_ring[ML*Hd];
__device__ float g_relay[Bx*Hd];
__device__ float g_part[Bx*16*Hd];
__device__ float g_rk  [Bx*Hd];
__device__ float g_rv  [Bx*Hd];
__device__ float g_sq  [Bx*Hd];
__device__ float g_satt[Bx*Hd];
__device__ float g_ft  [Bx*2*Hd];
__device__ float g_hid [Bx*3*NHID];
__device__ int   g_mask[Bx*Lx];

// ---------------- bf16 2-plane scratch ----------------
__device__ __nv_bfloat16 g_x2  [ML*2*Hd];
__device__ __nv_bfloat16 g_h2  [ML*2*Hd];
__device__ __nv_bfloat16 g_att2[ML*2*Hd];
__device__ __nv_bfloat16 g_mid2[(size_t)ML*2*DI];
__device__ __nv_bfloat16 g_w1p [(size_t)NLAYERS*DI*2*Hd];
__device__ __nv_bfloat16 g_w2p [(size_t)NLAYERS*Hd*2*DI];
__device__ __nv_bfloat16 g_qkvp[(size_t)NLAYERS*3*Hd*2*Hd];
__device__ __nv_bfloat16 g_rop [(size_t)NLAYERS*Hd*2*Hd];
__device__ __nv_bfloat16 g_skvp[(size_t)NLAYERS*2*Hd*2*Hd];
__device__ float g_bqkv[NLAYERS*3*Hd];
__device__ float g_bskv[NLAYERS*2*Hd];

// ---------------- helpers ----------------
__device__ __forceinline__ uint32_t cvta_s(const void* p) {
    return (uint32_t)__cvta_generic_to_shared(p);
}
__device__ __forceinline__ void ldsm4(uint32_t* r, uint32_t addr) {
    asm volatile("ldmatrix.sync.aligned.m8n8.x4.shared.b16 {%0,%1,%2,%3}, [%4];\n"
                 : "=r"(r[0]), "=r"(r[1]), "=r"(r[2]), "=r"(r[3]) : "r"(addr));
}
__device__ __forceinline__ void mma16816(float* c, const uint32_t* a, const uint32_t* b) {
    asm volatile("mma.sync.aligned.m16n8k16.row.col.f32.bf16.bf16.f32 "
                 "{%0,%1,%2,%3},{%4,%5,%6,%7},{%8,%9},{%0,%1,%2,%3};\n"
                 : "+f"(c[0]), "+f"(c[1]), "+f"(c[2]), "+f"(c[3])
                 : "r"(a[0]), "r"(a[1]), "r"(a[2]), "r"(a[3]), "r"(b[0]), "r"(b[1]));
}
__device__ __forceinline__ void cp16(uint32_t s, const void* g) {
    asm volatile("cp.async.cg.shared.global [%0], [%1], 16;\n" :: "r"(s), "l"(g));
}
__device__ __forceinline__ void split_hl(float v, __nv_bfloat16& hi, __nv_bfloat16& lo) {
    hi = __float2bfloat16(v);
    lo = __float2bfloat16(v - __bfloat162float(hi));
}
__device__ __forceinline__ void plane_write1(__nv_bfloat16* base, size_t row, int C, int c, float v) {
    __nv_bfloat16 hi, lo; split_hl(v, hi, lo);
    __nv_bfloat16* p = base + row * (size_t)(2 * C) + 32 * (c >> 4) + (c & 15);
    p[0]  = hi;
    p[16] = lo;
}
__device__ __forceinline__ uint32_t sw128(uint32_t o) { return o ^ ((o >> 3) & 0x70); }

// =====================================================================
// Tensor-core GEMM, 128x128 CTA tile, warp tile 64x32 (2x4 warps),
// 3-stage cp.async pipeline, per-group upfront fragment loads.
//   C[M,N] = act(A@W^T + bias), fp32-exact via 3 bf16 products.
// =====================================================================
#define TB 16384                     // bytes per matrix per buffer
#define BUFB (2*TB)                  // bytes per buffer (A+B)
#define SMEM_G (3*BUFB)              // 96 KB

__device__ __forceinline__ void fill_tile(uint32_t base, const __nv_bfloat16* A2,
                                          const __nv_bfloat16* W2, int lda2, int ldw2,
                                          int bm, int bn, int kc, int tid)
{
#pragma unroll
    for (int j = 0; j < 4; j++) {
        int idx = tid + j * 256;
        int row = idx >> 3, c16 = idx & 7;
        uint32_t off = sw128((uint32_t)(row * 128 + c16 * 16));
        cp16(base + off,      A2 + (size_t)(bm + row) * lda2 + kc * 64 + c16 * 8);
        cp16(base + TB + off, W2 + (size_t)(bn + row) * ldw2 + kc * 64 + c16 * 8);
    }
}

template<int ACT, int OUTP>
__global__ __launch_bounds__(256, 2)
void gemm_tc2(const __nv_bfloat16* __restrict__ A2, int lda2,
              const __nv_bfloat16* __restrict__ W2, int ldw2,
              const float* __restrict__ bias,
              float* __restrict__ C, int ldc,
              __nv_bfloat16* __restrict__ C2, int Nout,
              int T)
{
    extern __shared__ __align__(128) char smraw[];
    const uint32_t sb = cvta_s(smraw);

    const int tid  = threadIdx.x;
    const int lane = tid & 31;
    const int warp = tid >> 5;
    const int wm = warp >> 2;
    const int wn = warp & 3;
    const int bm = blockIdx.y * 128;
    const int bn = blockIdx.x * 128;

    float acc[4][4][4];
#pragma unroll
    for (int i = 0; i < 4; i++)
#pragma unroll
        for (int j = 0; j < 4; j++)
#pragma unroll
            for (int c = 0; c < 4; c++) acc[i][j][c] = 0.f;

    const int a_row = lane & 15;
    const int a_kb  = (lane >> 4) * 16;
    const int b_row = (lane & 7) + ((lane >> 4) << 3);
    const int b_kb  = ((lane >> 3) & 1) * 16;

    // prologue: chunks 0,1 into buffers 0,1
    fill_tile(sb, A2, W2, lda2, ldw2, bm, bn, 0, tid);
    asm volatile("cp.async.commit_group;\n");
    fill_tile(sb + BUFB, A2, W2, lda2, ldw2, bm, bn, 1, tid);
    asm volatile("cp.async.commit_group;\n");

    int bc = 0, bf = 2;
    for (int t = 0; t < T; t++) {
        if (t == T - 1) asm volatile("cp.async.wait_group 0;\n");
        else            asm volatile("cp.async.wait_group 1;\n");
        __syncthreads();

        if (t + 2 < T) {
            fill_tile(sb + bf * BUFB, A2, W2, lda2, ldw2, bm, bn, t + 2, tid);
            asm volatile("cp.async.commit_group;\n");
            bf = (bf == 2) ? 0 : bf + 1;
        }

        const uint32_t ab = sb + bc * BUFB;
        const uint32_t bb = ab + TB;
        bc = (bc == 2) ? 0 : bc + 1;

#pragma unroll
        for (int g = 0; g < 2; g++) {
            uint32_t bh[2][4], afh[4][4], bl_[2][4], afl[4][4];
            // issue ALL group-g ldsm up front (independent, pipeline at struct floor);
            // order so phase-0 operands (bh, afh) land first.
#pragma unroll
            for (int p = 0; p < 2; p++) {
                int row = wn * 32 + p * 16 + b_row;
                ldsm4(bh[p], bb + sw128((uint32_t)(row * 128 + g * 64 + b_kb)));
            }
#pragma unroll
            for (int mt = 0; mt < 4; mt++) {
                int row = wm * 64 + mt * 16 + a_row;
                ldsm4(afh[mt], ab + sw128((uint32_t)(row * 128 + g * 64 + a_kb)));
            }
#pragma unroll
            for (int p = 0; p < 2; p++) {
                int row = wn * 32 + p * 16 + b_row;
                ldsm4(bl_[p], bb + sw128((uint32_t)(row * 128 + g * 64 + 32 + b_kb)));
            }
#pragma unroll
            for (int mt = 0; mt < 4; mt++) {
                int row = wm * 64 + mt * 16 + a_row;
                ldsm4(afl[mt], ab + sw128((uint32_t)(row * 128 + g * 64 + 32 + a_kb)));
            }
            // 48-mma stream: hi*hi, hi*lo, lo*hi
#pragma unroll
            for (int mt = 0; mt < 4; mt++)
#pragma unroll
                for (int nt = 0; nt < 4; nt++)
                    mma16816(acc[mt][nt], afh[mt], &bh[nt >> 1][(nt & 1) * 2]);
#pragma unroll
            for (int mt = 0; mt < 4; mt++)
#pragma unroll
                for (int nt = 0; nt < 4; nt++)
                    mma16816(acc[mt][nt], afh[mt], &bl_[nt >> 1][(nt & 1) * 2]);
#pragma unroll
            for (int mt = 0; mt < 4; mt++)
#pragma unroll
                for (int nt = 0; nt < 4; nt++)
                    mma16816(acc[mt][nt], afl[mt], &bh[nt >> 1][(nt & 1) * 2]);
        }
    }

    // epilogue
#pragma unroll
    for (int mt = 0; mt < 4; mt++) {
#pragma unroll
        for (int nt = 0; nt < 4; nt++) {
            int row = bm + wm * 64 + mt * 16 + (lane >> 2);
            int col = bn + wn * 32 + nt * 8 + (lane & 3) * 2;
            float bi0 = bias[col], bi1 = bias[col + 1];
            float v0 = acc[mt][nt][0] + bi0;
            float v1 = acc[mt][nt][1] + bi1;
            float v2 = acc[mt][nt][2] + bi0;
            float v3 = acc[mt][nt][3] + bi1;
            if (ACT == 1) {
                v0 = fmaxf(v0, 0.f); v1 = fmaxf(v1, 0.f);
                v2 = fmaxf(v2, 0.f); v3 = fmaxf(v3, 0.f);
            }
            if (OUTP == 0) {
                *(float2*)(C + (size_t)row * ldc + col)       = make_float2(v0, v1);
                *(float2*)(C + (size_t)(row + 8) * ldc + col) = make_float2(v2, v3);
            } else {
                int gg = col >> 4, off = col & 15;
                __nv_bfloat16 h0, h1, h2, h3, l0, l1, l2, l3;
                split_hl(v0, h0, l0); split_hl(v1, h1, l1);
                split_hl(v2, h2, l2); split_hl(v3, h3, l3);
                __nv_bfloat16* p0 = C2 + (size_t)row * (2 * Nout) + 32 * gg + off;
                __nv_bfloat16* p1 = C2 + (size_t)(row + 8) * (2 * Nout) + 32 * gg + off;
                *(__nv_bfloat162*)(p0)      = __halves2bfloat162(h0, h1);
                *(__nv_bfloat162*)(p0 + 16) = __halves2bfloat162(l0, l1);
                *(__nv_bfloat162*)(p1)      = __halves2bfloat162(h2, h3);
                *(__nv_bfloat162*)(p1 + 16) = __halves2bfloat162(l2, l3);
            }
        }
    }
}

static void gemm_p(int act, int outp,
                   const __nv_bfloat16* A2, const __nv_bfloat16* W2,
                   const float* bias, float* C, int ldc, __nv_bfloat16* C2,
                   int M, int N, int K)
{
    dim3 grid(N / 128, M / 128);
    int T = K / 32;
    if (outp == 1)      gemm_tc2<1, 1><<<grid, 256, SMEM_G>>>(A2, 2 * K, W2, 2 * K, bias, nullptr, 0, C2, N, T);
    else if (act == 1)  gemm_tc2<1, 0><<<grid, 256, SMEM_G>>>(A2, 2 * K, W2, 2 * K, bias, C, ldc, nullptr, N, T);
    else                gemm_tc2<0, 0><<<grid, 256, SMEM_G>>>(A2, 2 * K, W2, 2 * K, bias, C, ldc, nullptr, N, T);
}

// =====================================================================
// fused weight plane conversion
// =====================================================================
#define S1 1179648
#define S2 2359296
#define S3 2654208
#define S4 2949120
#define S5 3244032
#define S6 3538944
#define S7 3833856
#define S8 4128768

__global__ void cvt_all(const float* w1, const float* w2, const float* rq, const float* rk,
                        const float* rv, const float* ro, const float* sk, const float* sv,
                        __nv_bfloat16* o1, __nv_bfloat16* o2, __nv_bfloat16* oqkv,
                        __nv_bfloat16* oro, __nv_bfloat16* oskv)
{
    int i = blockIdx.x * blockDim.x + threadIdx.x;
    if (i >= S8) return;
    const float* in; __nv_bfloat16* out; int C, base, extra;
    if      (i < S1) { in = w1; out = o1;   C = Hd; base = 0;  extra = 0; }
    else if (i < S2) { in = w2; out = o2;   C = DI; base = S1; extra = 0; }
    else if (i < S3) { in = rq; out = oqkv;                        C = Hd; base = S2; extra = 1536; }
    else if (i < S4) { in = rk; out = oqkv + (size_t)768 * 2 * Hd; C = Hd; base = S3; extra = 1536; }
    else if (i < S5) { in = rv; out = oqkv + (size_t)1536 * 2 * Hd;C = Hd; base = S4; extra = 1536; }
    else if (i < S6) { in = ro; out = oro;  C = Hd; base = S5; extra = 0; }
    else if (i < S7) { in = sk; out = oskv;                        C = Hd; base = S6; extra = 768; }
    else             { in = sv; out = oskv + (size_t)768 * 2 * Hd; C = Hd; base = S7; extra = 768; }
    int e = (i - base) * 4;
    int r = e / C, c = e % C;
    size_t ro_ = (size_t)r + (size_t)(r / Hd) * extra;
    if (extra == 0 && C == DI) ro_ = r;
    float4 f = *(const float4*)(in + e);
    __nv_bfloat16 h0, h1, h2, h3, l0, l1, l2, l3;
    split_hl(f.x, h0, l0); split_hl(f.y, h1, l1);
    split_hl(f.z, h2, l2); split_hl(f.w, h3, l3);
    __nv_bfloat16* p = out + ro_ * (2 * C) + 32 * (c >> 4) + (c & 15);
    *(__nv_bfloat162*)(p)      = __halves2bfloat162(h0, h1);
    *(__nv_bfloat162*)(p + 2)  = __halves2bfloat162(h2, h3);
    *(__nv_bfloat162*)(p + 16) = __halves2bfloat162(l0, l1);
    *(__nv_bfloat162*)(p + 18) = __halves2bfloat162(l2, l3);
}

__global__ void concat_bias(const float* bq, const float* bk, const float* bv,
                            const float* sk, const float* sv,
                            float* oqkv, float* oskv)
{
    int i = blockIdx.x * blockDim.x + threadIdx.x;
    int n1 = NLAYERS * 3 * Hd;
    if (i < n1) {
        int layer = i / (3 * Hd), c = i % (3 * Hd);
        const float* s = (c < Hd) ? bq : (c < 2 * Hd) ? bk : bv;
        oqkv[i] = s[layer * Hd + (c % Hd)];
    } else if (i < n1 + NLAYERS * 2 * Hd) {
        int j = i - n1;
        int layer = j / (2 * Hd), c = j % (2 * Hd);
        const float* s = (c < Hd) ? sk : sv;
        oskv[j] = s[layer * Hd + (c % Hd)];
    }
}

// =====================================================================
// Small-M GEMMs (M=8)
// =====================================================================
__device__ __forceinline__ void smalldot8(const float* __restrict__ A, int lda,
                                          const float* __restrict__ wrow, int K,
                                          int lane, float* s)
{
    const float4* w4 = (const float4*)wrow;
    int K4 = K >> 2;
#pragma unroll
    for (int m = 0; m < 8; m++) s[m] = 0.f;
    for (int k = lane; k < K4; k += 32) {
        float4 w = w4[k];
#pragma unroll
        for (int m = 0; m < 8; m++) {
            float4 a = ((const float4*)(A + (size_t)m * lda))[k];
            s[m] += a.x * w.x + a.y * w.y + a.z * w.z + a.w * w.w;
        }
    }
#pragma unroll
    for (int m = 0; m < 8; m++)
#pragma unroll
        for (int o = 16; o; o >>= 1) s[m] += __shfl_xor_sync(0xffffffffu, s[m], o);
}

__global__ __launch_bounds__(256)
void gemm_small8(const float* __restrict__ A, int lda,
                 const float* __restrict__ W, int ldw,
                 const float* __restrict__ bias,
                 float* __restrict__ C, int ldc,
                 int N, int K, int act)
{
    int n = (blockIdx.x * blockDim.x + threadIdx.x) >> 5;
    int lane = threadIdx.x & 31;
    if (n >= N) return;
    float s[8];
    smalldot8(A, lda, W + (size_t)n * ldw, K, lane, s);
    if (lane == 0) {
        float bv = bias[n];
#pragma unroll
        for (int m = 0; m < 8; m++) {
            float v = s[m] + bv;
            if (act == 1) v = fmaxf(v, 0.f);
            else if (act == 2) v = v > 0.f ? v : LEAKY * v;
            C[(size_t)m * ldc + n] = v;
        }
    }
}

__global__ __launch_bounds__(256)
void gemm_rel2(const float* __restrict__ relay,
               const float* __restrict__ wk, const float* __restrict__ bk,
               const float* __restrict__ wv, const float* __restrict__ bv,
               float* __restrict__ rk, float* __restrict__ rv)
{
    int n = (blockIdx.x * blockDim.x + threadIdx.x) >> 5;
    int lane = threadIdx.x & 31;
    if (n >= 2 * Hd) return;
    int seg = n >= Hd, c = n - seg * Hd;
    const float* W = seg ? wv : wk;
    const float* B = seg ? bv : bk;
    float* C = seg ? rv : rk;
    float s[8];
    smalldot8(relay, Hd, W + (size_t)c * Hd, Hd, lane, s);
    if (lane == 0) {
        float bb = B[c];
#pragma unroll
        for (int m = 0; m < 8; m++) C[(size_t)m * Hd + c] = s[m] + bb;
    }
}

__global__ __launch_bounds__(256)
void gemm_rel3(const float* __restrict__ relay,
               const float* __restrict__ wq, const float* __restrict__ bq,
               const float* __restrict__ wk, const float* __restrict__ bk,
               const float* __restrict__ wv, const float* __restrict__ bv,
               float* __restrict__ sq, float* __restrict__ rk, float* __restrict__ rv)
{
    int n = (blockIdx.x * blockDim.x + threadIdx.x) >> 5;
    int lane = threadIdx.x & 31;
    if (n >= 3 * Hd) return;
    int seg = n / Hd, c = n % Hd;
    const float* W = (seg == 0) ? wq : (seg == 1) ? wk : wv;
    const float* B = (seg == 0) ? bq : (seg == 1) ? bk : bv;
    float* C = (seg == 0) ? sq : (seg == 1) ? rk : rv;
    float s[8];
    smalldot8(relay, Hd, W + (size_t)c * Hd, Hd, lane, s);
    if (lane == 0) {
        float bb = B[c];
#pragma unroll
        for (int m = 0; m < 8; m++) C[(size_t)m * Hd + c] = s[m] + bb;
    }
}

__global__ __launch_bounds__(256)
void head2_kernel(const float* __restrict__ hid,
                  const float* __restrict__ w2,
                  const float* __restrict__ b2,
                  float* __restrict__ out)
{
    int n = (blockIdx.x * blockDim.x + threadIdx.x) >> 5;
    int lane = threadIdx.x & 31;
    if (n >= 3 * NOUT) return;
    int j = n / NOUT, c = n % NOUT;
    float s[8];
    smalldot8(hid + j * NHID, 3 * NHID, w2 + (size_t)n * NHID, NHID, lane, s);
    if (lane == 0) {
        float bb = b2[n];
#pragma unroll
        for (int m = 0; m < 8; m++)
            out[((size_t)m * 3 + j) * NOUT + c] = s[m] + bb;
    }
}

// ---------------- block reductions ----------------
__device__ __forceinline__ float2 block_reduce_sum2(float a, float b)
{
    static __shared__ float sa[8], sb2[8];
    __syncthreads();
    int lane = threadIdx.x & 31, w = threadIdx.x >> 5;
#pragma unroll
    for (int o = 16; o; o >>= 1) {
        a += __shfl_xor_sync(0xffffffffu, a, o);
        b += __shfl_xor_sync(0xffffffffu, b, o);
    }
    if (lane == 0) { sa[w] = a; sb2[w] = b; }
    __syncthreads();
    if (w == 0) {
        a = lane < 8 ? sa[lane] : 0.f;
        b = lane < 8 ? sb2[lane] : 0.f;
#pragma unroll
        for (int o = 4; o; o >>= 1) {
            a += __shfl_xor_sync(0xffffffffu, a, o);
            b += __shfl_xor_sync(0xffffffffu, b, o);
        }
        if (lane == 0) { sa[0] = a; sb2[0] = b; }
    }
    __syncthreads();
    return make_float2(sa[0], sb2[0]);
}
__device__ __forceinline__ float block_reduce_max(float a)
{
    static __shared__ float sm[8];
    __syncthreads();
    int lane = threadIdx.x & 31, w = threadIdx.x >> 5;
#pragma unroll
    for (int o = 16; o; o >>= 1) a = fmaxf(a, __shfl_xor_sync(0xffffffffu, a, o));
    if (lane == 0) sm[w] = a;
    __syncthreads();
    if (w == 0) {
        a = lane < 8 ? sm[lane] : -1e30f;
#pragma unroll
        for (int o = 4; o; o >>= 1) a = fmaxf(a, __shfl_xor_sync(0xffffffffu, a, o));
        if (lane == 0) sm[0] = a;
    }
    __syncthreads();
    return sm[0];
}
__device__ __forceinline__ float block_reduce_sum(float a)
{
    static __shared__ float ss[8];
    __syncthreads();
    int lane = threadIdx.x & 31, w = threadIdx.x >> 5;
#pragma unroll
    for (int o = 16; o; o >>= 1) a += __shfl_xor_sync(0xffffffffu, a, o);
    if (lane == 0) ss[w] = a;
    __syncthreads();
    if (w == 0) {
        a = lane < 8 ? ss[lane] : 0.f;
#pragma unroll
        for (int o = 4; o; o >>= 1) a += __shfl_xor_sync(0xffffffffu, a, o);
        if (lane == 0) ss[0] = a;
    }
    __syncthreads();
    return ss[0];
}

// ---------------- embed + mask + planes ----------------
__global__ void embed_kernel(const int* __restrict__ src, const float* __restrict__ emb,
                             const float* __restrict__ pos, float* __restrict__ x,
                             __nv_bfloat16* __restrict__ x2, int* __restrict__ mask)
{
    int idx = blockIdx.x * blockDim.x + threadIdx.x;
    if (idx >= ML * Hd) return;
    int h = idx % Hd;
    int bl = idx / Hd;
    int l = bl % Lx;
    int w = h >> 8;
    int dd = h & 255;
    int tok = src[bl * 3 + w];
    float v = emb[tok * 256 + dd] + pos[l * Hd + h];
    x[idx] = v;
    plane_write1(x2, bl, Hd, h, v);
    if (h == 0) mask[bl] = (src[bl * 3] == 0) ? 1 : 0;
}

// ---------------- relay mean: 2-stage ----------------
__global__ void relay_part_kernel(const float* __restrict__ x, float* __restrict__ part)
{
    int h = blockIdx.x * 128 + threadIdx.x;
    int ch = blockIdx.y;
    int b = blockIdx.z;
    const float* p = x + (size_t)b * Lx * Hd + (size_t)ch * 64 * Hd + h;
    float s = 0.f;
#pragma unroll 8
    for (int l = 0; l < 64; l++) s += p[(size_t)l * Hd];
    part[((size_t)b * 16 + ch) * Hd + h] = s;
}
__global__ void relay_fin_kernel(const float* __restrict__ part, float* __restrict__ relay)
{
    int h = blockIdx.x * 128 + threadIdx.x;
    int b = blockIdx.y;
    float s = 0.f;
#pragma unroll
    for (int ch = 0; ch < 16; ch++) s += part[((size_t)b * 16 + ch) * Hd + h];
    relay[b * Hd + h] = s * (1.0f / Lx);
}

// ---------------- layernorm ----------------
template<int RES, int ACT, int MODE, int MASKED>
__global__ __launch_bounds__(256)
void ln_kernel(const float* __restrict__ x, const float* __restrict__ res,
               const float* __restrict__ g, const float* __restrict__ b,
               float* __restrict__ out, __nv_bfloat16* __restrict__ out2,
               const int* __restrict__ mask)
{
    int row = blockIdx.x;
    const float* xr = x + (size_t)row * Hd;
    const float* rr = RES ? res + (size_t)row * Hd : nullptr;
    int mrow = MASKED ? mask[row] : 0;
    float t[3];
    float s = 0.f, ss = 0.f;
#pragma unroll
    for (int j = 0; j < 3; j++) {
        int i = threadIdx.x + j * 256;
        float v = xr[i];
        if (RES) v += rr[i];
        t[j] = v;
        s += v; ss += v * v;
    }
    float2 r = block_reduce_sum2(s, ss);
    float mu = r.x * (1.0f / Hd);
    float var = r.y * (1.0f / Hd) - mu * mu;
    float rstd = rsqrtf(var + 1e-5f);
#pragma unroll
    for (int j = 0; j < 3; j++) {
        int i = threadIdx.x + j * 256;
        float v = (t[j] - mu) * rstd * g[i] + b[i];
        if (ACT == 2) v = v > 0.f ? v : LEAKY * v;
        if (MASKED && mrow) v = 0.f;
        if (MODE != 1) out[(size_t)row * Hd + i] = v;
        if (MODE != 0) plane_write1(out2, row, Hd, i, v);
    }
}

// ---------------- ring attention ----------------
__global__ __launch_bounds__(256)
void ring_attn_kernel(const float* __restrict__ qkv, const float* __restrict__ rk,
                      const float* __restrict__ rv, __nv_bfloat16* __restrict__ out2)
{
    int gw = (blockIdx.x * blockDim.x + threadIdx.x) >> 5;
    int lane = threadIdx.x & 31;
    int n = gw % NHd;
    int bl = gw / NHd;
    int l = bl % Lx;
    int b = bl / Lx;

    const float* qp = qkv + (size_t)bl * (3 * Hd) + n * HDd;
    float q0 = qp[lane * 2], q1 = qp[lane * 2 + 1];

    float s[4];
#pragma unroll
    for (int w = 0; w < 3; w++) {
        int ll = l - 1 + w;
        float d = 0.f;
        if (ll >= 0 && ll < Lx) {
            const float* kp = qkv + ((size_t)(b * Lx + ll)) * (3 * Hd) + Hd + n * HDd;
            d = q0 * kp[lane * 2] + q1 * kp[lane * 2 + 1];
        }
#pragma unroll
        for (int o = 16; o; o >>= 1) d += __shfl_xor_sync(0xffffffffu, d, o);
        s[w] = d * SCALE_ATT;
    }
    {
        const float* kp = rk + b * Hd + n * HDd;
        float d = q0 * kp[lane * 2] + q1 * kp[lane * 2 + 1];
#pragma unroll
        for (int o = 16; o; o >>= 1) d += __shfl_xor_sync(0xffffffffu, d, o);
        s[3] = d * SCALE_ATT;
    }
    float m = fmaxf(fmaxf(s[0], s[1]), fmaxf(s[2], s[3]));
    float e[4], se = 0.f;
#pragma unroll
    for (int w = 0; w < 4; w++) { e[w] = expf(s[w] - m); se += e[w]; }
    float inv = 1.0f / se;

    float o0 = 0.f, o1 = 0.f;
#pragma unroll
    for (int w = 0; w < 3; w++) {
        int ll = l - 1 + w;
        if (ll >= 0 && ll < Lx) {
            const float* vp = qkv + ((size_t)(b * Lx + ll)) * (3 * Hd) + 2 * Hd + n * HDd;
            float p = e[w] * inv;
            o0 += p * vp[lane * 2];
            o1 += p * vp[lane * 2 + 1];
        }
    }
    {
        const float* vp = rv + b * Hd + n * HDd;
        float p = e[3] * inv;
        o0 += p * vp[lane * 2];
        o1 += p * vp[lane * 2 + 1];
    }
    int c0 = n * HDd + lane * 2;
    int gg = c0 >> 4, off = c0 & 15;
    __nv_bfloat16 h0, h1, l0b, l1b;
    split_hl(o0, h0, l0b); split_hl(o1, h1, l1b);
    __nv_bfloat16* p = out2 + (size_t)bl * (2 * Hd) + 32 * gg + off;
    *(__nv_bfloat162*)(p)      = __halves2bfloat162(h0, h1);
    *(__nv_bfloat162*)(p + 16) = __halves2bfloat162(l0b, l1b);
}

// ---------------- star attention ----------------
__global__ __launch_bounds__(256)
void star_attn_kernel(const float* __restrict__ sq, const float* __restrict__ kv,
                      const float* __restrict__ rk, const float* __restrict__ rv,
                      const int* __restrict__ mask, float* __restrict__ out)
{
    __shared__ float qs[HDd];
    __shared__ float sc[Lx + 1];
    __shared__ float red[4 * HDd];

    int b = blockIdx.x / NHd;
    int n = blockIdx.x % NHd;
    int tid = threadIdx.x;

    if (tid < HDd) qs[tid] = sq[b * Hd + n * HDd + tid];
    __syncthreads();

    float lmax = -1e30f;
    for (int s = tid; s < Lx + 1; s += 256) {
        const float* kp = (s == 0) ? rk + b * Hd + n * HDd
                                   : kv + ((size_t)(b * Lx + s - 1)) * (2 * Hd) + n * HDd;
        float d = 0.f;
#pragma unroll
        for (int i = 0; i < HDd; i++) d += qs[i] * kp[i];
        d *= SCALE_ATT;
        if (s > 0 && mask[b * Lx + s - 1]) d = -1e30f;
        sc[s] = d;
        lmax = fmaxf(lmax, d);
    }
    float bmax = block_reduce_max(lmax);

    float lsum = 0.f;
    for (int s = tid; s < Lx + 1; s += 256) {
        float ev = expf(sc[s] - bmax);
        sc[s] = ev;
        lsum += ev;
    }
    float bsum = block_reduce_sum(lsum);

    int gg = tid >> 6;
    int dd = tid & 63;
    float acc = 0.f;
    for (int s = gg; s < Lx + 1; s += 4) {
        const float* vp = (s == 0) ? rv + b * Hd + n * HDd
                                   : kv + ((size_t)(b * Lx + s - 1)) * (2 * Hd) + Hd + n * HDd;
        acc += sc[s] * vp[dd];
    }
    red[gg * HDd + dd] = acc;
    __syncthreads();
    if (tid < HDd) {
        float r = red[tid] + red[HDd + tid] + red[2 * HDd + tid] + red[3 * HDd + tid];
        out[b * Hd + n * HDd + tid] = r / bsum;
    }
}

// ---------------- gather ft ----------------
__global__ void gather_ft_kernel(const float* __restrict__ relay, const float* __restrict__ nodes,
                                 const int* __restrict__ positions, float* __restrict__ ft)
{
    int idx = blockIdx.x * blockDim.x + threadIdx.x;
    if (idx >= Bx * 2 * Hd) return;
    int b = idx / (2 * Hd);
    int i = idx % (2 * Hd);
    float v;
    if (i < Hd) v = relay[b * Hd + i];
    else        v = nodes[((size_t)b * Lx + positions[b]) * Hd + (i - Hd)];
    ft[idx] = v;
}

// ---------------- launch ----------------
extern "C" void kernel_launch(void* const* d_in, const int* in_sizes, int n_in,
                              void* d_out, int out_size)
{
    const int*   src       = (const int*)  d_in[0];
    const int*   positions = (const int*)  d_in[1];
    const float* emb       = (const float*)d_in[2];
    const float* pos_table = (const float*)d_in[3];
    const float* norm_g    = (const float*)d_in[4];
    const float* norm_b    = (const float*)d_in[5];
    const float* pw_w1     = (const float*)d_in[6];
    const float* pw_b1     = (const float*)d_in[7];
    const float* pw_w2     = (const float*)d_in[8];
    const float* pw_b2     = (const float*)d_in[9];
    const float* pw_g      = (const float*)d_in[10];
    const float* pw_bn     = (const float*)d_in[11];
    const float* ring_wq   = (const float*)d_in[12];
    const float* ring_bq   = (const float*)d_in[13];
    const float* ring_wk   = (const float*)d_in[14];
    const float* ring_bk   = (const float*)d_in[15];
    const float* ring_wv   = (const float*)d_in[16];
    const float* ring_bv   = (const float*)d_in[17];
    const float* ring_wo   = (const float*)d_in[18];
    const float* ring_bo   = (const float*)d_in[19];
    const float* star_wq   = (const float*)d_in[20];
    const float* star_bq   = (const float*)d_in[21];
    const float* star_wk   = (const float*)d_in[22];
    const float* star_bk   = (const float*)d_in[23];
    const float* star_wv   = (const float*)d_in[24];
    const float* star_bv   = (const float*)d_in[25];
    const float* star_wo   = (const float*)d_in[26];
    const float* star_bo   = (const float*)d_in[27];
    const float* head_w1   = (const float*)d_in[28];
    const float* head_b1   = (const float*)d_in[29];
    const float* head_w2   = (const float*)d_in[30];
    const float* head_b2   = (const float*)d_in[31];
    float* out = (float*)d_out;

    cudaFuncSetAttribute(gemm_tc2<0, 0>, cudaFuncAttributeMaxDynamicSharedMemorySize, SMEM_G);
    cudaFuncSetAttribute(gemm_tc2<1, 0>, cudaFuncAttributeMaxDynamicSharedMemorySize, SMEM_G);
    cudaFuncSetAttribute(gemm_tc2<1, 1>, cudaFuncAttributeMaxDynamicSharedMemorySize, SMEM_G);

    float *x, *qkv, *kv, *ring, *relay, *part, *rk, *rv, *sq, *satt, *ft, *hid, *bqkv, *bskv;
    int* mask;
    __nv_bfloat16 *x2, *h2, *att2, *mid2;
    __nv_bfloat16 *w1p, *w2p, *qkvp, *rop, *skvp;
    cudaGetSymbolAddress((void**)&x, g_x);
    cudaGetSymbolAddress((void**)&qkv, g_qkv);
    cudaGetSymbolAddress((void**)&kv, g_kv);
    cudaGetSymbolAddress((void**)&ring, g_ring);
    cudaGetSymbolAddress((void**)&relay, g_relay);
    cudaGetSymbolAddress((void**)&part, g_part);
    cudaGetSymbolAddress((void**)&rk, g_rk);
    cudaGetSymbolAddress((void**)&rv, g_rv);
    cudaGetSymbolAddress((void**)&sq, g_sq);
    cudaGetSymbolAddress((void**)&satt, g_satt);
    cudaGetSymbolAddress((void**)&ft, g_ft);
    cudaGetSymbolAddress((void**)&hid, g_hid);
    cudaGetSymbolAddress((void**)&mask, g_mask);
    cudaGetSymbolAddress((void**)&x2, g_x2);
    cudaGetSymbolAddress((void**)&h2, g_h2);
    cudaGetSymbolAddress((void**)&att2, g_att2);
    cudaGetSymbolAddress((void**)&mid2, g_mid2);
    cudaGetSymbolAddress((void**)&w1p, g_w1p);
    cudaGetSymbolAddress((void**)&w2p, g_w2p);
    cudaGetSymbolAddress((void**)&qkvp, g_qkvp);
    cudaGetSymbolAddress((void**)&rop, g_rop);
    cudaGetSymbolAddress((void**)&skvp, g_skvp);
    cudaGetSymbolAddress((void**)&bqkv, g_bqkv);
    cudaGetSymbolAddress((void**)&bskv, g_bskv);

    const int M = ML;

    // launch order: index 3 (the ncu-profiled slot) = PWFF1 GEMM
    cvt_all<<<(S8 + 255) / 256, 256>>>(pw_w1, pw_w2, ring_wq, ring_wk, ring_wv, ring_wo,
                                       star_wk, star_wv, w1p, w2p, qkvp, rop, skvp);   // 0
    concat_bias<<<(NLAYERS * 5 * Hd + 255) / 256, 256>>>(ring_bq, ring_bk, ring_bv,
                                                          star_bk, star_bv, bqkv, bskv); // 1
    embed_kernel<<<(ML * Hd + 255) / 256, 256>>>(src, emb, pos_table, x, x2, mask);      // 2

    bool relay_done = false;
    for (int i = 0; i < NLAYERS; i++) {
        const float* b1 = pw_b1 + (size_t)i * DI;
        const float* b2 = pw_b2 + (size_t)i * Hd;
        const float* pg = pw_g + (size_t)i * Hd;
        const float* pb = pw_bn + (size_t)i * Hd;
        const float* rbk = ring_bk + (size_t)i * Hd;
        const float* rbv = ring_bv + (size_t)i * Hd;
        const float* rbo = ring_bo + (size_t)i * Hd;
        const float* ng = norm_g + (size_t)i * Hd;
        const float* nb = norm_b + (size_t)i * Hd;
        const float* rwk = ring_wk + (size_t)i * Hd * Hd;
        const float* rwv = ring_wv + (size_t)i * Hd * Hd;
        const __nv_bfloat16* w1i = w1p + (size_t)i * DI * 2 * Hd;
        const __nv_bfloat16* w2i = w2p + (size_t)i * Hd * 2 * DI;
        const __nv_bfloat16* qkvi = qkvp + (size_t)i * 3 * Hd * 2 * Hd;
        const __nv_bfloat16* roi = rop + (size_t)i * Hd * 2 * Hd;
        const __nv_bfloat16* skvi = skvp + (size_t)i * 2 * Hd * 2 * Hd;
        const float* bqkvi = bqkv + (size_t)i * 3 * Hd;
        const float* bskvi = bskv + (size_t)i * 2 * Hd;

        // PWFF (layer 0: launches 3,4 = big GEMMs; 3 is the profiled slot)
        gemm_p(1, 1, x2, w1i, b1, nullptr, 0, mid2, M, DI, Hd);
        gemm_p(0, 0, mid2, w2i, b2, ring, Hd, nullptr, M, Hd, DI);
        ln_kernel<1, 0, 1, 0><<<M, 256>>>(ring, x, pg, pb, nullptr, h2, nullptr);

        // relay mean (needs only x from embed; deferred to keep GEMM at index 3)
        if (!relay_done) {
            dim3 gp(6, 16, Bx);
            relay_part_kernel<<<gp, 128>>>(x, part);
            dim3 gf(6, Bx);
            relay_fin_kernel<<<gf, 128>>>(part, relay);
            relay_done = true;
        }

        // Ring attention
        gemm_p(0, 0, h2, qkvi, bqkvi, qkv, 3 * Hd, nullptr, M, 3 * Hd, Hd);
        gemm_rel2<<<(2 * Hd * 32 + 255) / 256, 256>>>(relay, rwk, rbk, rwv, rbv, rk, rv);
        ring_attn_kernel<<<(M * NHd) / 8, 256>>>(qkv, rk, rv, att2);
        gemm_p(0, 0, att2, roi, rbo, ring, Hd, nullptr, M, Hd, Hd);
        ln_kernel<0, 2, 2, 1><<<M, 256>>>(ring, nullptr, ng, nb, x, x2, mask);

        // Star attention
        gemm_rel3<<<(3 * Hd * 32 + 255) / 256, 256>>>(relay,
            star_wq + (size_t)i * Hd * Hd, star_bq + (size_t)i * Hd,
            star_wk + (size_t)i * Hd * Hd, star_bk + (size_t)i * Hd,
            star_wv + (size_t)i * Hd * Hd, star_bv + (size_t)i * Hd,
            sq, rk, rv);
        gemm_p(0, 0, x2, skvi, bskvi, kv, 2 * Hd, nullptr, M, 2 * Hd, Hd);
        star_attn_kernel<<<Bx * NHd, 256>>>(sq, kv, rk, rv, mask, satt);
        gemm_small8<<<(Hd * 32 + 255) / 256, 256>>>(satt, Hd,
            star_wo + (size_t)i * Hd * Hd, Hd, star_bo + (size_t)i * Hd,
            relay, Hd, Hd, Hd, 2);
    }

    // heads
    gather_ft_kernel<<<(Bx * 2 * Hd + 255) / 256, 256>>>(relay, x, positions, ft);
    gemm_small8<<<(3 * NHID * 32 + 255) / 256, 256>>>(ft, 2 * Hd, head_w1, 2 * Hd,
                                                      head_b1, hid, 3 * NHID,
                                                      3 * NHID, 2 * Hd, 1);
    head2_kernel<<<(3 * NOUT * 32 + 255) / 256, 256>>>(hid, head_w2, head_b2, out);
}

// round 9
// speedup vs baseline: 1.1670x; 1.0159x over previous
#include <cuda_runtime.h>
#include <cuda_fp16.h>
#include <math.h>
#include <stdint.h>

// ---------------- problem constants ----------------
#define Bx 8
#define Lx 1024
#define Hd 768
#define NHd 12
#define HDd 64
#define DI 3072
#define NLAYERS 2
#define NHID 1024
#define NOUT 5000
#define SCALE_ATT 0.125f
#define LEAKY 0.01f
#define ML (Bx*Lx)      // 8192

// ---------------- fp32 scratch ----------------
__device__ float g_x   [ML*Hd];
__device__ float g_qkv [ML*3*Hd];
__device__ float g_kv  [ML*2*Hd];
__device__ float g_ring[ML*Hd];
__device__ float g_relay[Bx*Hd];
__device__ float g_part[Bx*16*Hd];
__device__ float g_rk  [Bx*Hd];
__device__ float g_rv  [Bx*Hd];
__device__ float g_sq  [Bx*Hd];
__device__ float g_satt[Bx*Hd];
__device__ float g_ft  [Bx*2*Hd];
__device__ float g_hid [Bx*3*NHID];
__device__ int   g_mask[Bx*Lx];

// ---------------- fp16 2-plane scratch ----------------
// Per 16-fp32 k-group g: [32g..32g+16)=hi, [32g+16..32g+32)=lo. Row stride 2*K.
__device__ __half g_x2  [ML*2*Hd];
__device__ __half g_h2  [ML*2*Hd];
__device__ __half g_att2[ML*2*Hd];
__device__ __half g_mid2[(size_t)ML*2*DI];
__device__ __half g_w1p [(size_t)NLAYERS*DI*2*Hd];
__device__ __half g_w2p [(size_t)NLAYERS*Hd*2*DI];
__device__ __half g_qkvp[(size_t)NLAYERS*3*Hd*2*Hd];
__device__ __half g_rop [(size_t)NLAYERS*Hd*2*Hd];
__device__ __half g_skvp[(size_t)NLAYERS*2*Hd*2*Hd];
__device__ float g_bqkv[NLAYERS*3*Hd];
__device__ float g_bskv[NLAYERS*2*Hd];

// ---------------- helpers ----------------
__device__ __forceinline__ uint32_t cvta_s(const void* p) {
    return (uint32_t)__cvta_generic_to_shared(p);
}
__device__ __forceinline__ void ldsm4(uint32_t* r, uint32_t addr) {
    asm volatile("ldmatrix.sync.aligned.m8n8.x4.shared.b16 {%0,%1,%2,%3}, [%4];\n"
                 : "=r"(r[0]), "=r"(r[1]), "=r"(r[2]), "=r"(r[3]) : "r"(addr));
}
__device__ __forceinline__ void mma16816(float* c, const uint32_t* a, const uint32_t* b) {
    asm volatile("mma.sync.aligned.m16n8k16.row.col.f32.f16.f16.f32 "
                 "{%0,%1,%2,%3},{%4,%5,%6,%7},{%8,%9},{%0,%1,%2,%3};\n"
                 : "+f"(c[0]), "+f"(c[1]), "+f"(c[2]), "+f"(c[3])
                 : "r"(a[0]), "r"(a[1]), "r"(a[2]), "r"(a[3]), "r"(b[0]), "r"(b[1]));
}
__device__ __forceinline__ void cp16(uint32_t s, const void* g) {
    asm volatile("cp.async.cg.shared.global [%0], [%1], 16;\n" :: "r"(s), "l"(g));
}
__device__ __forceinline__ void split_hl(float v, __half& hi, __half& lo) {
    hi = __float2half_rn(v);
    lo = __float2half_rn(v - __half2float(hi));
}
__device__ __forceinline__ void plane_write1(__half* base, size_t row, int C, int c, float v) {
    __half hi, lo; split_hl(v, hi, lo);
    __half* p = base + row * (size_t)(2 * C) + 32 * (c >> 4) + (c & 15);
    p[0]  = hi;
    p[16] = lo;
}
__device__ __forceinline__ uint32_t sw128(uint32_t o) { return o ^ ((o >> 3) & 0x70); }

// =====================================================================
// Tensor-core GEMM, 128x128 CTA tile, warp tile 64x32 (2x4 warps),
// 3-stage cp.async pipeline, upfront fragment loads.
//   C[M,N] = act(A@W^T + bias) from fp16 hi/lo planes.
// NP = 3: Ah*Bh + Ah*Bl + Al*Bh (fp32-exact, err ~2^-22)
// NP = 2: Ah*Bh + Ah*Bl        (err ~1.4e-4 statistical)
// =====================================================================
#define TB 16384                     // bytes per matrix per buffer
#define BUFB (2*TB)                  // bytes per buffer (A+B)
#define SMEM_G (3*BUFB)              // 96 KB

__device__ __forceinline__ void fill_tile(uint32_t base, const __half* A2,
                                          const __half* W2, int lda2, int ldw2,
                                          int bm, int bn, int kc, int tid)
{
#pragma unroll
    for (int j = 0; j < 4; j++) {
        int idx = tid + j * 256;
        int row = idx >> 3, c16 = idx & 7;
        uint32_t off = sw128((uint32_t)(row * 128 + c16 * 16));
        cp16(base + off,      A2 + (size_t)(bm + row) * lda2 + kc * 64 + c16 * 8);
        cp16(base + TB + off, W2 + (size_t)(bn + row) * ldw2 + kc * 64 + c16 * 8);
    }
}

template<int ACT, int OUTP, int NP>
__global__ __launch_bounds__(256, 2)
void gemm_tc2(const __half* __restrict__ A2, int lda2,
              const __half* __restrict__ W2, int ldw2,
              const float* __restrict__ bias,
              float* __restrict__ C, int ldc,
              __half* __restrict__ C2, int Nout,
              int T)
{
    extern __shared__ __align__(128) char smraw[];
    const uint32_t sb = cvta_s(smraw);

    const int tid  = threadIdx.x;
    const int lane = tid & 31;
    const int warp = tid >> 5;
    const int wm = warp >> 2;
    const int wn = warp & 3;
    const int bm = blockIdx.y * 128;
    const int bn = blockIdx.x * 128;

    float acc[4][4][4];
#pragma unroll
    for (int i = 0; i < 4; i++)
#pragma unroll
        for (int j = 0; j < 4; j++)
#pragma unroll
            for (int c = 0; c < 4; c++) acc[i][j][c] = 0.f;

    const int a_row = lane & 15;
    const int a_kb  = (lane >> 4) * 16;
    const int b_row = (lane & 7) + ((lane >> 4) << 3);
    const int b_kb  = ((lane >> 3) & 1) * 16;

    // prologue: chunks 0,1 into buffers 0,1
    fill_tile(sb, A2, W2, lda2, ldw2, bm, bn, 0, tid);
    asm volatile("cp.async.commit_group;\n");
    fill_tile(sb + BUFB, A2, W2, lda2, ldw2, bm, bn, 1, tid);
    asm volatile("cp.async.commit_group;\n");

    int bc = 0, bf = 2;
    for (int t = 0; t < T; t++) {
        if (t == T - 1) asm volatile("cp.async.wait_group 0;\n");
        else            asm volatile("cp.async.wait_group 1;\n");
        __syncthreads();

        const uint32_t ab = sb + bc * BUFB;
        const uint32_t bb = ab + TB;
        bc = (bc == 2) ? 0 : bc + 1;

        // ---- group 0 fragment loads first (max lead time for mma deps) ----
        uint32_t bh0[2][4], afh0[4][4], bl0[2][4], afl0[4][4];
#pragma unroll
        for (int p = 0; p < 2; p++) {
            int row = wn * 32 + p * 16 + b_row;
            ldsm4(bh0[p], bb + sw128((uint32_t)(row * 128 + b_kb)));
        }
#pragma unroll
        for (int mt = 0; mt < 4; mt++) {
            int row = wm * 64 + mt * 16 + a_row;
            ldsm4(afh0[mt], ab + sw128((uint32_t)(row * 128 + a_kb)));
        }
#pragma unroll
        for (int p = 0; p < 2; p++) {
            int row = wn * 32 + p * 16 + b_row;
            ldsm4(bl0[p], bb + sw128((uint32_t)(row * 128 + 32 + b_kb)));
        }
        if (NP == 3) {
#pragma unroll
            for (int mt = 0; mt < 4; mt++) {
                int row = wm * 64 + mt * 16 + a_row;
                ldsm4(afl0[mt], ab + sw128((uint32_t)(row * 128 + 32 + a_kb)));
            }
        }

        // next-chunk fill issues while group-0 ldsm are in flight
        if (t + 2 < T) {
            fill_tile(sb + bf * BUFB, A2, W2, lda2, ldw2, bm, bn, t + 2, tid);
            asm volatile("cp.async.commit_group;\n");
            bf = (bf == 2) ? 0 : bf + 1;
        }

        // ---- group 0 mma ----
#pragma unroll
        for (int mt = 0; mt < 4; mt++)
#pragma unroll
            for (int nt = 0; nt < 4; nt++)
                mma16816(acc[mt][nt], afh0[mt], &bh0[nt >> 1][(nt & 1) * 2]);
#pragma unroll
        for (int mt = 0; mt < 4; mt++)
#pragma unroll
            for (int nt = 0; nt < 4; nt++)
                mma16816(acc[mt][nt], afh0[mt], &bl0[nt >> 1][(nt & 1) * 2]);
        if (NP == 3) {
#pragma unroll
            for (int mt = 0; mt < 4; mt++)
#pragma unroll
                for (int nt = 0; nt < 4; nt++)
                    mma16816(acc[mt][nt], afl0[mt], &bh0[nt >> 1][(nt & 1) * 2]);
        }

        // ---- group 1: loads then mma ----
        {
            uint32_t bh[2][4], afh[4][4], bl_[2][4], afl[4][4];
#pragma unroll
            for (int p = 0; p < 2; p++) {
                int row = wn * 32 + p * 16 + b_row;
                ldsm4(bh[p], bb + sw128((uint32_t)(row * 128 + 64 + b_kb)));
            }
#pragma unroll
            for (int mt = 0; mt < 4; mt++) {
                int row = wm * 64 + mt * 16 + a_row;
                ldsm4(afh[mt], ab + sw128((uint32_t)(row * 128 + 64 + a_kb)));
            }
#pragma unroll
            for (int p = 0; p < 2; p++) {
                int row = wn * 32 + p * 16 + b_row;
                ldsm4(bl_[p], bb + sw128((uint32_t)(row * 128 + 96 + b_kb)));
            }
            if (NP == 3) {
#pragma unroll
                for (int mt = 0; mt < 4; mt++) {
                    int row = wm * 64 + mt * 16 + a_row;
                    ldsm4(afl[mt], ab + sw128((uint32_t)(row * 128 + 96 + a_kb)));
                }
            }
#pragma unroll
            for (int mt = 0; mt < 4; mt++)
#pragma unroll
                for (int nt = 0; nt < 4; nt++)
                    mma16816(acc[mt][nt], afh[mt], &bh[nt >> 1][(nt & 1) * 2]);
#pragma unroll
            for (int mt = 0; mt < 4; mt++)
#pragma unroll
                for (int nt = 0; nt < 4; nt++)
                    mma16816(acc[mt][nt], afh[mt], &bl_[nt >> 1][(nt & 1) * 2]);
            if (NP == 3) {
#pragma unroll
                for (int mt = 0; mt < 4; mt++)
#pragma unroll
                    for (int nt = 0; nt < 4; nt++)
                        mma16816(acc[mt][nt], afl[mt], &bh[nt >> 1][(nt & 1) * 2]);
            }
        }
    }

    // epilogue
#pragma unroll
    for (int mt = 0; mt < 4; mt++) {
#pragma unroll
        for (int nt = 0; nt < 4; nt++) {
            int row = bm + wm * 64 + mt * 16 + (lane >> 2);
            int col = bn + wn * 32 + nt * 8 + (lane & 3) * 2;
            float bi0 = bias[col], bi1 = bias[col + 1];
            float v0 = acc[mt][nt][0] + bi0;
            float v1 = acc[mt][nt][1] + bi1;
            float v2 = acc[mt][nt][2] + bi0;
            float v3 = acc[mt][nt][3] + bi1;
            if (ACT == 1) {
                v0 = fmaxf(v0, 0.f); v1 = fmaxf(v1, 0.f);
                v2 = fmaxf(v2, 0.f); v3 = fmaxf(v3, 0.f);
            }
            if (OUTP == 0) {
                *(float2*)(C + (size_t)row * ldc + col)       = make_float2(v0, v1);
                *(float2*)(C + (size_t)(row + 8) * ldc + col) = make_float2(v2, v3);
            } else {
                int gg = col >> 4, off = col & 15;
                __half h0, h1, h2, h3, l0, l1, l2, l3;
                split_hl(v0, h0, l0); split_hl(v1, h1, l1);
                split_hl(v2, h2, l2); split_hl(v3, h3, l3);
                __half* p0 = C2 + (size_t)row * (2 * Nout) + 32 * gg + off;
                __half* p1 = C2 + (size_t)(row + 8) * (2 * Nout) + 32 * gg + off;
                *(__half2*)(p0)      = __halves2half2(h0, h1);
                *(__half2*)(p0 + 16) = __halves2half2(l0, l1);
                *(__half2*)(p1)      = __halves2half2(h2, h3);
                *(__half2*)(p1 + 16) = __halves2half2(l2, l3);
            }
        }
    }
}

static void gemm_p(int act, int outp, int np,
                   const __half* A2, const __half* W2,
                   const float* bias, float* C, int ldc, __half* C2,
                   int M, int N, int K)
{
    dim3 grid(N / 128, M / 128);
    int T = K / 32;
    if (outp == 1)      gemm_tc2<1, 1, 3><<<grid, 256, SMEM_G>>>(A2, 2 * K, W2, 2 * K, bias, nullptr, 0, C2, N, T);
    else if (np == 2)   gemm_tc2<0, 0, 2><<<grid, 256, SMEM_G>>>(A2, 2 * K, W2, 2 * K, bias, C, ldc, nullptr, N, T);
    else                gemm_tc2<0, 0, 3><<<grid, 256, SMEM_G>>>(A2, 2 * K, W2, 2 * K, bias, C, ldc, nullptr, N, T);
}

// =====================================================================
// fused weight plane conversion
// =====================================================================
#define S1 1179648
#define S2 2359296
#define S3 2654208
#define S4 2949120
#define S5 3244032
#define S6 3538944
#define S7 3833856
#define S8 4128768

__global__ void cvt_all(const float* w1, const float* w2, const float* rq, const float* rk,
                        const float* rv, const float* ro, const float* sk, const float* sv,
                        __half* o1, __half* o2, __half* oqkv,
                        __half* oro, __half* oskv)
{
    int i = blockIdx.x * blockDim.x + threadIdx.x;
    if (i >= S8) return;
    const float* in; __half* out; int C, base, extra;
    if      (i < S1) { in = w1; out = o1;   C = Hd; base = 0;  extra = 0; }
    else if (i < S2) { in = w2; out = o2;   C = DI; base = S1; extra = 0; }
    else if (i < S3) { in = rq; out = oqkv;                        C = Hd; base = S2; extra = 1536; }
    else if (i < S4) { in = rk; out = oqkv + (size_t)768 * 2 * Hd; C = Hd; base = S3; extra = 1536; }
    else if (i < S5) { in = rv; out = oqkv + (size_t)1536 * 2 * Hd;C = Hd; base = S4; extra = 1536; }
    else if (i < S6) { in = ro; out = oro;  C = Hd; base = S5; extra = 0; }
    else if (i < S7) { in = sk; out = oskv;                        C = Hd; base = S6; extra = 768; }
    else             { in = sv; out = oskv + (size_t)768 * 2 * Hd; C = Hd; base = S7; extra = 768; }
    int e = (i - base) * 4;
    int r = e / C, c = e % C;
    size_t ro_ = (size_t)r + (size_t)(r / Hd) * extra;
    if (extra == 0 && C == DI) ro_ = r;
    float4 f = *(const float4*)(in + e);
    __half h0, h1, h2, h3, l0, l1, l2, l3;
    split_hl(f.x, h0, l0); split_hl(f.y, h1, l1);
    split_hl(f.z, h2, l2); split_hl(f.w, h3, l3);
    __half* p = out + ro_ * (2 * C) + 32 * (c >> 4) + (c & 15);
    *(__half2*)(p)      = __halves2half2(h0, h1);
    *(__half2*)(p + 2)  = __halves2half2(h2, h3);
    *(__half2*)(p + 16) = __halves2half2(l0, l1);
    *(__half2*)(p + 18) = __halves2half2(l2, l3);
}

__global__ void concat_bias(const float* bq, const float* bk, const float* bv,
                            const float* sk, const float* sv,
                            float* oqkv, float* oskv)
{
    int i = blockIdx.x * blockDim.x + threadIdx.x;
    int n1 = NLAYERS * 3 * Hd;
    if (i < n1) {
        int layer = i / (3 * Hd), c = i % (3 * Hd);
        const float* s = (c < Hd) ? bq : (c < 2 * Hd) ? bk : bv;
        oqkv[i] = s[layer * Hd + (c % Hd)];
    } else if (i < n1 + NLAYERS * 2 * Hd) {
        int j = i - n1;
        int layer = j / (2 * Hd), c = j % (2 * Hd);
        const float* s = (c < Hd) ? sk : sv;
        oskv[j] = s[layer * Hd + (c % Hd)];
    }
}

// =====================================================================
// Small-M GEMMs (M=8)
// =====================================================================
__device__ __forceinline__ void smalldot8(const float* __restrict__ A, int lda,
                                          const float* __restrict__ wrow, int K,
                                          int lane, float* s)
{
    const float4* w4 = (const float4*)wrow;
    int K4 = K >> 2;
#pragma unroll
    for (int m = 0; m < 8; m++) s[m] = 0.f;
    for (int k = lane; k < K4; k += 32) {
        float4 w = w4[k];
#pragma unroll
        for (int m = 0; m < 8; m++) {
            float4 a = ((const float4*)(A + (size_t)m * lda))[k];
            s[m] += a.x * w.x + a.y * w.y + a.z * w.z + a.w * w.w;
        }
    }
#pragma unroll
    for (int m = 0; m < 8; m++)
#pragma unroll
        for (int o = 16; o; o >>= 1) s[m] += __shfl_xor_sync(0xffffffffu, s[m], o);
}

__global__ __launch_bounds__(256)
void gemm_small8(const float* __restrict__ A, int lda,
                 const float* __restrict__ W, int ldw,
                 const float* __restrict__ bias,
                 float* __restrict__ C, int ldc,
                 int N, int K, int act)
{
    int n = (blockIdx.x * blockDim.x + threadIdx.x) >> 5;
    int lane = threadIdx.x & 31;
    if (n >= N) return;
    float s[8];
    smalldot8(A, lda, W + (size_t)n * ldw, K, lane, s);
    if (lane == 0) {
        float bv = bias[n];
#pragma unroll
        for (int m = 0; m < 8; m++) {
            float v = s[m] + bv;
            if (act == 1) v = fmaxf(v, 0.f);
            else if (act == 2) v = v > 0.f ? v : LEAKY * v;
            C[(size_t)m * ldc + n] = v;
        }
    }
}

__global__ __launch_bounds__(256)
void gemm_rel2(const float* __restrict__ relay,
               const float* __restrict__ wk, const float* __restrict__ bk,
               const float* __restrict__ wv, const float* __restrict__ bv,
               float* __restrict__ rk, float* __restrict__ rv)
{
    int n = (blockIdx.x * blockDim.x + threadIdx.x) >> 5;
    int lane = threadIdx.x & 31;
    if (n >= 2 * Hd) return;
    int seg = n >= Hd, c = n - seg * Hd;
    const float* W = seg ? wv : wk;
    const float* B = seg ? bv : bk;
    float* C = seg ? rv : rk;
    float s[8];
    smalldot8(relay, Hd, W + (size_t)c * Hd, Hd, lane, s);
    if (lane == 0) {
        float bb = B[c];
#pragma unroll
        for (int m = 0; m < 8; m++) C[(size_t)m * Hd + c] = s[m] + bb;
    }
}

__global__ __launch_bounds__(256)
void gemm_rel3(const float* __restrict__ relay,
               const float* __restrict__ wq, const float* __restrict__ bq,
               const float* __restrict__ wk, const float* __restrict__ bk,
               const float* __restrict__ wv, const float* __restrict__ bv,
               float* __restrict__ sq, float* __restrict__ rk, float* __restrict__ rv)
{
    int n = (blockIdx.x * blockDim.x + threadIdx.x) >> 5;
    int lane = threadIdx.x & 31;
    if (n >= 3 * Hd) return;
    int seg = n / Hd, c = n % Hd;
    const float* W = (seg == 0) ? wq : (seg == 1) ? wk : wv;
    const float* B = (seg == 0) ? bq : (seg == 1) ? bk : bv;
    float* C = (seg == 0) ? sq : (seg == 1) ? rk : rv;
    float s[8];
    smalldot8(relay, Hd, W + (size_t)c * Hd, Hd, lane, s);
    if (lane == 0) {
        float bb = B[c];
#pragma unroll
        for (int m = 0; m < 8; m++) C[(size_t)m * Hd + c] = s[m] + bb;
    }
}

__global__ __launch_bounds__(256)
void head2_kernel(const float* __restrict__ hid,
                  const float* __restrict__ w2,
                  const float* __restrict__ b2,
                  float* __restrict__ out)
{
    int n = (blockIdx.x * blockDim.x + threadIdx.x) >> 5;
    int lane = threadIdx.x & 31;
    if (n >= 3 * NOUT) return;
    int j = n / NOUT, c = n % NOUT;
    float s[8];
    smalldot8(hid + j * NHID, 3 * NHID, w2 + (size_t)n * NHID, NHID, lane, s);
    if (lane == 0) {
        float bb = b2[n];
#pragma unroll
        for (int m = 0; m < 8; m++)
            out[((size_t)m * 3 + j) * NOUT + c] = s[m] + bb;
    }
}

// ---------------- block reductions ----------------
__device__ __forceinline__ float2 block_reduce_sum2(float a, float b)
{
    static __shared__ float sa[8], sb2[8];
    __syncthreads();
    int lane = threadIdx.x & 31, w = threadIdx.x >> 5;
#pragma unroll
    for (int o = 16; o; o >>= 1) {
        a += __shfl_xor_sync(0xffffffffu, a, o);
        b += __shfl_xor_sync(0xffffffffu, b, o);
    }
    if (lane == 0) { sa[w] = a; sb2[w] = b; }
    __syncthreads();
    if (w == 0) {
        a = lane < 8 ? sa[lane] : 0.f;
        b = lane < 8 ? sb2[lane] : 0.f;
#pragma unroll
        for (int o = 4; o; o >>= 1) {
            a += __shfl_xor_sync(0xffffffffu, a, o);
            b += __shfl_xor_sync(0xffffffffu, b, o);
        }
        if (lane == 0) { sa[0] = a; sb2[0] = b; }
    }
    __syncthreads();
    return make_float2(sa[0], sb2[0]);
}
__device__ __forceinline__ float block_reduce_max(float a)
{
    static __shared__ float sm[8];
    __syncthreads();
    int lane = threadIdx.x & 31, w = threadIdx.x >> 5;
#pragma unroll
    for (int o = 16; o; o >>= 1) a = fmaxf(a, __shfl_xor_sync(0xffffffffu, a, o));
    if (lane == 0) sm[w] = a;
    __syncthreads();
    if (w == 0) {
        a = lane < 8 ? sm[lane] : -1e30f;
#pragma unroll
        for (int o = 4; o; o >>= 1) a = fmaxf(a, __shfl_xor_sync(0xffffffffu, a, o));
        if (lane == 0) sm[0] = a;
    }
    __syncthreads();
    return sm[0];
}
__device__ __forceinline__ float block_reduce_sum(float a)
{
    static __shared__ float ss[8];
    __syncthreads();
    int lane = threadIdx.x & 31, w = threadIdx.x >> 5;
#pragma unroll
    for (int o = 16; o; o >>= 1) a += __shfl_xor_sync(0xffffffffu, a, o);
    if (lane == 0) ss[w] = a;
    __syncthreads();
    if (w == 0) {
        a = lane < 8 ? ss[lane] : 0.f;
#pragma unroll
        for (int o = 4; o; o >>= 1) a += __shfl_xor_sync(0xffffffffu, a, o);
        if (lane == 0) ss[0] = a;
    }
    __syncthreads();
    return ss[0];
}

// ---------------- embed + mask + planes ----------------
__global__ void embed_kernel(const int* __restrict__ src, const float* __restrict__ emb,
                             const float* __restrict__ pos, float* __restrict__ x,
                             __half* __restrict__ x2, int* __restrict__ mask)
{
    int idx = blockIdx.x * blockDim.x + threadIdx.x;
    if (idx >= ML * Hd) return;
    int h = idx % Hd;
    int bl = idx / Hd;
    int l = bl % Lx;
    int w = h >> 8;
    int dd = h & 255;
    int tok = src[bl * 3 + w];
    float v = emb[tok * 256 + dd] + pos[l * Hd + h];
    x[idx] = v;
    plane_write1(x2, bl, Hd, h, v);
    if (h == 0) mask[bl] = (src[bl * 3] == 0) ? 1 : 0;
}

// ---------------- relay mean: 2-stage ----------------
__global__ void relay_part_kernel(const float* __restrict__ x, float* __restrict__ part)
{
    int h = blockIdx.x * 128 + threadIdx.x;
    int ch = blockIdx.y;
    int b = blockIdx.z;
    const float* p = x + (size_t)b * Lx * Hd + (size_t)ch * 64 * Hd + h;
    float s = 0.f;
#pragma unroll 8
    for (int l = 0; l < 64; l++) s += p[(size_t)l * Hd];
    part[((size_t)b * 16 + ch) * Hd + h] = s;
}
__global__ void relay_fin_kernel(const float* __restrict__ part, float* __restrict__ relay)
{
    int h = blockIdx.x * 128 + threadIdx.x;
    int b = blockIdx.y;
    float s = 0.f;
#pragma unroll
    for (int ch = 0; ch < 16; ch++) s += part[((size_t)b * 16 + ch) * Hd + h];
    relay[b * Hd + h] = s * (1.0f / Lx);
}

// ---------------- layernorm ----------------
template<int RES, int ACT, int MODE, int MASKED>
__global__ __launch_bounds__(256)
void ln_kernel(const float* __restrict__ x, const float* __restrict__ res,
               const float* __restrict__ g, const float* __restrict__ b,
               float* __restrict__ out, __half* __restrict__ out2,
               const int* __restrict__ mask)
{
    int row = blockIdx.x;
    const float* xr = x + (size_t)row * Hd;
    const float* rr = RES ? res + (size_t)row * Hd : nullptr;
    int mrow = MASKED ? mask[row] : 0;
    float t[3];
    float s = 0.f, ss = 0.f;
#pragma unroll
    for (int j = 0; j < 3; j++) {
        int i = threadIdx.x + j * 256;
        float v = xr[i];
        if (RES) v += rr[i];
        t[j] = v;
        s += v; ss += v * v;
    }
    float2 r = block_reduce_sum2(s, ss);
    float mu = r.x * (1.0f / Hd);
    float var = r.y * (1.0f / Hd) - mu * mu;
    float rstd = rsqrtf(var + 1e-5f);
#pragma unroll
    for (int j = 0; j < 3; j++) {
        int i = threadIdx.x + j * 256;
        float v = (t[j] - mu) * rstd * g[i] + b[i];
        if (ACT == 2) v = v > 0.f ? v : LEAKY * v;
        if (MASKED && mrow) v = 0.f;
        if (MODE != 1) out[(size_t)row * Hd + i] = v;
        if (MODE != 0) plane_write1(out2, row, Hd, i, v);
    }
}

// ---------------- ring attention ----------------
__global__ __launch_bounds__(256)
void ring_attn_kernel(const float* __restrict__ qkv, const float* __restrict__ rk,
                      const float* __restrict__ rv, __half* __restrict__ out2)
{
    int gw = (blockIdx.x * blockDim.x + threadIdx.x) >> 5;
    int lane = threadIdx.x & 31;
    int n = gw % NHd;
    int bl = gw / NHd;
    int l = bl % Lx;
    int b = bl / Lx;

    const float* qp = qkv + (size_t)bl * (3 * Hd) + n * HDd;
    float q0 = qp[lane * 2], q1 = qp[lane * 2 + 1];

    float s[4];
#pragma unroll
    for (int w = 0; w < 3; w++) {
        int ll = l - 1 + w;
        float d = 0.f;
        if (ll >= 0 && ll < Lx) {
            const float* kp = qkv + ((size_t)(b * Lx + ll)) * (3 * Hd) + Hd + n * HDd;
            d = q0 * kp[lane * 2] + q1 * kp[lane * 2 + 1];
        }
#pragma unroll
        for (int o = 16; o; o >>= 1) d += __shfl_xor_sync(0xffffffffu, d, o);
        s[w] = d * SCALE_ATT;
    }
    {
        const float* kp = rk + b * Hd + n * HDd;
        float d = q0 * kp[lane * 2] + q1 * kp[lane * 2 + 1];
#pragma unroll
        for (int o = 16; o; o >>= 1) d += __shfl_xor_sync(0xffffffffu, d, o);
        s[3] = d * SCALE_ATT;
    }
    float m = fmaxf(fmaxf(s[0], s[1]), fmaxf(s[2], s[3]));
    float e[4], se = 0.f;
#pragma unroll
    for (int w = 0; w < 4; w++) { e[w] = expf(s[w] - m); se += e[w]; }
    float inv = 1.0f / se;

    float o0 = 0.f, o1 = 0.f;
#pragma unroll
    for (int w = 0; w < 3; w++) {
        int ll = l - 1 + w;
        if (ll >= 0 && ll < Lx) {
            const float* vp = qkv + ((size_t)(b * Lx + ll)) * (3 * Hd) + 2 * Hd + n * HDd;
            float p = e[w] * inv;
            o0 += p * vp[lane * 2];
            o1 += p * vp[lane * 2 + 1];
        }
    }
    {
        const float* vp = rv + b * Hd + n * HDd;
        float p = e[3] * inv;
        o0 += p * vp[lane * 2];
        o1 += p * vp[lane * 2 + 1];
    }
    int c0 = n * HDd + lane * 2;
    int gg = c0 >> 4, off = c0 & 15;
    __half h0, h1, l0b, l1b;
    split_hl(o0, h0, l0b); split_hl(o1, h1, l1b);
    __half* p = out2 + (size_t)bl * (2 * Hd) + 32 * gg + off;
    *(__half2*)(p)      = __halves2half2(h0, h1);
    *(__half2*)(p + 16) = __halves2half2(l0b, l1b);
}

// ---------------- star attention ----------------
__global__ __launch_bounds__(256)
void star_attn_kernel(const float* __restrict__ sq, const float* __restrict__ kv,
                      const float* __restrict__ rk, const float* __restrict__ rv,
                      const int* __restrict__ mask, float* __restrict__ out)
{
    __shared__ float qs[HDd];
    __shared__ float sc[Lx + 1];
    __shared__ float red[4 * HDd];

    int b = blockIdx.x / NHd;
    int n = blockIdx.x % NHd;
    int tid = threadIdx.x;

    if (tid < HDd) qs[tid] = sq[b * Hd + n * HDd + tid];
    __syncthreads();

    float lmax = -1e30f;
    for (int s = tid; s < Lx + 1; s += 256) {
        const float* kp = (s == 0) ? rk + b * Hd + n * HDd
                                   : kv + ((size_t)(b * Lx + s - 1)) * (2 * Hd) + n * HDd;
        float d = 0.f;
#pragma unroll
        for (int i = 0; i < HDd; i++) d += qs[i] * kp[i];
        d *= SCALE_ATT;
        if (s > 0 && mask[b * Lx + s - 1]) d = -1e30f;
        sc[s] = d;
        lmax = fmaxf(lmax, d);
    }
    float bmax = block_reduce_max(lmax);

    float lsum = 0.f;
    for (int s = tid; s < Lx + 1; s += 256) {
        float ev = expf(sc[s] - bmax);
        sc[s] = ev;
        lsum += ev;
    }
    float bsum = block_reduce_sum(lsum);

    int gg = tid >> 6;
    int dd = tid & 63;
    float acc = 0.f;
    for (int s = gg; s < Lx + 1; s += 4) {
        const float* vp = (s == 0) ? rv + b * Hd + n * HDd
                                   : kv + ((size_t)(b * Lx + s - 1)) * (2 * Hd) + Hd + n * HDd;
        acc += sc[s] * vp[dd];
    }
    red[gg * HDd + dd] = acc;
    __syncthreads();
    if (tid < HDd) {
        float r = red[tid] + red[HDd + tid] + red[2 * HDd + tid] + red[3 * HDd + tid];
        out[b * Hd + n * HDd + tid] = r / bsum;
    }
}

// ---------------- gather ft ----------------
__global__ void gather_ft_kernel(const float* __restrict__ relay, const float* __restrict__ nodes,
                                 const int* __restrict__ positions, float* __restrict__ ft)
{
    int idx = blockIdx.x * blockDim.x + threadIdx.x;
    if (idx >= Bx * 2 * Hd) return;
    int b = idx / (2 * Hd);
    int i = idx % (2 * Hd);
    float v;
    if (i < Hd) v = relay[b * Hd + i];
    else        v = nodes[((size_t)b * Lx + positions[b]) * Hd + (i - Hd)];
    ft[idx] = v;
}

// ---------------- launch ----------------
extern "C" void kernel_launch(void* const* d_in, const int* in_sizes, int n_in,
                              void* d_out, int out_size)
{
    const int*   src       = (const int*)  d_in[0];
    const int*   positions = (const int*)  d_in[1];
    const float* emb       = (const float*)d_in[2];
    const float* pos_table = (const float*)d_in[3];
    const float* norm_g    = (const float*)d_in[4];
    const float* norm_b    = (const float*)d_in[5];
    const float* pw_w1     = (const float*)d_in[6];
    const float* pw_b1     = (const float*)d_in[7];
    const float* pw_w2     = (const float*)d_in[8];
    const float* pw_b2     = (const float*)d_in[9];
    const float* pw_g      = (const float*)d_in[10];
    const float* pw_bn     = (const float*)d_in[11];
    const float* ring_wq   = (const float*)d_in[12];
    const float* ring_bq   = (const float*)d_in[13];
    const float* ring_wk   = (const float*)d_in[14];
    const float* ring_bk   = (const float*)d_in[15];
    const float* ring_wv   = (const float*)d_in[16];
    const float* ring_bv   = (const float*)d_in[17];
    const float* ring_wo   = (const float*)d_in[18];
    const float* ring_bo   = (const float*)d_in[19];
    const float* star_wq   = (const float*)d_in[20];
    const float* star_bq   = (const float*)d_in[21];
    const float* star_wk   = (const float*)d_in[22];
    const float* star_bk   = (const float*)d_in[23];
    const float* star_wv   = (const float*)d_in[24];
    const float* star_bv   = (const float*)d_in[25];
    const float* star_wo   = (const float*)d_in[26];
    const float* star_bo   = (const float*)d_in[27];
    const float* head_w1   = (const float*)d_in[28];
    const float* head_b1   = (const float*)d_in[29];
    const float* head_w2   = (const float*)d_in[30];
    const float* head_b2   = (const float*)d_in[31];
    float* out = (float*)d_out;

    cudaFuncSetAttribute(gemm_tc2<0, 0, 3>, cudaFuncAttributeMaxDynamicSharedMemorySize, SMEM_G);
    cudaFuncSetAttribute(gemm_tc2<0, 0, 2>, cudaFuncAttributeMaxDynamicSharedMemorySize, SMEM_G);
    cudaFuncSetAttribute(gemm_tc2<1, 1, 3>, cudaFuncAttributeMaxDynamicSharedMemorySize, SMEM_G);

    float *x, *qkv, *kv, *ring, *relay, *part, *rk, *rv, *sq, *satt, *ft, *hid, *bqkv, *bskv;
    int* mask;
    __half *x2, *h2, *att2, *mid2;
    __half *w1p, *w2p, *qkvp, *rop, *skvp;
    cudaGetSymbolAddress((void**)&x, g_x);
    cudaGetSymbolAddress((void**)&qkv, g_qkv);
    cudaGetSymbolAddress((void**)&kv, g_kv);
    cudaGetSymbolAddress((void**)&ring, g_ring);
    cudaGetSymbolAddress((void**)&relay, g_relay);
    cudaGetSymbolAddress((void**)&part, g_part);
    cudaGetSymbolAddress((void**)&rk, g_rk);
    cudaGetSymbolAddress((void**)&rv, g_rv);
    cudaGetSymbolAddress((void**)&sq, g_sq);
    cudaGetSymbolAddress((void**)&satt, g_satt);
    cudaGetSymbolAddress((void**)&ft, g_ft);
    cudaGetSymbolAddress((void**)&hid, g_hid);
    cudaGetSymbolAddress((void**)&mask, g_mask);
    cudaGetSymbolAddress((void**)&x2, g_x2);
    cudaGetSymbolAddress((void**)&h2, g_h2);
    cudaGetSymbolAddress((void**)&att2, g_att2);
    cudaGetSymbolAddress((void**)&mid2, g_mid2);
    cudaGetSymbolAddress((void**)&w1p, g_w1p);
    cudaGetSymbolAddress((void**)&w2p, g_w2p);
    cudaGetSymbolAddress((void**)&qkvp, g_qkvp);
    cudaGetSymbolAddress((void**)&rop, g_rop);
    cudaGetSymbolAddress((void**)&skvp, g_skvp);
    cudaGetSymbolAddress((void**)&bqkv, g_bqkv);
    cudaGetSymbolAddress((void**)&bskv, g_bskv);

    const int M = ML;

    cvt_all<<<(S8 + 255) / 256, 256>>>(pw_w1, pw_w2, ring_wq, ring_wk, ring_wv, ring_wo,
                                       star_wk, star_wv, w1p, w2p, qkvp, rop, skvp);   // 0
    concat_bias<<<(NLAYERS * 5 * Hd + 255) / 256, 256>>>(ring_bq, ring_bk, ring_bv,
                                                          star_bk, star_bv, bqkv, bskv); // 1
    embed_kernel<<<(ML * Hd + 255) / 256, 256>>>(src, emb, pos_table, x, x2, mask);      // 2

    bool relay_done = false;
    for (int i = 0; i < NLAYERS; i++) {
        const float* b1 = pw_b1 + (size_t)i * DI;
        const float* b2 = pw_b2 + (size_t)i * Hd;
        const float* pg = pw_g + (size_t)i * Hd;
        const float* pb = pw_bn + (size_t)i * Hd;
        const float* rbk = ring_bk + (size_t)i * Hd;
        const float* rbv = ring_bv + (size_t)i * Hd;
        const float* rbo = ring_bo + (size_t)i * Hd;
        const float* ng = norm_g + (size_t)i * Hd;
        const float* nb = norm_b + (size_t)i * Hd;
        const float* rwk = ring_wk + (size_t)i * Hd * Hd;
        const float* rwv = ring_wv + (size_t)i * Hd * Hd;
        const __half* w1i = w1p + (size_t)i * DI * 2 * Hd;
        const __half* w2i = w2p + (size_t)i * Hd * 2 * DI;
        const __half* qkvi = qkvp + (size_t)i * 3 * Hd * 2 * Hd;
        const __half* roi = rop + (size_t)i * Hd * 2 * Hd;
        const __half* skvi = skvp + (size_t)i * 2 * Hd * 2 * Hd;
        const float* bqkvi = bqkv + (size_t)i * 3 * Hd;
        const float* bskvi = bskv + (size_t)i * 2 * Hd;

        // PWFF (3-product: fp32-exact)
        gemm_p(1, 1, 3, x2, w1i, b1, nullptr, 0, mid2, M, DI, Hd);       // launch 3 = profiled
        gemm_p(0, 0, 3, mid2, w2i, b2, ring, Hd, nullptr, M, Hd, DI);
        ln_kernel<1, 0, 1, 0><<<M, 256>>>(ring, x, pg, pb, nullptr, h2, nullptr);

        if (!relay_done) {
            dim3 gp(6, 16, Bx);
            relay_part_kernel<<<gp, 128>>>(x, part);
            dim3 gf(6, Bx);
            relay_fin_kernel<<<gf, 128>>>(part, relay);
            relay_done = true;
        }

        // Ring attention (2-product)
        gemm_p(0, 0, 2, h2, qkvi, bqkvi, qkv, 3 * Hd, nullptr, M, 3 * Hd, Hd);
        gemm_rel2<<<(2 * Hd * 32 + 255) / 256, 256>>>(relay, rwk, rbk, rwv, rbv, rk, rv);
        ring_attn_kernel<<<(M * NHd) / 8, 256>>>(qkv, rk, rv, att2);
        gemm_p(0, 0, 2, att2, roi, rbo, ring, Hd, nullptr, M, Hd, Hd);
        ln_kernel<0, 2, 2, 1><<<M, 256>>>(ring, nullptr, ng, nb, x, x2, mask);

        // Star attention (2-product KV)
        gemm_rel3<<<(3 * Hd * 32 + 255) / 256, 256>>>(relay,
            star_wq + (size_t)i * Hd * Hd, star_bq + (size_t)i * Hd,
            star_wk + (size_t)i * Hd * Hd, star_bk + (size_t)i * Hd,
            star_wv + (size_t)i * Hd * Hd, star_bv + (size_t)i * Hd,
            sq, rk, rv);
        gemm_p(0, 0, 2, x2, skvi, bskvi, kv, 2 * Hd, nullptr, M, 2 * Hd, Hd);
        star_attn_kernel<<<Bx * NHd, 256>>>(sq, kv, rk, rv, mask, satt);
        gemm_small8<<<(Hd * 32 + 255) / 256, 256>>>(satt, Hd,
            star_wo + (size_t)i * Hd * Hd, Hd, star_bo + (size_t)i * Hd,
            relay, Hd, Hd, Hd, 2);
    }

    // heads
    gather_ft_kernel<<<(Bx * 2 * Hd + 255) / 256, 256>>>(relay, x, positions, ft);
    gemm_small8<<<(3 * NHID * 32 + 255) / 256, 256>>>(ft, 2 * Hd, head_w1, 2 * Hd,
                                                      head_b1, hid, 3 * NHID,
                                                      3 * NHID, 2 * Hd, 1);
    head2_kernel<<<(3 * NOUT * 32 + 255) / 256, 256>>>(hid, head_w2, head_b2, out);
}

// round 10
// speedup vs baseline: 1.4600x; 1.2511x over previous
#include <cuda_runtime.h>
#include <cuda_fp16.h>
#include <math.h>
#include <stdint.h>

// ---------------- problem constants ----------------
#define Bx 8
#define Lx 1024
#define Hd 768
#define NHd 12
#define HDd 64
#define DI 3072
#define NLAYERS 2
#define NHID 1024
#define NOUT 5000
#define SCALE_ATT 0.125f
#define LEAKY 0.01f
#define ML (Bx*Lx)      // 8192

// ---------------- fp32 scratch ----------------
__device__ float g_x   [ML*Hd];
__device__ float g_qkv [ML*3*Hd];
__device__ float g_kv  [ML*2*Hd];
__device__ float g_ring[ML*Hd];
__device__ float g_relay[Bx*Hd];
__device__ float g_part[Bx*16*Hd];
__device__ float g_rk  [Bx*Hd];
__device__ float g_rv  [Bx*Hd];
__device__ float g_sq  [Bx*Hd];
__device__ float g_satt[Bx*Hd];
__device__ float g_ft  [Bx*2*Hd];
__device__ float g_hid [Bx*3*NHID];
__device__ int   g_mask[Bx*Lx];

// ---------------- fp16 2-plane scratch ----------------
__device__ __half g_x2  [ML*2*Hd];
__device__ __half g_h2  [ML*2*Hd];
__device__ __half g_att2[ML*2*Hd];
__device__ __half g_mid2[(size_t)ML*2*DI];
__device__ __half g_w1p [(size_t)NLAYERS*DI*2*Hd];
__device__ __half g_w2p [(size_t)NLAYERS*Hd*2*DI];
__device__ __half g_qkvp[(size_t)NLAYERS*3*Hd*2*Hd];
__device__ __half g_rop [(size_t)NLAYERS*Hd*2*Hd];
__device__ __half g_skvp[(size_t)NLAYERS*2*Hd*2*Hd];
__device__ float g_bqkv[NLAYERS*3*Hd];
__device__ float g_bskv[NLAYERS*2*Hd];

// ---------------- helpers ----------------
__device__ __forceinline__ uint32_t cvta_s(const void* p) {
    return (uint32_t)__cvta_generic_to_shared(p);
}
__device__ __forceinline__ void ldsm4(uint32_t* r, uint32_t addr) {
    asm volatile("ldmatrix.sync.aligned.m8n8.x4.shared.b16 {%0,%1,%2,%3}, [%4];\n"
                 : "=r"(r[0]), "=r"(r[1]), "=r"(r[2]), "=r"(r[3]) : "r"(addr));
}
__device__ __forceinline__ void mma16816(float* c, const uint32_t* a, const uint32_t* b) {
    asm volatile("mma.sync.aligned.m16n8k16.row.col.f32.f16.f16.f32 "
                 "{%0,%1,%2,%3},{%4,%5,%6,%7},{%8,%9},{%0,%1,%2,%3};\n"
                 : "+f"(c[0]), "+f"(c[1]), "+f"(c[2]), "+f"(c[3])
                 : "r"(a[0]), "r"(a[1]), "r"(a[2]), "r"(a[3]), "r"(b[0]), "r"(b[1]));
}
__device__ __forceinline__ void cp16(uint32_t s, const void* g) {
    asm volatile("cp.async.cg.shared.global [%0], [%1], 16;\n" :: "r"(s), "l"(g));
}
__device__ __forceinline__ void split_hl(float v, __half& hi, __half& lo) {
    hi = __float2half_rn(v);
    lo = __float2half_rn(v - __half2float(hi));
}
__device__ __forceinline__ void plane_write1(__half* base, size_t row, int C, int c, float v) {
    __half hi, lo; split_hl(v, hi, lo);
    __half* p = base + row * (size_t)(2 * C) + 32 * (c >> 4) + (c & 15);
    p[0]  = hi;
    p[16] = lo;
}
__device__ __forceinline__ uint32_t sw128(uint32_t o) { return o ^ ((o >> 3) & 0x70); }

// =====================================================================
// Tensor-core GEMM, 128x128 CTA tile, warp tile 64x32 (2x4 warps),
// 3-stage cp.async pipeline (fill-first ordering, R8-verified).
//   C[M,N] = act(A@W^T + bias) from fp16 hi/lo planes.
// NP=3: Ah*Bh + Ah*Bl + Al*Bh (err ~2^-22); NP=2: Ah*Bh + Ah*Bl (err ~2^-12).
// =====================================================================
#define TB 16384
#define BUFB (2*TB)
#define SMEM_G (3*BUFB)              // 96 KB

__device__ __forceinline__ void fill_tile(uint32_t base, const __half* A2,
                                          const __half* W2, int lda2, int ldw2,
                                          int bm, int bn, int kc, int tid)
{
#pragma unroll
    for (int j = 0; j < 4; j++) {
        int idx = tid + j * 256;
        int row = idx >> 3, c16 = idx & 7;
        uint32_t off = sw128((uint32_t)(row * 128 + c16 * 16));
        cp16(base + off,      A2 + (size_t)(bm + row) * lda2 + kc * 64 + c16 * 8);
        cp16(base + TB + off, W2 + (size_t)(bn + row) * ldw2 + kc * 64 + c16 * 8);
    }
}

template<int ACT, int OUTP, int NP>
__global__ __launch_bounds__(256, 2)
void gemm_tc2(const __half* __restrict__ A2, int lda2,
              const __half* __restrict__ W2, int ldw2,
              const float* __restrict__ bias,
              float* __restrict__ C, int ldc,
              __half* __restrict__ C2, int Nout,
              int T)
{
    extern __shared__ __align__(128) char smraw[];
    const uint32_t sb = cvta_s(smraw);

    const int tid  = threadIdx.x;
    const int lane = tid & 31;
    const int warp = tid >> 5;
    const int wm = warp >> 2;
    const int wn = warp & 3;
    const int bm = blockIdx.y * 128;
    const int bn = blockIdx.x * 128;

    float acc[4][4][4];
#pragma unroll
    for (int i = 0; i < 4; i++)
#pragma unroll
        for (int j = 0; j < 4; j++)
#pragma unroll
            for (int c = 0; c < 4; c++) acc[i][j][c] = 0.f;

    const int a_row = lane & 15;
    const int a_kb  = (lane >> 4) * 16;
    const int b_row = (lane & 7) + ((lane >> 4) << 3);
    const int b_kb  = ((lane >> 3) & 1) * 16;

    fill_tile(sb, A2, W2, lda2, ldw2, bm, bn, 0, tid);
    asm volatile("cp.async.commit_group;\n");
    fill_tile(sb + BUFB, A2, W2, lda2, ldw2, bm, bn, 1, tid);
    asm volatile("cp.async.commit_group;\n");

    int bc = 0, bf = 2;
    for (int t = 0; t < T; t++) {
        if (t == T - 1) asm volatile("cp.async.wait_group 0;\n");
        else            asm volatile("cp.async.wait_group 1;\n");
        __syncthreads();

        if (t + 2 < T) {
            fill_tile(sb + bf * BUFB, A2, W2, lda2, ldw2, bm, bn, t + 2, tid);
            asm volatile("cp.async.commit_group;\n");
            bf = (bf == 2) ? 0 : bf + 1;
        }

        const uint32_t ab = sb + bc * BUFB;
        const uint32_t bb = ab + TB;
        bc = (bc == 2) ? 0 : bc + 1;

#pragma unroll
        for (int g = 0; g < 2; g++) {
            uint32_t bh[2][4], afh[4][4], bl_[2][4], afl[4][4];
            // upfront fragment loads (independent, pipeline at struct floor)
#pragma unroll
            for (int p = 0; p < 2; p++) {
                int row = wn * 32 + p * 16 + b_row;
                ldsm4(bh[p], bb + sw128((uint32_t)(row * 128 + g * 64 + b_kb)));
            }
#pragma unroll
            for (int mt = 0; mt < 4; mt++) {
                int row = wm * 64 + mt * 16 + a_row;
                ldsm4(afh[mt], ab + sw128((uint32_t)(row * 128 + g * 64 + a_kb)));
            }
#pragma unroll
            for (int p = 0; p < 2; p++) {
                int row = wn * 32 + p * 16 + b_row;
                ldsm4(bl_[p], bb + sw128((uint32_t)(row * 128 + g * 64 + 32 + b_kb)));
            }
            if (NP == 3) {
#pragma unroll
                for (int mt = 0; mt < 4; mt++) {
                    int row = wm * 64 + mt * 16 + a_row;
                    ldsm4(afl[mt], ab + sw128((uint32_t)(row * 128 + g * 64 + 32 + a_kb)));
                }
            }
            // mma stream
#pragma unroll
            for (int mt = 0; mt < 4; mt++)
#pragma unroll
                for (int nt = 0; nt < 4; nt++)
                    mma16816(acc[mt][nt], afh[mt], &bh[nt >> 1][(nt & 1) * 2]);
#pragma unroll
            for (int mt = 0; mt < 4; mt++)
#pragma unroll
                for (int nt = 0; nt < 4; nt++)
                    mma16816(acc[mt][nt], afh[mt], &bl_[nt >> 1][(nt & 1) * 2]);
            if (NP == 3) {
#pragma unroll
                for (int mt = 0; mt < 4; mt++)
#pragma unroll
                    for (int nt = 0; nt < 4; nt++)
                        mma16816(acc[mt][nt], afl[mt], &bh[nt >> 1][(nt & 1) * 2]);
            }
        }
    }

    // epilogue
#pragma unroll
    for (int mt = 0; mt < 4; mt++) {
#pragma unroll
        for (int nt = 0; nt < 4; nt++) {
            int row = bm + wm * 64 + mt * 16 + (lane >> 2);
            int col = bn + wn * 32 + nt * 8 + (lane & 3) * 2;
            float bi0 = bias[col], bi1 = bias[col + 1];
            float v0 = acc[mt][nt][0] + bi0;
            float v1 = acc[mt][nt][1] + bi1;
            float v2 = acc[mt][nt][2] + bi0;
            float v3 = acc[mt][nt][3] + bi1;
            if (ACT == 1) {
                v0 = fmaxf(v0, 0.f); v1 = fmaxf(v1, 0.f);
                v2 = fmaxf(v2, 0.f); v3 = fmaxf(v3, 0.f);
            }
            if (OUTP == 0) {
                *(float2*)(C + (size_t)row * ldc + col)       = make_float2(v0, v1);
                *(float2*)(C + (size_t)(row + 8) * ldc + col) = make_float2(v2, v3);
            } else {
                int gg = col >> 4, off = col & 15;
                __half h0, h1, h2, h3, l0, l1, l2, l3;
                split_hl(v0, h0, l0); split_hl(v1, h1, l1);
                split_hl(v2, h2, l2); split_hl(v3, h3, l3);
                __half* p0 = C2 + (size_t)row * (2 * Nout) + 32 * gg + off;
                __half* p1 = C2 + (size_t)(row + 8) * (2 * Nout) + 32 * gg + off;
                *(__half2*)(p0)      = __halves2half2(h0, h1);
                *(__half2*)(p0 + 16) = __halves2half2(l0, l1);
                *(__half2*)(p1)      = __halves2half2(h2, h3);
                *(__half2*)(p1 + 16) = __halves2half2(l2, l3);
            }
        }
    }
}

static void gemm_p(int act, int outp, int np,
                   const __half* A2, const __half* W2,
                   const float* bias, float* C, int ldc, __half* C2,
                   int M, int N, int K)
{
    dim3 grid(N / 128, M / 128);
    int T = K / 32;
    if (outp == 1) {
        if (np == 2) gemm_tc2<1, 1, 2><<<grid, 256, SMEM_G>>>(A2, 2 * K, W2, 2 * K, bias, nullptr, 0, C2, N, T);
        else         gemm_tc2<1, 1, 3><<<grid, 256, SMEM_G>>>(A2, 2 * K, W2, 2 * K, bias, nullptr, 0, C2, N, T);
    } else {
        if (np == 2) gemm_tc2<0, 0, 2><<<grid, 256, SMEM_G>>>(A2, 2 * K, W2, 2 * K, bias, C, ldc, nullptr, N, T);
        else         gemm_tc2<0, 0, 3><<<grid, 256, SMEM_G>>>(A2, 2 * K, W2, 2 * K, bias, C, ldc, nullptr, N, T);
    }
}

// =====================================================================
// fused weight plane conversion
// =====================================================================
#define S1 1179648
#define S2 2359296
#define S3 2654208
#define S4 2949120
#define S5 3244032
#define S6 3538944
#define S7 3833856
#define S8 4128768

__global__ void cvt_all(const float* w1, const float* w2, const float* rq, const float* rk,
                        const float* rv, const float* ro, const float* sk, const float* sv,
                        __half* o1, __half* o2, __half* oqkv,
                        __half* oro, __half* oskv)
{
    int i = blockIdx.x * blockDim.x + threadIdx.x;
    if (i >= S8) return;
    const float* in; __half* out; int C, base, extra;
    if      (i < S1) { in = w1; out = o1;   C = Hd; base = 0;  extra = 0; }
    else if (i < S2) { in = w2; out = o2;   C = DI; base = S1; extra = 0; }
    else if (i < S3) { in = rq; out = oqkv;                        C = Hd; base = S2; extra = 1536; }
    else if (i < S4) { in = rk; out = oqkv + (size_t)768 * 2 * Hd; C = Hd; base = S3; extra = 1536; }
    else if (i < S5) { in = rv; out = oqkv + (size_t)1536 * 2 * Hd;C = Hd; base = S4; extra = 1536; }
    else if (i < S6) { in = ro; out = oro;  C = Hd; base = S5; extra = 0; }
    else if (i < S7) { in = sk; out = oskv;                        C = Hd; base = S6; extra = 768; }
    else             { in = sv; out = oskv + (size_t)768 * 2 * Hd; C = Hd; base = S7; extra = 768; }
    int e = (i - base) * 4;
    int r = e / C, c = e % C;
    size_t ro_ = (size_t)r + (size_t)(r / Hd) * extra;
    if (extra == 0 && C == DI) ro_ = r;
    float4 f = *(const float4*)(in + e);
    __half h0, h1, h2, h3, l0, l1, l2, l3;
    split_hl(f.x, h0, l0); split_hl(f.y, h1, l1);
    split_hl(f.z, h2, l2); split_hl(f.w, h3, l3);
    __half* p = out + ro_ * (2 * C) + 32 * (c >> 4) + (c & 15);
    *(__half2*)(p)      = __halves2half2(h0, h1);
    *(__half2*)(p + 2)  = __halves2half2(h2, h3);
    *(__half2*)(p + 16) = __halves2half2(l0, l1);
    *(__half2*)(p + 18) = __halves2half2(l2, l3);
}

__global__ void concat_bias(const float* bq, const float* bk, const float* bv,
                            const float* sk, const float* sv,
                            float* oqkv, float* oskv)
{
    int i = blockIdx.x * blockDim.x + threadIdx.x;
    int n1 = NLAYERS * 3 * Hd;
    if (i < n1) {
        int layer = i / (3 * Hd), c = i % (3 * Hd);
        const float* s = (c < Hd) ? bq : (c < 2 * Hd) ? bk : bv;
        oqkv[i] = s[layer * Hd + (c % Hd)];
    } else if (i < n1 + NLAYERS * 2 * Hd) {
        int j = i - n1;
        int layer = j / (2 * Hd), c = j % (2 * Hd);
        const float* s = (c < Hd) ? sk : sv;
        oskv[j] = s[layer * Hd + (c % Hd)];
    }
}

// =====================================================================
// Small-M GEMMs (M=8)
// =====================================================================
__device__ __forceinline__ void smalldot8(const float* __restrict__ A, int lda,
                                          const float* __restrict__ wrow, int K,
                                          int lane, float* s)
{
    const float4* w4 = (const float4*)wrow;
    int K4 = K >> 2;
#pragma unroll
    for (int m = 0; m < 8; m++) s[m] = 0.f;
    for (int k = lane; k < K4; k += 32) {
        float4 w = w4[k];
#pragma unroll
        for (int m = 0; m < 8; m++) {
            float4 a = ((const float4*)(A + (size_t)m * lda))[k];
            s[m] += a.x * w.x + a.y * w.y + a.z * w.z + a.w * w.w;
        }
    }
#pragma unroll
    for (int m = 0; m < 8; m++)
#pragma unroll
        for (int o = 16; o; o >>= 1) s[m] += __shfl_xor_sync(0xffffffffu, s[m], o);
}

__global__ __launch_bounds__(256)
void gemm_small8(const float* __restrict__ A, int lda,
                 const float* __restrict__ W, int ldw,
                 const float* __restrict__ bias,
                 float* __restrict__ C, int ldc,
                 int N, int K, int act)
{
    int n = (blockIdx.x * blockDim.x + threadIdx.x) >> 5;
    int lane = threadIdx.x & 31;
    if (n >= N) return;
    float s[8];
    smalldot8(A, lda, W + (size_t)n * ldw, K, lane, s);
    if (lane == 0) {
        float bv = bias[n];
#pragma unroll
        for (int m = 0; m < 8; m++) {
            float v = s[m] + bv;
            if (act == 1) v = fmaxf(v, 0.f);
            else if (act == 2) v = v > 0.f ? v : LEAKY * v;
            C[(size_t)m * ldc + n] = v;
        }
    }
}

__global__ __launch_bounds__(256)
void gemm_rel2(const float* __restrict__ relay,
               const float* __restrict__ wk, const float* __restrict__ bk,
               const float* __restrict__ wv, const float* __restrict__ bv,
               float* __restrict__ rk, float* __restrict__ rv)
{
    int n = (blockIdx.x * blockDim.x + threadIdx.x) >> 5;
    int lane = threadIdx.x & 31;
    if (n >= 2 * Hd) return;
    int seg = n >= Hd, c = n - seg * Hd;
    const float* W = seg ? wv : wk;
    const float* B = seg ? bv : bk;
    float* C = seg ? rv : rk;
    float s[8];
    smalldot8(relay, Hd, W + (size_t)c * Hd, Hd, lane, s);
    if (lane == 0) {
        float bb = B[c];
#pragma unroll
        for (int m = 0; m < 8; m++) C[(size_t)m * Hd + c] = s[m] + bb;
    }
}

__global__ __launch_bounds__(256)
void gemm_rel3(const float* __restrict__ relay,
               const float* __restrict__ wq, const float* __restrict__ bq,
               const float* __restrict__ wk, const float* __restrict__ bk,
               const float* __restrict__ wv, const float* __restrict__ bv,
               float* __restrict__ sq, float* __restrict__ rk, float* __restrict__ rv)
{
    int n = (blockIdx.x * blockDim.x + threadIdx.x) >> 5;
    int lane = threadIdx.x & 31;
    if (n >= 3 * Hd) return;
    int seg = n / Hd, c = n % Hd;
    const float* W = (seg == 0) ? wq : (seg == 1) ? wk : wv;
    const float* B = (seg == 0) ? bq : (seg == 1) ? bk : bv;
    float* C = (seg == 0) ? sq : (seg == 1) ? rk : rv;
    float s[8];
    smalldot8(relay, Hd, W + (size_t)c * Hd, Hd, lane, s);
    if (lane == 0) {
        float bb = B[c];
#pragma unroll
        for (int m = 0; m < 8; m++) C[(size_t)m * Hd + c] = s[m] + bb;
    }
}

__global__ __launch_bounds__(256)
void head2_kernel(const float* __restrict__ hid,
                  const float* __restrict__ w2,
                  const float* __restrict__ b2,
                  float* __restrict__ out)
{
    int n = (blockIdx.x * blockDim.x + threadIdx.x) >> 5;
    int lane = threadIdx.x & 31;
    if (n >= 3 * NOUT) return;
    int j = n / NOUT, c = n % NOUT;
    float s[8];
    smalldot8(hid + j * NHID, 3 * NHID, w2 + (size_t)n * NHID, NHID, lane, s);
    if (lane == 0) {
        float bb = b2[n];
#pragma unroll
        for (int m = 0; m < 8; m++)
            out[((size_t)m * 3 + j) * NOUT + c] = s[m] + bb;
    }
}

// ---------------- block reductions ----------------
__device__ __forceinline__ float2 block_reduce_sum2(float a, float b)
{
    static __shared__ float sa[8], sb2[8];
    __syncthreads();
    int lane = threadIdx.x & 31, w = threadIdx.x >> 5;
#pragma unroll
    for (int o = 16; o; o >>= 1) {
        a += __shfl_xor_sync(0xffffffffu, a, o);
        b += __shfl_xor_sync(0xffffffffu, b, o);
    }
    if (lane == 0) { sa[w] = a; sb2[w] = b; }
    __syncthreads();
    if (w == 0) {
        a = lane < 8 ? sa[lane] : 0.f;
        b = lane < 8 ? sb2[lane] : 0.f;
#pragma unroll
        for (int o = 4; o; o >>= 1) {
            a += __shfl_xor_sync(0xffffffffu, a, o);
            b += __shfl_xor_sync(0xffffffffu, b, o);
        }
        if (lane == 0) { sa[0] = a; sb2[0] = b; }
    }
    __syncthreads();
    return make_float2(sa[0], sb2[0]);
}
__device__ __forceinline__ float block_reduce_max(float a)
{
    static __shared__ float sm[8];
    __syncthreads();
    int lane = threadIdx.x & 31, w = threadIdx.x >> 5;
#pragma unroll
    for (int o = 16; o; o >>= 1) a = fmaxf(a, __shfl_xor_sync(0xffffffffu, a, o));
    if (lane == 0) sm[w] = a;
    __syncthreads();
    if (w == 0) {
        a = lane < 8 ? sm[lane] : -1e30f;
#pragma unroll
        for (int o = 4; o; o >>= 1) a = fmaxf(a, __shfl_xor_sync(0xffffffffu, a, o));
        if (lane == 0) sm[0] = a;
    }
    __syncthreads();
    return sm[0];
}
__device__ __forceinline__ float block_reduce_sum(float a)
{
    static __shared__ float ss[8];
    __syncthreads();
    int lane = threadIdx.x & 31, w = threadIdx.x >> 5;
#pragma unroll
    for (int o = 16; o; o >>= 1) a += __shfl_xor_sync(0xffffffffu, a, o);
    if (lane == 0) ss[w] = a;
    __syncthreads();
    if (w == 0) {
        a = lane < 8 ? ss[lane] : 0.f;
#pragma unroll
        for (int o = 4; o; o >>= 1) a += __shfl_xor_sync(0xffffffffu, a, o);
        if (lane == 0) ss[0] = a;
    }
    __syncthreads();
    return ss[0];
}

// ---------------- embed + mask + planes ----------------
__global__ void embed_kernel(const int* __restrict__ src, const float* __restrict__ emb,
                             const float* __restrict__ pos, float* __restrict__ x,
                             __half* __restrict__ x2, int* __restrict__ mask)
{
    int idx = blockIdx.x * blockDim.x + threadIdx.x;
    if (idx >= ML * Hd) return;
    int h = idx % Hd;
    int bl = idx / Hd;
    int l = bl % Lx;
    int w = h >> 8;
    int dd = h & 255;
    int tok = src[bl * 3 + w];
    float v = emb[tok * 256 + dd] + pos[l * Hd + h];
    x[idx] = v;
    plane_write1(x2, bl, Hd, h, v);
    if (h == 0) mask[bl] = (src[bl * 3] == 0) ? 1 : 0;
}

// ---------------- relay mean: 2-stage ----------------
__global__ void relay_part_kernel(const float* __restrict__ x, float* __restrict__ part)
{
    int h = blockIdx.x * 128 + threadIdx.x;
    int ch = blockIdx.y;
    int b = blockIdx.z;
    const float* p = x + (size_t)b * Lx * Hd + (size_t)ch * 64 * Hd + h;
    float s = 0.f;
#pragma unroll 8
    for (int l = 0; l < 64; l++) s += p[(size_t)l * Hd];
    part[((size_t)b * 16 + ch) * Hd + h] = s;
}
__global__ void relay_fin_kernel(const float* __restrict__ part, float* __restrict__ relay)
{
    int h = blockIdx.x * 128 + threadIdx.x;
    int b = blockIdx.y;
    float s = 0.f;
#pragma unroll
    for (int ch = 0; ch < 16; ch++) s += part[((size_t)b * 16 + ch) * Hd + h];
    relay[b * Hd + h] = s * (1.0f / Lx);
}

// ---------------- layernorm ----------------
template<int RES, int ACT, int MODE, int MASKED>
__global__ __launch_bounds__(256)
void ln_kernel(const float* __restrict__ x, const float* __restrict__ res,
               const float* __restrict__ g, const float* __restrict__ b,
               float* __restrict__ out, __half* __restrict__ out2,
               const int* __restrict__ mask)
{
    int row = blockIdx.x;
    const float* xr = x + (size_t)row * Hd;
    const float* rr = RES ? res + (size_t)row * Hd : nullptr;
    int mrow = MASKED ? mask[row] : 0;
    float t[3];
    float s = 0.f, ss = 0.f;
#pragma unroll
    for (int j = 0; j < 3; j++) {
        int i = threadIdx.x + j * 256;
        float v = xr[i];
        if (RES) v += rr[i];
        t[j] = v;
        s += v; ss += v * v;
    }
    float2 r = block_reduce_sum2(s, ss);
    float mu = r.x * (1.0f / Hd);
    float var = r.y * (1.0f / Hd) - mu * mu;
    float rstd = rsqrtf(var + 1e-5f);
#pragma unroll
    for (int j = 0; j < 3; j++) {
        int i = threadIdx.x + j * 256;
        float v = (t[j] - mu) * rstd * g[i] + b[i];
        if (ACT == 2) v = v > 0.f ? v : LEAKY * v;
        if (MASKED && mrow) v = 0.f;
        if (MODE != 1) out[(size_t)row * Hd + i] = v;
        if (MODE != 0) plane_write1(out2, row, Hd, i, v);
    }
}

// ---------------- ring attention ----------------
__global__ __launch_bounds__(256)
void ring_attn_kernel(const float* __restrict__ qkv, const float* __restrict__ rk,
                      const float* __restrict__ rv, __half* __restrict__ out2)
{
    int gw = (blockIdx.x * blockDim.x + threadIdx.x) >> 5;
    int lane = threadIdx.x & 31;
    int n = gw % NHd;
    int bl = gw / NHd;
    int l = bl % Lx;
    int b = bl / Lx;

    const float* qp = qkv + (size_t)bl * (3 * Hd) + n * HDd;
    float q0 = qp[lane * 2], q1 = qp[lane * 2 + 1];

    float s[4];
#pragma unroll
    for (int w = 0; w < 3; w++) {
        int ll = l - 1 + w;
        float d = 0.f;
        if (ll >= 0 && ll < Lx) {
            const float* kp = qkv + ((size_t)(b * Lx + ll)) * (3 * Hd) + Hd + n * HDd;
            d = q0 * kp[lane * 2] + q1 * kp[lane * 2 + 1];
        }
#pragma unroll
        for (int o = 16; o; o >>= 1) d += __shfl_xor_sync(0xffffffffu, d, o);
        s[w] = d * SCALE_ATT;
    }
    {
        const float* kp = rk + b * Hd + n * HDd;
        float d = q0 * kp[lane * 2] + q1 * kp[lane * 2 + 1];
#pragma unroll
        for (int o = 16; o; o >>= 1) d += __shfl_xor_sync(0xffffffffu, d, o);
        s[3] = d * SCALE_ATT;
    }
    float m = fmaxf(fmaxf(s[0], s[1]), fmaxf(s[2], s[3]));
    float e[4], se = 0.f;
#pragma unroll
    for (int w = 0; w < 4; w++) { e[w] = expf(s[w] - m); se += e[w]; }
    float inv = 1.0f / se;

    float o0 = 0.f, o1 = 0.f;
#pragma unroll
    for (int w = 0; w < 3; w++) {
        int ll = l - 1 + w;
        if (ll >= 0 && ll < Lx) {
            const float* vp = qkv + ((size_t)(b * Lx + ll)) * (3 * Hd) + 2 * Hd + n * HDd;
            float p = e[w] * inv;
            o0 += p * vp[lane * 2];
            o1 += p * vp[lane * 2 + 1];
        }
    }
    {
        const float* vp = rv + b * Hd + n * HDd;
        float p = e[3] * inv;
        o0 += p * vp[lane * 2];
        o1 += p * vp[lane * 2 + 1];
    }
    int c0 = n * HDd + lane * 2;
    int gg = c0 >> 4, off = c0 & 15;
    __half h0, h1, l0b, l1b;
    split_hl(o0, h0, l0b); split_hl(o1, h1, l1b);
    __half* p = out2 + (size_t)bl * (2 * Hd) + 32 * gg + off;
    *(__half2*)(p)      = __halves2half2(h0, h1);
    *(__half2*)(p + 16) = __halves2half2(l0b, l1b);
}

// ---------------- star attention ----------------
__global__ __launch_bounds__(256)
void star_attn_kernel(const float* __restrict__ sq, const float* __restrict__ kv,
                      const float* __restrict__ rk, const float* __restrict__ rv,
                      const int* __restrict__ mask, float* __restrict__ out)
{
    __shared__ float qs[HDd];
    __shared__ float sc[Lx + 1];
    __shared__ float red[4 * HDd];

    int b = blockIdx.x / NHd;
    int n = blockIdx.x % NHd;
    int tid = threadIdx.x;

    if (tid < HDd) qs[tid] = sq[b * Hd + n * HDd + tid];
    __syncthreads();

    float lmax = -1e30f;
    for (int s = tid; s < Lx + 1; s += 256) {
        const float* kp = (s == 0) ? rk + b * Hd + n * HDd
                                   : kv + ((size_t)(b * Lx + s - 1)) * (2 * Hd) + n * HDd;
        float d = 0.f;
#pragma unroll
        for (int i = 0; i < HDd; i++) d += qs[i] * kp[i];
        d *= SCALE_ATT;
        if (s > 0 && mask[b * Lx + s - 1]) d = -1e30f;
        sc[s] = d;
        lmax = fmaxf(lmax, d);
    }
    float bmax = block_reduce_max(lmax);

    float lsum = 0.f;
    for (int s = tid; s < Lx + 1; s += 256) {
        float ev = expf(sc[s] - bmax);
        sc[s] = ev;
        lsum += ev;
    }
    float bsum = block_reduce_sum(lsum);

    int gg = tid >> 6;
    int dd = tid & 63;
    float acc = 0.f;
    for (int s = gg; s < Lx + 1; s += 4) {
        const float* vp = (s == 0) ? rv + b * Hd + n * HDd
                                   : kv + ((size_t)(b * Lx + s - 1)) * (2 * Hd) + Hd + n * HDd;
        acc += sc[s] * vp[dd];
    }
    red[gg * HDd + dd] = acc;
    __syncthreads();
    if (tid < HDd) {
        float r = red[tid] + red[HDd + tid] + red[2 * HDd + tid] + red[3 * HDd + tid];
        out[b * Hd + n * HDd + tid] = r / bsum;
    }
}

// ---------------- gather ft ----------------
__global__ void gather_ft_kernel(const float* __restrict__ relay, const float* __restrict__ nodes,
                                 const int* __restrict__ positions, float* __restrict__ ft)
{
    int idx = blockIdx.x * blockDim.x + threadIdx.x;
    if (idx >= Bx * 2 * Hd) return;
    int b = idx / (2 * Hd);
    int i = idx % (2 * Hd);
    float v;
    if (i < Hd) v = relay[b * Hd + i];
    else        v = nodes[((size_t)b * Lx + positions[b]) * Hd + (i - Hd)];
    ft[idx] = v;
}

// ---------------- launch ----------------
extern "C" void kernel_launch(void* const* d_in, const int* in_sizes, int n_in,
                              void* d_out, int out_size)
{
    const int*   src       = (const int*)  d_in[0];
    const int*   positions = (const int*)  d_in[1];
    const float* emb       = (const float*)d_in[2];
    const float* pos_table = (const float*)d_in[3];
    const float* norm_g    = (const float*)d_in[4];
    const float* norm_b    = (const float*)d_in[5];
    const float* pw_w1     = (const float*)d_in[6];
    const float* pw_b1     = (const float*)d_in[7];
    const float* pw_w2     = (const float*)d_in[8];
    const float* pw_b2     = (const float*)d_in[9];
    const float* pw_g      = (const float*)d_in[10];
    const float* pw_bn     = (const float*)d_in[11];
    const float* ring_wq   = (const float*)d_in[12];
    const float* ring_bq   = (const float*)d_in[13];
    const float* ring_wk   = (const float*)d_in[14];
    const float* ring_bk   = (const float*)d_in[15];
    const float* ring_wv   = (const float*)d_in[16];
    const float* ring_bv   = (const float*)d_in[17];
    const float* ring_wo   = (const float*)d_in[18];
    const float* ring_bo   = (const float*)d_in[19];
    const float* star_wq   = (const float*)d_in[20];
    const float* star_bq   = (const float*)d_in[21];
    const float* star_wk   = (const float*)d_in[22];
    const float* star_bk   = (const float*)d_in[23];
    const float* star_wv   = (const float*)d_in[24];
    const float* star_bv   = (const float*)d_in[25];
    const float* star_wo   = (const float*)d_in[26];
    const float* star_bo   = (const float*)d_in[27];
    const float* head_w1   = (const float*)d_in[28];
    const float* head_b1   = (const float*)d_in[29];
    const float* head_w2   = (const float*)d_in[30];
    const float* head_b2   = (const float*)d_in[31];
    float* out = (float*)d_out;

    cudaFuncSetAttribute(gemm_tc2<0, 0, 3>, cudaFuncAttributeMaxDynamicSharedMemorySize, SMEM_G);
    cudaFuncSetAttribute(gemm_tc2<0, 0, 2>, cudaFuncAttributeMaxDynamicSharedMemorySize, SMEM_G);
    cudaFuncSetAttribute(gemm_tc2<1, 1, 3>, cudaFuncAttributeMaxDynamicSharedMemorySize, SMEM_G);
    cudaFuncSetAttribute(gemm_tc2<1, 1, 2>, cudaFuncAttributeMaxDynamicSharedMemorySize, SMEM_G);

    float *x, *qkv, *kv, *ring, *relay, *part, *rk, *rv, *sq, *satt, *ft, *hid, *bqkv, *bskv;
    int* mask;
    __half *x2, *h2, *att2, *mid2;
    __half *w1p, *w2p, *qkvp, *rop, *skvp;
    cudaGetSymbolAddress((void**)&x, g_x);
    cudaGetSymbolAddress((void**)&qkv, g_qkv);
    cudaGetSymbolAddress((void**)&kv, g_kv);
    cudaGetSymbolAddress((void**)&ring, g_ring);
    cudaGetSymbolAddress((void**)&relay, g_relay);
    cudaGetSymbolAddress((void**)&part, g_part);
    cudaGetSymbolAddress((void**)&rk, g_rk);
    cudaGetSymbolAddress((void**)&rv, g_rv);
    cudaGetSymbolAddress((void**)&sq, g_sq);
    cudaGetSymbolAddress((void**)&satt, g_satt);
    cudaGetSymbolAddress((void**)&ft, g_ft);
    cudaGetSymbolAddress((void**)&hid, g_hid);
    cudaGetSymbolAddress((void**)&mask, g_mask);
    cudaGetSymbolAddress((void**)&x2, g_x2);
    cudaGetSymbolAddress((void**)&h2, g_h2);
    cudaGetSymbolAddress((void**)&att2, g_att2);
    cudaGetSymbolAddress((void**)&mid2, g_mid2);
    cudaGetSymbolAddress((void**)&w1p, g_w1p);
    cudaGetSymbolAddress((void**)&w2p, g_w2p);
    cudaGetSymbolAddress((void**)&qkvp, g_qkvp);
    cudaGetSymbolAddress((void**)&rop, g_rop);
    cudaGetSymbolAddress((void**)&skvp, g_skvp);
    cudaGetSymbolAddress((void**)&bqkv, g_bqkv);
    cudaGetSymbolAddress((void**)&bskv, g_bskv);

    const int M = ML;

    cvt_all<<<(S8 + 255) / 256, 256>>>(pw_w1, pw_w2, ring_wq, ring_wk, ring_wv, ring_wo,
                                       star_wk, star_wv, w1p, w2p, qkvp, rop, skvp);   // 0
    concat_bias<<<(NLAYERS * 5 * Hd + 255) / 256, 256>>>(ring_bq, ring_bk, ring_bv,
                                                          star_bk, star_bv, bqkv, bskv); // 1
    embed_kernel<<<(ML * Hd + 255) / 256, 256>>>(src, emb, pos_table, x, x2, mask);      // 2

    bool relay_done = false;
    for (int i = 0; i < NLAYERS; i++) {
        const float* b1 = pw_b1 + (size_t)i * DI;
        const float* b2 = pw_b2 + (size_t)i * Hd;
        const float* pg = pw_g + (size_t)i * Hd;
        const float* pb = pw_bn + (size_t)i * Hd;
        const float* rbk = ring_bk + (size_t)i * Hd;
        const float* rbv = ring_bv + (size_t)i * Hd;
        const float* rbo = ring_bo + (size_t)i * Hd;
        const float* ng = norm_g + (size_t)i * Hd;
        const float* nb = norm_b + (size_t)i * Hd;
        const float* rwk = ring_wk + (size_t)i * Hd * Hd;
        const float* rwv = ring_wv + (size_t)i * Hd * Hd;
        const __half* w1i = w1p + (size_t)i * DI * 2 * Hd;
        const __half* w2i = w2p + (size_t)i * Hd * 2 * DI;
        const __half* qkvi = qkvp + (size_t)i * 3 * Hd * 2 * Hd;
        const __half* roi = rop + (size_t)i * Hd * 2 * Hd;
        const __half* skvi = skvp + (size_t)i * 2 * Hd * 2 * Hd;
        const float* bqkvi = bqkv + (size_t)i * 3 * Hd;
        const float* bskvi = bskv + (size_t)i * 2 * Hd;

        // PWFF (2-product fp16)
        gemm_p(1, 1, 2, x2, w1i, b1, nullptr, 0, mid2, M, DI, Hd);       // launch 3 = profiled
        gemm_p(0, 0, 2, mid2, w2i, b2, ring, Hd, nullptr, M, Hd, DI);
        ln_kernel<1, 0, 1, 0><<<M, 256>>>(ring, x, pg, pb, nullptr, h2, nullptr);

        if (!relay_done) {
            dim3 gp(6, 16, Bx);
            relay_part_kernel<<<gp, 128>>>(x, part);
            dim3 gf(6, Bx);
            relay_fin_kernel<<<gf, 128>>>(part, relay);
            relay_done = true;
        }

        // Ring attention (2-product)
        gemm_p(0, 0, 2, h2, qkvi, bqkvi, qkv, 3 * Hd, nullptr, M, 3 * Hd, Hd);
        gemm_rel2<<<(2 * Hd * 32 + 255) / 256, 256>>>(relay, rwk, rbk, rwv, rbv, rk, rv);
        ring_attn_kernel<<<(M * NHd) / 8, 256>>>(qkv, rk, rv, att2);
        gemm_p(0, 0, 2, att2, roi, rbo, ring, Hd, nullptr, M, Hd, Hd);
        ln_kernel<0, 2, 2, 1><<<M, 256>>>(ring, nullptr, ng, nb, x, x2, mask);

        // Star attention (2-product KV)
        gemm_rel3<<<(3 * Hd * 32 + 255) / 256, 256>>>(relay,
            star_wq + (size_t)i * Hd * Hd, star_bq + (size_t)i * Hd,
            star_wk + (size_t)i * Hd * Hd, star_bk + (size_t)i * Hd,
            star_wv + (size_t)i * Hd * Hd, star_bv + (size_t)i * Hd,
            sq, rk, rv);
        gemm_p(0, 0, 2, x2, skvi, bskvi, kv, 2 * Hd, nullptr, M, 2 * Hd, Hd);
        star_attn_kernel<<<Bx * NHd, 256>>>(sq, kv, rk, rv, mask, satt);
        gemm_small8<<<(Hd * 32 + 255) / 256, 256>>>(satt, Hd,
            star_wo + (size_t)i * Hd * Hd, Hd, star_bo + (size_t)i * Hd,
            relay, Hd, Hd, Hd, 2);
    }

    // heads
    gather_ft_kernel<<<(Bx * 2 * Hd + 255) / 256, 256>>>(relay, x, positions, ft);
    gemm_small8<<<(3 * NHID * 32 + 255) / 256, 256>>>(ft, 2 * Hd, head_w1, 2 * Hd,
                                                      head_b1, hid, 3 * NHID,
                                                      3 * NHID, 2 * Hd, 1);
    head2_kernel<<<(3 * NOUT * 32 + 255) / 256, 256>>>(hid, head_w2, head_b2, out);
}

// round 11
// speedup vs baseline: 1.5975x; 1.0942x over previous
#include <cuda_runtime.h>
#include <cuda_fp16.h>
#include <math.h>
#include <stdint.h>

// ---------------- problem constants ----------------
#define Bx 8
#define Lx 1024
#define Hd 768
#define NHd 12
#define HDd 64
#define DI 3072
#define NLAYERS 2
#define NHID 1024
#define NOUT 5000
#define SCALE_ATT 0.125f
#define LEAKY 0.01f
#define ML (Bx*Lx)      // 8192

// ---------------- fp32 scratch ----------------
__device__ float g_x   [ML*Hd];
__device__ float g_qkv [ML*3*Hd];
__device__ float g_kv  [ML*2*Hd];
__device__ float g_ring[ML*Hd];
__device__ float g_relay[Bx*Hd];
__device__ float g_part[Bx*16*Hd];
__device__ float g_rk  [Bx*Hd];
__device__ float g_rv  [Bx*Hd];
__device__ float g_sq  [Bx*Hd];
__device__ float g_satt[Bx*Hd];
__device__ float g_ft  [Bx*2*Hd];
__device__ float g_hid [Bx*3*NHID];
__device__ int   g_mask[Bx*Lx];

// ---------------- fp16 activation scratch (hi-only, plain row-major) ----------------
__device__ __half g_x2  [ML*Hd];
__device__ __half g_h2  [ML*Hd];
__device__ __half g_att2[ML*Hd];
__device__ __half g_mid2[(size_t)ML*DI];
// weights keep 2-plane layout: per 16-group g: [32g..+16)=hi, [+16..+32)=lo; row stride 2K
__device__ __half g_w1p [(size_t)NLAYERS*DI*2*Hd];
__device__ __half g_w2p [(size_t)NLAYERS*Hd*2*DI];
__device__ __half g_qkvp[(size_t)NLAYERS*3*Hd*2*Hd];
__device__ __half g_rop [(size_t)NLAYERS*Hd*2*Hd];
__device__ __half g_skvp[(size_t)NLAYERS*2*Hd*2*Hd];
__device__ float g_bqkv[NLAYERS*3*Hd];
__device__ float g_bskv[NLAYERS*2*Hd];

// ---------------- helpers ----------------
__device__ __forceinline__ uint32_t cvta_s(const void* p) {
    return (uint32_t)__cvta_generic_to_shared(p);
}
__device__ __forceinline__ void ldsm4(uint32_t* r, uint32_t addr) {
    asm volatile("ldmatrix.sync.aligned.m8n8.x4.shared.b16 {%0,%1,%2,%3}, [%4];\n"
                 : "=r"(r[0]), "=r"(r[1]), "=r"(r[2]), "=r"(r[3]) : "r"(addr));
}
__device__ __forceinline__ void mma16816(float* c, const uint32_t* a, const uint32_t* b) {
    asm volatile("mma.sync.aligned.m16n8k16.row.col.f32.f16.f16.f32 "
                 "{%0,%1,%2,%3},{%4,%5,%6,%7},{%8,%9},{%0,%1,%2,%3};\n"
                 : "+f"(c[0]), "+f"(c[1]), "+f"(c[2]), "+f"(c[3])
                 : "r"(a[0]), "r"(a[1]), "r"(a[2]), "r"(a[3]), "r"(b[0]), "r"(b[1]));
}
__device__ __forceinline__ void cp16(uint32_t s, const void* g) {
    asm volatile("cp.async.cg.shared.global [%0], [%1], 16;\n" :: "r"(s), "l"(g));
}
__device__ __forceinline__ void split_hl(float v, __half& hi, __half& lo) {
    hi = __float2half_rn(v);
    lo = __float2half_rn(v - __half2float(hi));
}
__device__ __forceinline__ uint32_t sw128(uint32_t o) { return o ^ ((o >> 3) & 0x70); }

// =====================================================================
// Tensor-core GEMM, 128x128 CTA tile, 2x4 warps, 2-stage pipeline,
// 64 fp32-k per chunk. A: plain fp16 hi [M,K]. W: 2-plane [N,2K].
//   C = act(A@W^T + bias); products: Ah*Bh + Ah*Bl (err ~2^-12).
// smem/buffer: A 16KB (128 rows x 128B) + B 2x16KB sub-tiles = 48KB.
// =====================================================================
#define ATB 16384
#define BUFB (3*16384)               // 48 KB
#define SMEM_G (2*BUFB)              // 96 KB

__device__ __forceinline__ void fill_tile(uint32_t base, const __half* A2, int lda,
                                          const __half* W2, int ldw2,
                                          int bm, int bn, int kc, int tid)
{
    // A: chunk kc covers halves [kc*64, kc*64+64) of hi-only rows
#pragma unroll
    for (int j = 0; j < 4; j++) {
        int idx = tid + j * 256;
        int row = idx >> 3, c16 = idx & 7;
        cp16(base + sw128((uint32_t)(row * 128 + c16 * 16)),
             A2 + (size_t)(bm + row) * lda + kc * 64 + c16 * 8);
    }
    // B: two sub-tiles, halves [kc*128, kc*128+64) and [+64, +128)
#pragma unroll
    for (int s = 0; s < 2; s++)
#pragma unroll
        for (int j = 0; j < 4; j++) {
            int idx = tid + j * 256;
            int row = idx >> 3, c16 = idx & 7;
            cp16(base + ATB + s * 16384 + sw128((uint32_t)(row * 128 + c16 * 16)),
                 W2 + (size_t)(bn + row) * ldw2 + kc * 128 + s * 64 + c16 * 8);
        }
}

template<int ACT, int OUTP>
__global__ __launch_bounds__(256, 2)
void gemm_tc2(const __half* __restrict__ A2, int lda,
              const __half* __restrict__ W2, int ldw2,
              const float* __restrict__ bias,
              float* __restrict__ C, int ldc,
              __half* __restrict__ C2, int Nout,
              int T /* chunks of 64 fp32-k */)
{
    extern __shared__ __align__(128) char smraw[];
    const uint32_t sb = cvta_s(smraw);

    const int tid  = threadIdx.x;
    const int lane = tid & 31;
    const int warp = tid >> 5;
    const int wm = warp >> 2;
    const int wn = warp & 3;
    const int bm = blockIdx.y * 128;
    const int bn = blockIdx.x * 128;

    float acc[4][4][4];
#pragma unroll
    for (int i = 0; i < 4; i++)
#pragma unroll
        for (int j = 0; j < 4; j++)
#pragma unroll
            for (int c = 0; c < 4; c++) acc[i][j][c] = 0.f;

    const int a_row = lane & 15;
    const int a_kb  = (lane >> 4) * 16;
    const int b_row = (lane & 7) + ((lane >> 4) << 3);
    const int b_kb  = ((lane >> 3) & 1) * 16;

    fill_tile(sb, A2, lda, W2, ldw2, bm, bn, 0, tid);
    asm volatile("cp.async.commit_group;\n");

    for (int t = 0; t < T; t++) {
        __syncthreads();                    // all warps done with buf[(t+1)&1]'s old chunk
        if (t + 1 < T) {
            fill_tile(sb + ((t + 1) & 1) * BUFB, A2, lda, W2, ldw2, bm, bn, t + 1, tid);
            asm volatile("cp.async.commit_group;\n");
            asm volatile("cp.async.wait_group 1;\n");
        } else {
            asm volatile("cp.async.wait_group 0;\n");
        }
        __syncthreads();

        const uint32_t ab = sb + (t & 1) * BUFB;
        const uint32_t bb = ab + ATB;

#pragma unroll
        for (int g2 = 0; g2 < 4; g2++) {
            const uint32_t bsub = bb + (g2 >> 1) * 16384;
            const int gb = (g2 & 1) * 64;
            uint32_t bh[2][4], afh[4][4], bl_[2][4];
#pragma unroll
            for (int p = 0; p < 2; p++) {
                int row = wn * 32 + p * 16 + b_row;
                ldsm4(bh[p], bsub + sw128((uint32_t)(row * 128 + gb + b_kb)));
            }
#pragma unroll
            for (int mt = 0; mt < 4; mt++) {
                int row = wm * 64 + mt * 16 + a_row;
                ldsm4(afh[mt], ab + sw128((uint32_t)(row * 128 + g2 * 32 + a_kb)));
            }
#pragma unroll
            for (int p = 0; p < 2; p++) {
                int row = wn * 32 + p * 16 + b_row;
                ldsm4(bl_[p], bsub + sw128((uint32_t)(row * 128 + gb + 32 + b_kb)));
            }
#pragma unroll
            for (int mt = 0; mt < 4; mt++)
#pragma unroll
                for (int nt = 0; nt < 4; nt++)
                    mma16816(acc[mt][nt], afh[mt], &bh[nt >> 1][(nt & 1) * 2]);
#pragma unroll
            for (int mt = 0; mt < 4; mt++)
#pragma unroll
                for (int nt = 0; nt < 4; nt++)
                    mma16816(acc[mt][nt], afh[mt], &bl_[nt >> 1][(nt & 1) * 2]);
        }
    }

    // epilogue
#pragma unroll
    for (int mt = 0; mt < 4; mt++) {
#pragma unroll
        for (int nt = 0; nt < 4; nt++) {
            int row = bm + wm * 64 + mt * 16 + (lane >> 2);
            int col = bn + wn * 32 + nt * 8 + (lane & 3) * 2;
            float bi0 = bias[col], bi1 = bias[col + 1];
            float v0 = acc[mt][nt][0] + bi0;
            float v1 = acc[mt][nt][1] + bi1;
            float v2 = acc[mt][nt][2] + bi0;
            float v3 = acc[mt][nt][3] + bi1;
            if (ACT == 1) {
                v0 = fmaxf(v0, 0.f); v1 = fmaxf(v1, 0.f);
                v2 = fmaxf(v2, 0.f); v3 = fmaxf(v3, 0.f);
            }
            if (OUTP == 0) {
                *(float2*)(C + (size_t)row * ldc + col)       = make_float2(v0, v1);
                *(float2*)(C + (size_t)(row + 8) * ldc + col) = make_float2(v2, v3);
            } else {
                *(__half2*)(C2 + (size_t)row * Nout + col) =
                    __halves2half2(__float2half_rn(v0), __float2half_rn(v1));
                *(__half2*)(C2 + (size_t)(row + 8) * Nout + col) =
                    __halves2half2(__float2half_rn(v2), __float2half_rn(v3));
            }
        }
    }
}

static void gemm_p(int act, int outp,
                   const __half* A2, const __half* W2,
                   const float* bias, float* C, int ldc, __half* C2,
                   int M, int N, int K)
{
    dim3 grid(N / 128, M / 128);
    int T = K / 64;
    if (outp == 1)      gemm_tc2<1, 1><<<grid, 256, SMEM_G>>>(A2, K, W2, 2 * K, bias, nullptr, 0, C2, N, T);
    else if (act == 1)  gemm_tc2<1, 0><<<grid, 256, SMEM_G>>>(A2, K, W2, 2 * K, bias, C, ldc, nullptr, N, T);
    else                gemm_tc2<0, 0><<<grid, 256, SMEM_G>>>(A2, K, W2, 2 * K, bias, C, ldc, nullptr, N, T);
}

// =====================================================================
// fused weight plane conversion (2-plane weights, unchanged layout)
// =====================================================================
#define S1 1179648
#define S2 2359296
#define S3 2654208
#define S4 2949120
#define S5 3244032
#define S6 3538944
#define S7 3833856
#define S8 4128768

__global__ void cvt_all(const float* w1, const float* w2, const float* rq, const float* rk,
                        const float* rv, const float* ro, const float* sk, const float* sv,
                        __half* o1, __half* o2, __half* oqkv,
                        __half* oro, __half* oskv)
{
    int i = blockIdx.x * blockDim.x + threadIdx.x;
    if (i >= S8) return;
    const float* in; __half* out; int C, base, extra;
    if      (i < S1) { in = w1; out = o1;   C = Hd; base = 0;  extra = 0; }
    else if (i < S2) { in = w2; out = o2;   C = DI; base = S1; extra = 0; }
    else if (i < S3) { in = rq; out = oqkv;                        C = Hd; base = S2; extra = 1536; }
    else if (i < S4) { in = rk; out = oqkv + (size_t)768 * 2 * Hd; C = Hd; base = S3; extra = 1536; }
    else if (i < S5) { in = rv; out = oqkv + (size_t)1536 * 2 * Hd;C = Hd; base = S4; extra = 1536; }
    else if (i < S6) { in = ro; out = oro;  C = Hd; base = S5; extra = 0; }
    else if (i < S7) { in = sk; out = oskv;                        C = Hd; base = S6; extra = 768; }
    else             { in = sv; out = oskv + (size_t)768 * 2 * Hd; C = Hd; base = S7; extra = 768; }
    int e = (i - base) * 4;
    int r = e / C, c = e % C;
    size_t ro_ = (size_t)r + (size_t)(r / Hd) * extra;
    if (extra == 0 && C == DI) ro_ = r;
    float4 f = *(const float4*)(in + e);
    __half h0, h1, h2, h3, l0, l1, l2, l3;
    split_hl(f.x, h0, l0); split_hl(f.y, h1, l1);
    split_hl(f.z, h2, l2); split_hl(f.w, h3, l3);
    __half* p = out + ro_ * (2 * C) + 32 * (c >> 4) + (c & 15);
    *(__half2*)(p)      = __halves2half2(h0, h1);
    *(__half2*)(p + 2)  = __halves2half2(h2, h3);
    *(__half2*)(p + 16) = __halves2half2(l0, l1);
    *(__half2*)(p + 18) = __halves2half2(l2, l3);
}

__global__ void concat_bias(const float* bq, const float* bk, const float* bv,
                            const float* sk, const float* sv,
                            float* oqkv, float* oskv)
{
    int i = blockIdx.x * blockDim.x + threadIdx.x;
    int n1 = NLAYERS * 3 * Hd;
    if (i < n1) {
        int layer = i / (3 * Hd), c = i % (3 * Hd);
        const float* s = (c < Hd) ? bq : (c < 2 * Hd) ? bk : bv;
        oqkv[i] = s[layer * Hd + (c % Hd)];
    } else if (i < n1 + NLAYERS * 2 * Hd) {
        int j = i - n1;
        int layer = j / (2 * Hd), c = j % (2 * Hd);
        const float* s = (c < Hd) ? sk : sv;
        oskv[j] = s[layer * Hd + (c % Hd)];
    }
}

// =====================================================================
// Small-M GEMMs (M=8)
// =====================================================================
__device__ __forceinline__ void smalldot8(const float* __restrict__ A, int lda,
                                          const float* __restrict__ wrow, int K,
                                          int lane, float* s)
{
    const float4* w4 = (const float4*)wrow;
    int K4 = K >> 2;
#pragma unroll
    for (int m = 0; m < 8; m++) s[m] = 0.f;
    for (int k = lane; k < K4; k += 32) {
        float4 w = w4[k];
#pragma unroll
        for (int m = 0; m < 8; m++) {
            float4 a = ((const float4*)(A + (size_t)m * lda))[k];
            s[m] += a.x * w.x + a.y * w.y + a.z * w.z + a.w * w.w;
        }
    }
#pragma unroll
    for (int m = 0; m < 8; m++)
#pragma unroll
        for (int o = 16; o; o >>= 1) s[m] += __shfl_xor_sync(0xffffffffu, s[m], o);
}

__global__ __launch_bounds__(256)
void gemm_small8(const float* __restrict__ A, int lda,
                 const float* __restrict__ W, int ldw,
                 const float* __restrict__ bias,
                 float* __restrict__ C, int ldc,
                 int N, int K, int act)
{
    int n = (blockIdx.x * blockDim.x + threadIdx.x) >> 5;
    int lane = threadIdx.x & 31;
    if (n >= N) return;
    float s[8];
    smalldot8(A, lda, W + (size_t)n * ldw, K, lane, s);
    if (lane == 0) {
        float bv = bias[n];
#pragma unroll
        for (int m = 0; m < 8; m++) {
            float v = s[m] + bv;
            if (act == 1) v = fmaxf(v, 0.f);
            else if (act == 2) v = v > 0.f ? v : LEAKY * v;
            C[(size_t)m * ldc + n] = v;
        }
    }
}

__global__ __launch_bounds__(256)
void gemm_rel2(const float* __restrict__ relay,
               const float* __restrict__ wk, const float* __restrict__ bk,
               const float* __restrict__ wv, const float* __restrict__ bv,
               float* __restrict__ rk, float* __restrict__ rv)
{
    int n = (blockIdx.x * blockDim.x + threadIdx.x) >> 5;
    int lane = threadIdx.x & 31;
    if (n >= 2 * Hd) return;
    int seg = n >= Hd, c = n - seg * Hd;
    const float* W = seg ? wv : wk;
    const float* B = seg ? bv : bk;
    float* C = seg ? rv : rk;
    float s[8];
    smalldot8(relay, Hd, W + (size_t)c * Hd, Hd, lane, s);
    if (lane == 0) {
        float bb = B[c];
#pragma unroll
        for (int m = 0; m < 8; m++) C[(size_t)m * Hd + c] = s[m] + bb;
    }
}

__global__ __launch_bounds__(256)
void gemm_rel3(const float* __restrict__ relay,
               const float* __restrict__ wq, const float* __restrict__ bq,
               const float* __restrict__ wk, const float* __restrict__ bk,
               const float* __restrict__ wv, const float* __restrict__ bv,
               float* __restrict__ sq, float* __restrict__ rk, float* __restrict__ rv)
{
    int n = (blockIdx.x * blockDim.x + threadIdx.x) >> 5;
    int lane = threadIdx.x & 31;
    if (n >= 3 * Hd) return;
    int seg = n / Hd, c = n % Hd;
    const float* W = (seg == 0) ? wq : (seg == 1) ? wk : wv;
    const float* B = (seg == 0) ? bq : (seg == 1) ? bk : bv;
    float* C = (seg == 0) ? sq : (seg == 1) ? rk : rv;
    float s[8];
    smalldot8(relay, Hd, W + (size_t)c * Hd, Hd, lane, s);
    if (lane == 0) {
        float bb = B[c];
#pragma unroll
        for (int m = 0; m < 8; m++) C[(size_t)m * Hd + c] = s[m] + bb;
    }
}

__global__ __launch_bounds__(256)
void head2_kernel(const float* __restrict__ hid,
                  const float* __restrict__ w2,
                  const float* __restrict__ b2,
                  float* __restrict__ out)
{
    int n = (blockIdx.x * blockDim.x + threadIdx.x) >> 5;
    int lane = threadIdx.x & 31;
    if (n >= 3 * NOUT) return;
    int j = n / NOUT, c = n % NOUT;
    float s[8];
    smalldot8(hid + j * NHID, 3 * NHID, w2 + (size_t)n * NHID, NHID, lane, s);
    if (lane == 0) {
        float bb = b2[n];
#pragma unroll
        for (int m = 0; m < 8; m++)
            out[((size_t)m * 3 + j) * NOUT + c] = s[m] + bb;
    }
}

// ---------------- block reductions ----------------
__device__ __forceinline__ float2 block_reduce_sum2(float a, float b)
{
    static __shared__ float sa[8], sb2[8];
    __syncthreads();
    int lane = threadIdx.x & 31, w = threadIdx.x >> 5;
#pragma unroll
    for (int o = 16; o; o >>= 1) {
        a += __shfl_xor_sync(0xffffffffu, a, o);
        b += __shfl_xor_sync(0xffffffffu, b, o);
    }
    if (lane == 0) { sa[w] = a; sb2[w] = b; }
    __syncthreads();
    if (w == 0) {
        a = lane < 8 ? sa[lane] : 0.f;
        b = lane < 8 ? sb2[lane] : 0.f;
#pragma unroll
        for (int o = 4; o; o >>= 1) {
            a += __shfl_xor_sync(0xffffffffu, a, o);
            b += __shfl_xor_sync(0xffffffffu, b, o);
        }
        if (lane == 0) { sa[0] = a; sb2[0] = b; }
    }
    __syncthreads();
    return make_float2(sa[0], sb2[0]);
}
__device__ __forceinline__ float block_reduce_max(float a)
{
    static __shared__ float sm[8];
    __syncthreads();
    int lane = threadIdx.x & 31, w = threadIdx.x >> 5;
#pragma unroll
    for (int o = 16; o; o >>= 1) a = fmaxf(a, __shfl_xor_sync(0xffffffffu, a, o));
    if (lane == 0) sm[w] = a;
    __syncthreads();
    if (w == 0) {
        a = lane < 8 ? sm[lane] : -1e30f;
#pragma unroll
        for (int o = 4; o; o >>= 1) a = fmaxf(a, __shfl_xor_sync(0xffffffffu, a, o));
        if (lane == 0) sm[0] = a;
    }
    __syncthreads();
    return sm[0];
}
__device__ __forceinline__ float block_reduce_sum(float a)
{
    static __shared__ float ss[8];
    __syncthreads();
    int lane = threadIdx.x & 31, w = threadIdx.x >> 5;
#pragma unroll
    for (int o = 16; o; o >>= 1) a += __shfl_xor_sync(0xffffffffu, a, o);
    if (lane == 0) ss[w] = a;
    __syncthreads();
    if (w == 0) {
        a = lane < 8 ? ss[lane] : 0.f;
#pragma unroll
        for (int o = 4; o; o >>= 1) a += __shfl_xor_sync(0xffffffffu, a, o);
        if (lane == 0) ss[0] = a;
    }
    __syncthreads();
    return ss[0];
}

// ---------------- embed + mask ----------------
__global__ void embed_kernel(const int* __restrict__ src, const float* __restrict__ emb,
                             const float* __restrict__ pos, float* __restrict__ x,
                             __half* __restrict__ x2, int* __restrict__ mask)
{
    int idx = blockIdx.x * blockDim.x + threadIdx.x;
    if (idx >= ML * Hd) return;
    int h = idx % Hd;
    int bl = idx / Hd;
    int l = bl % Lx;
    int w = h >> 8;
    int dd = h & 255;
    int tok = src[bl * 3 + w];
    float v = emb[tok * 256 + dd] + pos[l * Hd + h];
    x[idx] = v;
    x2[idx] = __float2half_rn(v);
    if (h == 0) mask[bl] = (src[bl * 3] == 0) ? 1 : 0;
}

// ---------------- relay mean: 2-stage ----------------
__global__ void relay_part_kernel(const float* __restrict__ x, float* __restrict__ part)
{
    int h = blockIdx.x * 128 + threadIdx.x;
    int ch = blockIdx.y;
    int b = blockIdx.z;
    const float* p = x + (size_t)b * Lx * Hd + (size_t)ch * 64 * Hd + h;
    float s = 0.f;
#pragma unroll 8
    for (int l = 0; l < 64; l++) s += p[(size_t)l * Hd];
    part[((size_t)b * 16 + ch) * Hd + h] = s;
}
__global__ void relay_fin_kernel(const float* __restrict__ part, float* __restrict__ relay)
{
    int h = blockIdx.x * 128 + threadIdx.x;
    int b = blockIdx.y;
    float s = 0.f;
#pragma unroll
    for (int ch = 0; ch < 16; ch++) s += part[((size_t)b * 16 + ch) * Hd + h];
    relay[b * Hd + h] = s * (1.0f / Lx);
}

// ---------------- layernorm ----------------
template<int RES, int ACT, int MODE, int MASKED>
__global__ __launch_bounds__(256)
void ln_kernel(const float* __restrict__ x, const float* __restrict__ res,
               const float* __restrict__ g, const float* __restrict__ b,
               float* __restrict__ out, __half* __restrict__ out2,
               const int* __restrict__ mask)
{
    int row = blockIdx.x;
    const float* xr = x + (size_t)row * Hd;
    const float* rr = RES ? res + (size_t)row * Hd : nullptr;
    int mrow = MASKED ? mask[row] : 0;
    float t[3];
    float s = 0.f, ss = 0.f;
#pragma unroll
    for (int j = 0; j < 3; j++) {
        int i = threadIdx.x + j * 256;
        float v = xr[i];
        if (RES) v += rr[i];
        t[j] = v;
        s += v; ss += v * v;
    }
    float2 r = block_reduce_sum2(s, ss);
    float mu = r.x * (1.0f / Hd);
    float var = r.y * (1.0f / Hd) - mu * mu;
    float rstd = rsqrtf(var + 1e-5f);
#pragma unroll
    for (int j = 0; j < 3; j++) {
        int i = threadIdx.x + j * 256;
        float v = (t[j] - mu) * rstd * g[i] + b[i];
        if (ACT == 2) v = v > 0.f ? v : LEAKY * v;
        if (MASKED && mrow) v = 0.f;
        if (MODE != 1) out[(size_t)row * Hd + i] = v;
        if (MODE != 0) out2[(size_t)row * Hd + i] = __float2half_rn(v);
    }
}

// ---------------- ring attention ----------------
__global__ __launch_bounds__(256)
void ring_attn_kernel(const float* __restrict__ qkv, const float* __restrict__ rk,
                      const float* __restrict__ rv, __half* __restrict__ out2)
{
    int gw = (blockIdx.x * blockDim.x + threadIdx.x) >> 5;
    int lane = threadIdx.x & 31;
    int n = gw % NHd;
    int bl = gw / NHd;
    int l = bl % Lx;
    int b = bl / Lx;

    const float* qp = qkv + (size_t)bl * (3 * Hd) + n * HDd;
    float q0 = qp[lane * 2], q1 = qp[lane * 2 + 1];

    float s[4];
#pragma unroll
    for (int w = 0; w < 3; w++) {
        int ll = l - 1 + w;
        float d = 0.f;
        if (ll >= 0 && ll < Lx) {
            const float* kp = qkv + ((size_t)(b * Lx + ll)) * (3 * Hd) + Hd + n * HDd;
            d = q0 * kp[lane * 2] + q1 * kp[lane * 2 + 1];
        }
#pragma unroll
        for (int o = 16; o; o >>= 1) d += __shfl_xor_sync(0xffffffffu, d, o);
        s[w] = d * SCALE_ATT;
    }
    {
        const float* kp = rk + b * Hd + n * HDd;
        float d = q0 * kp[lane * 2] + q1 * kp[lane * 2 + 1];
#pragma unroll
        for (int o = 16; o; o >>= 1) d += __shfl_xor_sync(0xffffffffu, d, o);
        s[3] = d * SCALE_ATT;
    }
    float m = fmaxf(fmaxf(s[0], s[1]), fmaxf(s[2], s[3]));
    float e[4], se = 0.f;
#pragma unroll
    for (int w = 0; w < 4; w++) { e[w] = expf(s[w] - m); se += e[w]; }
    float inv = 1.0f / se;

    float o0 = 0.f, o1 = 0.f;
#pragma unroll
    for (int w = 0; w < 3; w++) {
        int ll = l - 1 + w;
        if (ll >= 0 && ll < Lx) {
            const float* vp = qkv + ((size_t)(b * Lx + ll)) * (3 * Hd) + 2 * Hd + n * HDd;
            float p = e[w] * inv;
            o0 += p * vp[lane * 2];
            o1 += p * vp[lane * 2 + 1];
        }
    }
    {
        const float* vp = rv + b * Hd + n * HDd;
        float p = e[3] * inv;
        o0 += p * vp[lane * 2];
        o1 += p * vp[lane * 2 + 1];
    }
    int c0 = n * HDd + lane * 2;
    *(__half2*)(out2 + (size_t)bl * Hd + c0) =
        __halves2half2(__float2half_rn(o0), __float2half_rn(o1));
}

// ---------------- star attention ----------------
__global__ __launch_bounds__(256)
void star_attn_kernel(const float* __restrict__ sq, const float* __restrict__ kv,
                      const float* __restrict__ rk, const float* __restrict__ rv,
                      const int* __restrict__ mask, float* __restrict__ out)
{
    __shared__ float qs[HDd];
    __shared__ float sc[Lx + 1];
    __shared__ float red[4 * HDd];

    int b = blockIdx.x / NHd;
    int n = blockIdx.x % NHd;
    int tid = threadIdx.x;

    if (tid < HDd) qs[tid] = sq[b * Hd + n * HDd + tid];
    __syncthreads();

    float lmax = -1e30f;
    for (int s = tid; s < Lx + 1; s += 256) {
        const float* kp = (s == 0) ? rk + b * Hd + n * HDd
                                   : kv + ((size_t)(b * Lx + s - 1)) * (2 * Hd) + n * HDd;
        float d = 0.f;
#pragma unroll
        for (int i = 0; i < HDd; i++) d += qs[i] * kp[i];
        d *= SCALE_ATT;
        if (s > 0 && mask[b * Lx + s - 1]) d = -1e30f;
        sc[s] = d;
        lmax = fmaxf(lmax, d);
    }
    float bmax = block_reduce_max(lmax);

    float lsum = 0.f;
    for (int s = tid; s < Lx + 1; s += 256) {
        float ev = expf(sc[s] - bmax);
        sc[s] = ev;
        lsum += ev;
    }
    float bsum = block_reduce_sum(lsum);

    int gg = tid >> 6;
    int dd = tid & 63;
    float acc = 0.f;
    for (int s = gg; s < Lx + 1; s += 4) {
        const float* vp = (s == 0) ? rv + b * Hd + n * HDd
                                   : kv + ((size_t)(b * Lx + s - 1)) * (2 * Hd) + Hd + n * HDd;
        acc += sc[s] * vp[dd];
    }
    red[gg * HDd + dd] = acc;
    __syncthreads();
    if (tid < HDd) {
        float r = red[tid] + red[HDd + tid] + red[2 * HDd + tid] + red[3 * HDd + tid];
        out[b * Hd + n * HDd + tid] = r / bsum;
    }
}

// ---------------- gather ft ----------------
__global__ void gather_ft_kernel(const float* __restrict__ relay, const float* __restrict__ nodes,
                                 const int* __restrict__ positions, float* __restrict__ ft)
{
    int idx = blockIdx.x * blockDim.x + threadIdx.x;
    if (idx >= Bx * 2 * Hd) return;
    int b = idx / (2 * Hd);
    int i = idx % (2 * Hd);
    float v;
    if (i < Hd) v = relay[b * Hd + i];
    else        v = nodes[((size_t)b * Lx + positions[b]) * Hd + (i - Hd)];
    ft[idx] = v;
}

// ---------------- launch ----------------
extern "C" void kernel_launch(void* const* d_in, const int* in_sizes, int n_in,
                              void* d_out, int out_size)
{
    const int*   src       = (const int*)  d_in[0];
    const int*   positions = (const int*)  d_in[1];
    const float* emb       = (const float*)d_in[2];
    const float* pos_table = (const float*)d_in[3];
    const float* norm_g    = (const float*)d_in[4];
    const float* norm_b    = (const float*)d_in[5];
    const float* pw_w1     = (const float*)d_in[6];
    const float* pw_b1     = (const float*)d_in[7];
    const float* pw_w2     = (const float*)d_in[8];
    const float* pw_b2     = (const float*)d_in[9];
    const float* pw_g      = (const float*)d_in[10];
    const float* pw_bn     = (const float*)d_in[11];
    const float* ring_wq   = (const float*)d_in[12];
    const float* ring_bq   = (const float*)d_in[13];
    const float* ring_wk   = (const float*)d_in[14];
    const float* ring_bk   = (const float*)d_in[15];
    const float* ring_wv   = (const float*)d_in[16];
    const float* ring_bv   = (const float*)d_in[17];
    const float* ring_wo   = (const float*)d_in[18];
    const float* ring_bo   = (const float*)d_in[19];
    const float* star_wq   = (const float*)d_in[20];
    const float* star_bq   = (const float*)d_in[21];
    const float* star_wk   = (const float*)d_in[22];
    const float* star_bk   = (const float*)d_in[23];
    const float* star_wv   = (const float*)d_in[24];
    const float* star_bv   = (const float*)d_in[25];
    const float* star_wo   = (const float*)d_in[26];
    const float* star_bo   = (const float*)d_in[27];
    const float* head_w1   = (const float*)d_in[28];
    const float* head_b1   = (const float*)d_in[29];
    const float* head_w2   = (const float*)d_in[30];
    const float* head_b2   = (const float*)d_in[31];
    float* out = (float*)d_out;

    cudaFuncSetAttribute(gemm_tc2<0, 0>, cudaFuncAttributeMaxDynamicSharedMemorySize, SMEM_G);
    cudaFuncSetAttribute(gemm_tc2<1, 0>, cudaFuncAttributeMaxDynamicSharedMemorySize, SMEM_G);
    cudaFuncSetAttribute(gemm_tc2<1, 1>, cudaFuncAttributeMaxDynamicSharedMemorySize, SMEM_G);

    float *x, *qkv, *kv, *ring, *relay, *part, *rk, *rv, *sq, *satt, *ft, *hid, *bqkv, *bskv;
    int* mask;
    __half *x2, *h2, *att2, *mid2;
    __half *w1p, *w2p, *qkvp, *rop, *skvp;
    cudaGetSymbolAddress((void**)&x, g_x);
    cudaGetSymbolAddress((void**)&qkv, g_qkv);
    cudaGetSymbolAddress((void**)&kv, g_kv);
    cudaGetSymbolAddress((void**)&ring, g_ring);
    cudaGetSymbolAddress((void**)&relay, g_relay);
    cudaGetSymbolAddress((void**)&part, g_part);
    cudaGetSymbolAddress((void**)&rk, g_rk);
    cudaGetSymbolAddress((void**)&rv, g_rv);
    cudaGetSymbolAddress((void**)&sq, g_sq);
    cudaGetSymbolAddress((void**)&satt, g_satt);
    cudaGetSymbolAddress((void**)&ft, g_ft);
    cudaGetSymbolAddress((void**)&hid, g_hid);
    cudaGetSymbolAddress((void**)&mask, g_mask);
    cudaGetSymbolAddress((void**)&x2, g_x2);
    cudaGetSymbolAddress((void**)&h2, g_h2);
    cudaGetSymbolAddress((void**)&att2, g_att2);
    cudaGetSymbolAddress((void**)&mid2, g_mid2);
    cudaGetSymbolAddress((void**)&w1p, g_w1p);
    cudaGetSymbolAddress((void**)&w2p, g_w2p);
    cudaGetSymbolAddress((void**)&qkvp, g_qkvp);
    cudaGetSymbolAddress((void**)&rop, g_rop);
    cudaGetSymbolAddress((void**)&skvp, g_skvp);
    cudaGetSymbolAddress((void**)&bqkv, g_bqkv);
    cudaGetSymbolAddress((void**)&bskv, g_bskv);

    const int M = ML;

    cvt_all<<<(S8 + 255) / 256, 256>>>(pw_w1, pw_w2, ring_wq, ring_wk, ring_wv, ring_wo,
                                       star_wk, star_wv, w1p, w2p, qkvp, rop, skvp);   // 0
    concat_bias<<<(NLAYERS * 5 * Hd + 255) / 256, 256>>>(ring_bq, ring_bk, ring_bv,
                                                          star_bk, star_bv, bqkv, bskv); // 1
    embed_kernel<<<(ML * Hd + 255) / 256, 256>>>(src, emb, pos_table, x, x2, mask);      // 2

    bool relay_done = false;
    for (int i = 0; i < NLAYERS; i++) {
        const float* b1 = pw_b1 + (size_t)i * DI;
        const float* b2 = pw_b2 + (size_t)i * Hd;
        const float* pg = pw_g + (size_t)i * Hd;
        const float* pb = pw_bn + (size_t)i * Hd;
        const float* rbk = ring_bk + (size_t)i * Hd;
        const float* rbv = ring_bv + (size_t)i * Hd;
        const float* rbo = ring_bo + (size_t)i * Hd;
        const float* ng = norm_g + (size_t)i * Hd;
        const float* nb = norm_b + (size_t)i * Hd;
        const float* rwk = ring_wk + (size_t)i * Hd * Hd;
        const float* rwv = ring_wv + (size_t)i * Hd * Hd;
        const __half* w1i = w1p + (size_t)i * DI * 2 * Hd;
        const __half* w2i = w2p + (size_t)i * Hd * 2 * DI;
        const __half* qkvi = qkvp + (size_t)i * 3 * Hd * 2 * Hd;
        const __half* roi = rop + (size_t)i * Hd * 2 * Hd;
        const __half* skvi = skvp + (size_t)i * 2 * Hd * 2 * Hd;
        const float* bqkvi = bqkv + (size_t)i * 3 * Hd;
        const float* bskvi = bskv + (size_t)i * 2 * Hd;

        // PWFF
        gemm_p(1, 1, x2, w1i, b1, nullptr, 0, mid2, M, DI, Hd);       // launch 3 = profiled
        gemm_p(0, 0, mid2, w2i, b2, ring, Hd, nullptr, M, Hd, DI);
        ln_kernel<1, 0, 1, 0><<<M, 256>>>(ring, x, pg, pb, nullptr, h2, nullptr);

        if (!relay_done) {
            dim3 gp(6, 16, Bx);
            relay_part_kernel<<<gp, 128>>>(x, part);
            dim3 gf(6, Bx);
            relay_fin_kernel<<<gf, 128>>>(part, relay);
            relay_done = true;
        }

        // Ring attention
        gemm_p(0, 0, h2, qkvi, bqkvi, qkv, 3 * Hd, nullptr, M, 3 * Hd, Hd);
        gemm_rel2<<<(2 * Hd * 32 + 255) / 256, 256>>>(relay, rwk, rbk, rwv, rbv, rk, rv);
        ring_attn_kernel<<<(M * NHd) / 8, 256>>>(qkv, rk, rv, att2);
        gemm_p(0, 0, att2, roi, rbo, ring, Hd, nullptr, M, Hd, Hd);
        ln_kernel<0, 2, 2, 1><<<M, 256>>>(ring, nullptr, ng, nb, x, x2, mask);

        // Star attention
        gemm_rel3<<<(3 * Hd * 32 + 255) / 256, 256>>>(relay,
            star_wq + (size_t)i * Hd * Hd, star_bq + (size_t)i * Hd,
            star_wk + (size_t)i * Hd * Hd, star_bk + (size_t)i * Hd,
            star_wv + (size_t)i * Hd * Hd, star_bv + (size_t)i * Hd,
            sq, rk, rv);
        gemm_p(0, 0, x2, skvi, bskvi, kv, 2 * Hd, nullptr, M, 2 * Hd, Hd);
        star_attn_kernel<<<Bx * NHd, 256>>>(sq, kv, rk, rv, mask, satt);
        gemm_small8<<<(Hd * 32 + 255) / 256, 256>>>(satt, Hd,
            star_wo + (size_t)i * Hd * Hd, Hd, star_bo + (size_t)i * Hd,
            relay, Hd, Hd, Hd, 2);
    }

    // heads
    gather_ft_kernel<<<(Bx * 2 * Hd + 255) / 256, 256>>>(relay, x, positions, ft);
    gemm_small8<<<(3 * NHID * 32 + 255) / 256, 256>>>(ft, 2 * Hd, head_w1, 2 * Hd,
                                                      head_b1, hid, 3 * NHID,
                                                      3 * NHID, 2 * Hd, 1);
    head2_kernel<<<(3 * NOUT * 32 + 255) / 256, 256>>>(hid, head_w2, head_b2, out);
}

// round 12
// speedup vs baseline: 1.6190x; 1.0134x over previous
#include <cuda_runtime.h>
#include <cuda_fp16.h>
#include <math.h>
#include <stdint.h>

// ---------------- problem constants ----------------
#define Bx 8
#define Lx 1024
#define Hd 768
#define NHd 12
#define HDd 64
#define DI 3072
#define NLAYERS 2
#define NHID 1024
#define NOUT 5000
#define SCALE_ATT 0.125f
#define LEAKY 0.01f
#define ML (Bx*Lx)      // 8192

// ---------------- fp32 scratch ----------------
__device__ float g_x    [ML*Hd];
__device__ float g_qkv  [ML*3*Hd];
__device__ float g_kv   [ML*2*Hd];
__device__ float g_ring [ML*Hd];
__device__ float g_ring2[ML*Hd];     // split-K partial
__device__ float g_relay[Bx*Hd];
__device__ float g_part[Bx*16*Hd];
__device__ float g_rk  [Bx*Hd];
__device__ float g_rv  [Bx*Hd];
__device__ float g_sq  [Bx*Hd];
__device__ float g_srk [Bx*Hd];
__device__ float g_srv [Bx*Hd];
__device__ float g_satt[Bx*Hd];
__device__ float g_ft  [Bx*2*Hd];
__device__ float g_hid [Bx*3*NHID];
__device__ int   g_mask[Bx*Lx];

// ---------------- fp16 activation scratch (hi-only, plain row-major) ----------------
__device__ __half g_x2  [ML*Hd];
__device__ __half g_h2  [ML*Hd];
__device__ __half g_att2[ML*Hd];
__device__ __half g_mid2[(size_t)ML*DI];
// weights: 2-plane layout (per 16-group: 16 hi then 16 lo), row stride 2K
__device__ __half g_w1p [(size_t)NLAYERS*DI*2*Hd];
__device__ __half g_w2p [(size_t)NLAYERS*Hd*2*DI];
__device__ __half g_qkvp[(size_t)NLAYERS*3*Hd*2*Hd];
__device__ __half g_rop [(size_t)NLAYERS*Hd*2*Hd];
__device__ __half g_skvp[(size_t)NLAYERS*2*Hd*2*Hd];
__device__ float g_bqkv[NLAYERS*3*Hd];
__device__ float g_bskv[NLAYERS*2*Hd];

// ---------------- helpers ----------------
__device__ __forceinline__ uint32_t cvta_s(const void* p) {
    return (uint32_t)__cvta_generic_to_shared(p);
}
__device__ __forceinline__ void ldsm4(uint32_t* r, uint32_t addr) {
    asm volatile("ldmatrix.sync.aligned.m8n8.x4.shared.b16 {%0,%1,%2,%3}, [%4];\n"
                 : "=r"(r[0]), "=r"(r[1]), "=r"(r[2]), "=r"(r[3]) : "r"(addr));
}
__device__ __forceinline__ void mma16816(float* c, const uint32_t* a, const uint32_t* b) {
    asm volatile("mma.sync.aligned.m16n8k16.row.col.f32.f16.f16.f32 "
                 "{%0,%1,%2,%3},{%4,%5,%6,%7},{%8,%9},{%0,%1,%2,%3};\n"
                 : "+f"(c[0]), "+f"(c[1]), "+f"(c[2]), "+f"(c[3])
                 : "r"(a[0]), "r"(a[1]), "r"(a[2]), "r"(a[3]), "r"(b[0]), "r"(b[1]));
}
__device__ __forceinline__ void cp16(uint32_t s, const void* g) {
    asm volatile("cp.async.cg.shared.global [%0], [%1], 16;\n" :: "r"(s), "l"(g));
}
__device__ __forceinline__ void split_hl(float v, __half& hi, __half& lo) {
    hi = __float2half_rn(v);
    lo = __float2half_rn(v - __half2float(hi));
}
__device__ __forceinline__ uint32_t sw128(uint32_t o) { return o ^ ((o >> 3) & 0x70); }

// =====================================================================
// Tensor-core GEMM, 128x128 CTA tile, 2x4 warps, 2-stage pipeline,
// 64 fp32-k per chunk. A: plain fp16 hi [M,K]. W: 2-plane [N,2K].
//   C = act(A@W^T + bias); products: Ah*Bh + Ah*Bl.
// grid.z = 2 enables internal split-K: z=1 computes the second K-half
// into Cs with zero bias (combined later by the consumer LN).
// =====================================================================
#define ATB 16384
#define BUFB (3*16384)               // 48 KB
#define SMEM_G (2*BUFB)              // 96 KB

__device__ __forceinline__ void fill_tile(uint32_t base, const __half* A2, int lda,
                                          const __half* W2, int ldw2,
                                          int bm, int bn, int kc, int tid)
{
#pragma unroll
    for (int j = 0; j < 4; j++) {
        int idx = tid + j * 256;
        int row = idx >> 3, c16 = idx & 7;
        cp16(base + sw128((uint32_t)(row * 128 + c16 * 16)),
             A2 + (size_t)(bm + row) * lda + kc * 64 + c16 * 8);
    }
#pragma unroll
    for (int s = 0; s < 2; s++)
#pragma unroll
        for (int j = 0; j < 4; j++) {
            int idx = tid + j * 256;
            int row = idx >> 3, c16 = idx & 7;
            cp16(base + ATB + s * 16384 + sw128((uint32_t)(row * 128 + c16 * 16)),
                 W2 + (size_t)(bn + row) * ldw2 + kc * 128 + s * 64 + c16 * 8);
        }
}

template<int ACT, int OUTP>
__global__ __launch_bounds__(256, 2)
void gemm_tc2(const __half* __restrict__ A2, int lda,
              const __half* __restrict__ W2, int ldw2,
              const float* __restrict__ bias,
              float* __restrict__ C, int ldc,
              __half* __restrict__ C2, int Nout,
              float* __restrict__ Cs,          // split-K z=1 output
              int kAoff, int kWoff,            // per-z offsets (halves)
              int T)
{
    extern __shared__ __align__(128) char smraw[];
    const uint32_t sb = cvta_s(smraw);

    const int zz = blockIdx.z;
    if (zz) { A2 += kAoff; W2 += kWoff; }

    const int tid  = threadIdx.x;
    const int lane = tid & 31;
    const int warp = tid >> 5;
    const int wm = warp >> 2;
    const int wn = warp & 3;
    const int bm = blockIdx.y * 128;
    const int bn = blockIdx.x * 128;

    float acc[4][4][4];
#pragma unroll
    for (int i = 0; i < 4; i++)
#pragma unroll
        for (int j = 0; j < 4; j++)
#pragma unroll
            for (int c = 0; c < 4; c++) acc[i][j][c] = 0.f;

    const int a_row = lane & 15;
    const int a_kb  = (lane >> 4) * 16;
    const int b_row = (lane & 7) + ((lane >> 4) << 3);
    const int b_kb  = ((lane >> 3) & 1) * 16;

    fill_tile(sb, A2, lda, W2, ldw2, bm, bn, 0, tid);
    asm volatile("cp.async.commit_group;\n");

    for (int t = 0; t < T; t++) {
        __syncthreads();
        if (t + 1 < T) {
            fill_tile(sb + ((t + 1) & 1) * BUFB, A2, lda, W2, ldw2, bm, bn, t + 1, tid);
            asm volatile("cp.async.commit_group;\n");
            asm volatile("cp.async.wait_group 1;\n");
        } else {
            asm volatile("cp.async.wait_group 0;\n");
        }
        __syncthreads();

        const uint32_t ab = sb + (t & 1) * BUFB;
        const uint32_t bb = ab + ATB;

#pragma unroll
        for (int g2 = 0; g2 < 4; g2++) {
            const uint32_t bsub = bb + (g2 >> 1) * 16384;
            const int gb = (g2 & 1) * 64;
            uint32_t bh[2][4], afh[4][4], bl_[2][4];
#pragma unroll
            for (int p = 0; p < 2; p++) {
                int row = wn * 32 + p * 16 + b_row;
                ldsm4(bh[p], bsub + sw128((uint32_t)(row * 128 + gb + b_kb)));
            }
#pragma unroll
            for (int mt = 0; mt < 4; mt++) {
                int row = wm * 64 + mt * 16 + a_row;
                ldsm4(afh[mt], ab + sw128((uint32_t)(row * 128 + g2 * 32 + a_kb)));
            }
#pragma unroll
            for (int p = 0; p < 2; p++) {
                int row = wn * 32 + p * 16 + b_row;
                ldsm4(bl_[p], bsub + sw128((uint32_t)(row * 128 + gb + 32 + b_kb)));
            }
#pragma unroll
            for (int mt = 0; mt < 4; mt++)
#pragma unroll
                for (int nt = 0; nt < 4; nt++)
                    mma16816(acc[mt][nt], afh[mt], &bh[nt >> 1][(nt & 1) * 2]);
#pragma unroll
            for (int mt = 0; mt < 4; mt++)
#pragma unroll
                for (int nt = 0; nt < 4; nt++)
                    mma16816(acc[mt][nt], afh[mt], &bl_[nt >> 1][(nt & 1) * 2]);
        }
    }

    // epilogue
    float* Co = zz ? Cs : C;
#pragma unroll
    for (int mt = 0; mt < 4; mt++) {
#pragma unroll
        for (int nt = 0; nt < 4; nt++) {
            int row = bm + wm * 64 + mt * 16 + (lane >> 2);
            int col = bn + wn * 32 + nt * 8 + (lane & 3) * 2;
            float bi0 = zz ? 0.f : bias[col];
            float bi1 = zz ? 0.f : bias[col + 1];
            float v0 = acc[mt][nt][0] + bi0;
            float v1 = acc[mt][nt][1] + bi1;
            float v2 = acc[mt][nt][2] + bi0;
            float v3 = acc[mt][nt][3] + bi1;
            if (ACT == 1) {
                v0 = fmaxf(v0, 0.f); v1 = fmaxf(v1, 0.f);
                v2 = fmaxf(v2, 0.f); v3 = fmaxf(v3, 0.f);
            }
            if (OUTP == 0) {
                *(float2*)(Co + (size_t)row * ldc + col)       = make_float2(v0, v1);
                *(float2*)(Co + (size_t)(row + 8) * ldc + col) = make_float2(v2, v3);
            } else {
                *(__half2*)(C2 + (size_t)row * Nout + col) =
                    __halves2half2(__float2half_rn(v0), __float2half_rn(v1));
                *(__half2*)(C2 + (size_t)(row + 8) * Nout + col) =
                    __halves2half2(__float2half_rn(v2), __float2half_rn(v3));
            }
        }
    }
}

static void gemm_p(int act, int outp, int split,
                   const __half* A2, const __half* W2,
                   const float* bias, float* C, int ldc, __half* C2, float* Cs,
                   int M, int N, int K)
{
    int Keff = split ? K / 2 : K;
    dim3 grid(N / 128, M / 128, split ? 2 : 1);
    int T = Keff / 64;
    int kAoff = Keff;          // halves within A row
    int kWoff = 2 * Keff;      // halves within W row (2-plane)
    if (outp == 1)      gemm_tc2<1, 1><<<grid, 256, SMEM_G>>>(A2, K, W2, 2 * K, bias, nullptr, 0, C2, N, nullptr, 0, 0, T);
    else if (act == 1)  gemm_tc2<1, 0><<<grid, 256, SMEM_G>>>(A2, K, W2, 2 * K, bias, C, ldc, nullptr, N, Cs, kAoff, kWoff, T);
    else                gemm_tc2<0, 0><<<grid, 256, SMEM_G>>>(A2, K, W2, 2 * K, bias, C, ldc, nullptr, N, Cs, kAoff, kWoff, T);
}

// =====================================================================
// fused weight plane conversion
// =====================================================================
#define S1 1179648
#define S2 2359296
#define S3 2654208
#define S4 2949120
#define S5 3244032
#define S6 3538944
#define S7 3833856
#define S8 4128768

__global__ void cvt_all(const float* w1, const float* w2, const float* rq, const float* rk,
                        const float* rv, const float* ro, const float* sk, const float* sv,
                        __half* o1, __half* o2, __half* oqkv,
                        __half* oro, __half* oskv)
{
    int i = blockIdx.x * blockDim.x + threadIdx.x;
    if (i >= S8) return;
    const float* in; __half* out; int C, base, extra;
    if      (i < S1) { in = w1; out = o1;   C = Hd; base = 0;  extra = 0; }
    else if (i < S2) { in = w2; out = o2;   C = DI; base = S1; extra = 0; }
    else if (i < S3) { in = rq; out = oqkv;                        C = Hd; base = S2; extra = 1536; }
    else if (i < S4) { in = rk; out = oqkv + (size_t)768 * 2 * Hd; C = Hd; base = S3; extra = 1536; }
    else if (i < S5) { in = rv; out = oqkv + (size_t)1536 * 2 * Hd;C = Hd; base = S4; extra = 1536; }
    else if (i < S6) { in = ro; out = oro;  C = Hd; base = S5; extra = 0; }
    else if (i < S7) { in = sk; out = oskv;                        C = Hd; base = S6; extra = 768; }
    else             { in = sv; out = oskv + (size_t)768 * 2 * Hd; C = Hd; base = S7; extra = 768; }
    int e = (i - base) * 4;
    int r = e / C, c = e % C;
    size_t ro_ = (size_t)r + (size_t)(r / Hd) * extra;
    if (extra == 0 && C == DI) ro_ = r;
    float4 f = *(const float4*)(in + e);
    __half h0, h1, h2, h3, l0, l1, l2, l3;
    split_hl(f.x, h0, l0); split_hl(f.y, h1, l1);
    split_hl(f.z, h2, l2); split_hl(f.w, h3, l3);
    __half* p = out + ro_ * (2 * C) + 32 * (c >> 4) + (c & 15);
    *(__half2*)(p)      = __halves2half2(h0, h1);
    *(__half2*)(p + 2)  = __halves2half2(h2, h3);
    *(__half2*)(p + 16) = __halves2half2(l0, l1);
    *(__half2*)(p + 18) = __halves2half2(l2, l3);
}

__global__ void concat_bias(const float* bq, const float* bk, const float* bv,
                            const float* sk, const float* sv,
                            float* oqkv, float* oskv)
{
    int i = blockIdx.x * blockDim.x + threadIdx.x;
    int n1 = NLAYERS * 3 * Hd;
    if (i < n1) {
        int layer = i / (3 * Hd), c = i % (3 * Hd);
        const float* s = (c < Hd) ? bq : (c < 2 * Hd) ? bk : bv;
        oqkv[i] = s[layer * Hd + (c % Hd)];
    } else if (i < n1 + NLAYERS * 2 * Hd) {
        int j = i - n1;
        int layer = j / (2 * Hd), c = j % (2 * Hd);
        const float* s = (c < Hd) ? sk : sv;
        oskv[j] = s[layer * Hd + (c % Hd)];
    }
}

// =====================================================================
// Small-M GEMMs (M=8)
// =====================================================================
__device__ __forceinline__ void smalldot8(const float* __restrict__ A, int lda,
                                          const float* __restrict__ wrow, int K,
                                          int lane, float* s)
{
    const float4* w4 = (const float4*)wrow;
    int K4 = K >> 2;
#pragma unroll
    for (int m = 0; m < 8; m++) s[m] = 0.f;
    for (int k = lane; k < K4; k += 32) {
        float4 w = w4[k];
#pragma unroll
        for (int m = 0; m < 8; m++) {
            float4 a = ((const float4*)(A + (size_t)m * lda))[k];
            s[m] += a.x * w.x + a.y * w.y + a.z * w.z + a.w * w.w;
        }
    }
#pragma unroll
    for (int m = 0; m < 8; m++)
#pragma unroll
        for (int o = 16; o; o >>= 1) s[m] += __shfl_xor_sync(0xffffffffu, s[m], o);
}

__global__ __launch_bounds__(256)
void gemm_small8(const float* __restrict__ A, int lda,
                 const float* __restrict__ W, int ldw,
                 const float* __restrict__ bias,
                 float* __restrict__ C, int ldc,
                 int N, int K, int act)
{
    int n = (blockIdx.x * blockDim.x + threadIdx.x) >> 5;
    int lane = threadIdx.x & 31;
    if (n >= N) return;
    float s[8];
    smalldot8(A, lda, W + (size_t)n * ldw, K, lane, s);
    if (lane == 0) {
        float bv = bias[n];
#pragma unroll
        for (int m = 0; m < 8; m++) {
            float v = s[m] + bv;
            if (act == 1) v = fmaxf(v, 0.f);
            else if (act == 2) v = v > 0.f ? v : LEAKY * v;
            C[(size_t)m * ldc + n] = v;
        }
    }
}

// all 5 relay projections in one launch: [ring_k | ring_v | star_q | star_k | star_v]
__global__ __launch_bounds__(256)
void gemm_rel5(const float* __restrict__ relay,
               const float* __restrict__ rwk, const float* __restrict__ rbk,
               const float* __restrict__ rwv, const float* __restrict__ rbv,
               const float* __restrict__ swq, const float* __restrict__ sbq,
               const float* __restrict__ swk, const float* __restrict__ sbk,
               const float* __restrict__ swv, const float* __restrict__ sbv,
               float* __restrict__ rk, float* __restrict__ rv, float* __restrict__ sq,
               float* __restrict__ srk, float* __restrict__ srv)
{
    int n = (blockIdx.x * blockDim.x + threadIdx.x) >> 5;
    int lane = threadIdx.x & 31;
    if (n >= 5 * Hd) return;
    int seg = n / Hd, c = n % Hd;
    const float* W = (seg == 0) ? rwk : (seg == 1) ? rwv : (seg == 2) ? swq : (seg == 3) ? swk : swv;
    const float* B = (seg == 0) ? rbk : (seg == 1) ? rbv : (seg == 2) ? sbq : (seg == 3) ? sbk : sbv;
    float* C       = (seg == 0) ? rk  : (seg == 1) ? rv  : (seg == 2) ? sq  : (seg == 3) ? srk : srv;
    float s[8];
    smalldot8(relay, Hd, W + (size_t)c * Hd, Hd, lane, s);
    if (lane == 0) {
        float bb = B[c];
#pragma unroll
        for (int m = 0; m < 8; m++) C[(size_t)m * Hd + c] = s[m] + bb;
    }
}

__global__ __launch_bounds__(256)
void head2_kernel(const float* __restrict__ hid,
                  const float* __restrict__ w2,
                  const float* __restrict__ b2,
                  float* __restrict__ out)
{
    int n = (blockIdx.x * blockDim.x + threadIdx.x) >> 5;
    int lane = threadIdx.x & 31;
    if (n >= 3 * NOUT) return;
    int j = n / NOUT, c = n % NOUT;
    float s[8];
    smalldot8(hid + j * NHID, 3 * NHID, w2 + (size_t)n * NHID, NHID, lane, s);
    if (lane == 0) {
        float bb = b2[n];
#pragma unroll
        for (int m = 0; m < 8; m++)
            out[((size_t)m * 3 + j) * NOUT + c] = s[m] + bb;
    }
}

// ---------------- block reductions (NW = warps per block) ----------------
template<int NW>
__device__ __forceinline__ float2 block_reduce_sum2(float a, float b)
{
    static __shared__ float sa[NW], sb2[NW];
    __syncthreads();
    int lane = threadIdx.x & 31, w = threadIdx.x >> 5;
#pragma unroll
    for (int o = 16; o; o >>= 1) {
        a += __shfl_xor_sync(0xffffffffu, a, o);
        b += __shfl_xor_sync(0xffffffffu, b, o);
    }
    if (lane == 0) { sa[w] = a; sb2[w] = b; }
    __syncthreads();
    if (w == 0) {
        a = lane < NW ? sa[lane] : 0.f;
        b = lane < NW ? sb2[lane] : 0.f;
#pragma unroll
        for (int o = NW / 2; o; o >>= 1) {
            a += __shfl_xor_sync(0xffffffffu, a, o);
            b += __shfl_xor_sync(0xffffffffu, b, o);
        }
        if (lane == 0) { sa[0] = a; sb2[0] = b; }
    }
    __syncthreads();
    return make_float2(sa[0], sb2[0]);
}
template<int NW>
__device__ __forceinline__ float block_reduce_max(float a)
{
    static __shared__ float sm[NW];
    __syncthreads();
    int lane = threadIdx.x & 31, w = threadIdx.x >> 5;
#pragma unroll
    for (int o = 16; o; o >>= 1) a = fmaxf(a, __shfl_xor_sync(0xffffffffu, a, o));
    if (lane == 0) sm[w] = a;
    __syncthreads();
    if (w == 0) {
        a = lane < NW ? sm[lane] : -1e30f;
#pragma unroll
        for (int o = NW / 2; o; o >>= 1) a = fmaxf(a, __shfl_xor_sync(0xffffffffu, a, o));
        if (lane == 0) sm[0] = a;
    }
    __syncthreads();
    return sm[0];
}
template<int NW>
__device__ __forceinline__ float block_reduce_sum(float a)
{
    static __shared__ float ss[NW];
    __syncthreads();
    int lane = threadIdx.x & 31, w = threadIdx.x >> 5;
#pragma unroll
    for (int o = 16; o; o >>= 1) a += __shfl_xor_sync(0xffffffffu, a, o);
    if (lane == 0) ss[w] = a;
    __syncthreads();
    if (w == 0) {
        a = lane < NW ? ss[lane] : 0.f;
#pragma unroll
        for (int o = NW / 2; o; o >>= 1) a += __shfl_xor_sync(0xffffffffu, a, o);
        if (lane == 0) ss[0] = a;
    }
    __syncthreads();
    return ss[0];
}

// ---------------- embed + mask ----------------
__global__ void embed_kernel(const int* __restrict__ src, const float* __restrict__ emb,
                             const float* __restrict__ pos, float* __restrict__ x,
                             __half* __restrict__ x2, int* __restrict__ mask)
{
    int idx = blockIdx.x * blockDim.x + threadIdx.x;
    if (idx >= ML * Hd) return;
    int h = idx % Hd;
    int bl = idx / Hd;
    int l = bl % Lx;
    int w = h >> 8;
    int dd = h & 255;
    int tok = src[bl * 3 + w];
    float v = emb[tok * 256 + dd] + pos[l * Hd + h];
    x[idx] = v;
    x2[idx] = __float2half_rn(v);
    if (h == 0) mask[bl] = (src[bl * 3] == 0) ? 1 : 0;
}

// ---------------- relay mean: 2-stage ----------------
__global__ void relay_part_kernel(const float* __restrict__ x, float* __restrict__ part)
{
    int h = blockIdx.x * 128 + threadIdx.x;
    int ch = blockIdx.y;
    int b = blockIdx.z;
    const float* p = x + (size_t)b * Lx * Hd + (size_t)ch * 64 * Hd + h;
    float s = 0.f;
#pragma unroll 8
    for (int l = 0; l < 64; l++) s += p[(size_t)l * Hd];
    part[((size_t)b * 16 + ch) * Hd + h] = s;
}
__global__ void relay_fin_kernel(const float* __restrict__ part, float* __restrict__ relay)
{
    int h = blockIdx.x * 128 + threadIdx.x;
    int b = blockIdx.y;
    float s = 0.f;
#pragma unroll
    for (int ch = 0; ch < 16; ch++) s += part[((size_t)b * 16 + ch) * Hd + h];
    relay[b * Hd + h] = s * (1.0f / Lx);
}

// ---------------- layernorm (res2 = optional split-K partial) ----------------
template<int RES, int ACT, int MODE, int MASKED>
__global__ __launch_bounds__(256)
void ln_kernel(const float* __restrict__ x, const float* __restrict__ res,
               const float* __restrict__ res2,
               const float* __restrict__ g, const float* __restrict__ b,
               float* __restrict__ out, __half* __restrict__ out2,
               const int* __restrict__ mask)
{
    int row = blockIdx.x;
    const float* xr = x + (size_t)row * Hd;
    const float* rr = RES ? res + (size_t)row * Hd : nullptr;
    const float* r2 = res2 ? res2 + (size_t)row * Hd : nullptr;
    int mrow = MASKED ? mask[row] : 0;
    float t[3];
    float s = 0.f, ss = 0.f;
#pragma unroll
    for (int j = 0; j < 3; j++) {
        int i = threadIdx.x + j * 256;
        float v = xr[i];
        if (r2) v += r2[i];
        if (RES) v += rr[i];
        t[j] = v;
        s += v; ss += v * v;
    }
    float2 r = block_reduce_sum2<8>(s, ss);
    float mu = r.x * (1.0f / Hd);
    float var = r.y * (1.0f / Hd) - mu * mu;
    float rstd = rsqrtf(var + 1e-5f);
#pragma unroll
    for (int j = 0; j < 3; j++) {
        int i = threadIdx.x + j * 256;
        float v = (t[j] - mu) * rstd * g[i] + b[i];
        if (ACT == 2) v = v > 0.f ? v : LEAKY * v;
        if (MASKED && mrow) v = 0.f;
        if (MODE != 1) out[(size_t)row * Hd + i] = v;
        if (MODE != 0) out2[(size_t)row * Hd + i] = __float2half_rn(v);
    }
}

// ---------------- ring attention ----------------
__global__ __launch_bounds__(256)
void ring_attn_kernel(const float* __restrict__ qkv, const float* __restrict__ rk,
                      const float* __restrict__ rv, __half* __restrict__ out2)
{
    int gw = (blockIdx.x * blockDim.x + threadIdx.x) >> 5;
    int lane = threadIdx.x & 31;
    int n = gw % NHd;
    int bl = gw / NHd;
    int l = bl % Lx;
    int b = bl / Lx;

    const float* qp = qkv + (size_t)bl * (3 * Hd) + n * HDd;
    float q0 = qp[lane * 2], q1 = qp[lane * 2 + 1];

    float s[4];
#pragma unroll
    for (int w = 0; w < 3; w++) {
        int ll = l - 1 + w;
        float d = 0.f;
        if (ll >= 0 && ll < Lx) {
            const float* kp = qkv + ((size_t)(b * Lx + ll)) * (3 * Hd) + Hd + n * HDd;
            d = q0 * kp[lane * 2] + q1 * kp[lane * 2 + 1];
        }
#pragma unroll
        for (int o = 16; o; o >>= 1) d += __shfl_xor_sync(0xffffffffu, d, o);
        s[w] = d * SCALE_ATT;
    }
    {
        const float* kp = rk + b * Hd + n * HDd;
        float d = q0 * kp[lane * 2] + q1 * kp[lane * 2 + 1];
#pragma unroll
        for (int o = 16; o; o >>= 1) d += __shfl_xor_sync(0xffffffffu, d, o);
        s[3] = d * SCALE_ATT;
    }
    float m = fmaxf(fmaxf(s[0], s[1]), fmaxf(s[2], s[3]));
    float e[4], se = 0.f;
#pragma unroll
    for (int w = 0; w < 4; w++) { e[w] = expf(s[w] - m); se += e[w]; }
    float inv = 1.0f / se;

    float o0 = 0.f, o1 = 0.f;
#pragma unroll
    for (int w = 0; w < 3; w++) {
        int ll = l - 1 + w;
        if (ll >= 0 && ll < Lx) {
            const float* vp = qkv + ((size_t)(b * Lx + ll)) * (3 * Hd) + 2 * Hd + n * HDd;
            float p = e[w] * inv;
            o0 += p * vp[lane * 2];
            o1 += p * vp[lane * 2 + 1];
        }
    }
    {
        const float* vp = rv + b * Hd + n * HDd;
        float p = e[3] * inv;
        o0 += p * vp[lane * 2];
        o1 += p * vp[lane * 2 + 1];
    }
    int c0 = n * HDd + lane * 2;
    *(__half2*)(out2 + (size_t)bl * Hd + c0) =
        __halves2half2(__float2half_rn(o0), __float2half_rn(o1));
}

// ---------------- star attention (1024 threads) ----------------
__global__ __launch_bounds__(1024)
void star_attn_kernel(const float* __restrict__ sq, const float* __restrict__ kv,
                      const float* __restrict__ rk, const float* __restrict__ rv,
                      const int* __restrict__ mask, float* __restrict__ out)
{
    __shared__ float qs[HDd];
    __shared__ float sc[Lx + 1];
    __shared__ float red[16 * HDd];

    int b = blockIdx.x / NHd;
    int n = blockIdx.x % NHd;
    int tid = threadIdx.x;

    if (tid < HDd) qs[tid] = sq[b * Hd + n * HDd + tid];
    __syncthreads();

    float lmax = -1e30f;
    for (int s = tid; s < Lx + 1; s += 1024) {
        const float* kp = (s == 0) ? rk + b * Hd + n * HDd
                                   : kv + ((size_t)(b * Lx + s - 1)) * (2 * Hd) + n * HDd;
        float d = 0.f;
#pragma unroll
        for (int i = 0; i < HDd; i++) d += qs[i] * kp[i];
        d *= SCALE_ATT;
        if (s > 0 && mask[b * Lx + s - 1]) d = -1e30f;
        sc[s] = d;
        lmax = fmaxf(lmax, d);
    }
    float bmax = block_reduce_max<32>(lmax);

    float lsum = 0.f;
    for (int s = tid; s < Lx + 1; s += 1024) {
        float ev = expf(sc[s] - bmax);
        sc[s] = ev;
        lsum += ev;
    }
    float bsum = block_reduce_sum<32>(lsum);

    int gg = tid >> 6;      // 0..15
    int dd = tid & 63;
    float acc = 0.f;
    for (int s = gg; s < Lx + 1; s += 16) {
        const float* vp = (s == 0) ? rv + b * Hd + n * HDd
                                   : kv + ((size_t)(b * Lx + s - 1)) * (2 * Hd) + Hd + n * HDd;
        acc += sc[s] * vp[dd];
    }
    red[gg * HDd + dd] = acc;
    __syncthreads();
    if (tid < HDd) {
        float r = 0.f;
#pragma unroll
        for (int g = 0; g < 16; g++) r += red[g * HDd + tid];
        out[b * Hd + n * HDd + tid] = r / bsum;
    }
}

// ---------------- gather ft ----------------
__global__ void gather_ft_kernel(const float* __restrict__ relay, const float* __restrict__ nodes,
                                 const int* __restrict__ positions, float* __restrict__ ft)
{
    int idx = blockIdx.x * blockDim.x + threadIdx.x;
    if (idx >= Bx * 2 * Hd) return;
    int b = idx / (2 * Hd);
    int i = idx % (2 * Hd);
    float v;
    if (i < Hd) v = relay[b * Hd + i];
    else        v = nodes[((size_t)b * Lx + positions[b]) * Hd + (i - Hd)];
    ft[idx] = v;
}

// ---------------- launch ----------------
extern "C" void kernel_launch(void* const* d_in, const int* in_sizes, int n_in,
                              void* d_out, int out_size)
{
    const int*   src       = (const int*)  d_in[0];
    const int*   positions = (const int*)  d_in[1];
    const float* emb       = (const float*)d_in[2];
    const float* pos_table = (const float*)d_in[3];
    const float* norm_g    = (const float*)d_in[4];
    const float* norm_b    = (const float*)d_in[5];
    const float* pw_w1     = (const float*)d_in[6];
    const float* pw_b1     = (const float*)d_in[7];
    const float* pw_w2     = (const float*)d_in[8];
    const float* pw_b2     = (const float*)d_in[9];
    const float* pw_g      = (const float*)d_in[10];
    const float* pw_bn     = (const float*)d_in[11];
    const float* ring_wq   = (const float*)d_in[12];
    const float* ring_bq   = (const float*)d_in[13];
    const float* ring_wk   = (const float*)d_in[14];
    const float* ring_bk   = (const float*)d_in[15];
    const float* ring_wv   = (const float*)d_in[16];
    const float* ring_bv   = (const float*)d_in[17];
    const float* ring_wo   = (const float*)d_in[18];
    const float* ring_bo   = (const float*)d_in[19];
    const float* star_wq   = (const float*)d_in[20];
    const float* star_bq   = (const float*)d_in[21];
    const float* star_wk   = (const float*)d_in[22];
    const float* star_bk   = (const float*)d_in[23];
    const float* star_wv   = (const float*)d_in[24];
    const float* star_bv   = (const float*)d_in[25];
    const float* star_wo   = (const float*)d_in[26];
    const float* star_bo   = (const float*)d_in[27];
    const float* head_w1   = (const float*)d_in[28];
    const float* head_b1   = (const float*)d_in[29];
    const float* head_w2   = (const float*)d_in[30];
    const float* head_b2   = (const float*)d_in[31];
    float* out = (float*)d_out;

    cudaFuncSetAttribute(gemm_tc2<0, 0>, cudaFuncAttributeMaxDynamicSharedMemorySize, SMEM_G);
    cudaFuncSetAttribute(gemm_tc2<1, 0>, cudaFuncAttributeMaxDynamicSharedMemorySize, SMEM_G);
    cudaFuncSetAttribute(gemm_tc2<1, 1>, cudaFuncAttributeMaxDynamicSharedMemorySize, SMEM_G);

    float *x, *qkv, *kv, *ring, *ring2, *relay, *part, *rk, *rv, *sq, *srk, *srv;
    float *satt, *ft, *hid, *bqkv, *bskv;
    int* mask;
    __half *x2, *h2, *att2, *mid2;
    __half *w1p, *w2p, *qkvp, *rop, *skvp;
    cudaGetSymbolAddress((void**)&x, g_x);
    cudaGetSymbolAddress((void**)&qkv, g_qkv);
    cudaGetSymbolAddress((void**)&kv, g_kv);
    cudaGetSymbolAddress((void**)&ring, g_ring);
    cudaGetSymbolAddress((void**)&ring2, g_ring2);
    cudaGetSymbolAddress((void**)&relay, g_relay);
    cudaGetSymbolAddress((void**)&part, g_part);
    cudaGetSymbolAddress((void**)&rk, g_rk);
    cudaGetSymbolAddress((void**)&rv, g_rv);
    cudaGetSymbolAddress((void**)&sq, g_sq);
    cudaGetSymbolAddress((void**)&srk, g_srk);
    cudaGetSymbolAddress((void**)&srv, g_srv);
    cudaGetSymbolAddress((void**)&satt, g_satt);
    cudaGetSymbolAddress((void**)&ft, g_ft);
    cudaGetSymbolAddress((void**)&hid, g_hid);
    cudaGetSymbolAddress((void**)&mask, g_mask);
    cudaGetSymbolAddress((void**)&x2, g_x2);
    cudaGetSymbolAddress((void**)&h2, g_h2);
    cudaGetSymbolAddress((void**)&att2, g_att2);
    cudaGetSymbolAddress((void**)&mid2, g_mid2);
    cudaGetSymbolAddress((void**)&w1p, g_w1p);
    cudaGetSymbolAddress((void**)&w2p, g_w2p);
    cudaGetSymbolAddress((void**)&qkvp, g_qkvp);
    cudaGetSymbolAddress((void**)&rop, g_rop);
    cudaGetSymbolAddress((void**)&skvp, g_skvp);
    cudaGetSymbolAddress((void**)&bqkv, g_bqkv);
    cudaGetSymbolAddress((void**)&bskv, g_bskv);

    const int M = ML;

    cvt_all<<<(S8 + 255) / 256, 256>>>(pw_w1, pw_w2, ring_wq, ring_wk, ring_wv, ring_wo,
                                       star_wk, star_wv, w1p, w2p, qkvp, rop, skvp);
    concat_bias<<<(NLAYERS * 5 * Hd + 255) / 256, 256>>>(ring_bq, ring_bk, ring_bv,
                                                          star_bk, star_bv, bqkv, bskv);
    embed_kernel<<<(ML * Hd + 255) / 256, 256>>>(src, emb, pos_table, x, x2, mask);

    bool relay_done = false;
    for (int i = 0; i < NLAYERS; i++) {
        const float* b1 = pw_b1 + (size_t)i * DI;
        const float* b2 = pw_b2 + (size_t)i * Hd;
        const float* pg = pw_g + (size_t)i * Hd;
        const float* pb = pw_bn + (size_t)i * Hd;
        const float* rbk = ring_bk + (size_t)i * Hd;
        const float* rbv = ring_bv + (size_t)i * Hd;
        const float* rbo = ring_bo + (size_t)i * Hd;
        const float* ng = norm_g + (size_t)i * Hd;
        const float* nb = norm_b + (size_t)i * Hd;
        const float* rwk = ring_wk + (size_t)i * Hd * Hd;
        const float* rwv = ring_wv + (size_t)i * Hd * Hd;
        const __half* w1i = w1p + (size_t)i * DI * 2 * Hd;
        const __half* w2i = w2p + (size_t)i * Hd * 2 * DI;
        const __half* qkvi = qkvp + (size_t)i * 3 * Hd * 2 * Hd;
        const __half* roi = rop + (size_t)i * Hd * 2 * Hd;
        const __half* skvi = skvp + (size_t)i * 2 * Hd * 2 * Hd;
        const float* bqkvi = bqkv + (size_t)i * 3 * Hd;
        const float* bskvi = bskv + (size_t)i * 2 * Hd;

        // PWFF
        gemm_p(1, 1, 0, x2, w1i, b1, nullptr, 0, mid2, nullptr, M, DI, Hd);      // launch 3 = profiled
        gemm_p(0, 0, 1, mid2, w2i, b2, ring, Hd, nullptr, ring2, M, Hd, DI);     // split-K
        ln_kernel<1, 0, 1, 0><<<M, 256>>>(ring, x, ring2, pg, pb, nullptr, h2, nullptr);

        if (!relay_done) {
            dim3 gp(6, 16, Bx);
            relay_part_kernel<<<gp, 128>>>(x, part);
            dim3 gf(6, Bx);
            relay_fin_kernel<<<gf, 128>>>(part, relay);
            relay_done = true;
        }

        // all relay projections (ring k/v + star q/k/v) in one launch
        gemm_rel5<<<(5 * Hd * 32 + 255) / 256, 256>>>(relay,
            rwk, rbk, rwv, rbv,
            star_wq + (size_t)i * Hd * Hd, star_bq + (size_t)i * Hd,
            star_wk + (size_t)i * Hd * Hd, star_bk + (size_t)i * Hd,
            star_wv + (size_t)i * Hd * Hd, star_bv + (size_t)i * Hd,
            rk, rv, sq, srk, srv);

        // Ring attention
        gemm_p(0, 0, 0, h2, qkvi, bqkvi, qkv, 3 * Hd, nullptr, nullptr, M, 3 * Hd, Hd);
        ring_attn_kernel<<<(M * NHd) / 8, 256>>>(qkv, rk, rv, att2);
        gemm_p(0, 0, 1, att2, roi, rbo, ring, Hd, nullptr, ring2, M, Hd, Hd);    // split-K
        ln_kernel<0, 2, 2, 1><<<M, 256>>>(ring, nullptr, ring2, ng, nb, x, x2, mask);

        // Star attention
        gemm_p(0, 0, 0, x2, skvi, bskvi, kv, 2 * Hd, nullptr, nullptr, M, 2 * Hd, Hd);
        star_attn_kernel<<<Bx * NHd, 1024>>>(sq, kv, srk, srv, mask, satt);
        gemm_small8<<<(Hd * 32 + 255) / 256, 256>>>(satt, Hd,
            star_wo + (size_t)i * Hd * Hd, Hd, star_bo + (size_t)i * Hd,
            relay, Hd, Hd, Hd, 2);
    }

    // heads
    gather_ft_kernel<<<(Bx * 2 * Hd + 255) / 256, 256>>>(relay, x, positions, ft);
    gemm_small8<<<(3 * NHID * 32 + 255) / 256, 256>>>(ft, 2 * Hd, head_w1, 2 * Hd,
                                                      head_b1, hid, 3 * NHID,
                                                      3 * NHID, 2 * Hd, 1);
    head2_kernel<<<(3 * NOUT * 32 + 255) / 256, 256>>>(hid, head_w2, head_b2, out);
}

// round 13
// speedup vs baseline: 1.6726x; 1.0331x over previous
#include <cuda_runtime.h>
#include <cuda_fp16.h>
#include <math.h>
#include <stdint.h>

// ---------------- problem constants ----------------
#define Bx 8
#define Lx 1024
#define Hd 768
#define NHd 12
#define HDd 64
#define DI 3072
#define NLAYERS 2
#define NHID 1024
#define NOUT 5000
#define SCALE_ATT 0.125f
#define LEAKY 0.01f
#define ML (Bx*Lx)      // 8192

// ---------------- fp32 scratch ----------------
__device__ float g_x    [ML*Hd];
__device__ float g_ring [ML*Hd];
__device__ float g_ring2[ML*Hd];
__device__ float g_relay[Bx*Hd];
__device__ float g_part[Bx*16*Hd];
__device__ float g_rk  [Bx*Hd];
__device__ float g_rv  [Bx*Hd];
__device__ float g_sq  [Bx*Hd];
__device__ float g_srk [Bx*Hd];
__device__ float g_srv [Bx*Hd];
__device__ float g_satt[Bx*Hd];
__device__ float g_ft  [Bx*2*Hd];
__device__ float g_hid [Bx*3*NHID];
__device__ int   g_mask[Bx*Lx];

// ---------------- fp16 scratch ----------------
__device__ __half g_x2  [ML*Hd];
__device__ __half g_h2  [ML*Hd];
__device__ __half g_att2[ML*Hd];
__device__ __half g_mid2[(size_t)ML*DI];
__device__ __half g_qkv [ML*3*Hd];     // fused ring q|k|v (fp16)
__device__ __half g_kv  [ML*2*Hd];     // fused star k|v (fp16)
// weights: 2-plane layout (per 16-group: 16 hi then 16 lo), row stride 2K
__device__ __half g_w1p [(size_t)NLAYERS*DI*2*Hd];
__device__ __half g_w2p [(size_t)NLAYERS*Hd*2*DI];
__device__ __half g_qkvp[(size_t)NLAYERS*3*Hd*2*Hd];
__device__ __half g_rop [(size_t)NLAYERS*Hd*2*Hd];
__device__ __half g_skvp[(size_t)NLAYERS*2*Hd*2*Hd];
__device__ float g_bqkv[NLAYERS*3*Hd];
__device__ float g_bskv[NLAYERS*2*Hd];

// ---------------- helpers ----------------
__device__ __forceinline__ uint32_t cvta_s(const void* p) {
    return (uint32_t)__cvta_generic_to_shared(p);
}
__device__ __forceinline__ void ldsm4(uint32_t* r, uint32_t addr) {
    asm volatile("ldmatrix.sync.aligned.m8n8.x4.shared.b16 {%0,%1,%2,%3}, [%4];\n"
                 : "=r"(r[0]), "=r"(r[1]), "=r"(r[2]), "=r"(r[3]) : "r"(addr));
}
__device__ __forceinline__ void mma16816(float* c, const uint32_t* a, const uint32_t* b) {
    asm volatile("mma.sync.aligned.m16n8k16.row.col.f32.f16.f16.f32 "
                 "{%0,%1,%2,%3},{%4,%5,%6,%7},{%8,%9},{%0,%1,%2,%3};\n"
                 : "+f"(c[0]), "+f"(c[1]), "+f"(c[2]), "+f"(c[3])
                 : "r"(a[0]), "r"(a[1]), "r"(a[2]), "r"(a[3]), "r"(b[0]), "r"(b[1]));
}
__device__ __forceinline__ void cp16(uint32_t s, const void* g) {
    asm volatile("cp.async.cg.shared.global [%0], [%1], 16;\n" :: "r"(s), "l"(g));
}
__device__ __forceinline__ void split_hl(float v, __half& hi, __half& lo) {
    hi = __float2half_rn(v);
    lo = __float2half_rn(v - __half2float(hi));
}
__device__ __forceinline__ uint32_t sw128(uint32_t o) { return o ^ ((o >> 3) & 0x70); }

// =====================================================================
// Tensor-core GEMM, 128x128 tile, 2x4 warps, 2-stage pipeline,
// 64 fp32-k per chunk. A: plain fp16 [M,K]. W: 2-plane [N,2K].
// OUTP 0 = fp32 C (optional split-K via grid.z), 1 = fp16 C2.
// =====================================================================
#define ATB 16384
#define BUFB (3*16384)
#define SMEM_G (2*BUFB)              // 96 KB

__device__ __forceinline__ void fill_tile(uint32_t base, const __half* A2, int lda,
                                          const __half* W2, int ldw2,
                                          int bm, int bn, int kc, int tid)
{
#pragma unroll
    for (int j = 0; j < 4; j++) {
        int idx = tid + j * 256;
        int row = idx >> 3, c16 = idx & 7;
        cp16(base + sw128((uint32_t)(row * 128 + c16 * 16)),
             A2 + (size_t)(bm + row) * lda + kc * 64 + c16 * 8);
    }
#pragma unroll
    for (int s = 0; s < 2; s++)
#pragma unroll
        for (int j = 0; j < 4; j++) {
            int idx = tid + j * 256;
            int row = idx >> 3, c16 = idx & 7;
            cp16(base + ATB + s * 16384 + sw128((uint32_t)(row * 128 + c16 * 16)),
                 W2 + (size_t)(bn + row) * ldw2 + kc * 128 + s * 64 + c16 * 8);
        }
}

template<int ACT, int OUTP>
__global__ __launch_bounds__(256, 2)
void gemm_tc2(const __half* __restrict__ A2, int lda,
              const __half* __restrict__ W2, int ldw2,
              const float* __restrict__ bias,
              float* __restrict__ C, int ldc,
              __half* __restrict__ C2, int Nout,
              float* __restrict__ Cs,
              int kAoff, int kWoff,
              int T)
{
    extern __shared__ __align__(128) char smraw[];
    const uint32_t sb = cvta_s(smraw);

    const int zz = blockIdx.z;
    if (zz) { A2 += kAoff; W2 += kWoff; }

    const int tid  = threadIdx.x;
    const int lane = tid & 31;
    const int warp = tid >> 5;
    const int wm = warp >> 2;
    const int wn = warp & 3;
    const int bm = blockIdx.y * 128;
    const int bn = blockIdx.x * 128;

    float acc[4][4][4];
#pragma unroll
    for (int i = 0; i < 4; i++)
#pragma unroll
        for (int j = 0; j < 4; j++)
#pragma unroll
            for (int c = 0; c < 4; c++) acc[i][j][c] = 0.f;

    const int a_row = lane & 15;
    const int a_kb  = (lane >> 4) * 16;
    const int b_row = (lane & 7) + ((lane >> 4) << 3);
    const int b_kb  = ((lane >> 3) & 1) * 16;

    fill_tile(sb, A2, lda, W2, ldw2, bm, bn, 0, tid);
    asm volatile("cp.async.commit_group;\n");

    for (int t = 0; t < T; t++) {
        __syncthreads();
        if (t + 1 < T) {
            fill_tile(sb + ((t + 1) & 1) * BUFB, A2, lda, W2, ldw2, bm, bn, t + 1, tid);
            asm volatile("cp.async.commit_group;\n");
            asm volatile("cp.async.wait_group 1;\n");
        } else {
            asm volatile("cp.async.wait_group 0;\n");
        }
        __syncthreads();

        const uint32_t ab = sb + (t & 1) * BUFB;
        const uint32_t bb = ab + ATB;

#pragma unroll
        for (int g2 = 0; g2 < 4; g2++) {
            const uint32_t bsub = bb + (g2 >> 1) * 16384;
            const int gb = (g2 & 1) * 64;
            uint32_t bh[2][4], afh[4][4], bl_[2][4];
#pragma unroll
            for (int p = 0; p < 2; p++) {
                int row = wn * 32 + p * 16 + b_row;
                ldsm4(bh[p], bsub + sw128((uint32_t)(row * 128 + gb + b_kb)));
            }
#pragma unroll
            for (int mt = 0; mt < 4; mt++) {
                int row = wm * 64 + mt * 16 + a_row;
                ldsm4(afh[mt], ab + sw128((uint32_t)(row * 128 + g2 * 32 + a_kb)));
            }
#pragma unroll
            for (int p = 0; p < 2; p++) {
                int row = wn * 32 + p * 16 + b_row;
                ldsm4(bl_[p], bsub + sw128((uint32_t)(row * 128 + gb + 32 + b_kb)));
            }
#pragma unroll
            for (int mt = 0; mt < 4; mt++)
#pragma unroll
                for (int nt = 0; nt < 4; nt++)
                    mma16816(acc[mt][nt], afh[mt], &bh[nt >> 1][(nt & 1) * 2]);
#pragma unroll
            for (int mt = 0; mt < 4; mt++)
#pragma unroll
                for (int nt = 0; nt < 4; nt++)
                    mma16816(acc[mt][nt], afh[mt], &bl_[nt >> 1][(nt & 1) * 2]);
        }
    }

    float* Co = zz ? Cs : C;
#pragma unroll
    for (int mt = 0; mt < 4; mt++) {
#pragma unroll
        for (int nt = 0; nt < 4; nt++) {
            int row = bm + wm * 64 + mt * 16 + (lane >> 2);
            int col = bn + wn * 32 + nt * 8 + (lane & 3) * 2;
            float bi0 = zz ? 0.f : bias[col];
            float bi1 = zz ? 0.f : bias[col + 1];
            float v0 = acc[mt][nt][0] + bi0;
            float v1 = acc[mt][nt][1] + bi1;
            float v2 = acc[mt][nt][2] + bi0;
            float v3 = acc[mt][nt][3] + bi1;
            if (ACT == 1) {
                v0 = fmaxf(v0, 0.f); v1 = fmaxf(v1, 0.f);
                v2 = fmaxf(v2, 0.f); v3 = fmaxf(v3, 0.f);
            }
            if (OUTP == 0) {
                *(float2*)(Co + (size_t)row * ldc + col)       = make_float2(v0, v1);
                *(float2*)(Co + (size_t)(row + 8) * ldc + col) = make_float2(v2, v3);
            } else {
                *(__half2*)(C2 + (size_t)row * Nout + col) =
                    __halves2half2(__float2half_rn(v0), __float2half_rn(v1));
                *(__half2*)(C2 + (size_t)(row + 8) * Nout + col) =
                    __halves2half2(__float2half_rn(v2), __float2half_rn(v3));
            }
        }
    }
}

static void gemm_p(int act, int outp, int split,
                   const __half* A2, const __half* W2,
                   const float* bias, float* C, int ldc, __half* C2, float* Cs,
                   int M, int N, int K)
{
    int Keff = split ? K / 2 : K;
    dim3 grid(N / 128, M / 128, split ? 2 : 1);
    int T = Keff / 64;
    int kAoff = Keff;
    int kWoff = 2 * Keff;
    if (outp == 1) {
        if (act == 1) gemm_tc2<1, 1><<<grid, 256, SMEM_G>>>(A2, K, W2, 2 * K, bias, nullptr, 0, C2, N, nullptr, 0, 0, T);
        else          gemm_tc2<0, 1><<<grid, 256, SMEM_G>>>(A2, K, W2, 2 * K, bias, nullptr, 0, C2, N, nullptr, 0, 0, T);
    } else {
        gemm_tc2<0, 0><<<grid, 256, SMEM_G>>>(A2, K, W2, 2 * K, bias, C, ldc, nullptr, N, Cs, kAoff, kWoff, T);
    }
}

// =====================================================================
// fused weight plane conversion
// =====================================================================
#define S1 1179648
#define S2 2359296
#define S3 2654208
#define S4 2949120
#define S5 3244032
#define S6 3538944
#define S7 3833856
#define S8 4128768

__global__ void cvt_all(const float* w1, const float* w2, const float* rq, const float* rk,
                        const float* rv, const float* ro, const float* sk, const float* sv,
                        __half* o1, __half* o2, __half* oqkv,
                        __half* oro, __half* oskv)
{
    int i = blockIdx.x * blockDim.x + threadIdx.x;
    if (i >= S8) return;
    const float* in; __half* out; int C, base, extra;
    if      (i < S1) { in = w1; out = o1;   C = Hd; base = 0;  extra = 0; }
    else if (i < S2) { in = w2; out = o2;   C = DI; base = S1; extra = 0; }
    else if (i < S3) { in = rq; out = oqkv;                        C = Hd; base = S2; extra = 1536; }
    else if (i < S4) { in = rk; out = oqkv + (size_t)768 * 2 * Hd; C = Hd; base = S3; extra = 1536; }
    else if (i < S5) { in = rv; out = oqkv + (size_t)1536 * 2 * Hd;C = Hd; base = S4; extra = 1536; }
    else if (i < S6) { in = ro; out = oro;  C = Hd; base = S5; extra = 0; }
    else if (i < S7) { in = sk; out = oskv;                        C = Hd; base = S6; extra = 768; }
    else             { in = sv; out = oskv + (size_t)768 * 2 * Hd; C = Hd; base = S7; extra = 768; }
    int e = (i - base) * 4;
    int r = e / C, c = e % C;
    size_t ro_ = (size_t)r + (size_t)(r / Hd) * extra;
    if (extra == 0 && C == DI) ro_ = r;
    float4 f = *(const float4*)(in + e);
    __half h0, h1, h2, h3, l0, l1, l2, l3;
    split_hl(f.x, h0, l0); split_hl(f.y, h1, l1);
    split_hl(f.z, h2, l2); split_hl(f.w, h3, l3);
    __half* p = out + ro_ * (2 * C) + 32 * (c >> 4) + (c & 15);
    *(__half2*)(p)      = __halves2half2(h0, h1);
    *(__half2*)(p + 2)  = __halves2half2(h2, h3);
    *(__half2*)(p + 16) = __halves2half2(l0, l1);
    *(__half2*)(p + 18) = __halves2half2(l2, l3);
}

__global__ void concat_bias(const float* bq, const float* bk, const float* bv,
                            const float* sk, const float* sv,
                            float* oqkv, float* oskv)
{
    int i = blockIdx.x * blockDim.x + threadIdx.x;
    int n1 = NLAYERS * 3 * Hd;
    if (i < n1) {
        int layer = i / (3 * Hd), c = i % (3 * Hd);
        const float* s = (c < Hd) ? bq : (c < 2 * Hd) ? bk : bv;
        oqkv[i] = s[layer * Hd + (c % Hd)];
    } else if (i < n1 + NLAYERS * 2 * Hd) {
        int j = i - n1;
        int layer = j / (2 * Hd), c = j % (2 * Hd);
        const float* s = (c < Hd) ? sk : sv;
        oskv[j] = s[layer * Hd + (c % Hd)];
    }
}

// =====================================================================
// Small-M GEMMs (M=8)
// =====================================================================
__device__ __forceinline__ void smalldot8(const float* __restrict__ A, int lda,
                                          const float* __restrict__ wrow, int K,
                                          int lane, float* s)
{
    const float4* w4 = (const float4*)wrow;
    int K4 = K >> 2;
#pragma unroll
    for (int m = 0; m < 8; m++) s[m] = 0.f;
    for (int k = lane; k < K4; k += 32) {
        float4 w = w4[k];
#pragma unroll
        for (int m = 0; m < 8; m++) {
            float4 a = ((const float4*)(A + (size_t)m * lda))[k];
            s[m] += a.x * w.x + a.y * w.y + a.z * w.z + a.w * w.w;
        }
    }
#pragma unroll
    for (int m = 0; m < 8; m++)
#pragma unroll
        for (int o = 16; o; o >>= 1) s[m] += __shfl_xor_sync(0xffffffffu, s[m], o);
}

__global__ __launch_bounds__(256)
void gemm_small8(const float* __restrict__ A, int lda,
                 const float* __restrict__ W, int ldw,
                 const float* __restrict__ bias,
                 float* __restrict__ C, int ldc,
                 int N, int K, int act)
{
    int n = (blockIdx.x * blockDim.x + threadIdx.x) >> 5;
    int lane = threadIdx.x & 31;
    if (n >= N) return;
    float s[8];
    smalldot8(A, lda, W + (size_t)n * ldw, K, lane, s);
    if (lane == 0) {
        float bv = bias[n];
#pragma unroll
        for (int m = 0; m < 8; m++) {
            float v = s[m] + bv;
            if (act == 1) v = fmaxf(v, 0.f);
            else if (act == 2) v = v > 0.f ? v : LEAKY * v;
            C[(size_t)m * ldc + n] = v;
        }
    }
}

__global__ __launch_bounds__(256)
void gemm_rel5(const float* __restrict__ relay,
               const float* __restrict__ rwk, const float* __restrict__ rbk,
               const float* __restrict__ rwv, const float* __restrict__ rbv,
               const float* __restrict__ swq, const float* __restrict__ sbq,
               const float* __restrict__ swk, const float* __restrict__ sbk,
               const float* __restrict__ swv, const float* __restrict__ sbv,
               float* __restrict__ rk, float* __restrict__ rv, float* __restrict__ sq,
               float* __restrict__ srk, float* __restrict__ srv)
{
    int n = (blockIdx.x * blockDim.x + threadIdx.x) >> 5;
    int lane = threadIdx.x & 31;
    if (n >= 5 * Hd) return;
    int seg = n / Hd, c = n % Hd;
    const float* W = (seg == 0) ? rwk : (seg == 1) ? rwv : (seg == 2) ? swq : (seg == 3) ? swk : swv;
    const float* B = (seg == 0) ? rbk : (seg == 1) ? rbv : (seg == 2) ? sbq : (seg == 3) ? sbk : sbv;
    float* C       = (seg == 0) ? rk  : (seg == 1) ? rv  : (seg == 2) ? sq  : (seg == 3) ? srk : srv;
    float s[8];
    smalldot8(relay, Hd, W + (size_t)c * Hd, Hd, lane, s);
    if (lane == 0) {
        float bb = B[c];
#pragma unroll
        for (int m = 0; m < 8; m++) C[(size_t)m * Hd + c] = s[m] + bb;
    }
}

__global__ __launch_bounds__(256)
void head2_kernel(const float* __restrict__ hid,
                  const float* __restrict__ w2,
                  const float* __restrict__ b2,
                  float* __restrict__ out)
{
    int n = (blockIdx.x * blockDim.x + threadIdx.x) >> 5;
    int lane = threadIdx.x & 31;
    if (n >= 3 * NOUT) return;
    int j = n / NOUT, c = n % NOUT;
    float s[8];
    smalldot8(hid + j * NHID, 3 * NHID, w2 + (size_t)n * NHID, NHID, lane, s);
    if (lane == 0) {
        float bb = b2[n];
#pragma unroll
        for (int m = 0; m < 8; m++)
            out[((size_t)m * 3 + j) * NOUT + c] = s[m] + bb;
    }
}

// ---------------- block reductions (for star_attn) ----------------
template<int NW>
__device__ __forceinline__ float block_reduce_max(float a)
{
    static __shared__ float sm[NW];
    __syncthreads();
    int lane = threadIdx.x & 31, w = threadIdx.x >> 5;
#pragma unroll
    for (int o = 16; o; o >>= 1) a = fmaxf(a, __shfl_xor_sync(0xffffffffu, a, o));
    if (lane == 0) sm[w] = a;
    __syncthreads();
    if (w == 0) {
        a = lane < NW ? sm[lane] : -1e30f;
#pragma unroll
        for (int o = NW / 2; o; o >>= 1) a = fmaxf(a, __shfl_xor_sync(0xffffffffu, a, o));
        if (lane == 0) sm[0] = a;
    }
    __syncthreads();
    return sm[0];
}
template<int NW>
__device__ __forceinline__ float block_reduce_sum(float a)
{
    static __shared__ float ss[NW];
    __syncthreads();
    int lane = threadIdx.x & 31, w = threadIdx.x >> 5;
#pragma unroll
    for (int o = 16; o; o >>= 1) a += __shfl_xor_sync(0xffffffffu, a, o);
    if (lane == 0) ss[w] = a;
    __syncthreads();
    if (w == 0) {
        a = lane < NW ? ss[lane] : 0.f;
#pragma unroll
        for (int o = NW / 2; o; o >>= 1) a += __shfl_xor_sync(0xffffffffu, a, o);
        if (lane == 0) ss[0] = a;
    }
    __syncthreads();
    return ss[0];
}

// ---------------- embed + mask ----------------
__global__ void embed_kernel(const int* __restrict__ src, const float* __restrict__ emb,
                             const float* __restrict__ pos, float* __restrict__ x,
                             __half* __restrict__ x2, int* __restrict__ mask)
{
    int idx = blockIdx.x * blockDim.x + threadIdx.x;
    if (idx >= ML * Hd) return;
    int h = idx % Hd;
    int bl = idx / Hd;
    int l = bl % Lx;
    int w = h >> 8;
    int dd = h & 255;
    int tok = src[bl * 3 + w];
    float v = emb[tok * 256 + dd] + pos[l * Hd + h];
    x[idx] = v;
    x2[idx] = __float2half_rn(v);
    if (h == 0) mask[bl] = (src[bl * 3] == 0) ? 1 : 0;
}

// ---------------- relay mean: 2-stage ----------------
__global__ void relay_part_kernel(const float* __restrict__ x, float* __restrict__ part)
{
    int h = blockIdx.x * 128 + threadIdx.x;
    int ch = blockIdx.y;
    int b = blockIdx.z;
    const float* p = x + (size_t)b * Lx * Hd + (size_t)ch * 64 * Hd + h;
    float s = 0.f;
#pragma unroll 8
    for (int l = 0; l < 64; l++) s += p[(size_t)l * Hd];
    part[((size_t)b * 16 + ch) * Hd + h] = s;
}
__global__ void relay_fin_kernel(const float* __restrict__ part, float* __restrict__ relay)
{
    int h = blockIdx.x * 128 + threadIdx.x;
    int b = blockIdx.y;
    float s = 0.f;
#pragma unroll
    for (int ch = 0; ch < 16; ch++) s += part[((size_t)b * 16 + ch) * Hd + h];
    relay[b * Hd + h] = s * (1.0f / Lx);
}

// ---------------- layernorm: warp-per-row (8 rows/block, no block sync) ----------------
template<int RES, int ACT, int MODE, int MASKED>
__global__ __launch_bounds__(256)
void ln_kernel(const float* __restrict__ x, const float* __restrict__ res,
               const float* __restrict__ res2,
               const float* __restrict__ g, const float* __restrict__ b,
               float* __restrict__ out, __half* __restrict__ out2,
               const int* __restrict__ mask)
{
    int row = blockIdx.x * 8 + (threadIdx.x >> 5);
    int lane = threadIdx.x & 31;
    const float* xr = x + (size_t)row * Hd;
    const float* rr = RES ? res + (size_t)row * Hd : nullptr;
    const float* r2 = res2 ? res2 + (size_t)row * Hd : nullptr;
    int mrow = MASKED ? mask[row] : 0;

    float t[24];
    float s = 0.f, ss = 0.f;
#pragma unroll
    for (int j = 0; j < 6; j++) {
        int off = j * 128 + lane * 4;
        float4 v = *(const float4*)(xr + off);
        if (r2) {
            float4 w = *(const float4*)(r2 + off);
            v.x += w.x; v.y += w.y; v.z += w.z; v.w += w.w;
        }
        if (RES) {
            float4 w = *(const float4*)(rr + off);
            v.x += w.x; v.y += w.y; v.z += w.z; v.w += w.w;
        }
        t[j * 4] = v.x; t[j * 4 + 1] = v.y; t[j * 4 + 2] = v.z; t[j * 4 + 3] = v.w;
        s += v.x + v.y + v.z + v.w;
        ss += v.x * v.x + v.y * v.y + v.z * v.z + v.w * v.w;
    }
#pragma unroll
    for (int o = 16; o; o >>= 1) {
        s  += __shfl_xor_sync(0xffffffffu, s, o);
        ss += __shfl_xor_sync(0xffffffffu, ss, o);
    }
    float mu = s * (1.0f / Hd);
    float var = ss * (1.0f / Hd) - mu * mu;
    float rstd = rsqrtf(var + 1e-5f);

#pragma unroll
    for (int j = 0; j < 6; j++) {
        int off = j * 128 + lane * 4;
        float4 gg = *(const float4*)(g + off);
        float4 bb = *(const float4*)(b + off);
        float v0 = (t[j * 4]     - mu) * rstd * gg.x + bb.x;
        float v1 = (t[j * 4 + 1] - mu) * rstd * gg.y + bb.y;
        float v2 = (t[j * 4 + 2] - mu) * rstd * gg.z + bb.z;
        float v3 = (t[j * 4 + 3] - mu) * rstd * gg.w + bb.w;
        if (ACT == 2) {
            v0 = v0 > 0.f ? v0 : LEAKY * v0;
            v1 = v1 > 0.f ? v1 : LEAKY * v1;
            v2 = v2 > 0.f ? v2 : LEAKY * v2;
            v3 = v3 > 0.f ? v3 : LEAKY * v3;
        }
        if (MASKED && mrow) { v0 = v1 = v2 = v3 = 0.f; }
        if (MODE != 1) {
            *(float4*)(out + (size_t)row * Hd + off) = make_float4(v0, v1, v2, v3);
        }
        if (MODE != 0) {
            __half* po = out2 + (size_t)row * Hd + off;
            *(__half2*)(po)     = __halves2half2(__float2half_rn(v0), __float2half_rn(v1));
            *(__half2*)(po + 2) = __halves2half2(__float2half_rn(v2), __float2half_rn(v3));
        }
    }
}

// ---------------- ring attention (fp16 node q/k/v, fp32 relay k/v) ----------------
__global__ __launch_bounds__(256)
void ring_attn_kernel(const __half* __restrict__ qkv, const float* __restrict__ rk,
                      const float* __restrict__ rv, __half* __restrict__ out2)
{
    int gw = (blockIdx.x * blockDim.x + threadIdx.x) >> 5;
    int lane = threadIdx.x & 31;
    int n = gw % NHd;
    int bl = gw / NHd;
    int l = bl % Lx;
    int b = bl / Lx;

    float2 qf = __half22float2(*(const __half2*)(qkv + (size_t)bl * (3 * Hd) + n * HDd + lane * 2));
    float q0 = qf.x, q1 = qf.y;

    float s[4];
#pragma unroll
    for (int w = 0; w < 3; w++) {
        int ll = l - 1 + w;
        float d = 0.f;
        if (ll >= 0 && ll < Lx) {
            float2 kf = __half22float2(*(const __half2*)(qkv + ((size_t)(b * Lx + ll)) * (3 * Hd) + Hd + n * HDd + lane * 2));
            d = q0 * kf.x + q1 * kf.y;
        }
#pragma unroll
        for (int o = 16; o; o >>= 1) d += __shfl_xor_sync(0xffffffffu, d, o);
        s[w] = d * SCALE_ATT;
    }
    {
        const float* kp = rk + b * Hd + n * HDd;
        float d = q0 * kp[lane * 2] + q1 * kp[lane * 2 + 1];
#pragma unroll
        for (int o = 16; o; o >>= 1) d += __shfl_xor_sync(0xffffffffu, d, o);
        s[3] = d * SCALE_ATT;
    }
    float m = fmaxf(fmaxf(s[0], s[1]), fmaxf(s[2], s[3]));
    float e[4], se = 0.f;
#pragma unroll
    for (int w = 0; w < 4; w++) { e[w] = expf(s[w] - m); se += e[w]; }
    float inv = 1.0f / se;

    float o0 = 0.f, o1 = 0.f;
#pragma unroll
    for (int w = 0; w < 3; w++) {
        int ll = l - 1 + w;
        if (ll >= 0 && ll < Lx) {
            float2 vf = __half22float2(*(const __half2*)(qkv + ((size_t)(b * Lx + ll)) * (3 * Hd) + 2 * Hd + n * HDd + lane * 2));
            float p = e[w] * inv;
            o0 += p * vf.x;
            o1 += p * vf.y;
        }
    }
    {
        const float* vp = rv + b * Hd + n * HDd;
        float p = e[3] * inv;
        o0 += p * vp[lane * 2];
        o1 += p * vp[lane * 2 + 1];
    }
    int c0 = n * HDd + lane * 2;
    *(__half2*)(out2 + (size_t)bl * Hd + c0) =
        __halves2half2(__float2half_rn(o0), __float2half_rn(o1));
}

// ---------------- star attention (fp16 node k/v, fp32 relay) ----------------
__global__ __launch_bounds__(1024)
void star_attn_kernel(const float* __restrict__ sq, const __half* __restrict__ kv,
                      const float* __restrict__ rk, const float* __restrict__ rv,
                      const int* __restrict__ mask, float* __restrict__ out)
{
    __shared__ float qs[HDd];
    __shared__ float sc[Lx + 1];
    __shared__ float red[16 * HDd];

    int b = blockIdx.x / NHd;
    int n = blockIdx.x % NHd;
    int tid = threadIdx.x;

    if (tid < HDd) qs[tid] = sq[b * Hd + n * HDd + tid];
    __syncthreads();

    float lmax = -1e30f;
    for (int s = tid; s < Lx + 1; s += 1024) {
        float d = 0.f;
        if (s == 0) {
            const float* kp = rk + b * Hd + n * HDd;
#pragma unroll
            for (int i = 0; i < HDd; i++) d += qs[i] * kp[i];
        } else {
            const __half2* kp2 = (const __half2*)(kv + ((size_t)(b * Lx + s - 1)) * (2 * Hd) + n * HDd);
#pragma unroll
            for (int i = 0; i < HDd / 2; i++) {
                float2 f = __half22float2(kp2[i]);
                d += qs[2 * i] * f.x + qs[2 * i + 1] * f.y;
            }
        }
        d *= SCALE_ATT;
        if (s > 0 && mask[b * Lx + s - 1]) d = -1e30f;
        sc[s] = d;
        lmax = fmaxf(lmax, d);
    }
    float bmax = block_reduce_max<32>(lmax);

    float lsum = 0.f;
    for (int s = tid; s < Lx + 1; s += 1024) {
        float ev = expf(sc[s] - bmax);
        sc[s] = ev;
        lsum += ev;
    }
    float bsum = block_reduce_sum<32>(lsum);

    int gg = tid >> 6;
    int dd = tid & 63;
    float acc = 0.f;
    for (int s = gg; s < Lx + 1; s += 16) {
        float vv;
        if (s == 0) vv = rv[b * Hd + n * HDd + dd];
        else        vv = __half2float(kv[((size_t)(b * Lx + s - 1)) * (2 * Hd) + Hd + n * HDd + dd]);
        acc += sc[s] * vv;
    }
    red[gg * HDd + dd] = acc;
    __syncthreads();
    if (tid < HDd) {
        float r = 0.f;
#pragma unroll
        for (int g = 0; g < 16; g++) r += red[g * HDd + tid];
        out[b * Hd + n * HDd + tid] = r / bsum;
    }
}

// ---------------- gather ft ----------------
__global__ void gather_ft_kernel(const float* __restrict__ relay, const float* __restrict__ nodes,
                                 const int* __restrict__ positions, float* __restrict__ ft)
{
    int idx = blockIdx.x * blockDim.x + threadIdx.x;
    if (idx >= Bx * 2 * Hd) return;
    int b = idx / (2 * Hd);
    int i = idx % (2 * Hd);
    float v;
    if (i < Hd) v = relay[b * Hd + i];
    else        v = nodes[((size_t)b * Lx + positions[b]) * Hd + (i - Hd)];
    ft[idx] = v;
}

// ---------------- launch ----------------
extern "C" void kernel_launch(void* const* d_in, const int* in_sizes, int n_in,
                              void* d_out, int out_size)
{
    const int*   src       = (const int*)  d_in[0];
    const int*   positions = (const int*)  d_in[1];
    const float* emb       = (const float*)d_in[2];
    const float* pos_table = (const float*)d_in[3];
    const float* norm_g    = (const float*)d_in[4];
    const float* norm_b    = (const float*)d_in[5];
    const float* pw_w1     = (const float*)d_in[6];
    const float* pw_b1     = (const float*)d_in[7];
    const float* pw_w2     = (const float*)d_in[8];
    const float* pw_b2     = (const float*)d_in[9];
    const float* pw_g      = (const float*)d_in[10];
    const float* pw_bn     = (const float*)d_in[11];
    const float* ring_wq   = (const float*)d_in[12];
    const float* ring_bq   = (const float*)d_in[13];
    const float* ring_wk   = (const float*)d_in[14];
    const float* ring_bk   = (const float*)d_in[15];
    const float* ring_wv   = (const float*)d_in[16];
    const float* ring_bv   = (const float*)d_in[17];
    const float* ring_wo   = (const float*)d_in[18];
    const float* ring_bo   = (const float*)d_in[19];
    const float* star_wq   = (const float*)d_in[20];
    const float* star_bq   = (const float*)d_in[21];
    const float* star_wk   = (const float*)d_in[22];
    const float* star_bk   = (const float*)d_in[23];
    const float* star_wv   = (const float*)d_in[24];
    const float* star_bv   = (const float*)d_in[25];
    const float* star_wo   = (const float*)d_in[26];
    const float* star_bo   = (const float*)d_in[27];
    const float* head_w1   = (const float*)d_in[28];
    const float* head_b1   = (const float*)d_in[29];
    const float* head_w2   = (const float*)d_in[30];
    const float* head_b2   = (const float*)d_in[31];
    float* out = (float*)d_out;

    cudaFuncSetAttribute(gemm_tc2<0, 0>, cudaFuncAttributeMaxDynamicSharedMemorySize, SMEM_G);
    cudaFuncSetAttribute(gemm_tc2<0, 1>, cudaFuncAttributeMaxDynamicSharedMemorySize, SMEM_G);
    cudaFuncSetAttribute(gemm_tc2<1, 1>, cudaFuncAttributeMaxDynamicSharedMemorySize, SMEM_G);

    float *x, *ring, *ring2, *relay, *part, *rk, *rv, *sq, *srk, *srv;
    float *satt, *ft, *hid, *bqkv, *bskv;
    int* mask;
    __half *x2, *h2, *att2, *mid2, *qkv, *kv;
    __half *w1p, *w2p, *qkvp, *rop, *skvp;
    cudaGetSymbolAddress((void**)&x, g_x);
    cudaGetSymbolAddress((void**)&ring, g_ring);
    cudaGetSymbolAddress((void**)&ring2, g_ring2);
    cudaGetSymbolAddress((void**)&relay, g_relay);
    cudaGetSymbolAddress((void**)&part, g_part);
    cudaGetSymbolAddress((void**)&rk, g_rk);
    cudaGetSymbolAddress((void**)&rv, g_rv);
    cudaGetSymbolAddress((void**)&sq, g_sq);
    cudaGetSymbolAddress((void**)&srk, g_srk);
    cudaGetSymbolAddress((void**)&srv, g_srv);
    cudaGetSymbolAddress((void**)&satt, g_satt);
    cudaGetSymbolAddress((void**)&ft, g_ft);
    cudaGetSymbolAddress((void**)&hid, g_hid);
    cudaGetSymbolAddress((void**)&mask, g_mask);
    cudaGetSymbolAddress((void**)&x2, g_x2);
    cudaGetSymbolAddress((void**)&h2, g_h2);
    cudaGetSymbolAddress((void**)&att2, g_att2);
    cudaGetSymbolAddress((void**)&mid2, g_mid2);
    cudaGetSymbolAddress((void**)&qkv, g_qkv);
    cudaGetSymbolAddress((void**)&kv, g_kv);
    cudaGetSymbolAddress((void**)&w1p, g_w1p);
    cudaGetSymbolAddress((void**)&w2p, g_w2p);
    cudaGetSymbolAddress((void**)&qkvp, g_qkvp);
    cudaGetSymbolAddress((void**)&rop, g_rop);
    cudaGetSymbolAddress((void**)&skvp, g_skvp);
    cudaGetSymbolAddress((void**)&bqkv, g_bqkv);
    cudaGetSymbolAddress((void**)&bskv, g_bskv);

    const int M = ML;

    cvt_all<<<(S8 + 255) / 256, 256>>>(pw_w1, pw_w2, ring_wq, ring_wk, ring_wv, ring_wo,
                                       star_wk, star_wv, w1p, w2p, qkvp, rop, skvp);
    concat_bias<<<(NLAYERS * 5 * Hd + 255) / 256, 256>>>(ring_bq, ring_bk, ring_bv,
                                                          star_bk, star_bv, bqkv, bskv);
    embed_kernel<<<(ML * Hd + 255) / 256, 256>>>(src, emb, pos_table, x, x2, mask);

    bool relay_done = false;
    for (int i = 0; i < NLAYERS; i++) {
        const float* b1 = pw_b1 + (size_t)i * DI;
        const float* b2 = pw_b2 + (size_t)i * Hd;
        const float* pg = pw_g + (size_t)i * Hd;
        const float* pb = pw_bn + (size_t)i * Hd;
        const float* rbk = ring_bk + (size_t)i * Hd;
        const float* rbv = ring_bv + (size_t)i * Hd;
        const float* rbo = ring_bo + (size_t)i * Hd;
        const float* ng = norm_g + (size_t)i * Hd;
        const float* nb = norm_b + (size_t)i * Hd;
        const float* rwk = ring_wk + (size_t)i * Hd * Hd;
        const float* rwv = ring_wv + (size_t)i * Hd * Hd;
        const __half* w1i = w1p + (size_t)i * DI * 2 * Hd;
        const __half* w2i = w2p + (size_t)i * Hd * 2 * DI;
        const __half* qkvi = qkvp + (size_t)i * 3 * Hd * 2 * Hd;
        const __half* roi = rop + (size_t)i * Hd * 2 * Hd;
        const __half* skvi = skvp + (size_t)i * 2 * Hd * 2 * Hd;
        const float* bqkvi = bqkv + (size_t)i * 3 * Hd;
        const float* bskvi = bskv + (size_t)i * 2 * Hd;

        // PWFF
        gemm_p(1, 1, 0, x2, w1i, b1, nullptr, 0, mid2, nullptr, M, DI, Hd);      // launch 3 = profiled
        gemm_p(0, 0, 1, mid2, w2i, b2, ring, Hd, nullptr, ring2, M, Hd, DI);
        ln_kernel<1, 0, 1, 0><<<M / 8, 256>>>(ring, x, ring2, pg, pb, nullptr, h2, nullptr);

        if (!relay_done) {
            dim3 gp(6, 16, Bx);
            relay_part_kernel<<<gp, 128>>>(x, part);
            dim3 gf(6, Bx);
            relay_fin_kernel<<<gf, 128>>>(part, relay);
            relay_done = true;
        }

        gemm_rel5<<<(5 * Hd * 32 + 255) / 256, 256>>>(relay,
            rwk, rbk, rwv, rbv,
            star_wq + (size_t)i * Hd * Hd, star_bq + (size_t)i * Hd,
            star_wk + (size_t)i * Hd * Hd, star_bk + (size_t)i * Hd,
            star_wv + (size_t)i * Hd * Hd, star_bv + (size_t)i * Hd,
            rk, rv, sq, srk, srv);

        // Ring attention (fp16 qkv)
        gemm_p(0, 1, 0, h2, qkvi, bqkvi, nullptr, 0, qkv, nullptr, M, 3 * Hd, Hd);
        ring_attn_kernel<<<(M * NHd) / 8, 256>>>(qkv, rk, rv, att2);
        gemm_p(0, 0, 1, att2, roi, rbo, ring, Hd, nullptr, ring2, M, Hd, Hd);
        ln_kernel<0, 2, 2, 1><<<M / 8, 256>>>(ring, nullptr, ring2, ng, nb, x, x2, mask);

        // Star attention (fp16 kv)
        gemm_p(0, 1, 0, x2, skvi, bskvi, nullptr, 0, kv, nullptr, M, 2 * Hd, Hd);
        star_attn_kernel<<<Bx * NHd, 1024>>>(sq, kv, srk, srv, mask, satt);
        gemm_small8<<<(Hd * 32 + 255) / 256, 256>>>(satt, Hd,
            star_wo + (size_t)i * Hd * Hd, Hd, star_bo + (size_t)i * Hd,
            relay, Hd, Hd, Hd, 2);
    }

    // heads
    gather_ft_kernel<<<(Bx * 2 * Hd + 255) / 256, 256>>>(relay, x, positions, ft);
    gemm_small8<<<(3 * NHID * 32 + 255) / 256, 256>>>(ft, 2 * Hd, head_w1, 2 * Hd,
                                                      head_b1, hid, 3 * NHID,
                                                      3 * NHID, 2 * Hd, 1);
    head2_kernel<<<(3 * NOUT * 32 + 255) / 256, 256>>>(hid, head_w2, head_b2, out);
}

// round 14
// speedup vs baseline: 1.7548x; 1.0491x over previous
#include <cuda_runtime.h>
#include <cuda_fp16.h>
#include <math.h>
#include <stdint.h>

// ---------------- problem constants ----------------
#define Bx 8
#define Lx 1024
#define Hd 768
#define NHd 12
#define HDd 64
#define DI 3072
#define NLAYERS 2
#define NHID 1024
#define NOUT 5000
#define SCALE_ATT 0.125f
#define LEAKY 0.01f
#define ML (Bx*Lx)      // 8192

// ---------------- fp32 scratch ----------------
__device__ float g_x    [ML*Hd];
__device__ float g_ring [ML*Hd];
__device__ float g_ring2[ML*Hd];
__device__ float g_relay[Bx*Hd];
__device__ float g_part[Bx*16*Hd];
__device__ float g_rk  [Bx*Hd];
__device__ float g_rv  [Bx*Hd];
__device__ float g_sq  [Bx*Hd];
__device__ float g_srk [Bx*Hd];
__device__ float g_srv [Bx*Hd];
__device__ float g_satt[Bx*Hd];
__device__ float g_ft  [Bx*2*Hd];
__device__ float g_hid [Bx*3*NHID];
__device__ int   g_mask[Bx*Lx];

// ---------------- fp16 scratch ----------------
__device__ __half g_x2  [ML*Hd];
__device__ __half g_h2  [ML*Hd];
__device__ __half g_att2[ML*Hd];
__device__ __half g_mid2[(size_t)ML*DI];
__device__ __half g_qkv [ML*3*Hd];
__device__ __half g_kv  [ML*2*Hd];
// weights: 2-plane layout (per 16-group: 16 hi then 16 lo), row stride 2K
__device__ __half g_w1p [(size_t)NLAYERS*DI*2*Hd];
__device__ __half g_w2p [(size_t)NLAYERS*Hd*2*DI];
__device__ __half g_qkvp[(size_t)NLAYERS*3*Hd*2*Hd];
__device__ __half g_rop [(size_t)NLAYERS*Hd*2*Hd];
__device__ __half g_skvp[(size_t)NLAYERS*2*Hd*2*Hd];
__device__ float g_bqkv[NLAYERS*3*Hd];
__device__ float g_bskv[NLAYERS*2*Hd];

// ---------------- helpers ----------------
__device__ __forceinline__ uint32_t cvta_s(const void* p) {
    return (uint32_t)__cvta_generic_to_shared(p);
}
__device__ __forceinline__ void ldsm4(uint32_t* r, uint32_t addr) {
    asm volatile("ldmatrix.sync.aligned.m8n8.x4.shared.b16 {%0,%1,%2,%3}, [%4];\n"
                 : "=r"(r[0]), "=r"(r[1]), "=r"(r[2]), "=r"(r[3]) : "r"(addr));
}
__device__ __forceinline__ void mma16816(float* c, const uint32_t* a, const uint32_t* b) {
    asm volatile("mma.sync.aligned.m16n8k16.row.col.f32.f16.f16.f32 "
                 "{%0,%1,%2,%3},{%4,%5,%6,%7},{%8,%9},{%0,%1,%2,%3};\n"
                 : "+f"(c[0]), "+f"(c[1]), "+f"(c[2]), "+f"(c[3])
                 : "r"(a[0]), "r"(a[1]), "r"(a[2]), "r"(a[3]), "r"(b[0]), "r"(b[1]));
}
__device__ __forceinline__ void cp16(uint32_t s, const void* g) {
    asm volatile("cp.async.cg.shared.global [%0], [%1], 16;\n" :: "r"(s), "l"(g));
}
__device__ __forceinline__ void split_hl(float v, __half& hi, __half& lo) {
    hi = __float2half_rn(v);
    lo = __float2half_rn(v - __half2float(hi));
}
__device__ __forceinline__ uint32_t sw128(uint32_t o) { return o ^ ((o >> 3) & 0x70); }

// =====================================================================
// Tensor-core GEMM, 128x128 tile, 2x4 warps, 2-stage pipeline,
// 64 fp32-k per chunk. A: plain fp16 [M,K]. W: 2-plane [N,2K].
// NP=2: Ah*Bh + Ah*Bl (err ~2^-12). NP=1: Ah*Bh only (err ~2^-11).
// OUTP 0 = fp32 C (optional split-K via grid.z), 1 = fp16 C2.
// =====================================================================
#define ATB 16384
#define BUFB (3*16384)
#define SMEM_G (2*BUFB)              // 96 KB

__device__ __forceinline__ void fill_tile(uint32_t base, const __half* A2, int lda,
                                          const __half* W2, int ldw2,
                                          int bm, int bn, int kc, int tid)
{
#pragma unroll
    for (int j = 0; j < 4; j++) {
        int idx = tid + j * 256;
        int row = idx >> 3, c16 = idx & 7;
        cp16(base + sw128((uint32_t)(row * 128 + c16 * 16)),
             A2 + (size_t)(bm + row) * lda + kc * 64 + c16 * 8);
    }
#pragma unroll
    for (int s = 0; s < 2; s++)
#pragma unroll
        for (int j = 0; j < 4; j++) {
            int idx = tid + j * 256;
            int row = idx >> 3, c16 = idx & 7;
            cp16(base + ATB + s * 16384 + sw128((uint32_t)(row * 128 + c16 * 16)),
                 W2 + (size_t)(bn + row) * ldw2 + kc * 128 + s * 64 + c16 * 8);
        }
}

template<int ACT, int OUTP, int NP>
__global__ __launch_bounds__(256, 2)
void gemm_tc2(const __half* __restrict__ A2, int lda,
              const __half* __restrict__ W2, int ldw2,
              const float* __restrict__ bias,
              float* __restrict__ C, int ldc,
              __half* __restrict__ C2, int Nout,
              float* __restrict__ Cs,
              int kAoff, int kWoff,
              int T)
{
    extern __shared__ __align__(128) char smraw[];
    const uint32_t sb = cvta_s(smraw);

    const int zz = blockIdx.z;
    if (zz) { A2 += kAoff; W2 += kWoff; }

    const int tid  = threadIdx.x;
    const int lane = tid & 31;
    const int warp = tid >> 5;
    const int wm = warp >> 2;
    const int wn = warp & 3;
    const int bm = blockIdx.y * 128;
    const int bn = blockIdx.x * 128;

    float acc[4][4][4];
#pragma unroll
    for (int i = 0; i < 4; i++)
#pragma unroll
        for (int j = 0; j < 4; j++)
#pragma unroll
            for (int c = 0; c < 4; c++) acc[i][j][c] = 0.f;

    const int a_row = lane & 15;
    const int a_kb  = (lane >> 4) * 16;
    const int b_row = (lane & 7) + ((lane >> 4) << 3);
    const int b_kb  = ((lane >> 3) & 1) * 16;

    fill_tile(sb, A2, lda, W2, ldw2, bm, bn, 0, tid);
    asm volatile("cp.async.commit_group;\n");

    for (int t = 0; t < T; t++) {
        __syncthreads();
        if (t + 1 < T) {
            fill_tile(sb + ((t + 1) & 1) * BUFB, A2, lda, W2, ldw2, bm, bn, t + 1, tid);
            asm volatile("cp.async.commit_group;\n");
            asm volatile("cp.async.wait_group 1;\n");
        } else {
            asm volatile("cp.async.wait_group 0;\n");
        }
        __syncthreads();

        const uint32_t ab = sb + (t & 1) * BUFB;
        const uint32_t bb = ab + ATB;

#pragma unroll
        for (int g2 = 0; g2 < 4; g2++) {
            const uint32_t bsub = bb + (g2 >> 1) * 16384;
            const int gb = (g2 & 1) * 64;
            uint32_t bh[2][4], afh[4][4], bl_[2][4];
#pragma unroll
            for (int p = 0; p < 2; p++) {
                int row = wn * 32 + p * 16 + b_row;
                ldsm4(bh[p], bsub + sw128((uint32_t)(row * 128 + gb + b_kb)));
            }
#pragma unroll
            for (int mt = 0; mt < 4; mt++) {
                int row = wm * 64 + mt * 16 + a_row;
                ldsm4(afh[mt], ab + sw128((uint32_t)(row * 128 + g2 * 32 + a_kb)));
            }
            if (NP == 2) {
#pragma unroll
                for (int p = 0; p < 2; p++) {
                    int row = wn * 32 + p * 16 + b_row;
                    ldsm4(bl_[p], bsub + sw128((uint32_t)(row * 128 + gb + 32 + b_kb)));
                }
            }
#pragma unroll
            for (int mt = 0; mt < 4; mt++)
#pragma unroll
                for (int nt = 0; nt < 4; nt++)
                    mma16816(acc[mt][nt], afh[mt], &bh[nt >> 1][(nt & 1) * 2]);
            if (NP == 2) {
#pragma unroll
                for (int mt = 0; mt < 4; mt++)
#pragma unroll
                    for (int nt = 0; nt < 4; nt++)
                        mma16816(acc[mt][nt], afh[mt], &bl_[nt >> 1][(nt & 1) * 2]);
            }
        }
    }

    float* Co = zz ? Cs : C;
#pragma unroll
    for (int mt = 0; mt < 4; mt++) {
#pragma unroll
        for (int nt = 0; nt < 4; nt++) {
            int row = bm + wm * 64 + mt * 16 + (lane >> 2);
            int col = bn + wn * 32 + nt * 8 + (lane & 3) * 2;
            float bi0 = zz ? 0.f : bias[col];
            float bi1 = zz ? 0.f : bias[col + 1];
            float v0 = acc[mt][nt][0] + bi0;
            float v1 = acc[mt][nt][1] + bi1;
            float v2 = acc[mt][nt][2] + bi0;
            float v3 = acc[mt][nt][3] + bi1;
            if (ACT == 1) {
                v0 = fmaxf(v0, 0.f); v1 = fmaxf(v1, 0.f);
                v2 = fmaxf(v2, 0.f); v3 = fmaxf(v3, 0.f);
            }
            if (OUTP == 0) {
                *(float2*)(Co + (size_t)row * ldc + col)       = make_float2(v0, v1);
                *(float2*)(Co + (size_t)(row + 8) * ldc + col) = make_float2(v2, v3);
            } else {
                *(__half2*)(C2 + (size_t)row * Nout + col) =
                    __halves2half2(__float2half_rn(v0), __float2half_rn(v1));
                *(__half2*)(C2 + (size_t)(row + 8) * Nout + col) =
                    __halves2half2(__float2half_rn(v2), __float2half_rn(v3));
            }
        }
    }
}

static void gemm_p(int act, int outp, int split, int np,
                   const __half* A2, const __half* W2,
                   const float* bias, float* C, int ldc, __half* C2, float* Cs,
                   int M, int N, int K)
{
    int Keff = split ? K / 2 : K;
    dim3 grid(N / 128, M / 128, split ? 2 : 1);
    int T = Keff / 64;
    int kAoff = Keff;
    int kWoff = 2 * Keff;
    if (outp == 1) {
        if (act == 1)      gemm_tc2<1, 1, 2><<<grid, 256, SMEM_G>>>(A2, K, W2, 2 * K, bias, nullptr, 0, C2, N, nullptr, 0, 0, T);
        else if (np == 1)  gemm_tc2<0, 1, 1><<<grid, 256, SMEM_G>>>(A2, K, W2, 2 * K, bias, nullptr, 0, C2, N, nullptr, 0, 0, T);
        else               gemm_tc2<0, 1, 2><<<grid, 256, SMEM_G>>>(A2, K, W2, 2 * K, bias, nullptr, 0, C2, N, nullptr, 0, 0, T);
    } else {
        gemm_tc2<0, 0, 2><<<grid, 256, SMEM_G>>>(A2, K, W2, 2 * K, bias, C, ldc, nullptr, N, Cs, kAoff, kWoff, T);
    }
}

// =====================================================================
// fused weight plane conversion
// =====================================================================
#define S1 1179648
#define S2 2359296
#define S3 2654208
#define S4 2949120
#define S5 3244032
#define S6 3538944
#define S7 3833856
#define S8 4128768

__global__ void cvt_all(const float* w1, const float* w2, const float* rq, const float* rk,
                        const float* rv, const float* ro, const float* sk, const float* sv,
                        __half* o1, __half* o2, __half* oqkv,
                        __half* oro, __half* oskv)
{
    int i = blockIdx.x * blockDim.x + threadIdx.x;
    if (i >= S8) return;
    const float* in; __half* out; int C, base, extra;
    if      (i < S1) { in = w1; out = o1;   C = Hd; base = 0;  extra = 0; }
    else if (i < S2) { in = w2; out = o2;   C = DI; base = S1; extra = 0; }
    else if (i < S3) { in = rq; out = oqkv;                        C = Hd; base = S2; extra = 1536; }
    else if (i < S4) { in = rk; out = oqkv + (size_t)768 * 2 * Hd; C = Hd; base = S3; extra = 1536; }
    else if (i < S5) { in = rv; out = oqkv + (size_t)1536 * 2 * Hd;C = Hd; base = S4; extra = 1536; }
    else if (i < S6) { in = ro; out = oro;  C = Hd; base = S5; extra = 0; }
    else if (i < S7) { in = sk; out = oskv;                        C = Hd; base = S6; extra = 768; }
    else             { in = sv; out = oskv + (size_t)768 * 2 * Hd; C = Hd; base = S7; extra = 768; }
    int e = (i - base) * 4;
    int r = e / C, c = e % C;
    size_t ro_ = (size_t)r + (size_t)(r / Hd) * extra;
    if (extra == 0 && C == DI) ro_ = r;
    float4 f = *(const float4*)(in + e);
    __half h0, h1, h2, h3, l0, l1, l2, l3;
    split_hl(f.x, h0, l0); split_hl(f.y, h1, l1);
    split_hl(f.z, h2, l2); split_hl(f.w, h3, l3);
    __half* p = out + ro_ * (2 * C) + 32 * (c >> 4) + (c & 15);
    *(__half2*)(p)      = __halves2half2(h0, h1);
    *(__half2*)(p + 2)  = __halves2half2(h2, h3);
    *(__half2*)(p + 16) = __halves2half2(l0, l1);
    *(__half2*)(p + 18) = __halves2half2(l2, l3);
}

__global__ void concat_bias(const float* bq, const float* bk, const float* bv,
                            const float* sk, const float* sv,
                            float* oqkv, float* oskv)
{
    int i = blockIdx.x * blockDim.x + threadIdx.x;
    int n1 = NLAYERS * 3 * Hd;
    if (i < n1) {
        int layer = i / (3 * Hd), c = i % (3 * Hd);
        const float* s = (c < Hd) ? bq : (c < 2 * Hd) ? bk : bv;
        oqkv[i] = s[layer * Hd + (c % Hd)];
    } else if (i < n1 + NLAYERS * 2 * Hd) {
        int j = i - n1;
        int layer = j / (2 * Hd), c = j % (2 * Hd);
        const float* s = (c < Hd) ? sk : sv;
        oskv[j] = s[layer * Hd + (c % Hd)];
    }
}

// =====================================================================
// Small-M GEMMs (M=8)
// =====================================================================
__device__ __forceinline__ void smalldot8(const float* __restrict__ A, int lda,
                                          const float* __restrict__ wrow, int K,
                                          int lane, float* s)
{
    const float4* w4 = (const float4*)wrow;
    int K4 = K >> 2;
#pragma unroll
    for (int m = 0; m < 8; m++) s[m] = 0.f;
    for (int k = lane; k < K4; k += 32) {
        float4 w = w4[k];
#pragma unroll
        for (int m = 0; m < 8; m++) {
            float4 a = ((const float4*)(A + (size_t)m * lda))[k];
            s[m] += a.x * w.x + a.y * w.y + a.z * w.z + a.w * w.w;
        }
    }
#pragma unroll
    for (int m = 0; m < 8; m++)
#pragma unroll
        for (int o = 16; o; o >>= 1) s[m] += __shfl_xor_sync(0xffffffffu, s[m], o);
}

__global__ __launch_bounds__(256)
void gemm_small8(const float* __restrict__ A, int lda,
                 const float* __restrict__ W, int ldw,
                 const float* __restrict__ bias,
                 float* __restrict__ C, int ldc,
                 int N, int K, int act)
{
    int n = (blockIdx.x * blockDim.x + threadIdx.x) >> 5;
    int lane = threadIdx.x & 31;
    if (n >= N) return;
    float s[8];
    smalldot8(A, lda, W + (size_t)n * ldw, K, lane, s);
    if (lane == 0) {
        float bv = bias[n];
#pragma unroll
        for (int m = 0; m < 8; m++) {
            float v = s[m] + bv;
            if (act == 1) v = fmaxf(v, 0.f);
            else if (act == 2) v = v > 0.f ? v : LEAKY * v;
            C[(size_t)m * ldc + n] = v;
        }
    }
}

__global__ __launch_bounds__(256)
void gemm_rel5(const float* __restrict__ relay,
               const float* __restrict__ rwk, const float* __restrict__ rbk,
               const float* __restrict__ rwv, const float* __restrict__ rbv,
               const float* __restrict__ swq, const float* __restrict__ sbq,
               const float* __restrict__ swk, const float* __restrict__ sbk,
               const float* __restrict__ swv, const float* __restrict__ sbv,
               float* __restrict__ rk, float* __restrict__ rv, float* __restrict__ sq,
               float* __restrict__ srk, float* __restrict__ srv)
{
    int n = (blockIdx.x * blockDim.x + threadIdx.x) >> 5;
    int lane = threadIdx.x & 31;
    if (n >= 5 * Hd) return;
    int seg = n / Hd, c = n % Hd;
    const float* W = (seg == 0) ? rwk : (seg == 1) ? rwv : (seg == 2) ? swq : (seg == 3) ? swk : swv;
    const float* B = (seg == 0) ? rbk : (seg == 1) ? rbv : (seg == 2) ? sbq : (seg == 3) ? sbk : sbv;
    float* C       = (seg == 0) ? rk  : (seg == 1) ? rv  : (seg == 2) ? sq  : (seg == 3) ? srk : srv;
    float s[8];
    smalldot8(relay, Hd, W + (size_t)c * Hd, Hd, lane, s);
    if (lane == 0) {
        float bb = B[c];
#pragma unroll
        for (int m = 0; m < 8; m++) C[(size_t)m * Hd + c] = s[m] + bb;
    }
}

__global__ __launch_bounds__(256)
void head2_kernel(const float* __restrict__ hid,
                  const float* __restrict__ w2,
                  const float* __restrict__ b2,
                  float* __restrict__ out)
{
    int n = (blockIdx.x * blockDim.x + threadIdx.x) >> 5;
    int lane = threadIdx.x & 31;
    if (n >= 3 * NOUT) return;
    int j = n / NOUT, c = n % NOUT;
    float s[8];
    smalldot8(hid + j * NHID, 3 * NHID, w2 + (size_t)n * NHID, NHID, lane, s);
    if (lane == 0) {
        float bb = b2[n];
#pragma unroll
        for (int m = 0; m < 8; m++)
            out[((size_t)m * 3 + j) * NOUT + c] = s[m] + bb;
    }
}

// ---------------- block reductions (for star_attn) ----------------
template<int NW>
__device__ __forceinline__ float block_reduce_max(float a)
{
    static __shared__ float sm[NW];
    __syncthreads();
    int lane = threadIdx.x & 31, w = threadIdx.x >> 5;
#pragma unroll
    for (int o = 16; o; o >>= 1) a = fmaxf(a, __shfl_xor_sync(0xffffffffu, a, o));
    if (lane == 0) sm[w] = a;
    __syncthreads();
    if (w == 0) {
        a = lane < NW ? sm[lane] : -1e30f;
#pragma unroll
        for (int o = NW / 2; o; o >>= 1) a = fmaxf(a, __shfl_xor_sync(0xffffffffu, a, o));
        if (lane == 0) sm[0] = a;
    }
    __syncthreads();
    return sm[0];
}
template<int NW>
__device__ __forceinline__ float block_reduce_sum(float a)
{
    static __shared__ float ss[NW];
    __syncthreads();
    int lane = threadIdx.x & 31, w = threadIdx.x >> 5;
#pragma unroll
    for (int o = 16; o; o >>= 1) a += __shfl_xor_sync(0xffffffffu, a, o);
    if (lane == 0) ss[w] = a;
    __syncthreads();
    if (w == 0) {
        a = lane < NW ? ss[lane] : 0.f;
#pragma unroll
        for (int o = NW / 2; o; o >>= 1) a += __shfl_xor_sync(0xffffffffu, a, o);
        if (lane == 0) ss[0] = a;
    }
    __syncthreads();
    return ss[0];
}

// ---------------- embed + mask ----------------
__global__ void embed_kernel(const int* __restrict__ src, const float* __restrict__ emb,
                             const float* __restrict__ pos, float* __restrict__ x,
                             __half* __restrict__ x2, int* __restrict__ mask)
{
    int idx = blockIdx.x * blockDim.x + threadIdx.x;
    if (idx >= ML * Hd) return;
    int h = idx % Hd;
    int bl = idx / Hd;
    int l = bl % Lx;
    int w = h >> 8;
    int dd = h & 255;
    int tok = src[bl * 3 + w];
    float v = emb[tok * 256 + dd] + pos[l * Hd + h];
    x[idx] = v;
    x2[idx] = __float2half_rn(v);
    if (h == 0) mask[bl] = (src[bl * 3] == 0) ? 1 : 0;
}

// ---------------- relay mean: 2-stage (reads fp16 x2) ----------------
__global__ void relay_part_kernel(const __half* __restrict__ x2, float* __restrict__ part)
{
    int h = blockIdx.x * 128 + threadIdx.x;
    int ch = blockIdx.y;
    int b = blockIdx.z;
    const __half* p = x2 + (size_t)b * Lx * Hd + (size_t)ch * 64 * Hd + h;
    float s = 0.f;
#pragma unroll 8
    for (int l = 0; l < 64; l++) s += __half2float(p[(size_t)l * Hd]);
    part[((size_t)b * 16 + ch) * Hd + h] = s;
}
__global__ void relay_fin_kernel(const float* __restrict__ part, float* __restrict__ relay)
{
    int h = blockIdx.x * 128 + threadIdx.x;
    int b = blockIdx.y;
    float s = 0.f;
#pragma unroll
    for (int ch = 0; ch < 16; ch++) s += part[((size_t)b * 16 + ch) * Hd + h];
    relay[b * Hd + h] = s * (1.0f / Lx);
}

// ---------------- layernorm: warp-per-row ----------------
template<int RES, int ACT, int MODE, int MASKED>
__global__ __launch_bounds__(256)
void ln_kernel(const float* __restrict__ x, const float* __restrict__ res,
               const float* __restrict__ res2,
               const float* __restrict__ g, const float* __restrict__ b,
               float* __restrict__ out, __half* __restrict__ out2,
               const int* __restrict__ mask)
{
    int row = blockIdx.x * 8 + (threadIdx.x >> 5);
    int lane = threadIdx.x & 31;
    const float* xr = x + (size_t)row * Hd;
    const float* rr = RES ? res + (size_t)row * Hd : nullptr;
    const float* r2 = res2 ? res2 + (size_t)row * Hd : nullptr;
    int mrow = MASKED ? mask[row] : 0;

    float t[24];
    float s = 0.f, ss = 0.f;
#pragma unroll
    for (int j = 0; j < 6; j++) {
        int off = j * 128 + lane * 4;
        float4 v = *(const float4*)(xr + off);
        if (r2) {
            float4 w = *(const float4*)(r2 + off);
            v.x += w.x; v.y += w.y; v.z += w.z; v.w += w.w;
        }
        if (RES) {
            float4 w = *(const float4*)(rr + off);
            v.x += w.x; v.y += w.y; v.z += w.z; v.w += w.w;
        }
        t[j * 4] = v.x; t[j * 4 + 1] = v.y; t[j * 4 + 2] = v.z; t[j * 4 + 3] = v.w;
        s += v.x + v.y + v.z + v.w;
        ss += v.x * v.x + v.y * v.y + v.z * v.z + v.w * v.w;
    }
#pragma unroll
    for (int o = 16; o; o >>= 1) {
        s  += __shfl_xor_sync(0xffffffffu, s, o);
        ss += __shfl_xor_sync(0xffffffffu, ss, o);
    }
    float mu = s * (1.0f / Hd);
    float var = ss * (1.0f / Hd) - mu * mu;
    float rstd = rsqrtf(var + 1e-5f);

#pragma unroll
    for (int j = 0; j < 6; j++) {
        int off = j * 128 + lane * 4;
        float4 gg = *(const float4*)(g + off);
        float4 bb = *(const float4*)(b + off);
        float v0 = (t[j * 4]     - mu) * rstd * gg.x + bb.x;
        float v1 = (t[j * 4 + 1] - mu) * rstd * gg.y + bb.y;
        float v2 = (t[j * 4 + 2] - mu) * rstd * gg.z + bb.z;
        float v3 = (t[j * 4 + 3] - mu) * rstd * gg.w + bb.w;
        if (ACT == 2) {
            v0 = v0 > 0.f ? v0 : LEAKY * v0;
            v1 = v1 > 0.f ? v1 : LEAKY * v1;
            v2 = v2 > 0.f ? v2 : LEAKY * v2;
            v3 = v3 > 0.f ? v3 : LEAKY * v3;
        }
        if (MASKED && mrow) { v0 = v1 = v2 = v3 = 0.f; }
        if (MODE != 1) {
            *(float4*)(out + (size_t)row * Hd + off) = make_float4(v0, v1, v2, v3);
        }
        if (MODE != 0) {
            __half* po = out2 + (size_t)row * Hd + off;
            *(__half2*)(po)     = __halves2half2(__float2half_rn(v0), __float2half_rn(v1));
            *(__half2*)(po + 2) = __halves2half2(__float2half_rn(v2), __float2half_rn(v3));
        }
    }
}

// ---------------- ring attention ----------------
__global__ __launch_bounds__(256)
void ring_attn_kernel(const __half* __restrict__ qkv, const float* __restrict__ rk,
                      const float* __restrict__ rv, __half* __restrict__ out2)
{
    int gw = (blockIdx.x * blockDim.x + threadIdx.x) >> 5;
    int lane = threadIdx.x & 31;
    int n = gw % NHd;
    int bl = gw / NHd;
    int l = bl % Lx;
    int b = bl / Lx;

    float2 qf = __half22float2(*(const __half2*)(qkv + (size_t)bl * (3 * Hd) + n * HDd + lane * 2));
    float q0 = qf.x, q1 = qf.y;

    float s[4];
#pragma unroll
    for (int w = 0; w < 3; w++) {
        int ll = l - 1 + w;
        float d = 0.f;
        if (ll >= 0 && ll < Lx) {
            float2 kf = __half22float2(*(const __half2*)(qkv + ((size_t)(b * Lx + ll)) * (3 * Hd) + Hd + n * HDd + lane * 2));
            d = q0 * kf.x + q1 * kf.y;
        }
#pragma unroll
        for (int o = 16; o; o >>= 1) d += __shfl_xor_sync(0xffffffffu, d, o);
        s[w] = d * SCALE_ATT;
    }
    {
        const float* kp = rk + b * Hd + n * HDd;
        float d = q0 * kp[lane * 2] + q1 * kp[lane * 2 + 1];
#pragma unroll
        for (int o = 16; o; o >>= 1) d += __shfl_xor_sync(0xffffffffu, d, o);
        s[3] = d * SCALE_ATT;
    }
    float m = fmaxf(fmaxf(s[0], s[1]), fmaxf(s[2], s[3]));
    float e[4], se = 0.f;
#pragma unroll
    for (int w = 0; w < 4; w++) { e[w] = expf(s[w] - m); se += e[w]; }
    float inv = 1.0f / se;

    float o0 = 0.f, o1 = 0.f;
#pragma unroll
    for (int w = 0; w < 3; w++) {
        int ll = l - 1 + w;
        if (ll >= 0 && ll < Lx) {
            float2 vf = __half22float2(*(const __half2*)(qkv + ((size_t)(b * Lx + ll)) * (3 * Hd) + 2 * Hd + n * HDd + lane * 2));
            float p = e[w] * inv;
            o0 += p * vf.x;
            o1 += p * vf.y;
        }
    }
    {
        const float* vp = rv + b * Hd + n * HDd;
        float p = e[3] * inv;
        o0 += p * vp[lane * 2];
        o1 += p * vp[lane * 2 + 1];
    }
    int c0 = n * HDd + lane * 2;
    *(__half2*)(out2 + (size_t)bl * Hd + c0) =
        __halves2half2(__float2half_rn(o0), __float2half_rn(o1));
}

// ---------------- star attention ----------------
__global__ __launch_bounds__(1024)
void star_attn_kernel(const float* __restrict__ sq, const __half* __restrict__ kv,
                      const float* __restrict__ rk, const float* __restrict__ rv,
                      const int* __restrict__ mask, float* __restrict__ out)
{
    __shared__ float qs[HDd];
    __shared__ float sc[Lx + 1];
    __shared__ float red[16 * HDd];

    int b = blockIdx.x / NHd;
    int n = blockIdx.x % NHd;
    int tid = threadIdx.x;

    if (tid < HDd) qs[tid] = sq[b * Hd + n * HDd + tid];
    __syncthreads();

    float lmax = -1e30f;
    for (int s = tid; s < Lx + 1; s += 1024) {
        float d = 0.f;
        if (s == 0) {
            const float* kp = rk + b * Hd + n * HDd;
#pragma unroll
            for (int i = 0; i < HDd; i++) d += qs[i] * kp[i];
        } else {
            const __half2* kp2 = (const __half2*)(kv + ((size_t)(b * Lx + s - 1)) * (2 * Hd) + n * HDd);
#pragma unroll
            for (int i = 0; i < HDd / 2; i++) {
                float2 f = __half22float2(kp2[i]);
                d += qs[2 * i] * f.x + qs[2 * i + 1] * f.y;
            }
        }
        d *= SCALE_ATT;
        if (s > 0 && mask[b * Lx + s - 1]) d = -1e30f;
        sc[s] = d;
        lmax = fmaxf(lmax, d);
    }
    float bmax = block_reduce_max<32>(lmax);

    float lsum = 0.f;
    for (int s = tid; s < Lx + 1; s += 1024) {
        float ev = expf(sc[s] - bmax);
        sc[s] = ev;
        lsum += ev;
    }
    float bsum = block_reduce_sum<32>(lsum);

    int gg = tid >> 6;
    int dd = tid & 63;
    float acc = 0.f;
    for (int s = gg; s < Lx + 1; s += 16) {
        float vv;
        if (s == 0) vv = rv[b * Hd + n * HDd + dd];
        else        vv = __half2float(kv[((size_t)(b * Lx + s - 1)) * (2 * Hd) + Hd + n * HDd + dd]);
        acc += sc[s] * vv;
    }
    red[gg * HDd + dd] = acc;
    __syncthreads();
    if (tid < HDd) {
        float r = 0.f;
#pragma unroll
        for (int g = 0; g < 16; g++) r += red[g * HDd + tid];
        out[b * Hd + n * HDd + tid] = r / bsum;
    }
}

// ---------------- gather ft ----------------
__global__ void gather_ft_kernel(const float* __restrict__ relay, const float* __restrict__ nodes,
                                 const int* __restrict__ positions, float* __restrict__ ft)
{
    int idx = blockIdx.x * blockDim.x + threadIdx.x;
    if (idx >= Bx * 2 * Hd) return;
    int b = idx / (2 * Hd);
    int i = idx % (2 * Hd);
    float v;
    if (i < Hd) v = relay[b * Hd + i];
    else        v = nodes[((size_t)b * Lx + positions[b]) * Hd + (i - Hd)];
    ft[idx] = v;
}

// ---------------- launch ----------------
extern "C" void kernel_launch(void* const* d_in, const int* in_sizes, int n_in,
                              void* d_out, int out_size)
{
    const int*   src       = (const int*)  d_in[0];
    const int*   positions = (const int*)  d_in[1];
    const float* emb       = (const float*)d_in[2];
    const float* pos_table = (const float*)d_in[3];
    const float* norm_g    = (const float*)d_in[4];
    const float* norm_b    = (const float*)d_in[5];
    const float* pw_w1     = (const float*)d_in[6];
    const float* pw_b1     = (const float*)d_in[7];
    const float* pw_w2     = (const float*)d_in[8];
    const float* pw_b2     = (const float*)d_in[9];
    const float* pw_g      = (const float*)d_in[10];
    const float* pw_bn     = (const float*)d_in[11];
    const float* ring_wq   = (const float*)d_in[12];
    const float* ring_bq   = (const float*)d_in[13];
    const float* ring_wk   = (const float*)d_in[14];
    const float* ring_bk   = (const float*)d_in[15];
    const float* ring_wv   = (const float*)d_in[16];
    const float* ring_bv   = (const float*)d_in[17];
    const float* ring_wo   = (const float*)d_in[18];
    const float* ring_bo   = (const float*)d_in[19];
    const float* star_wq   = (const float*)d_in[20];
    const float* star_bq   = (const float*)d_in[21];
    const float* star_wk   = (const float*)d_in[22];
    const float* star_bk   = (const float*)d_in[23];
    const float* star_wv   = (const float*)d_in[24];
    const float* star_bv   = (const float*)d_in[25];
    const float* star_wo   = (const float*)d_in[26];
    const float* star_bo   = (const float*)d_in[27];
    const float* head_w1   = (const float*)d_in[28];
    const float* head_b1   = (const float*)d_in[29];
    const float* head_w2   = (const float*)d_in[30];
    const float* head_b2   = (const float*)d_in[31];
    float* out = (float*)d_out;

    cudaFuncSetAttribute(gemm_tc2<0, 0, 2>, cudaFuncAttributeMaxDynamicSharedMemorySize, SMEM_G);
    cudaFuncSetAttribute(gemm_tc2<0, 1, 2>, cudaFuncAttributeMaxDynamicSharedMemorySize, SMEM_G);
    cudaFuncSetAttribute(gemm_tc2<0, 1, 1>, cudaFuncAttributeMaxDynamicSharedMemorySize, SMEM_G);
    cudaFuncSetAttribute(gemm_tc2<1, 1, 2>, cudaFuncAttributeMaxDynamicSharedMemorySize, SMEM_G);

    float *x, *ring, *ring2, *relay, *part, *rk, *rv, *sq, *srk, *srv;
    float *satt, *ft, *hid, *bqkv, *bskv;
    int* mask;
    __half *x2, *h2, *att2, *mid2, *qkv, *kv;
    __half *w1p, *w2p, *qkvp, *rop, *skvp;
    cudaGetSymbolAddress((void**)&x, g_x);
    cudaGetSymbolAddress((void**)&ring, g_ring);
    cudaGetSymbolAddress((void**)&ring2, g_ring2);
    cudaGetSymbolAddress((void**)&relay, g_relay);
    cudaGetSymbolAddress((void**)&part, g_part);
    cudaGetSymbolAddress((void**)&rk, g_rk);
    cudaGetSymbolAddress((void**)&rv, g_rv);
    cudaGetSymbolAddress((void**)&sq, g_sq);
    cudaGetSymbolAddress((void**)&srk, g_srk);
    cudaGetSymbolAddress((void**)&srv, g_srv);
    cudaGetSymbolAddress((void**)&satt, g_satt);
    cudaGetSymbolAddress((void**)&ft, g_ft);
    cudaGetSymbolAddress((void**)&hid, g_hid);
    cudaGetSymbolAddress((void**)&mask, g_mask);
    cudaGetSymbolAddress((void**)&x2, g_x2);
    cudaGetSymbolAddress((void**)&h2, g_h2);
    cudaGetSymbolAddress((void**)&att2, g_att2);
    cudaGetSymbolAddress((void**)&mid2, g_mid2);
    cudaGetSymbolAddress((void**)&qkv, g_qkv);
    cudaGetSymbolAddress((void**)&kv, g_kv);
    cudaGetSymbolAddress((void**)&w1p, g_w1p);
    cudaGetSymbolAddress((void**)&w2p, g_w2p);
    cudaGetSymbolAddress((void**)&qkvp, g_qkvp);
    cudaGetSymbolAddress((void**)&rop, g_rop);
    cudaGetSymbolAddress((void**)&skvp, g_skvp);
    cudaGetSymbolAddress((void**)&bqkv, g_bqkv);
    cudaGetSymbolAddress((void**)&bskv, g_bskv);

    const int M = ML;

    cvt_all<<<(S8 + 255) / 256, 256>>>(pw_w1, pw_w2, ring_wq, ring_wk, ring_wv, ring_wo,
                                       star_wk, star_wv, w1p, w2p, qkvp, rop, skvp);
    concat_bias<<<(NLAYERS * 5 * Hd + 255) / 256, 256>>>(ring_bq, ring_bk, ring_bv,
                                                          star_bk, star_bv, bqkv, bskv);
    embed_kernel<<<(ML * Hd + 255) / 256, 256>>>(src, emb, pos_table, x, x2, mask);

    bool relay_done = false;
    for (int i = 0; i < NLAYERS; i++) {
        const float* b1 = pw_b1 + (size_t)i * DI;
        const float* b2 = pw_b2 + (size_t)i * Hd;
        const float* pg = pw_g + (size_t)i * Hd;
        const float* pb = pw_bn + (size_t)i * Hd;
        const float* rbk = ring_bk + (size_t)i * Hd;
        const float* rbv = ring_bv + (size_t)i * Hd;
        const float* rbo = ring_bo + (size_t)i * Hd;
        const float* ng = norm_g + (size_t)i * Hd;
        const float* nb = norm_b + (size_t)i * Hd;
        const float* rwk = ring_wk + (size_t)i * Hd * Hd;
        const float* rwv = ring_wv + (size_t)i * Hd * Hd;
        const __half* w1i = w1p + (size_t)i * DI * 2 * Hd;
        const __half* w2i = w2p + (size_t)i * Hd * 2 * DI;
        const __half* qkvi = qkvp + (size_t)i * 3 * Hd * 2 * Hd;
        const __half* roi = rop + (size_t)i * Hd * 2 * Hd;
        const __half* skvi = skvp + (size_t)i * 2 * Hd * 2 * Hd;
        const float* bqkvi = bqkv + (size_t)i * 3 * Hd;
        const float* bskvi = bskv + (size_t)i * 2 * Hd;

        // PWFF
        gemm_p(1, 1, 0, 2, x2, w1i, b1, nullptr, 0, mid2, nullptr, M, DI, Hd);   // launch 3 = profiled
        gemm_p(0, 0, 1, 2, mid2, w2i, b2, ring, Hd, nullptr, ring2, M, Hd, DI);
        ln_kernel<1, 0, 1, 0><<<M / 8, 256>>>(ring, x, ring2, pg, pb, nullptr, h2, nullptr);

        if (!relay_done) {
            dim3 gp(6, 16, Bx);
            relay_part_kernel<<<gp, 128>>>(x2, part);
            dim3 gf(6, Bx);
            relay_fin_kernel<<<gf, 128>>>(part, relay);
            relay_done = true;
        }

        gemm_rel5<<<(5 * Hd * 32 + 255) / 256, 256>>>(relay,
            rwk, rbk, rwv, rbv,
            star_wq + (size_t)i * Hd * Hd, star_bq + (size_t)i * Hd,
            star_wk + (size_t)i * Hd * Hd, star_bk + (size_t)i * Hd,
            star_wv + (size_t)i * Hd * Hd, star_bv + (size_t)i * Hd,
            rk, rv, sq, srk, srv);

        // Ring attention
        gemm_p(0, 1, 0, 2, h2, qkvi, bqkvi, nullptr, 0, qkv, nullptr, M, 3 * Hd, Hd);
        ring_attn_kernel<<<(M * NHd) / 8, 256>>>(qkv, rk, rv, att2);
        gemm_p(0, 0, 1, 2, att2, roi, rbo, ring, Hd, nullptr, ring2, M, Hd, Hd);
        ln_kernel<0, 2, 2, 1><<<M / 8, 256>>>(ring, nullptr, ring2, ng, nb, x, x2, mask);

        // Star attention (1-product KV GEMM: relay-path precision budgeted)
        gemm_p(0, 1, 0, 1, x2, skvi, bskvi, nullptr, 0, kv, nullptr, M, 2 * Hd, Hd);
        star_attn_kernel<<<Bx * NHd, 1024>>>(sq, kv, srk, srv, mask, satt);
        gemm_small8<<<(Hd * 32 + 255) / 256, 256>>>(satt, Hd,
            star_wo + (size_t)i * Hd * Hd, Hd, star_bo + (size_t)i * Hd,
            relay, Hd, Hd, Hd, 2);
    }

    // heads
    gather_ft_kernel<<<(Bx * 2 * Hd + 255) / 256, 256>>>(relay, x, positions, ft);
    gemm_small8<<<(3 * NHID * 32 + 255) / 256, 256>>>(ft, 2 * Hd, head_w1, 2 * Hd,
                                                      head_b1, hid, 3 * NHID,
                                                      3 * NHID, 2 * Hd, 1);
    head2_kernel<<<(3 * NOUT * 32 + 255) / 256, 256>>>(hid, head_w2, head_b2, out);
}

// round 15
// speedup vs baseline: 1.9482x; 1.1102x over previous
#include <cuda_runtime.h>
#include <cuda_fp16.h>
#include <math.h>
#include <stdint.h>

// ---------------- problem constants ----------------
#define Bx 8
#define Lx 1024
#define Hd 768
#define NHd 12
#define HDd 64
#define DI 3072
#define NLAYERS 2
#define NHID 1024
#define NOUT 5000
#define SCALE_ATT 0.125f
#define LEAKY 0.01f
#define ML (Bx*Lx)      // 8192

// ---------------- fp32 scratch ----------------
__device__ float g_x    [ML*Hd];
__device__ float g_ring [ML*Hd];
__device__ float g_ring2[ML*Hd];
__device__ float g_relay[Bx*Hd];
__device__ float g_part[Bx*16*Hd];
__device__ float g_rk  [Bx*Hd];
__device__ float g_rv  [Bx*Hd];
__device__ float g_sq  [Bx*Hd];
__device__ float g_srk [Bx*Hd];
__device__ float g_srv [Bx*Hd];
__device__ float g_satt[Bx*Hd];
__device__ float g_ft  [Bx*2*Hd];
__device__ float g_hid [Bx*3*NHID];
__device__ int   g_mask[Bx*Lx];

// ---------------- fp16 scratch ----------------
__device__ __half g_x2  [ML*Hd];
__device__ __half g_h2  [ML*Hd];
__device__ __half g_att2[ML*Hd];
__device__ __half g_mid2[(size_t)ML*DI];
__device__ __half g_qkv [ML*3*Hd];
__device__ __half g_kv  [ML*2*Hd];
// weights: 2-plane layout (per 16-group: 16 hi then 16 lo), row stride 2K
__device__ __half g_w1p [(size_t)NLAYERS*DI*2*Hd];
__device__ __half g_w2p [(size_t)NLAYERS*Hd*2*DI];
__device__ __half g_qkvp[(size_t)NLAYERS*3*Hd*2*Hd];
__device__ __half g_rop [(size_t)NLAYERS*Hd*2*Hd];
__device__ __half g_skvp[(size_t)NLAYERS*2*Hd*2*Hd];
__device__ float g_bqkv[NLAYERS*3*Hd];
__device__ float g_bskv[NLAYERS*2*Hd];

// ---------------- helpers ----------------
__device__ __forceinline__ uint32_t cvta_s(const void* p) {
    return (uint32_t)__cvta_generic_to_shared(p);
}
__device__ __forceinline__ void ldsm4(uint32_t* r, uint32_t addr) {
    asm volatile("ldmatrix.sync.aligned.m8n8.x4.shared.b16 {%0,%1,%2,%3}, [%4];\n"
                 : "=r"(r[0]), "=r"(r[1]), "=r"(r[2]), "=r"(r[3]) : "r"(addr));
}
__device__ __forceinline__ void mma16816(float* c, const uint32_t* a, const uint32_t* b) {
    asm volatile("mma.sync.aligned.m16n8k16.row.col.f32.f16.f16.f32 "
                 "{%0,%1,%2,%3},{%4,%5,%6,%7},{%8,%9},{%0,%1,%2,%3};\n"
                 : "+f"(c[0]), "+f"(c[1]), "+f"(c[2]), "+f"(c[3])
                 : "r"(a[0]), "r"(a[1]), "r"(a[2]), "r"(a[3]), "r"(b[0]), "r"(b[1]));
}
__device__ __forceinline__ void cp16(uint32_t s, const void* g) {
    asm volatile("cp.async.cg.shared.global [%0], [%1], 16;\n" :: "r"(s), "l"(g));
}
__device__ __forceinline__ void split_hl(float v, __half& hi, __half& lo) {
    hi = __float2half_rn(v);
    lo = __float2half_rn(v - __half2float(hi));
}
__device__ __forceinline__ uint32_t sw128(uint32_t o) { return o ^ ((o >> 3) & 0x70); }

// =====================================================================
// Tensor-core GEMM, 128x128 tile, 2x4 warps, 2-stage pipeline,
// 64 fp32-k per chunk. A: plain fp16 [M,K]. W: 2-plane [N,2K].
// NP=2: Ah*Bh + Ah*Bl (err ~2^-12). NP=1: Ah*Bh only (err ~2^-11).
// OUTP 0 = fp32 C (optional split-K via grid.z), 1 = fp16 C2.
// =====================================================================
#define ATB 16384
#define BUFB (3*16384)
#define SMEM_G (2*BUFB)              // 96 KB

__device__ __forceinline__ void fill_tile(uint32_t base, const __half* A2, int lda,
                                          const __half* W2, int ldw2,
                                          int bm, int bn, int kc, int tid)
{
#pragma unroll
    for (int j = 0; j < 4; j++) {
        int idx = tid + j * 256;
        int row = idx >> 3, c16 = idx & 7;
        cp16(base + sw128((uint32_t)(row * 128 + c16 * 16)),
             A2 + (size_t)(bm + row) * lda + kc * 64 + c16 * 8);
    }
#pragma unroll
    for (int s = 0; s < 2; s++)
#pragma unroll
        for (int j = 0; j < 4; j++) {
            int idx = tid + j * 256;
            int row = idx >> 3, c16 = idx & 7;
            cp16(base + ATB + s * 16384 + sw128((uint32_t)(row * 128 + c16 * 16)),
                 W2 + (size_t)(bn + row) * ldw2 + kc * 128 + s * 64 + c16 * 8);
        }
}

template<int ACT, int OUTP, int NP>
__global__ __launch_bounds__(256, 2)
void gemm_tc2(const __half* __restrict__ A2, int lda,
              const __half* __restrict__ W2, int ldw2,
              const float* __restrict__ bias,
              float* __restrict__ C, int ldc,
              __half* __restrict__ C2, int Nout,
              float* __restrict__ Cs,
              int kAoff, int kWoff,
              int T)
{
    extern __shared__ __align__(128) char smraw[];
    const uint32_t sb = cvta_s(smraw);

    const int zz = blockIdx.z;
    if (zz) { A2 += kAoff; W2 += kWoff; }

    const int tid  = threadIdx.x;
    const int lane = tid & 31;
    const int warp = tid >> 5;
    const int wm = warp >> 2;
    const int wn = warp & 3;
    const int bm = blockIdx.y * 128;
    const int bn = blockIdx.x * 128;

    float acc[4][4][4];
#pragma unroll
    for (int i = 0; i < 4; i++)
#pragma unroll
        for (int j = 0; j < 4; j++)
#pragma unroll
            for (int c = 0; c < 4; c++) acc[i][j][c] = 0.f;

    const int a_row = lane & 15;
    const int a_kb  = (lane >> 4) * 16;
    const int b_row = (lane & 7) + ((lane >> 4) << 3);
    const int b_kb  = ((lane >> 3) & 1) * 16;

    fill_tile(sb, A2, lda, W2, ldw2, bm, bn, 0, tid);
    asm volatile("cp.async.commit_group;\n");

    for (int t = 0; t < T; t++) {
        __syncthreads();
        if (t + 1 < T) {
            fill_tile(sb + ((t + 1) & 1) * BUFB, A2, lda, W2, ldw2, bm, bn, t + 1, tid);
            asm volatile("cp.async.commit_group;\n");
            asm volatile("cp.async.wait_group 1;\n");
        } else {
            asm volatile("cp.async.wait_group 0;\n");
        }
        __syncthreads();

        const uint32_t ab = sb + (t & 1) * BUFB;
        const uint32_t bb = ab + ATB;

#pragma unroll
        for (int g2 = 0; g2 < 4; g2++) {
            const uint32_t bsub = bb + (g2 >> 1) * 16384;
            const int gb = (g2 & 1) * 64;
            uint32_t bh[2][4], afh[4][4], bl_[2][4];
#pragma unroll
            for (int p = 0; p < 2; p++) {
                int row = wn * 32 + p * 16 + b_row;
                ldsm4(bh[p], bsub + sw128((uint32_t)(row * 128 + gb + b_kb)));
            }
#pragma unroll
            for (int mt = 0; mt < 4; mt++) {
                int row = wm * 64 + mt * 16 + a_row;
                ldsm4(afh[mt], ab + sw128((uint32_t)(row * 128 + g2 * 32 + a_kb)));
            }
            if (NP == 2) {
#pragma unroll
                for (int p = 0; p < 2; p++) {
                    int row = wn * 32 + p * 16 + b_row;
                    ldsm4(bl_[p], bsub + sw128((uint32_t)(row * 128 + gb + 32 + b_kb)));
                }
            }
#pragma unroll
            for (int mt = 0; mt < 4; mt++)
#pragma unroll
                for (int nt = 0; nt < 4; nt++)
                    mma16816(acc[mt][nt], afh[mt], &bh[nt >> 1][(nt & 1) * 2]);
            if (NP == 2) {
#pragma unroll
                for (int mt = 0; mt < 4; mt++)
#pragma unroll
                    for (int nt = 0; nt < 4; nt++)
                        mma16816(acc[mt][nt], afh[mt], &bl_[nt >> 1][(nt & 1) * 2]);
            }
        }
    }

    float* Co = zz ? Cs : C;
#pragma unroll
    for (int mt = 0; mt < 4; mt++) {
#pragma unroll
        for (int nt = 0; nt < 4; nt++) {
            int row = bm + wm * 64 + mt * 16 + (lane >> 2);
            int col = bn + wn * 32 + nt * 8 + (lane & 3) * 2;
            float bi0 = zz ? 0.f : bias[col];
            float bi1 = zz ? 0.f : bias[col + 1];
            float v0 = acc[mt][nt][0] + bi0;
            float v1 = acc[mt][nt][1] + bi1;
            float v2 = acc[mt][nt][2] + bi0;
            float v3 = acc[mt][nt][3] + bi1;
            if (ACT == 1) {
                v0 = fmaxf(v0, 0.f); v1 = fmaxf(v1, 0.f);
                v2 = fmaxf(v2, 0.f); v3 = fmaxf(v3, 0.f);
            }
            if (OUTP == 0) {
                *(float2*)(Co + (size_t)row * ldc + col)       = make_float2(v0, v1);
                *(float2*)(Co + (size_t)(row + 8) * ldc + col) = make_float2(v2, v3);
            } else {
                *(__half2*)(C2 + (size_t)row * Nout + col) =
                    __halves2half2(__float2half_rn(v0), __float2half_rn(v1));
                *(__half2*)(C2 + (size_t)(row + 8) * Nout + col) =
                    __halves2half2(__float2half_rn(v2), __float2half_rn(v3));
            }
        }
    }
}

static void gemm_p(int act, int outp, int split, int np,
                   const __half* A2, const __half* W2,
                   const float* bias, float* C, int ldc, __half* C2, float* Cs,
                   int M, int N, int K)
{
    int Keff = split ? K / 2 : K;
    dim3 grid(N / 128, M / 128, split ? 2 : 1);
    int T = Keff / 64;
    int kAoff = Keff;
    int kWoff = 2 * Keff;
    if (outp == 1) {
        if (act == 1)      gemm_tc2<1, 1, 2><<<grid, 256, SMEM_G>>>(A2, K, W2, 2 * K, bias, nullptr, 0, C2, N, nullptr, 0, 0, T);
        else if (np == 1)  gemm_tc2<0, 1, 1><<<grid, 256, SMEM_G>>>(A2, K, W2, 2 * K, bias, nullptr, 0, C2, N, nullptr, 0, 0, T);
        else               gemm_tc2<0, 1, 2><<<grid, 256, SMEM_G>>>(A2, K, W2, 2 * K, bias, nullptr, 0, C2, N, nullptr, 0, 0, T);
    } else {
        if (np == 1)       gemm_tc2<0, 0, 1><<<grid, 256, SMEM_G>>>(A2, K, W2, 2 * K, bias, C, ldc, nullptr, N, Cs, kAoff, kWoff, T);
        else               gemm_tc2<0, 0, 2><<<grid, 256, SMEM_G>>>(A2, K, W2, 2 * K, bias, C, ldc, nullptr, N, Cs, kAoff, kWoff, T);
    }
}

// =====================================================================
// fused weight plane conversion
// =====================================================================
#define S1 1179648
#define S2 2359296
#define S3 2654208
#define S4 2949120
#define S5 3244032
#define S6 3538944
#define S7 3833856
#define S8 4128768

__global__ void cvt_all(const float* w1, const float* w2, const float* rq, const float* rk,
                        const float* rv, const float* ro, const float* sk, const float* sv,
                        __half* o1, __half* o2, __half* oqkv,
                        __half* oro, __half* oskv)
{
    int i = blockIdx.x * blockDim.x + threadIdx.x;
    if (i >= S8) return;
    const float* in; __half* out; int C, base, extra;
    if      (i < S1) { in = w1; out = o1;   C = Hd; base = 0;  extra = 0; }
    else if (i < S2) { in = w2; out = o2;   C = DI; base = S1; extra = 0; }
    else if (i < S3) { in = rq; out = oqkv;                        C = Hd; base = S2; extra = 1536; }
    else if (i < S4) { in = rk; out = oqkv + (size_t)768 * 2 * Hd; C = Hd; base = S3; extra = 1536; }
    else if (i < S5) { in = rv; out = oqkv + (size_t)1536 * 2 * Hd;C = Hd; base = S4; extra = 1536; }
    else if (i < S6) { in = ro; out = oro;  C = Hd; base = S5; extra = 0; }
    else if (i < S7) { in = sk; out = oskv;                        C = Hd; base = S6; extra = 768; }
    else             { in = sv; out = oskv + (size_t)768 * 2 * Hd; C = Hd; base = S7; extra = 768; }
    int e = (i - base) * 4;
    int r = e / C, c = e % C;
    size_t ro_ = (size_t)r + (size_t)(r / Hd) * extra;
    if (extra == 0 && C == DI) ro_ = r;
    float4 f = *(const float4*)(in + e);
    __half h0, h1, h2, h3, l0, l1, l2, l3;
    split_hl(f.x, h0, l0); split_hl(f.y, h1, l1);
    split_hl(f.z, h2, l2); split_hl(f.w, h3, l3);
    __half* p = out + ro_ * (2 * C) + 32 * (c >> 4) + (c & 15);
    *(__half2*)(p)      = __halves2half2(h0, h1);
    *(__half2*)(p + 2)  = __halves2half2(h2, h3);
    *(__half2*)(p + 16) = __halves2half2(l0, l1);
    *(__half2*)(p + 18) = __halves2half2(l2, l3);
}

__global__ void concat_bias(const float* bq, const float* bk, const float* bv,
                            const float* sk, const float* sv,
                            float* oqkv, float* oskv)
{
    int i = blockIdx.x * blockDim.x + threadIdx.x;
    int n1 = NLAYERS * 3 * Hd;
    if (i < n1) {
        int layer = i / (3 * Hd), c = i % (3 * Hd);
        const float* s = (c < Hd) ? bq : (c < 2 * Hd) ? bk : bv;
        oqkv[i] = s[layer * Hd + (c % Hd)];
    } else if (i < n1 + NLAYERS * 2 * Hd) {
        int j = i - n1;
        int layer = j / (2 * Hd), c = j % (2 * Hd);
        const float* s = (c < Hd) ? sk : sv;
        oskv[j] = s[layer * Hd + (c % Hd)];
    }
}

// =====================================================================
// Small-M GEMMs (M=8)
// =====================================================================
__device__ __forceinline__ void smalldot8(const float* __restrict__ A, int lda,
                                          const float* __restrict__ wrow, int K,
                                          int lane, float* s)
{
    const float4* w4 = (const float4*)wrow;
    int K4 = K >> 2;
#pragma unroll
    for (int m = 0; m < 8; m++) s[m] = 0.f;
    for (int k = lane; k < K4; k += 32) {
        float4 w = w4[k];
#pragma unroll
        for (int m = 0; m < 8; m++) {
            float4 a = ((const float4*)(A + (size_t)m * lda))[k];
            s[m] += a.x * w.x + a.y * w.y + a.z * w.z + a.w * w.w;
        }
    }
#pragma unroll
    for (int m = 0; m < 8; m++)
#pragma unroll
        for (int o = 16; o; o >>= 1) s[m] += __shfl_xor_sync(0xffffffffu, s[m], o);
}

__global__ __launch_bounds__(256)
void gemm_small8(const float* __restrict__ A, int lda,
                 const float* __restrict__ W, int ldw,
                 const float* __restrict__ bias,
                 float* __restrict__ C, int ldc,
                 int N, int K, int act)
{
    int n = (blockIdx.x * blockDim.x + threadIdx.x) >> 5;
    int lane = threadIdx.x & 31;
    if (n >= N) return;
    float s[8];
    smalldot8(A, lda, W + (size_t)n * ldw, K, lane, s);
    if (lane == 0) {
        float bv = bias[n];
#pragma unroll
        for (int m = 0; m < 8; m++) {
            float v = s[m] + bv;
            if (act == 1) v = fmaxf(v, 0.f);
            else if (act == 2) v = v > 0.f ? v : LEAKY * v;
            C[(size_t)m * ldc + n] = v;
        }
    }
}

__global__ __launch_bounds__(256)
void gemm_rel5(const float* __restrict__ relay,
               const float* __restrict__ rwk, const float* __restrict__ rbk,
               const float* __restrict__ rwv, const float* __restrict__ rbv,
               const float* __restrict__ swq, const float* __restrict__ sbq,
               const float* __restrict__ swk, const float* __restrict__ sbk,
               const float* __restrict__ swv, const float* __restrict__ sbv,
               float* __restrict__ rk, float* __restrict__ rv, float* __restrict__ sq,
               float* __restrict__ srk, float* __restrict__ srv)
{
    int n = (blockIdx.x * blockDim.x + threadIdx.x) >> 5;
    int lane = threadIdx.x & 31;
    if (n >= 5 * Hd) return;
    int seg = n / Hd, c = n % Hd;
    const float* W = (seg == 0) ? rwk : (seg == 1) ? rwv : (seg == 2) ? swq : (seg == 3) ? swk : swv;
    const float* B = (seg == 0) ? rbk : (seg == 1) ? rbv : (seg == 2) ? sbq : (seg == 3) ? sbk : sbv;
    float* C       = (seg == 0) ? rk  : (seg == 1) ? rv  : (seg == 2) ? sq  : (seg == 3) ? srk : srv;
    float s[8];
    smalldot8(relay, Hd, W + (size_t)c * Hd, Hd, lane, s);
    if (lane == 0) {
        float bb = B[c];
#pragma unroll
        for (int m = 0; m < 8; m++) C[(size_t)m * Hd + c] = s[m] + bb;
    }
}

__global__ __launch_bounds__(256)
void head2_kernel(const float* __restrict__ hid,
                  const float* __restrict__ w2,
                  const float* __restrict__ b2,
                  float* __restrict__ out)
{
    int n = (blockIdx.x * blockDim.x + threadIdx.x) >> 5;
    int lane = threadIdx.x & 31;
    if (n >= 3 * NOUT) return;
    int j = n / NOUT, c = n % NOUT;
    float s[8];
    smalldot8(hid + j * NHID, 3 * NHID, w2 + (size_t)n * NHID, NHID, lane, s);
    if (lane == 0) {
        float bb = b2[n];
#pragma unroll
        for (int m = 0; m < 8; m++)
            out[((size_t)m * 3 + j) * NOUT + c] = s[m] + bb;
    }
}

// ---------------- block reductions (for star_attn) ----------------
template<int NW>
__device__ __forceinline__ float block_reduce_max(float a)
{
    static __shared__ float sm[NW];
    __syncthreads();
    int lane = threadIdx.x & 31, w = threadIdx.x >> 5;
#pragma unroll
    for (int o = 16; o; o >>= 1) a = fmaxf(a, __shfl_xor_sync(0xffffffffu, a, o));
    if (lane == 0) sm[w] = a;
    __syncthreads();
    if (w == 0) {
        a = lane < NW ? sm[lane] : -1e30f;
#pragma unroll
        for (int o = NW / 2; o; o >>= 1) a = fmaxf(a, __shfl_xor_sync(0xffffffffu, a, o));
        if (lane == 0) sm[0] = a;
    }
    __syncthreads();
    return sm[0];
}
template<int NW>
__device__ __forceinline__ float block_reduce_sum(float a)
{
    static __shared__ float ss[NW];
    __syncthreads();
    int lane = threadIdx.x & 31, w = threadIdx.x >> 5;
#pragma unroll
    for (int o = 16; o; o >>= 1) a += __shfl_xor_sync(0xffffffffu, a, o);
    if (lane == 0) ss[w] = a;
    __syncthreads();
    if (w == 0) {
        a = lane < NW ? ss[lane] : 0.f;
#pragma unroll
        for (int o = NW / 2; o; o >>= 1) a += __shfl_xor_sync(0xffffffffu, a, o);
        if (lane == 0) ss[0] = a;
    }
    __syncthreads();
    return ss[0];
}

// ---------------- embed + mask ----------------
__global__ void embed_kernel(const int* __restrict__ src, const float* __restrict__ emb,
                             const float* __restrict__ pos, float* __restrict__ x,
                             __half* __restrict__ x2, int* __restrict__ mask)
{
    int idx = blockIdx.x * blockDim.x + threadIdx.x;
    if (idx >= ML * Hd) return;
    int h = idx % Hd;
    int bl = idx / Hd;
    int l = bl % Lx;
    int w = h >> 8;
    int dd = h & 255;
    int tok = src[bl * 3 + w];
    float v = emb[tok * 256 + dd] + pos[l * Hd + h];
    x[idx] = v;
    x2[idx] = __float2half_rn(v);
    if (h == 0) mask[bl] = (src[bl * 3] == 0) ? 1 : 0;
}

// ---------------- relay mean: 2-stage ----------------
__global__ void relay_part_kernel(const __half* __restrict__ x2, float* __restrict__ part)
{
    int h = blockIdx.x * 128 + threadIdx.x;
    int ch = blockIdx.y;
    int b = blockIdx.z;
    const __half* p = x2 + (size_t)b * Lx * Hd + (size_t)ch * 64 * Hd + h;
    float s = 0.f;
#pragma unroll 8
    for (int l = 0; l < 64; l++) s += __half2float(p[(size_t)l * Hd]);
    part[((size_t)b * 16 + ch) * Hd + h] = s;
}
__global__ void relay_fin_kernel(const float* __restrict__ part, float* __restrict__ relay)
{
    int h = blockIdx.x * 128 + threadIdx.x;
    int b = blockIdx.y;
    float s = 0.f;
#pragma unroll
    for (int ch = 0; ch < 16; ch++) s += part[((size_t)b * 16 + ch) * Hd + h];
    relay[b * Hd + h] = s * (1.0f / Lx);
}

// ---------------- layernorm: warp-per-row ----------------
template<int RES, int ACT, int MODE, int MASKED>
__global__ __launch_bounds__(256)
void ln_kernel(const float* __restrict__ x, const float* __restrict__ res,
               const float* __restrict__ res2,
               const float* __restrict__ g, const float* __restrict__ b,
               float* __restrict__ out, __half* __restrict__ out2,
               const int* __restrict__ mask)
{
    int row = blockIdx.x * 8 + (threadIdx.x >> 5);
    int lane = threadIdx.x & 31;
    const float* xr = x + (size_t)row * Hd;
    const float* rr = RES ? res + (size_t)row * Hd : nullptr;
    const float* r2 = res2 ? res2 + (size_t)row * Hd : nullptr;
    int mrow = MASKED ? mask[row] : 0;

    float t[24];
    float s = 0.f, ss = 0.f;
#pragma unroll
    for (int j = 0; j < 6; j++) {
        int off = j * 128 + lane * 4;
        float4 v = *(const float4*)(xr + off);
        if (r2) {
            float4 w = *(const float4*)(r2 + off);
            v.x += w.x; v.y += w.y; v.z += w.z; v.w += w.w;
        }
        if (RES) {
            float4 w = *(const float4*)(rr + off);
            v.x += w.x; v.y += w.y; v.z += w.z; v.w += w.w;
        }
        t[j * 4] = v.x; t[j * 4 + 1] = v.y; t[j * 4 + 2] = v.z; t[j * 4 + 3] = v.w;
        s += v.x + v.y + v.z + v.w;
        ss += v.x * v.x + v.y * v.y + v.z * v.z + v.w * v.w;
    }
#pragma unroll
    for (int o = 16; o; o >>= 1) {
        s  += __shfl_xor_sync(0xffffffffu, s, o);
        ss += __shfl_xor_sync(0xffffffffu, ss, o);
    }
    float mu = s * (1.0f / Hd);
    float var = ss * (1.0f / Hd) - mu * mu;
    float rstd = rsqrtf(var + 1e-5f);

#pragma unroll
    for (int j = 0; j < 6; j++) {
        int off = j * 128 + lane * 4;
        float4 gg = *(const float4*)(g + off);
        float4 bb = *(const float4*)(b + off);
        float v0 = (t[j * 4]     - mu) * rstd * gg.x + bb.x;
        float v1 = (t[j * 4 + 1] - mu) * rstd * gg.y + bb.y;
        float v2 = (t[j * 4 + 2] - mu) * rstd * gg.z + bb.z;
        float v3 = (t[j * 4 + 3] - mu) * rstd * gg.w + bb.w;
        if (ACT == 2) {
            v0 = v0 > 0.f ? v0 : LEAKY * v0;
            v1 = v1 > 0.f ? v1 : LEAKY * v1;
            v2 = v2 > 0.f ? v2 : LEAKY * v2;
            v3 = v3 > 0.f ? v3 : LEAKY * v3;
        }
        if (MASKED && mrow) { v0 = v1 = v2 = v3 = 0.f; }
        if (MODE != 1) {
            *(float4*)(out + (size_t)row * Hd + off) = make_float4(v0, v1, v2, v3);
        }
        if (MODE != 0) {
            __half* po = out2 + (size_t)row * Hd + off;
            *(__half2*)(po)     = __halves2half2(__float2half_rn(v0), __float2half_rn(v1));
            *(__half2*)(po + 2) = __halves2half2(__float2half_rn(v2), __float2half_rn(v3));
        }
    }
}

// ---------------- ring attention ----------------
__global__ __launch_bounds__(256)
void ring_attn_kernel(const __half* __restrict__ qkv, const float* __restrict__ rk,
                      const float* __restrict__ rv, __half* __restrict__ out2)
{
    int gw = (blockIdx.x * blockDim.x + threadIdx.x) >> 5;
    int lane = threadIdx.x & 31;
    int n = gw % NHd;
    int bl = gw / NHd;
    int l = bl % Lx;
    int b = bl / Lx;

    float2 qf = __half22float2(*(const __half2*)(qkv + (size_t)bl * (3 * Hd) + n * HDd + lane * 2));
    float q0 = qf.x, q1 = qf.y;

    float s[4];
#pragma unroll
    for (int w = 0; w < 3; w++) {
        int ll = l - 1 + w;
        float d = 0.f;
        if (ll >= 0 && ll < Lx) {
            float2 kf = __half22float2(*(const __half2*)(qkv + ((size_t)(b * Lx + ll)) * (3 * Hd) + Hd + n * HDd + lane * 2));
            d = q0 * kf.x + q1 * kf.y;
        }
#pragma unroll
        for (int o = 16; o; o >>= 1) d += __shfl_xor_sync(0xffffffffu, d, o);
        s[w] = d * SCALE_ATT;
    }
    {
        const float* kp = rk + b * Hd + n * HDd;
        float d = q0 * kp[lane * 2] + q1 * kp[lane * 2 + 1];
#pragma unroll
        for (int o = 16; o; o >>= 1) d += __shfl_xor_sync(0xffffffffu, d, o);
        s[3] = d * SCALE_ATT;
    }
    float m = fmaxf(fmaxf(s[0], s[1]), fmaxf(s[2], s[3]));
    float e[4], se = 0.f;
#pragma unroll
    for (int w = 0; w < 4; w++) { e[w] = expf(s[w] - m); se += e[w]; }
    float inv = 1.0f / se;

    float o0 = 0.f, o1 = 0.f;
#pragma unroll
    for (int w = 0; w < 3; w++) {
        int ll = l - 1 + w;
        if (ll >= 0 && ll < Lx) {
            float2 vf = __half22float2(*(const __half2*)(qkv + ((size_t)(b * Lx + ll)) * (3 * Hd) + 2 * Hd + n * HDd + lane * 2));
            float p = e[w] * inv;
            o0 += p * vf.x;
            o1 += p * vf.y;
        }
    }
    {
        const float* vp = rv + b * Hd + n * HDd;
        float p = e[3] * inv;
        o0 += p * vp[lane * 2];
        o1 += p * vp[lane * 2 + 1];
    }
    int c0 = n * HDd + lane * 2;
    *(__half2*)(out2 + (size_t)bl * Hd + c0) =
        __halves2half2(__float2half_rn(o0), __float2half_rn(o1));
}

// ---------------- star attention ----------------
__global__ __launch_bounds__(1024)
void star_attn_kernel(const float* __restrict__ sq, const __half* __restrict__ kv,
                      const float* __restrict__ rk, const float* __restrict__ rv,
                      const int* __restrict__ mask, float* __restrict__ out)
{
    __shared__ float qs[HDd];
    __shared__ float sc[Lx + 1];
    __shared__ float red[16 * HDd];

    int b = blockIdx.x / NHd;
    int n = blockIdx.x % NHd;
    int tid = threadIdx.x;

    if (tid < HDd) qs[tid] = sq[b * Hd + n * HDd + tid];
    __syncthreads();

    float lmax = -1e30f;
    for (int s = tid; s < Lx + 1; s += 1024) {
        float d = 0.f;
        if (s == 0) {
            const float* kp = rk + b * Hd + n * HDd;
#pragma unroll
            for (int i = 0; i < HDd; i++) d += qs[i] * kp[i];
        } else {
            const __half2* kp2 = (const __half2*)(kv + ((size_t)(b * Lx + s - 1)) * (2 * Hd) + n * HDd);
#pragma unroll
            for (int i = 0; i < HDd / 2; i++) {
                float2 f = __half22float2(kp2[i]);
                d += qs[2 * i] * f.x + qs[2 * i + 1] * f.y;
            }
        }
        d *= SCALE_ATT;
        if (s > 0 && mask[b * Lx + s - 1]) d = -1e30f;
        sc[s] = d;
        lmax = fmaxf(lmax, d);
    }
    float bmax = block_reduce_max<32>(lmax);

    float lsum = 0.f;
    for (int s = tid; s < Lx + 1; s += 1024) {
        float ev = expf(sc[s] - bmax);
        sc[s] = ev;
        lsum += ev;
    }
    float bsum = block_reduce_sum<32>(lsum);

    int gg = tid >> 6;
    int dd = tid & 63;
    float acc = 0.f;
    for (int s = gg; s < Lx + 1; s += 16) {
        float vv;
        if (s == 0) vv = rv[b * Hd + n * HDd + dd];
        else        vv = __half2float(kv[((size_t)(b * Lx + s - 1)) * (2 * Hd) + Hd + n * HDd + dd]);
        acc += sc[s] * vv;
    }
    red[gg * HDd + dd] = acc;
    __syncthreads();
    if (tid < HDd) {
        float r = 0.f;
#pragma unroll
        for (int g = 0; g < 16; g++) r += red[g * HDd + tid];
        out[b * Hd + n * HDd + tid] = r / bsum;
    }
}

// ---------------- gather ft ----------------
__global__ void gather_ft_kernel(const float* __restrict__ relay, const float* __restrict__ nodes,
                                 const int* __restrict__ positions, float* __restrict__ ft)
{
    int idx = blockIdx.x * blockDim.x + threadIdx.x;
    if (idx >= Bx * 2 * Hd) return;
    int b = idx / (2 * Hd);
    int i = idx % (2 * Hd);
    float v;
    if (i < Hd) v = relay[b * Hd + i];
    else        v = nodes[((size_t)b * Lx + positions[b]) * Hd + (i - Hd)];
    ft[idx] = v;
}

// ---------------- launch ----------------
extern "C" void kernel_launch(void* const* d_in, const int* in_sizes, int n_in,
                              void* d_out, int out_size)
{
    const int*   src       = (const int*)  d_in[0];
    const int*   positions = (const int*)  d_in[1];
    const float* emb       = (const float*)d_in[2];
    const float* pos_table = (const float*)d_in[3];
    const float* norm_g    = (const float*)d_in[4];
    const float* norm_b    = (const float*)d_in[5];
    const float* pw_w1     = (const float*)d_in[6];
    const float* pw_b1     = (const float*)d_in[7];
    const float* pw_w2     = (const float*)d_in[8];
    const float* pw_b2     = (const float*)d_in[9];
    const float* pw_g      = (const float*)d_in[10];
    const float* pw_bn     = (const float*)d_in[11];
    const float* ring_wq   = (const float*)d_in[12];
    const float* ring_bq   = (const float*)d_in[13];
    const float* ring_wk   = (const float*)d_in[14];
    const float* ring_bk   = (const float*)d_in[15];
    const float* ring_wv   = (const float*)d_in[16];
    const float* ring_bv   = (const float*)d_in[17];
    const float* ring_wo   = (const float*)d_in[18];
    const float* ring_bo   = (const float*)d_in[19];
    const float* star_wq   = (const float*)d_in[20];
    const float* star_bq   = (const float*)d_in[21];
    const float* star_wk   = (const float*)d_in[22];
    const float* star_bk   = (const float*)d_in[23];
    const float* star_wv   = (const float*)d_in[24];
    const float* star_bv   = (const float*)d_in[25];
    const float* star_wo   = (const float*)d_in[26];
    const float* star_bo   = (const float*)d_in[27];
    const float* head_w1   = (const float*)d_in[28];
    const float* head_b1   = (const float*)d_in[29];
    const float* head_w2   = (const float*)d_in[30];
    const float* head_b2   = (const float*)d_in[31];
    float* out = (float*)d_out;

    cudaFuncSetAttribute(gemm_tc2<0, 0, 2>, cudaFuncAttributeMaxDynamicSharedMemorySize, SMEM_G);
    cudaFuncSetAttribute(gemm_tc2<0, 0, 1>, cudaFuncAttributeMaxDynamicSharedMemorySize, SMEM_G);
    cudaFuncSetAttribute(gemm_tc2<0, 1, 2>, cudaFuncAttributeMaxDynamicSharedMemorySize, SMEM_G);
    cudaFuncSetAttribute(gemm_tc2<0, 1, 1>, cudaFuncAttributeMaxDynamicSharedMemorySize, SMEM_G);
    cudaFuncSetAttribute(gemm_tc2<1, 1, 2>, cudaFuncAttributeMaxDynamicSharedMemorySize, SMEM_G);

    float *x, *ring, *ring2, *relay, *part, *rk, *rv, *sq, *srk, *srv;
    float *satt, *ft, *hid, *bqkv, *bskv;
    int* mask;
    __half *x2, *h2, *att2, *mid2, *qkv, *kv;
    __half *w1p, *w2p, *qkvp, *rop, *skvp;
    cudaGetSymbolAddress((void**)&x, g_x);
    cudaGetSymbolAddress((void**)&ring, g_ring);
    cudaGetSymbolAddress((void**)&ring2, g_ring2);
    cudaGetSymbolAddress((void**)&relay, g_relay);
    cudaGetSymbolAddress((void**)&part, g_part);
    cudaGetSymbolAddress((void**)&rk, g_rk);
    cudaGetSymbolAddress((void**)&rv, g_rv);
    cudaGetSymbolAddress((void**)&sq, g_sq);
    cudaGetSymbolAddress((void**)&srk, g_srk);
    cudaGetSymbolAddress((void**)&srv, g_srv);
    cudaGetSymbolAddress((void**)&satt, g_satt);
    cudaGetSymbolAddress((void**)&ft, g_ft);
    cudaGetSymbolAddress((void**)&hid, g_hid);
    cudaGetSymbolAddress((void**)&mask, g_mask);
    cudaGetSymbolAddress((void**)&x2, g_x2);
    cudaGetSymbolAddress((void**)&h2, g_h2);
    cudaGetSymbolAddress((void**)&att2, g_att2);
    cudaGetSymbolAddress((void**)&mid2, g_mid2);
    cudaGetSymbolAddress((void**)&qkv, g_qkv);
    cudaGetSymbolAddress((void**)&kv, g_kv);
    cudaGetSymbolAddress((void**)&w1p, g_w1p);
    cudaGetSymbolAddress((void**)&w2p, g_w2p);
    cudaGetSymbolAddress((void**)&qkvp, g_qkvp);
    cudaGetSymbolAddress((void**)&rop, g_rop);
    cudaGetSymbolAddress((void**)&skvp, g_skvp);
    cudaGetSymbolAddress((void**)&bqkv, g_bqkv);
    cudaGetSymbolAddress((void**)&bskv, g_bskv);

    const int M = ML;

    cvt_all<<<(S8 + 255) / 256, 256>>>(pw_w1, pw_w2, ring_wq, ring_wk, ring_wv, ring_wo,
                                       star_wk, star_wv, w1p, w2p, qkvp, rop, skvp);
    concat_bias<<<(NLAYERS * 5 * Hd + 255) / 256, 256>>>(ring_bq, ring_bk, ring_bv,
                                                          star_bk, star_bv, bqkv, bskv);
    embed_kernel<<<(ML * Hd + 255) / 256, 256>>>(src, emb, pos_table, x, x2, mask);

    bool relay_done = false;
    for (int i = 0; i < NLAYERS; i++) {
        const float* b1 = pw_b1 + (size_t)i * DI;
        const float* b2 = pw_b2 + (size_t)i * Hd;
        const float* pg = pw_g + (size_t)i * Hd;
        const float* pb = pw_bn + (size_t)i * Hd;
        const float* rbk = ring_bk + (size_t)i * Hd;
        const float* rbv = ring_bv + (size_t)i * Hd;
        const float* rbo = ring_bo + (size_t)i * Hd;
        const float* ng = norm_g + (size_t)i * Hd;
        const float* nb = norm_b + (size_t)i * Hd;
        const float* rwk = ring_wk + (size_t)i * Hd * Hd;
        const float* rwv = ring_wv + (size_t)i * Hd * Hd;
        const __half* w1i = w1p + (size_t)i * DI * 2 * Hd;
        const __half* w2i = w2p + (size_t)i * Hd * 2 * DI;
        const __half* qkvi = qkvp + (size_t)i * 3 * Hd * 2 * Hd;
        const __half* roi = rop + (size_t)i * Hd * 2 * Hd;
        const __half* skvi = skvp + (size_t)i * 2 * Hd * 2 * Hd;
        const float* bqkvi = bqkv + (size_t)i * 3 * Hd;
        const float* bskvi = bskv + (size_t)i * 2 * Hd;

        // PWFF (2-product: main trunk, keep precision)
        gemm_p(1, 1, 0, 2, x2, w1i, b1, nullptr, 0, mid2, nullptr, M, DI, Hd);   // launch 3 = profiled
        gemm_p(0, 0, 1, 2, mid2, w2i, b2, ring, Hd, nullptr, ring2, M, Hd, DI);
        ln_kernel<1, 0, 1, 0><<<M / 8, 256>>>(ring, x, ring2, pg, pb, nullptr, h2, nullptr);

        if (!relay_done) {
            dim3 gp(6, 16, Bx);
            relay_part_kernel<<<gp, 128>>>(x2, part);
            dim3 gf(6, Bx);
            relay_fin_kernel<<<gf, 128>>>(part, relay);
            relay_done = true;
        }

        gemm_rel5<<<(5 * Hd * 32 + 255) / 256, 256>>>(relay,
            rwk, rbk, rwv, rbv,
            star_wq + (size_t)i * Hd * Hd, star_bq + (size_t)i * Hd,
            star_wk + (size_t)i * Hd * Hd, star_bk + (size_t)i * Hd,
            star_wv + (size_t)i * Hd * Hd, star_bv + (size_t)i * Hd,
            rk, rv, sq, srk, srv);

        // Ring attention (1-product QKV: attention-path precision budgeted)
        gemm_p(0, 1, 0, 1, h2, qkvi, bqkvi, nullptr, 0, qkv, nullptr, M, 3 * Hd, Hd);
        ring_attn_kernel<<<(M * NHd) / 8, 256>>>(qkv, rk, rv, att2);
        // ring-O (1-product, split-K)
        gemm_p(0, 0, 1, 1, att2, roi, rbo, ring, Hd, nullptr, ring2, M, Hd, Hd);
        ln_kernel<0, 2, 2, 1><<<M / 8, 256>>>(ring, nullptr, ring2, ng, nb, x, x2, mask);

        // Star attention (1-product KV)
        gemm_p(0, 1, 0, 1, x2, skvi, bskvi, nullptr, 0, kv, nullptr, M, 2 * Hd, Hd);
        star_attn_kernel<<<Bx * NHd, 1024>>>(sq, kv, srk, srv, mask, satt);
        gemm_small8<<<(Hd * 32 + 255) / 256, 256>>>(satt, Hd,
            star_wo + (size_t)i * Hd * Hd, Hd, star_bo + (size_t)i * Hd,
            relay, Hd, Hd, Hd, 2);
    }

    // heads
    gather_ft_kernel<<<(Bx * 2 * Hd + 255) / 256, 256>>>(relay, x, positions, ft);
    gemm_small8<<<(3 * NHID * 32 + 255) / 256, 256>>>(ft, 2 * Hd, head_w1, 2 * Hd,
                                                      head_b1, hid, 3 * NHID,
                                                      3 * NHID, 2 * Hd, 1);
    head2_kernel<<<(3 * NOUT * 32 + 255) / 256, 256>>>(hid, head_w2, head_b2, out);
}

// round 16
// speedup vs baseline: 2.5024x; 1.2845x over previous
#include <cuda_runtime.h>
#include <cuda_fp16.h>
#include <math.h>
#include <stdint.h>

// ---------------- problem constants ----------------
#define Bx 8
#define Lx 1024
#define Hd 768
#define NHd 12
#define HDd 64
#define DI 3072
#define NLAYERS 2
#define NHID 1024
#define NOUT 5000
#define SCALE_ATT 0.125f
#define LEAKY 0.01f
#define ML (Bx*Lx)      // 8192

// ---------------- fp32 scratch ----------------
__device__ float g_x    [ML*Hd];
__device__ float g_ring [ML*Hd];
__device__ float g_ring2[ML*Hd];
__device__ float g_relay[Bx*Hd];
__device__ float g_part[Bx*16*Hd];
__device__ float g_rk  [Bx*Hd];
__device__ float g_rv  [Bx*Hd];
__device__ float g_sq  [Bx*Hd];
__device__ float g_srk [Bx*Hd];
__device__ float g_srv [Bx*Hd];
__device__ float g_satt[Bx*Hd];
__device__ float g_ft  [Bx*2*Hd];
__device__ float g_hid [Bx*3*NHID];
__device__ int   g_mask[Bx*Lx];

// ---------------- fp16 scratch ----------------
__device__ __half g_x2  [ML*Hd];
__device__ __half g_h2  [ML*Hd];
__device__ __half g_att2[ML*Hd];
__device__ __half g_mid2[(size_t)ML*DI];
__device__ __half g_qkv [ML*3*Hd];
__device__ __half g_kv  [ML*2*Hd];
// weights: 2-plane layout (per 16-group: 16 hi then 16 lo), row stride 2K
__device__ __half g_w1p [(size_t)NLAYERS*DI*2*Hd];
__device__ __half g_w2p [(size_t)NLAYERS*Hd*2*DI];
__device__ __half g_qkvp[(size_t)NLAYERS*3*Hd*2*Hd];
__device__ __half g_rop [(size_t)NLAYERS*Hd*2*Hd];
__device__ __half g_skvp[(size_t)NLAYERS*2*Hd*2*Hd];
__device__ float g_bqkv[NLAYERS*3*Hd];
__device__ float g_bskv[NLAYERS*2*Hd];

// ---------------- helpers ----------------
__device__ __forceinline__ uint32_t cvta_s(const void* p) {
    return (uint32_t)__cvta_generic_to_shared(p);
}
__device__ __forceinline__ void ldsm4(uint32_t* r, uint32_t addr) {
    asm volatile("ldmatrix.sync.aligned.m8n8.x4.shared.b16 {%0,%1,%2,%3}, [%4];\n"
                 : "=r"(r[0]), "=r"(r[1]), "=r"(r[2]), "=r"(r[3]) : "r"(addr));
}
__device__ __forceinline__ void mma16816(float* c, const uint32_t* a, const uint32_t* b) {
    asm volatile("mma.sync.aligned.m16n8k16.row.col.f32.f16.f16.f32 "
                 "{%0,%1,%2,%3},{%4,%5,%6,%7},{%8,%9},{%0,%1,%2,%3};\n"
                 : "+f"(c[0]), "+f"(c[1]), "+f"(c[2]), "+f"(c[3])
                 : "r"(a[0]), "r"(a[1]), "r"(a[2]), "r"(a[3]), "r"(b[0]), "r"(b[1]));
}
__device__ __forceinline__ void cp16(uint32_t s, const void* g) {
    asm volatile("cp.async.cg.shared.global [%0], [%1], 16;\n" :: "r"(s), "l"(g));
}
__device__ __forceinline__ void split_hl(float v, __half& hi, __half& lo) {
    hi = __float2half_rn(v);
    lo = __float2half_rn(v - __half2float(hi));
}
__device__ __forceinline__ uint32_t sw128(uint32_t o) { return o ^ ((o >> 3) & 0x70); }

// =====================================================================
// Tensor-core GEMM, 128x128 tile, 2x4 warps, 2-stage pipeline,
// 64 fp32-k per chunk. A: plain fp16 [M,K]. W: 2-plane [N,2K].
// NP=2: Ah*Bh + Ah*Bl (err ~2^-12). NP=1: Ah*Bh only (err ~2^-11).
// OUTP 0 = fp32 C (optional split-K via grid.z), 1 = fp16 C2.
// =====================================================================
#define ATB 16384
#define BUFB (3*16384)
#define SMEM_G (2*BUFB)              // 96 KB

__device__ __forceinline__ void fill_tile(uint32_t base, const __half* A2, int lda,
                                          const __half* W2, int ldw2,
                                          int bm, int bn, int kc, int tid)
{
#pragma unroll
    for (int j = 0; j < 4; j++) {
        int idx = tid + j * 256;
        int row = idx >> 3, c16 = idx & 7;
        cp16(base + sw128((uint32_t)(row * 128 + c16 * 16)),
             A2 + (size_t)(bm + row) * lda + kc * 64 + c16 * 8);
    }
#pragma unroll
    for (int s = 0; s < 2; s++)
#pragma unroll
        for (int j = 0; j < 4; j++) {
            int idx = tid + j * 256;
            int row = idx >> 3, c16 = idx & 7;
            cp16(base + ATB + s * 16384 + sw128((uint32_t)(row * 128 + c16 * 16)),
                 W2 + (size_t)(bn + row) * ldw2 + kc * 128 + s * 64 + c16 * 8);
        }
}

template<int ACT, int OUTP, int NP>
__global__ __launch_bounds__(256, 2)
void gemm_tc2(const __half* __restrict__ A2, int lda,
              const __half* __restrict__ W2, int ldw2,
              const float* __restrict__ bias,
              float* __restrict__ C, int ldc,
              __half* __restrict__ C2, int Nout,
              float* __restrict__ Cs,
              int kAoff, int kWoff,
              int T)
{
    extern __shared__ __align__(128) char smraw[];
    const uint32_t sb = cvta_s(smraw);

    const int zz = blockIdx.z;
    if (zz) { A2 += kAoff; W2 += kWoff; }

    const int tid  = threadIdx.x;
    const int lane = tid & 31;
    const int warp = tid >> 5;
    const int wm = warp >> 2;
    const int wn = warp & 3;
    const int bm = blockIdx.y * 128;
    const int bn = blockIdx.x * 128;

    float acc[4][4][4];
#pragma unroll
    for (int i = 0; i < 4; i++)
#pragma unroll
        for (int j = 0; j < 4; j++)
#pragma unroll
            for (int c = 0; c < 4; c++) acc[i][j][c] = 0.f;

    const int a_row = lane & 15;
    const int a_kb  = (lane >> 4) * 16;
    const int b_row = (lane & 7) + ((lane >> 4) << 3);
    const int b_kb  = ((lane >> 3) & 1) * 16;

    fill_tile(sb, A2, lda, W2, ldw2, bm, bn, 0, tid);
    asm volatile("cp.async.commit_group;\n");

    for (int t = 0; t < T; t++) {
        __syncthreads();
        if (t + 1 < T) {
            fill_tile(sb + ((t + 1) & 1) * BUFB, A2, lda, W2, ldw2, bm, bn, t + 1, tid);
            asm volatile("cp.async.commit_group;\n");
            asm volatile("cp.async.wait_group 1;\n");
        } else {
            asm volatile("cp.async.wait_group 0;\n");
        }
        __syncthreads();

        const uint32_t ab = sb + (t & 1) * BUFB;
        const uint32_t bb = ab + ATB;

#pragma unroll
        for (int g2 = 0; g2 < 4; g2++) {
            const uint32_t bsub = bb + (g2 >> 1) * 16384;
            const int gb = (g2 & 1) * 64;
            uint32_t bh[2][4], afh[4][4], bl_[2][4];
#pragma unroll
            for (int p = 0; p < 2; p++) {
                int row = wn * 32 + p * 16 + b_row;
                ldsm4(bh[p], bsub + sw128((uint32_t)(row * 128 + gb + b_kb)));
            }
#pragma unroll
            for (int mt = 0; mt < 4; mt++) {
                int row = wm * 64 + mt * 16 + a_row;
                ldsm4(afh[mt], ab + sw128((uint32_t)(row * 128 + g2 * 32 + a_kb)));
            }
            if (NP == 2) {
#pragma unroll
                for (int p = 0; p < 2; p++) {
                    int row = wn * 32 + p * 16 + b_row;
                    ldsm4(bl_[p], bsub + sw128((uint32_t)(row * 128 + gb + 32 + b_kb)));
                }
            }
#pragma unroll
            for (int mt = 0; mt < 4; mt++)
#pragma unroll
                for (int nt = 0; nt < 4; nt++)
                    mma16816(acc[mt][nt], afh[mt], &bh[nt >> 1][(nt & 1) * 2]);
            if (NP == 2) {
#pragma unroll
                for (int mt = 0; mt < 4; mt++)
#pragma unroll
                    for (int nt = 0; nt < 4; nt++)
                        mma16816(acc[mt][nt], afh[mt], &bl_[nt >> 1][(nt & 1) * 2]);
            }
        }
    }

    float* Co = zz ? Cs : C;
#pragma unroll
    for (int mt = 0; mt < 4; mt++) {
#pragma unroll
        for (int nt = 0; nt < 4; nt++) {
            int row = bm + wm * 64 + mt * 16 + (lane >> 2);
            int col = bn + wn * 32 + nt * 8 + (lane & 3) * 2;
            float bi0 = zz ? 0.f : bias[col];
            float bi1 = zz ? 0.f : bias[col + 1];
            float v0 = acc[mt][nt][0] + bi0;
            float v1 = acc[mt][nt][1] + bi1;
            float v2 = acc[mt][nt][2] + bi0;
            float v3 = acc[mt][nt][3] + bi1;
            if (ACT == 1) {
                v0 = fmaxf(v0, 0.f); v1 = fmaxf(v1, 0.f);
                v2 = fmaxf(v2, 0.f); v3 = fmaxf(v3, 0.f);
            }
            if (OUTP == 0) {
                *(float2*)(Co + (size_t)row * ldc + col)       = make_float2(v0, v1);
                *(float2*)(Co + (size_t)(row + 8) * ldc + col) = make_float2(v2, v3);
            } else {
                *(__half2*)(C2 + (size_t)row * Nout + col) =
                    __halves2half2(__float2half_rn(v0), __float2half_rn(v1));
                *(__half2*)(C2 + (size_t)(row + 8) * Nout + col) =
                    __halves2half2(__float2half_rn(v2), __float2half_rn(v3));
            }
        }
    }
}

static void gemm_p(int act, int outp, int split, int np,
                   const __half* A2, const __half* W2,
                   const float* bias, float* C, int ldc, __half* C2, float* Cs,
                   int M, int N, int K)
{
    int Keff = split ? K / 2 : K;
    dim3 grid(N / 128, M / 128, split ? 2 : 1);
    int T = Keff / 64;
    int kAoff = Keff;
    int kWoff = 2 * Keff;
    if (outp == 1) {
        if (act == 1 && np == 1)      gemm_tc2<1, 1, 1><<<grid, 256, SMEM_G>>>(A2, K, W2, 2 * K, bias, nullptr, 0, C2, N, nullptr, 0, 0, T);
        else if (act == 1)            gemm_tc2<1, 1, 2><<<grid, 256, SMEM_G>>>(A2, K, W2, 2 * K, bias, nullptr, 0, C2, N, nullptr, 0, 0, T);
        else if (np == 1)             gemm_tc2<0, 1, 1><<<grid, 256, SMEM_G>>>(A2, K, W2, 2 * K, bias, nullptr, 0, C2, N, nullptr, 0, 0, T);
        else                          gemm_tc2<0, 1, 2><<<grid, 256, SMEM_G>>>(A2, K, W2, 2 * K, bias, nullptr, 0, C2, N, nullptr, 0, 0, T);
    } else {
        if (np == 1)       gemm_tc2<0, 0, 1><<<grid, 256, SMEM_G>>>(A2, K, W2, 2 * K, bias, C, ldc, nullptr, N, Cs, kAoff, kWoff, T);
        else               gemm_tc2<0, 0, 2><<<grid, 256, SMEM_G>>>(A2, K, W2, 2 * K, bias, C, ldc, nullptr, N, Cs, kAoff, kWoff, T);
    }
}

// =====================================================================
// fused weight plane conversion
// =====================================================================
#define S1 1179648
#define S2 2359296
#define S3 2654208
#define S4 2949120
#define S5 3244032
#define S6 3538944
#define S7 3833856
#define S8 4128768

__global__ void cvt_all(const float* w1, const float* w2, const float* rq, const float* rk,
                        const float* rv, const float* ro, const float* sk, const float* sv,
                        __half* o1, __half* o2, __half* oqkv,
                        __half* oro, __half* oskv)
{
    int i = blockIdx.x * blockDim.x + threadIdx.x;
    if (i >= S8) return;
    const float* in; __half* out; int C, base, extra;
    if      (i < S1) { in = w1; out = o1;   C = Hd; base = 0;  extra = 0; }
    else if (i < S2) { in = w2; out = o2;   C = DI; base = S1; extra = 0; }
    else if (i < S3) { in = rq; out = oqkv;                        C = Hd; base = S2; extra = 1536; }
    else if (i < S4) { in = rk; out = oqkv + (size_t)768 * 2 * Hd; C = Hd; base = S3; extra = 1536; }
    else if (i < S5) { in = rv; out = oqkv + (size_t)1536 * 2 * Hd;C = Hd; base = S4; extra = 1536; }
    else if (i < S6) { in = ro; out = oro;  C = Hd; base = S5; extra = 0; }
    else if (i < S7) { in = sk; out = oskv;                        C = Hd; base = S6; extra = 768; }
    else             { in = sv; out = oskv + (size_t)768 * 2 * Hd; C = Hd; base = S7; extra = 768; }
    int e = (i - base) * 4;
    int r = e / C, c = e % C;
    size_t ro_ = (size_t)r + (size_t)(r / Hd) * extra;
    if (extra == 0 && C == DI) ro_ = r;
    float4 f = *(const float4*)(in + e);
    __half h0, h1, h2, h3, l0, l1, l2, l3;
    split_hl(f.x, h0, l0); split_hl(f.y, h1, l1);
    split_hl(f.z, h2, l2); split_hl(f.w, h3, l3);
    __half* p = out + ro_ * (2 * C) + 32 * (c >> 4) + (c & 15);
    *(__half2*)(p)      = __halves2half2(h0, h1);
    *(__half2*)(p + 2)  = __halves2half2(h2, h3);
    *(__half2*)(p + 16) = __halves2half2(l0, l1);
    *(__half2*)(p + 18) = __halves2half2(l2, l3);
}

__global__ void concat_bias(const float* bq, const float* bk, const float* bv,
                            const float* sk, const float* sv,
                            float* oqkv, float* oskv)
{
    int i = blockIdx.x * blockDim.x + threadIdx.x;
    int n1 = NLAYERS * 3 * Hd;
    if (i < n1) {
        int layer = i / (3 * Hd), c = i % (3 * Hd);
        const float* s = (c < Hd) ? bq : (c < 2 * Hd) ? bk : bv;
        oqkv[i] = s[layer * Hd + (c % Hd)];
    } else if (i < n1 + NLAYERS * 2 * Hd) {
        int j = i - n1;
        int layer = j / (2 * Hd), c = j % (2 * Hd);
        const float* s = (c < Hd) ? sk : sv;
        oskv[j] = s[layer * Hd + (c % Hd)];
    }
}

// =====================================================================
// Small-M GEMMs (M=8)
// =====================================================================
__device__ __forceinline__ void smalldot8(const float* __restrict__ A, int lda,
                                          const float* __restrict__ wrow, int K,
                                          int lane, float* s)
{
    const float4* w4 = (const float4*)wrow;
    int K4 = K >> 2;
#pragma unroll
    for (int m = 0; m < 8; m++) s[m] = 0.f;
    for (int k = lane; k < K4; k += 32) {
        float4 w = w4[k];
#pragma unroll
        for (int m = 0; m < 8; m++) {
            float4 a = ((const float4*)(A + (size_t)m * lda))[k];
            s[m] += a.x * w.x + a.y * w.y + a.z * w.z + a.w * w.w;
        }
    }
#pragma unroll
    for (int m = 0; m < 8; m++)
#pragma unroll
        for (int o = 16; o; o >>= 1) s[m] += __shfl_xor_sync(0xffffffffu, s[m], o);
}

__global__ __launch_bounds__(256)
void gemm_small8(const float* __restrict__ A, int lda,
                 const float* __restrict__ W, int ldw,
                 const float* __restrict__ bias,
                 float* __restrict__ C, int ldc,
                 int N, int K, int act)
{
    int n = (blockIdx.x * blockDim.x + threadIdx.x) >> 5;
    int lane = threadIdx.x & 31;
    if (n >= N) return;
    float s[8];
    smalldot8(A, lda, W + (size_t)n * ldw, K, lane, s);
    if (lane == 0) {
        float bv = bias[n];
#pragma unroll
        for (int m = 0; m < 8; m++) {
            float v = s[m] + bv;
            if (act == 1) v = fmaxf(v, 0.f);
            else if (act == 2) v = v > 0.f ? v : LEAKY * v;
            C[(size_t)m * ldc + n] = v;
        }
    }
}

__global__ __launch_bounds__(256)
void gemm_rel5(const float* __restrict__ relay,
               const float* __restrict__ rwk, const float* __restrict__ rbk,
               const float* __restrict__ rwv, const float* __restrict__ rbv,
               const float* __restrict__ swq, const float* __restrict__ sbq,
               const float* __restrict__ swk, const float* __restrict__ sbk,
               const float* __restrict__ swv, const float* __restrict__ sbv,
               float* __restrict__ rk, float* __restrict__ rv, float* __restrict__ sq,
               float* __restrict__ srk, float* __restrict__ srv)
{
    int n = (blockIdx.x * blockDim.x + threadIdx.x) >> 5;
    int lane = threadIdx.x & 31;
    if (n >= 5 * Hd) return;
    int seg = n / Hd, c = n % Hd;
    const float* W = (seg == 0) ? rwk : (seg == 1) ? rwv : (seg == 2) ? swq : (seg == 3) ? swk : swv;
    const float* B = (seg == 0) ? rbk : (seg == 1) ? rbv : (seg == 2) ? sbq : (seg == 3) ? sbk : sbv;
    float* C       = (seg == 0) ? rk  : (seg == 1) ? rv  : (seg == 2) ? sq  : (seg == 3) ? srk : srv;
    float s[8];
    smalldot8(relay, Hd, W + (size_t)c * Hd, Hd, lane, s);
    if (lane == 0) {
        float bb = B[c];
#pragma unroll
        for (int m = 0; m < 8; m++) C[(size_t)m * Hd + c] = s[m] + bb;
    }
}

__global__ __launch_bounds__(256)
void head2_kernel(const float* __restrict__ hid,
                  const float* __restrict__ w2,
                  const float* __restrict__ b2,
                  float* __restrict__ out)
{
    int n = (blockIdx.x * blockDim.x + threadIdx.x) >> 5;
    int lane = threadIdx.x & 31;
    if (n >= 3 * NOUT) return;
    int j = n / NOUT, c = n % NOUT;
    float s[8];
    smalldot8(hid + j * NHID, 3 * NHID, w2 + (size_t)n * NHID, NHID, lane, s);
    if (lane == 0) {
        float bb = b2[n];
#pragma unroll
        for (int m = 0; m < 8; m++)
            out[((size_t)m * 3 + j) * NOUT + c] = s[m] + bb;
    }
}

// ---------------- block reductions (for star_attn) ----------------
template<int NW>
__device__ __forceinline__ float block_reduce_max(float a)
{
    static __shared__ float sm[NW];
    __syncthreads();
    int lane = threadIdx.x & 31, w = threadIdx.x >> 5;
#pragma unroll
    for (int o = 16; o; o >>= 1) a = fmaxf(a, __shfl_xor_sync(0xffffffffu, a, o));
    if (lane == 0) sm[w] = a;
    __syncthreads();
    if (w == 0) {
        a = lane < NW ? sm[lane] : -1e30f;
#pragma unroll
        for (int o = NW / 2; o; o >>= 1) a = fmaxf(a, __shfl_xor_sync(0xffffffffu, a, o));
        if (lane == 0) sm[0] = a;
    }
    __syncthreads();
    return sm[0];
}
template<int NW>
__device__ __forceinline__ float block_reduce_sum(float a)
{
    static __shared__ float ss[NW];
    __syncthreads();
    int lane = threadIdx.x & 31, w = threadIdx.x >> 5;
#pragma unroll
    for (int o = 16; o; o >>= 1) a += __shfl_xor_sync(0xffffffffu, a, o);
    if (lane == 0) ss[w] = a;
    __syncthreads();
    if (w == 0) {
        a = lane < NW ? ss[lane] : 0.f;
#pragma unroll
        for (int o = NW / 2; o; o >>= 1) a += __shfl_xor_sync(0xffffffffu, a, o);
        if (lane == 0) ss[0] = a;
    }
    __syncthreads();
    return ss[0];
}

// ---------------- embed + mask ----------------
__global__ void embed_kernel(const int* __restrict__ src, const float* __restrict__ emb,
                             const float* __restrict__ pos, float* __restrict__ x,
                             __half* __restrict__ x2, int* __restrict__ mask)
{
    int idx = blockIdx.x * blockDim.x + threadIdx.x;
    if (idx >= ML * Hd) return;
    int h = idx % Hd;
    int bl = idx / Hd;
    int l = bl % Lx;
    int w = h >> 8;
    int dd = h & 255;
    int tok = src[bl * 3 + w];
    float v = emb[tok * 256 + dd] + pos[l * Hd + h];
    x[idx] = v;
    x2[idx] = __float2half_rn(v);
    if (h == 0) mask[bl] = (src[bl * 3] == 0) ? 1 : 0;
}

// ---------------- relay mean: 2-stage ----------------
__global__ void relay_part_kernel(const __half* __restrict__ x2, float* __restrict__ part)
{
    int h = blockIdx.x * 128 + threadIdx.x;
    int ch = blockIdx.y;
    int b = blockIdx.z;
    const __half* p = x2 + (size_t)b * Lx * Hd + (size_t)ch * 64 * Hd + h;
    float s = 0.f;
#pragma unroll 8
    for (int l = 0; l < 64; l++) s += __half2float(p[(size_t)l * Hd]);
    part[((size_t)b * 16 + ch) * Hd + h] = s;
}
__global__ void relay_fin_kernel(const float* __restrict__ part, float* __restrict__ relay)
{
    int h = blockIdx.x * 128 + threadIdx.x;
    int b = blockIdx.y;
    float s = 0.f;
#pragma unroll
    for (int ch = 0; ch < 16; ch++) s += part[((size_t)b * 16 + ch) * Hd + h];
    relay[b * Hd + h] = s * (1.0f / Lx);
}

// ---------------- layernorm: warp-per-row ----------------
template<int RES, int ACT, int MODE, int MASKED>
__global__ __launch_bounds__(256)
void ln_kernel(const float* __restrict__ x, const float* __restrict__ res,
               const float* __restrict__ res2,
               const float* __restrict__ g, const float* __restrict__ b,
               float* __restrict__ out, __half* __restrict__ out2,
               const int* __restrict__ mask)
{
    int row = blockIdx.x * 8 + (threadIdx.x >> 5);
    int lane = threadIdx.x & 31;
    const float* xr = x + (size_t)row * Hd;
    const float* rr = RES ? res + (size_t)row * Hd : nullptr;
    const float* r2 = res2 ? res2 + (size_t)row * Hd : nullptr;
    int mrow = MASKED ? mask[row] : 0;

    float t[24];
    float s = 0.f, ss = 0.f;
#pragma unroll
    for (int j = 0; j < 6; j++) {
        int off = j * 128 + lane * 4;
        float4 v = *(const float4*)(xr + off);
        if (r2) {
            float4 w = *(const float4*)(r2 + off);
            v.x += w.x; v.y += w.y; v.z += w.z; v.w += w.w;
        }
        if (RES) {
            float4 w = *(const float4*)(rr + off);
            v.x += w.x; v.y += w.y; v.z += w.z; v.w += w.w;
        }
        t[j * 4] = v.x; t[j * 4 + 1] = v.y; t[j * 4 + 2] = v.z; t[j * 4 + 3] = v.w;
        s += v.x + v.y + v.z + v.w;
        ss += v.x * v.x + v.y * v.y + v.z * v.z + v.w * v.w;
    }
#pragma unroll
    for (int o = 16; o; o >>= 1) {
        s  += __shfl_xor_sync(0xffffffffu, s, o);
        ss += __shfl_xor_sync(0xffffffffu, ss, o);
    }
    float mu = s * (1.0f / Hd);
    float var = ss * (1.0f / Hd) - mu * mu;
    float rstd = rsqrtf(var + 1e-5f);

#pragma unroll
    for (int j = 0; j < 6; j++) {
        int off = j * 128 + lane * 4;
        float4 gg = *(const float4*)(g + off);
        float4 bb = *(const float4*)(b + off);
        float v0 = (t[j * 4]     - mu) * rstd * gg.x + bb.x;
        float v1 = (t[j * 4 + 1] - mu) * rstd * gg.y + bb.y;
        float v2 = (t[j * 4 + 2] - mu) * rstd * gg.z + bb.z;
        float v3 = (t[j * 4 + 3] - mu) * rstd * gg.w + bb.w;
        if (ACT == 2) {
            v0 = v0 > 0.f ? v0 : LEAKY * v0;
            v1 = v1 > 0.f ? v1 : LEAKY * v1;
            v2 = v2 > 0.f ? v2 : LEAKY * v2;
            v3 = v3 > 0.f ? v3 : LEAKY * v3;
        }
        if (MASKED && mrow) { v0 = v1 = v2 = v3 = 0.f; }
        if (MODE != 1) {
            *(float4*)(out + (size_t)row * Hd + off) = make_float4(v0, v1, v2, v3);
        }
        if (MODE != 0) {
            __half* po = out2 + (size_t)row * Hd + off;
            *(__half2*)(po)     = __halves2half2(__float2half_rn(v0), __float2half_rn(v1));
            *(__half2*)(po + 2) = __halves2half2(__float2half_rn(v2), __float2half_rn(v3));
        }
    }
}

// ---------------- ring attention ----------------
__global__ __launch_bounds__(256)
void ring_attn_kernel(const __half* __restrict__ qkv, const float* __restrict__ rk,
                      const float* __restrict__ rv, __half* __restrict__ out2)
{
    int gw = (blockIdx.x * blockDim.x + threadIdx.x) >> 5;
    int lane = threadIdx.x & 31;
    int n = gw % NHd;
    int bl = gw / NHd;
    int l = bl % Lx;
    int b = bl / Lx;

    float2 qf = __half22float2(*(const __half2*)(qkv + (size_t)bl * (3 * Hd) + n * HDd + lane * 2));
    float q0 = qf.x, q1 = qf.y;

    float s[4];
#pragma unroll
    for (int w = 0; w < 3; w++) {
        int ll = l - 1 + w;
        float d = 0.f;
        if (ll >= 0 && ll < Lx) {
            float2 kf = __half22float2(*(const __half2*)(qkv + ((size_t)(b * Lx + ll)) * (3 * Hd) + Hd + n * HDd + lane * 2));
            d = q0 * kf.x + q1 * kf.y;
        }
#pragma unroll
        for (int o = 16; o; o >>= 1) d += __shfl_xor_sync(0xffffffffu, d, o);
        s[w] = d * SCALE_ATT;
    }
    {
        const float* kp = rk + b * Hd + n * HDd;
        float d = q0 * kp[lane * 2] + q1 * kp[lane * 2 + 1];
#pragma unroll
        for (int o = 16; o; o >>= 1) d += __shfl_xor_sync(0xffffffffu, d, o);
        s[3] = d * SCALE_ATT;
    }
    float m = fmaxf(fmaxf(s[0], s[1]), fmaxf(s[2], s[3]));
    float e[4], se = 0.f;
#pragma unroll
    for (int w = 0; w < 4; w++) { e[w] = expf(s[w] - m); se += e[w]; }
    float inv = 1.0f / se;

    float o0 = 0.f, o1 = 0.f;
#pragma unroll
    for (int w = 0; w < 3; w++) {
        int ll = l - 1 + w;
        if (ll >= 0 && ll < Lx) {
            float2 vf = __half22float2(*(const __half2*)(qkv + ((size_t)(b * Lx + ll)) * (3 * Hd) + 2 * Hd + n * HDd + lane * 2));
            float p = e[w] * inv;
            o0 += p * vf.x;
            o1 += p * vf.y;
        }
    }
    {
        const float* vp = rv + b * Hd + n * HDd;
        float p = e[3] * inv;
        o0 += p * vp[lane * 2];
        o1 += p * vp[lane * 2 + 1];
    }
    int c0 = n * HDd + lane * 2;
    *(__half2*)(out2 + (size_t)bl * Hd + c0) =
        __halves2half2(__float2half_rn(o0), __float2half_rn(o1));
}

// ---------------- star attention ----------------
__global__ __launch_bounds__(1024)
void star_attn_kernel(const float* __restrict__ sq, const __half* __restrict__ kv,
                      const float* __restrict__ rk, const float* __restrict__ rv,
                      const int* __restrict__ mask, float* __restrict__ out)
{
    __shared__ float qs[HDd];
    __shared__ float sc[Lx + 1];
    __shared__ float red[16 * HDd];

    int b = blockIdx.x / NHd;
    int n = blockIdx.x % NHd;
    int tid = threadIdx.x;

    if (tid < HDd) qs[tid] = sq[b * Hd + n * HDd + tid];
    __syncthreads();

    float lmax = -1e30f;
    for (int s = tid; s < Lx + 1; s += 1024) {
        float d = 0.f;
        if (s == 0) {
            const float* kp = rk + b * Hd + n * HDd;
#pragma unroll
            for (int i = 0; i < HDd; i++) d += qs[i] * kp[i];
        } else {
            const __half2* kp2 = (const __half2*)(kv + ((size_t)(b * Lx + s - 1)) * (2 * Hd) + n * HDd);
#pragma unroll
            for (int i = 0; i < HDd / 2; i++) {
                float2 f = __half22float2(kp2[i]);
                d += qs[2 * i] * f.x + qs[2 * i + 1] * f.y;
            }
        }
        d *= SCALE_ATT;
        if (s > 0 && mask[b * Lx + s - 1]) d = -1e30f;
        sc[s] = d;
        lmax = fmaxf(lmax, d);
    }
    float bmax = block_reduce_max<32>(lmax);

    float lsum = 0.f;
    for (int s = tid; s < Lx + 1; s += 1024) {
        float ev = expf(sc[s] - bmax);
        sc[s] = ev;
        lsum += ev;
    }
    float bsum = block_reduce_sum<32>(lsum);

    int gg = tid >> 6;
    int dd = tid & 63;
    float acc = 0.f;
    for (int s = gg; s < Lx + 1; s += 16) {
        float vv;
        if (s == 0) vv = rv[b * Hd + n * HDd + dd];
        else        vv = __half2float(kv[((size_t)(b * Lx + s - 1)) * (2 * Hd) + Hd + n * HDd + dd]);
        acc += sc[s] * vv;
    }
    red[gg * HDd + dd] = acc;
    __syncthreads();
    if (tid < HDd) {
        float r = 0.f;
#pragma unroll
        for (int g = 0; g < 16; g++) r += red[g * HDd + tid];
        out[b * Hd + n * HDd + tid] = r / bsum;
    }
}

// ---------------- gather ft ----------------
__global__ void gather_ft_kernel(const float* __restrict__ relay, const float* __restrict__ nodes,
                                 const int* __restrict__ positions, float* __restrict__ ft)
{
    int idx = blockIdx.x * blockDim.x + threadIdx.x;
    if (idx >= Bx * 2 * Hd) return;
    int b = idx / (2 * Hd);
    int i = idx % (2 * Hd);
    float v;
    if (i < Hd) v = relay[b * Hd + i];
    else        v = nodes[((size_t)b * Lx + positions[b]) * Hd + (i - Hd)];
    ft[idx] = v;
}

// ---------------- launch ----------------
extern "C" void kernel_launch(void* const* d_in, const int* in_sizes, int n_in,
                              void* d_out, int out_size)
{
    const int*   src       = (const int*)  d_in[0];
    const int*   positions = (const int*)  d_in[1];
    const float* emb       = (const float*)d_in[2];
    const float* pos_table = (const float*)d_in[3];
    const float* norm_g    = (const float*)d_in[4];
    const float* norm_b    = (const float*)d_in[5];
    const float* pw_w1     = (const float*)d_in[6];
    const float* pw_b1     = (const float*)d_in[7];
    const float* pw_w2     = (const float*)d_in[8];
    const float* pw_b2     = (const float*)d_in[9];
    const float* pw_g      = (const float*)d_in[10];
    const float* pw_bn     = (const float*)d_in[11];
    const float* ring_wq   = (const float*)d_in[12];
    const float* ring_bq   = (const float*)d_in[13];
    const float* ring_wk   = (const float*)d_in[14];
    const float* ring_bk   = (const float*)d_in[15];
    const float* ring_wv   = (const float*)d_in[16];
    const float* ring_bv   = (const float*)d_in[17];
    const float* ring_wo   = (const float*)d_in[18];
    const float* ring_bo   = (const float*)d_in[19];
    const float* star_wq   = (const float*)d_in[20];
    const float* star_bq   = (const float*)d_in[21];
    const float* star_wk   = (const float*)d_in[22];
    const float* star_bk   = (const float*)d_in[23];
    const float* star_wv   = (const float*)d_in[24];
    const float* star_bv   = (const float*)d_in[25];
    const float* star_wo   = (const float*)d_in[26];
    const float* star_bo   = (const float*)d_in[27];
    const float* head_w1   = (const float*)d_in[28];
    const float* head_b1   = (const float*)d_in[29];
    const float* head_w2   = (const float*)d_in[30];
    const float* head_b2   = (const float*)d_in[31];
    float* out = (float*)d_out;

    cudaFuncSetAttribute(gemm_tc2<0, 0, 2>, cudaFuncAttributeMaxDynamicSharedMemorySize, SMEM_G);
    cudaFuncSetAttribute(gemm_tc2<0, 0, 1>, cudaFuncAttributeMaxDynamicSharedMemorySize, SMEM_G);
    cudaFuncSetAttribute(gemm_tc2<0, 1, 2>, cudaFuncAttributeMaxDynamicSharedMemorySize, SMEM_G);
    cudaFuncSetAttribute(gemm_tc2<0, 1, 1>, cudaFuncAttributeMaxDynamicSharedMemorySize, SMEM_G);
    cudaFuncSetAttribute(gemm_tc2<1, 1, 2>, cudaFuncAttributeMaxDynamicSharedMemorySize, SMEM_G);
    cudaFuncSetAttribute(gemm_tc2<1, 1, 1>, cudaFuncAttributeMaxDynamicSharedMemorySize, SMEM_G);

    float *x, *ring, *ring2, *relay, *part, *rk, *rv, *sq, *srk, *srv;
    float *satt, *ft, *hid, *bqkv, *bskv;
    int* mask;
    __half *x2, *h2, *att2, *mid2, *qkv, *kv;
    __half *w1p, *w2p, *qkvp, *rop, *skvp;
    cudaGetSymbolAddress((void**)&x, g_x);
    cudaGetSymbolAddress((void**)&ring, g_ring);
    cudaGetSymbolAddress((void**)&ring2, g_ring2);
    cudaGetSymbolAddress((void**)&relay, g_relay);
    cudaGetSymbolAddress((void**)&part, g_part);
    cudaGetSymbolAddress((void**)&rk, g_rk);
    cudaGetSymbolAddress((void**)&rv, g_rv);
    cudaGetSymbolAddress((void**)&sq, g_sq);
    cudaGetSymbolAddress((void**)&srk, g_srk);
    cudaGetSymbolAddress((void**)&srv, g_srv);
    cudaGetSymbolAddress((void**)&satt, g_satt);
    cudaGetSymbolAddress((void**)&ft, g_ft);
    cudaGetSymbolAddress((void**)&hid, g_hid);
    cudaGetSymbolAddress((void**)&mask, g_mask);
    cudaGetSymbolAddress((void**)&x2, g_x2);
    cudaGetSymbolAddress((void**)&h2, g_h2);
    cudaGetSymbolAddress((void**)&att2, g_att2);
    cudaGetSymbolAddress((void**)&mid2, g_mid2);
    cudaGetSymbolAddress((void**)&qkv, g_qkv);
    cudaGetSymbolAddress((void**)&kv, g_kv);
    cudaGetSymbolAddress((void**)&w1p, g_w1p);
    cudaGetSymbolAddress((void**)&w2p, g_w2p);
    cudaGetSymbolAddress((void**)&qkvp, g_qkvp);
    cudaGetSymbolAddress((void**)&rop, g_rop);
    cudaGetSymbolAddress((void**)&skvp, g_skvp);
    cudaGetSymbolAddress((void**)&bqkv, g_bqkv);
    cudaGetSymbolAddress((void**)&bskv, g_bskv);

    const int M = ML;

    cvt_all<<<(S8 + 255) / 256, 256>>>(pw_w1, pw_w2, ring_wq, ring_wk, ring_wv, ring_wo,
                                       star_wk, star_wv, w1p, w2p, qkvp, rop, skvp);
    concat_bias<<<(NLAYERS * 5 * Hd + 255) / 256, 256>>>(ring_bq, ring_bk, ring_bv,
                                                          star_bk, star_bv, bqkv, bskv);
    embed_kernel<<<(ML * Hd + 255) / 256, 256>>>(src, emb, pos_table, x, x2, mask);

    bool relay_done = false;
    for (int i = 0; i < NLAYERS; i++) {
        const float* b1 = pw_b1 + (size_t)i * DI;
        const float* b2 = pw_b2 + (size_t)i * Hd;
        const float* pg = pw_g + (size_t)i * Hd;
        const float* pb = pw_bn + (size_t)i * Hd;
        const float* rbk = ring_bk + (size_t)i * Hd;
        const float* rbv = ring_bv + (size_t)i * Hd;
        const float* rbo = ring_bo + (size_t)i * Hd;
        const float* ng = norm_g + (size_t)i * Hd;
        const float* nb = norm_b + (size_t)i * Hd;
        const float* rwk = ring_wk + (size_t)i * Hd * Hd;
        const float* rwv = ring_wv + (size_t)i * Hd * Hd;
        const __half* w1i = w1p + (size_t)i * DI * 2 * Hd;
        const __half* w2i = w2p + (size_t)i * Hd * 2 * DI;
        const __half* qkvi = qkvp + (size_t)i * 3 * Hd * 2 * Hd;
        const __half* roi = rop + (size_t)i * Hd * 2 * Hd;
        const __half* skvi = skvp + (size_t)i * 2 * Hd * 2 * Hd;
        const float* bqkvi = bqkv + (size_t)i * 3 * Hd;
        const float* bskvi = bskv + (size_t)i * 2 * Hd;

        // PWFF (1-product: calibrated error budget, saves 1/2 of mma)
        gemm_p(1, 1, 0, 1, x2, w1i, b1, nullptr, 0, mid2, nullptr, M, DI, Hd);   // launch 3 = profiled
        gemm_p(0, 0, 1, 1, mid2, w2i, b2, ring, Hd, nullptr, ring2, M, Hd, DI);
        ln_kernel<1, 0, 1, 0><<<M / 8, 256>>>(ring, x, ring2, pg, pb, nullptr, h2, nullptr);

        if (!relay_done) {
            dim3 gp(6, 16, Bx);
            relay_part_kernel<<<gp, 128>>>(x2, part);
            dim3 gf(6, Bx);
            relay_fin_kernel<<<gf, 128>>>(part, relay);
            relay_done = true;
        }

        gemm_rel5<<<(5 * Hd * 32 + 255) / 256, 256>>>(relay,
            rwk, rbk, rwv, rbv,
            star_wq + (size_t)i * Hd * Hd, star_bq + (size_t)i * Hd,
            star_wk + (size_t)i * Hd * Hd, star_bk + (size_t)i * Hd,
            star_wv + (size_t)i * Hd * Hd, star_bv + (size_t)i * Hd,
            rk, rv, sq, srk, srv);

        // Ring attention (1-product QKV)
        gemm_p(0, 1, 0, 1, h2, qkvi, bqkvi, nullptr, 0, qkv, nullptr, M, 3 * Hd, Hd);
        ring_attn_kernel<<<(M * NHd) / 8, 256>>>(qkv, rk, rv, att2);
        gemm_p(0, 0, 1, 1, att2, roi, rbo, ring, Hd, nullptr, ring2, M, Hd, Hd);
        ln_kernel<0, 2, 2, 1><<<M / 8, 256>>>(ring, nullptr, ring2, ng, nb, x, x2, mask);

        // Star attention (1-product KV)
        gemm_p(0, 1, 0, 1, x2, skvi, bskvi, nullptr, 0, kv, nullptr, M, 2 * Hd, Hd);
        star_attn_kernel<<<Bx * NHd, 1024>>>(sq, kv, srk, srv, mask, satt);
        gemm_small8<<<(Hd * 32 + 255) / 256, 256>>>(satt, Hd,
            star_wo + (size_t)i * Hd * Hd, Hd, star_bo + (size_t)i * Hd,
            relay, Hd, Hd, Hd, 2);
    }

    // heads
    gather_ft_kernel<<<(Bx * 2 * Hd + 255) / 256, 256>>>(relay, x, positions, ft);
    gemm_small8<<<(3 * NHID * 32 + 255) / 256, 256>>>(ft, 2 * Hd, head_w1, 2 * Hd,
                                                      head_b1, hid, 3 * NHID,
                                                      3 * NHID, 2 * Hd, 1);
    head2_kernel<<<(3 * NOUT * 32 + 255) / 256, 256>>>(hid, head_w2, head_b2, out);
}

// round 17
// speedup vs baseline: 2.5307x; 1.0113x over previous
#include <cuda_runtime.h>
#include <cuda_fp16.h>
#include <math.h>
#include <stdint.h>

// ---------------- problem constants ----------------
#define Bx 8
#define Lx 1024
#define Hd 768
#define NHd 12
#define HDd 64
#define DI 3072
#define NLAYERS 2
#define NHID 1024
#define NOUT 5000
#define SCALE_ATT 0.125f
#define LEAKY 0.01f
#define ML (Bx*Lx)      // 8192

// ---------------- fp32 scratch ----------------
__device__ float g_x    [ML*Hd];
__device__ float g_ring [ML*Hd];
__device__ float g_ring2[ML*Hd];
__device__ float g_relay[Bx*Hd];
__device__ float g_part[Bx*16*Hd];
__device__ float g_rk  [Bx*Hd];
__device__ float g_rv  [Bx*Hd];
__device__ float g_sq  [Bx*Hd];
__device__ float g_srk [Bx*Hd];
__device__ float g_srv [Bx*Hd];
__device__ float g_satt[Bx*Hd];
__device__ float g_ft  [Bx*2*Hd];
__device__ float g_hid [Bx*3*NHID];
__device__ int   g_mask[Bx*Lx];

// ---------------- fp16 scratch ----------------
__device__ __half g_x2  [ML*Hd];
__device__ __half g_h2  [ML*Hd];
__device__ __half g_att2[ML*Hd];
__device__ __half g_mid2[(size_t)ML*DI];
__device__ __half g_qkv [ML*3*Hd];
__device__ __half g_kv  [ML*2*Hd];
// weights: hi-only fp16, plain row-major [rows, K]
__device__ __half g_w1p [(size_t)NLAYERS*DI*Hd];
__device__ __half g_w2p [(size_t)NLAYERS*Hd*DI];
__device__ __half g_qkvp[(size_t)NLAYERS*3*Hd*Hd];
__device__ __half g_rop [(size_t)NLAYERS*Hd*Hd];
__device__ __half g_skvp[(size_t)NLAYERS*2*Hd*Hd];
__device__ float g_bqkv[NLAYERS*3*Hd];
__device__ float g_bskv[NLAYERS*2*Hd];

// ---------------- helpers ----------------
__device__ __forceinline__ uint32_t cvta_s(const void* p) {
    return (uint32_t)__cvta_generic_to_shared(p);
}
__device__ __forceinline__ void ldsm4(uint32_t* r, uint32_t addr) {
    asm volatile("ldmatrix.sync.aligned.m8n8.x4.shared.b16 {%0,%1,%2,%3}, [%4];\n"
                 : "=r"(r[0]), "=r"(r[1]), "=r"(r[2]), "=r"(r[3]) : "r"(addr));
}
__device__ __forceinline__ void mma16816(float* c, const uint32_t* a, const uint32_t* b) {
    asm volatile("mma.sync.aligned.m16n8k16.row.col.f32.f16.f16.f32 "
                 "{%0,%1,%2,%3},{%4,%5,%6,%7},{%8,%9},{%0,%1,%2,%3};\n"
                 : "+f"(c[0]), "+f"(c[1]), "+f"(c[2]), "+f"(c[3])
                 : "r"(a[0]), "r"(a[1]), "r"(a[2]), "r"(a[3]), "r"(b[0]), "r"(b[1]));
}
__device__ __forceinline__ void cp16(uint32_t s, const void* g) {
    asm volatile("cp.async.cg.shared.global [%0], [%1], 16;\n" :: "r"(s), "l"(g));
}
__device__ __forceinline__ uint32_t sw128(uint32_t o) { return o ^ ((o >> 3) & 0x70); }

// =====================================================================
// Tensor-core GEMM, 128x128 tile, 2x4 warps, 2-stage pipeline,
// 64 fp32-k per chunk. A [M,K] fp16, W [N,K] fp16 (hi-only).
// Single product Ah*Bh. OUTP 0 = fp32 C (optional split-K), 1 = fp16 C2.
// Per chunk per matrix: 128 rows x 64 halves (128B SW128 rows), 16KB.
// =====================================================================
#define ATB 16384
#define BUFB (2*16384)               // 32 KB per buffer
#define SMEM_G (2*BUFB)              // 64 KB

__device__ __forceinline__ void fill_tile(uint32_t base, const __half* A2, int lda,
                                          const __half* W2, int ldw,
                                          int bm, int bn, int kc, int tid)
{
#pragma unroll
    for (int j = 0; j < 4; j++) {
        int idx = tid + j * 256;
        int row = idx >> 3, c16 = idx & 7;
        uint32_t off = sw128((uint32_t)(row * 128 + c16 * 16));
        cp16(base + off,       A2 + (size_t)(bm + row) * lda + kc * 64 + c16 * 8);
        cp16(base + ATB + off, W2 + (size_t)(bn + row) * ldw + kc * 64 + c16 * 8);
    }
}

template<int ACT, int OUTP>
__global__ __launch_bounds__(256, 2)
void gemm_tc2(const __half* __restrict__ A2, int lda,
              const __half* __restrict__ W2, int ldw,
              const float* __restrict__ bias,
              float* __restrict__ C, int ldc,
              __half* __restrict__ C2, int Nout,
              float* __restrict__ Cs,
              int kOff,
              int T)
{
    extern __shared__ __align__(128) char smraw[];
    const uint32_t sb = cvta_s(smraw);

    const int zz = blockIdx.z;
    if (zz) { A2 += kOff; W2 += kOff; }

    const int tid  = threadIdx.x;
    const int lane = tid & 31;
    const int warp = tid >> 5;
    const int wm = warp >> 2;
    const int wn = warp & 3;
    const int bm = blockIdx.y * 128;
    const int bn = blockIdx.x * 128;

    float acc[4][4][4];
#pragma unroll
    for (int i = 0; i < 4; i++)
#pragma unroll
        for (int j = 0; j < 4; j++)
#pragma unroll
            for (int c = 0; c < 4; c++) acc[i][j][c] = 0.f;

    const int a_row = lane & 15;
    const int a_kb  = (lane >> 4) * 16;
    const int b_row = (lane & 7) + ((lane >> 4) << 3);
    const int b_kb  = ((lane >> 3) & 1) * 16;

    fill_tile(sb, A2, lda, W2, ldw, bm, bn, 0, tid);
    asm volatile("cp.async.commit_group;\n");

    for (int t = 0; t < T; t++) {
        __syncthreads();
        if (t + 1 < T) {
            fill_tile(sb + ((t + 1) & 1) * BUFB, A2, lda, W2, ldw, bm, bn, t + 1, tid);
            asm volatile("cp.async.commit_group;\n");
            asm volatile("cp.async.wait_group 1;\n");
        } else {
            asm volatile("cp.async.wait_group 0;\n");
        }
        __syncthreads();

        const uint32_t ab = sb + (t & 1) * BUFB;
        const uint32_t bb = ab + ATB;

#pragma unroll
        for (int g2 = 0; g2 < 4; g2++) {
            uint32_t bh[2][4], afh[4][4];
#pragma unroll
            for (int p = 0; p < 2; p++) {
                int row = wn * 32 + p * 16 + b_row;
                ldsm4(bh[p], bb + sw128((uint32_t)(row * 128 + g2 * 32 + b_kb)));
            }
#pragma unroll
            for (int mt = 0; mt < 4; mt++) {
                int row = wm * 64 + mt * 16 + a_row;
                ldsm4(afh[mt], ab + sw128((uint32_t)(row * 128 + g2 * 32 + a_kb)));
            }
#pragma unroll
            for (int mt = 0; mt < 4; mt++)
#pragma unroll
                for (int nt = 0; nt < 4; nt++)
                    mma16816(acc[mt][nt], afh[mt], &bh[nt >> 1][(nt & 1) * 2]);
        }
    }

    float* Co = zz ? Cs : C;
#pragma unroll
    for (int mt = 0; mt < 4; mt++) {
#pragma unroll
        for (int nt = 0; nt < 4; nt++) {
            int row = bm + wm * 64 + mt * 16 + (lane >> 2);
            int col = bn + wn * 32 + nt * 8 + (lane & 3) * 2;
            float bi0 = zz ? 0.f : bias[col];
            float bi1 = zz ? 0.f : bias[col + 1];
            float v0 = acc[mt][nt][0] + bi0;
            float v1 = acc[mt][nt][1] + bi1;
            float v2 = acc[mt][nt][2] + bi0;
            float v3 = acc[mt][nt][3] + bi1;
            if (ACT == 1) {
                v0 = fmaxf(v0, 0.f); v1 = fmaxf(v1, 0.f);
                v2 = fmaxf(v2, 0.f); v3 = fmaxf(v3, 0.f);
            }
            if (OUTP == 0) {
                *(float2*)(Co + (size_t)row * ldc + col)       = make_float2(v0, v1);
                *(float2*)(Co + (size_t)(row + 8) * ldc + col) = make_float2(v2, v3);
            } else {
                *(__half2*)(C2 + (size_t)row * Nout + col) =
                    __halves2half2(__float2half_rn(v0), __float2half_rn(v1));
                *(__half2*)(C2 + (size_t)(row + 8) * Nout + col) =
                    __halves2half2(__float2half_rn(v2), __float2half_rn(v3));
            }
        }
    }
}

static void gemm_p(int act, int outp, int split,
                   const __half* A2, const __half* W2,
                   const float* bias, float* C, int ldc, __half* C2, float* Cs,
                   int M, int N, int K)
{
    int Keff = split ? K / 2 : K;
    dim3 grid(N / 128, M / 128, split ? 2 : 1);
    int T = Keff / 64;
    if (outp == 1) {
        if (act == 1) gemm_tc2<1, 1><<<grid, 256, SMEM_G>>>(A2, K, W2, K, bias, nullptr, 0, C2, N, nullptr, 0, T);
        else          gemm_tc2<0, 1><<<grid, 256, SMEM_G>>>(A2, K, W2, K, bias, nullptr, 0, C2, N, nullptr, 0, T);
    } else {
        gemm_tc2<0, 0><<<grid, 256, SMEM_G>>>(A2, K, W2, K, bias, C, ldc, nullptr, N, Cs, Keff, T);
    }
}

// =====================================================================
// fused weight conversion: fp32 -> hi-only fp16 row-major slabs
// segments in float4 units (same totals as before)
// =====================================================================
#define S1 1179648
#define S2 2359296
#define S3 2654208
#define S4 2949120
#define S5 3244032
#define S6 3538944
#define S7 3833856
#define S8 4128768

__global__ void cvt_all(const float* w1, const float* w2, const float* rq, const float* rk,
                        const float* rv, const float* ro, const float* sk, const float* sv,
                        __half* o1, __half* o2, __half* oqkv,
                        __half* oro, __half* oskv)
{
    int i = blockIdx.x * blockDim.x + threadIdx.x;
    if (i >= S8) return;
    const float* in; __half* out; int C, base, extra;
    if      (i < S1) { in = w1; out = o1;   C = Hd; base = 0;  extra = 0; }
    else if (i < S2) { in = w2; out = o2;   C = DI; base = S1; extra = 0; }
    else if (i < S3) { in = rq; out = oqkv;                    C = Hd; base = S2; extra = 1536; }
    else if (i < S4) { in = rk; out = oqkv + (size_t)768 * Hd; C = Hd; base = S3; extra = 1536; }
    else if (i < S5) { in = rv; out = oqkv + (size_t)1536 * Hd;C = Hd; base = S4; extra = 1536; }
    else if (i < S6) { in = ro; out = oro;  C = Hd; base = S5; extra = 0; }
    else if (i < S7) { in = sk; out = oskv;                    C = Hd; base = S6; extra = 768; }
    else             { in = sv; out = oskv + (size_t)768 * Hd; C = Hd; base = S7; extra = 768; }
    int e = (i - base) * 4;
    int r = e / C, c = e % C;
    size_t ro_ = (size_t)r + (size_t)(r / Hd) * extra;
    if (extra == 0 && C == DI) ro_ = r;
    float4 f = *(const float4*)(in + e);
    __half* p = out + ro_ * C + c;
    *(__half2*)(p)     = __halves2half2(__float2half_rn(f.x), __float2half_rn(f.y));
    *(__half2*)(p + 2) = __halves2half2(__float2half_rn(f.z), __float2half_rn(f.w));
}

__global__ void concat_bias(const float* bq, const float* bk, const float* bv,
                            const float* sk, const float* sv,
                            float* oqkv, float* oskv)
{
    int i = blockIdx.x * blockDim.x + threadIdx.x;
    int n1 = NLAYERS * 3 * Hd;
    if (i < n1) {
        int layer = i / (3 * Hd), c = i % (3 * Hd);
        const float* s = (c < Hd) ? bq : (c < 2 * Hd) ? bk : bv;
        oqkv[i] = s[layer * Hd + (c % Hd)];
    } else if (i < n1 + NLAYERS * 2 * Hd) {
        int j = i - n1;
        int layer = j / (2 * Hd), c = j % (2 * Hd);
        const float* s = (c < Hd) ? sk : sv;
        oskv[j] = s[layer * Hd + (c % Hd)];
    }
}

// =====================================================================
// Small-M GEMMs (M=8)
// =====================================================================
__device__ __forceinline__ void smalldot8(const float* __restrict__ A, int lda,
                                          const float* __restrict__ wrow, int K,
                                          int lane, float* s)
{
    const float4* w4 = (const float4*)wrow;
    int K4 = K >> 2;
#pragma unroll
    for (int m = 0; m < 8; m++) s[m] = 0.f;
    for (int k = lane; k < K4; k += 32) {
        float4 w = w4[k];
#pragma unroll
        for (int m = 0; m < 8; m++) {
            float4 a = ((const float4*)(A + (size_t)m * lda))[k];
            s[m] += a.x * w.x + a.y * w.y + a.z * w.z + a.w * w.w;
        }
    }
#pragma unroll
    for (int m = 0; m < 8; m++)
#pragma unroll
        for (int o = 16; o; o >>= 1) s[m] += __shfl_xor_sync(0xffffffffu, s[m], o);
}

__global__ __launch_bounds__(256)
void gemm_small8(const float* __restrict__ A, int lda,
                 const float* __restrict__ W, int ldw,
                 const float* __restrict__ bias,
                 float* __restrict__ C, int ldc,
                 int N, int K, int act)
{
    int n = (blockIdx.x * blockDim.x + threadIdx.x) >> 5;
    int lane = threadIdx.x & 31;
    if (n >= N) return;
    float s[8];
    smalldot8(A, lda, W + (size_t)n * ldw, K, lane, s);
    if (lane == 0) {
        float bv = bias[n];
#pragma unroll
        for (int m = 0; m < 8; m++) {
            float v = s[m] + bv;
            if (act == 1) v = fmaxf(v, 0.f);
            else if (act == 2) v = v > 0.f ? v : LEAKY * v;
            C[(size_t)m * ldc + n] = v;
        }
    }
}

__global__ __launch_bounds__(256)
void gemm_rel5(const float* __restrict__ relay,
               const float* __restrict__ rwk, const float* __restrict__ rbk,
               const float* __restrict__ rwv, const float* __restrict__ rbv,
               const float* __restrict__ swq, const float* __restrict__ sbq,
               const float* __restrict__ swk, const float* __restrict__ sbk,
               const float* __restrict__ swv, const float* __restrict__ sbv,
               float* __restrict__ rk, float* __restrict__ rv, float* __restrict__ sq,
               float* __restrict__ srk, float* __restrict__ srv)
{
    int n = (blockIdx.x * blockDim.x + threadIdx.x) >> 5;
    int lane = threadIdx.x & 31;
    if (n >= 5 * Hd) return;
    int seg = n / Hd, c = n % Hd;
    const float* W = (seg == 0) ? rwk : (seg == 1) ? rwv : (seg == 2) ? swq : (seg == 3) ? swk : swv;
    const float* B = (seg == 0) ? rbk : (seg == 1) ? rbv : (seg == 2) ? sbq : (seg == 3) ? sbk : sbv;
    float* C       = (seg == 0) ? rk  : (seg == 1) ? rv  : (seg == 2) ? sq  : (seg == 3) ? srk : srv;
    float s[8];
    smalldot8(relay, Hd, W + (size_t)c * Hd, Hd, lane, s);
    if (lane == 0) {
        float bb = B[c];
#pragma unroll
        for (int m = 0; m < 8; m++) C[(size_t)m * Hd + c] = s[m] + bb;
    }
}

__global__ __launch_bounds__(256)
void head2_kernel(const float* __restrict__ hid,
                  const float* __restrict__ w2,
                  const float* __restrict__ b2,
                  float* __restrict__ out)
{
    int n = (blockIdx.x * blockDim.x + threadIdx.x) >> 5;
    int lane = threadIdx.x & 31;
    if (n >= 3 * NOUT) return;
    int j = n / NOUT, c = n % NOUT;
    float s[8];
    smalldot8(hid + j * NHID, 3 * NHID, w2 + (size_t)n * NHID, NHID, lane, s);
    if (lane == 0) {
        float bb = b2[n];
#pragma unroll
        for (int m = 0; m < 8; m++)
            out[((size_t)m * 3 + j) * NOUT + c] = s[m] + bb;
    }
}

// ---------------- block reductions (for star_attn) ----------------
template<int NW>
__device__ __forceinline__ float block_reduce_max(float a)
{
    static __shared__ float sm[NW];
    __syncthreads();
    int lane = threadIdx.x & 31, w = threadIdx.x >> 5;
#pragma unroll
    for (int o = 16; o; o >>= 1) a = fmaxf(a, __shfl_xor_sync(0xffffffffu, a, o));
    if (lane == 0) sm[w] = a;
    __syncthreads();
    if (w == 0) {
        a = lane < NW ? sm[lane] : -1e30f;
#pragma unroll
        for (int o = NW / 2; o; o >>= 1) a = fmaxf(a, __shfl_xor_sync(0xffffffffu, a, o));
        if (lane == 0) sm[0] = a;
    }
    __syncthreads();
    return sm[0];
}
template<int NW>
__device__ __forceinline__ float block_reduce_sum(float a)
{
    static __shared__ float ss[NW];
    __syncthreads();
    int lane = threadIdx.x & 31, w = threadIdx.x >> 5;
#pragma unroll
    for (int o = 16; o; o >>= 1) a += __shfl_xor_sync(0xffffffffu, a, o);
    if (lane == 0) ss[w] = a;
    __syncthreads();
    if (w == 0) {
        a = lane < NW ? ss[lane] : 0.f;
#pragma unroll
        for (int o = NW / 2; o; o >>= 1) a += __shfl_xor_sync(0xffffffffu, a, o);
        if (lane == 0) ss[0] = a;
    }
    __syncthreads();
    return ss[0];
}

// ---------------- embed + mask ----------------
__global__ void embed_kernel(const int* __restrict__ src, const float* __restrict__ emb,
                             const float* __restrict__ pos, float* __restrict__ x,
                             __half* __restrict__ x2, int* __restrict__ mask)
{
    int idx = blockIdx.x * blockDim.x + threadIdx.x;
    if (idx >= ML * Hd) return;
    int h = idx % Hd;
    int bl = idx / Hd;
    int l = bl % Lx;
    int w = h >> 8;
    int dd = h & 255;
    int tok = src[bl * 3 + w];
    float v = emb[tok * 256 + dd] + pos[l * Hd + h];
    x[idx] = v;
    x2[idx] = __float2half_rn(v);
    if (h == 0) mask[bl] = (src[bl * 3] == 0) ? 1 : 0;
}

// ---------------- relay mean: 2-stage ----------------
__global__ void relay_part_kernel(const __half* __restrict__ x2, float* __restrict__ part)
{
    int h = blockIdx.x * 128 + threadIdx.x;
    int ch = blockIdx.y;
    int b = blockIdx.z;
    const __half* p = x2 + (size_t)b * Lx * Hd + (size_t)ch * 64 * Hd + h;
    float s = 0.f;
#pragma unroll 8
    for (int l = 0; l < 64; l++) s += __half2float(p[(size_t)l * Hd]);
    part[((size_t)b * 16 + ch) * Hd + h] = s;
}
__global__ void relay_fin_kernel(const float* __restrict__ part, float* __restrict__ relay)
{
    int h = blockIdx.x * 128 + threadIdx.x;
    int b = blockIdx.y;
    float s = 0.f;
#pragma unroll
    for (int ch = 0; ch < 16; ch++) s += part[((size_t)b * 16 + ch) * Hd + h];
    relay[b * Hd + h] = s * (1.0f / Lx);
}

// ---------------- layernorm: warp-per-row ----------------
template<int RES, int ACT, int MODE, int MASKED>
__global__ __launch_bounds__(256)
void ln_kernel(const float* __restrict__ x, const float* __restrict__ res,
               const float* __restrict__ res2,
               const float* __restrict__ g, const float* __restrict__ b,
               float* __restrict__ out, __half* __restrict__ out2,
               const int* __restrict__ mask)
{
    int row = blockIdx.x * 8 + (threadIdx.x >> 5);
    int lane = threadIdx.x & 31;
    const float* xr = x + (size_t)row * Hd;
    const float* rr = RES ? res + (size_t)row * Hd : nullptr;
    const float* r2 = res2 ? res2 + (size_t)row * Hd : nullptr;
    int mrow = MASKED ? mask[row] : 0;

    float t[24];
    float s = 0.f, ss = 0.f;
#pragma unroll
    for (int j = 0; j < 6; j++) {
        int off = j * 128 + lane * 4;
        float4 v = *(const float4*)(xr + off);
        if (r2) {
            float4 w = *(const float4*)(r2 + off);
            v.x += w.x; v.y += w.y; v.z += w.z; v.w += w.w;
        }
        if (RES) {
            float4 w = *(const float4*)(rr + off);
            v.x += w.x; v.y += w.y; v.z += w.z; v.w += w.w;
        }
        t[j * 4] = v.x; t[j * 4 + 1] = v.y; t[j * 4 + 2] = v.z; t[j * 4 + 3] = v.w;
        s += v.x + v.y + v.z + v.w;
        ss += v.x * v.x + v.y * v.y + v.z * v.z + v.w * v.w;
    }
#pragma unroll
    for (int o = 16; o; o >>= 1) {
        s  += __shfl_xor_sync(0xffffffffu, s, o);
        ss += __shfl_xor_sync(0xffffffffu, ss, o);
    }
    float mu = s * (1.0f / Hd);
    float var = ss * (1.0f / Hd) - mu * mu;
    float rstd = rsqrtf(var + 1e-5f);

#pragma unroll
    for (int j = 0; j < 6; j++) {
        int off = j * 128 + lane * 4;
        float4 gg = *(const float4*)(g + off);
        float4 bb = *(const float4*)(b + off);
        float v0 = (t[j * 4]     - mu) * rstd * gg.x + bb.x;
        float v1 = (t[j * 4 + 1] - mu) * rstd * gg.y + bb.y;
        float v2 = (t[j * 4 + 2] - mu) * rstd * gg.z + bb.z;
        float v3 = (t[j * 4 + 3] - mu) * rstd * gg.w + bb.w;
        if (ACT == 2) {
            v0 = v0 > 0.f ? v0 : LEAKY * v0;
            v1 = v1 > 0.f ? v1 : LEAKY * v1;
            v2 = v2 > 0.f ? v2 : LEAKY * v2;
            v3 = v3 > 0.f ? v3 : LEAKY * v3;
        }
        if (MASKED && mrow) { v0 = v1 = v2 = v3 = 0.f; }
        if (MODE != 1) {
            *(float4*)(out + (size_t)row * Hd + off) = make_float4(v0, v1, v2, v3);
        }
        if (MODE != 0) {
            __half* po = out2 + (size_t)row * Hd + off;
            *(__half2*)(po)     = __halves2half2(__float2half_rn(v0), __float2half_rn(v1));
            *(__half2*)(po + 2) = __halves2half2(__float2half_rn(v2), __float2half_rn(v3));
        }
    }
}

// ---------------- ring attention ----------------
__global__ __launch_bounds__(256)
void ring_attn_kernel(const __half* __restrict__ qkv, const float* __restrict__ rk,
                      const float* __restrict__ rv, __half* __restrict__ out2)
{
    int gw = (blockIdx.x * blockDim.x + threadIdx.x) >> 5;
    int lane = threadIdx.x & 31;
    int n = gw % NHd;
    int bl = gw / NHd;
    int l = bl % Lx;
    int b = bl / Lx;

    float2 qf = __half22float2(*(const __half2*)(qkv + (size_t)bl * (3 * Hd) + n * HDd + lane * 2));
    float q0 = qf.x, q1 = qf.y;

    float s[4];
#pragma unroll
    for (int w = 0; w < 3; w++) {
        int ll = l - 1 + w;
        float d = 0.f;
        if (ll >= 0 && ll < Lx) {
            float2 kf = __half22float2(*(const __half2*)(qkv + ((size_t)(b * Lx + ll)) * (3 * Hd) + Hd + n * HDd + lane * 2));
            d = q0 * kf.x + q1 * kf.y;
        }
#pragma unroll
        for (int o = 16; o; o >>= 1) d += __shfl_xor_sync(0xffffffffu, d, o);
        s[w] = d * SCALE_ATT;
    }
    {
        const float* kp = rk + b * Hd + n * HDd;
        float d = q0 * kp[lane * 2] + q1 * kp[lane * 2 + 1];
#pragma unroll
        for (int o = 16; o; o >>= 1) d += __shfl_xor_sync(0xffffffffu, d, o);
        s[3] = d * SCALE_ATT;
    }
    float m = fmaxf(fmaxf(s[0], s[1]), fmaxf(s[2], s[3]));
    float e[4], se = 0.f;
#pragma unroll
    for (int w = 0; w < 4; w++) { e[w] = expf(s[w] - m); se += e[w]; }
    float inv = 1.0f / se;

    float o0 = 0.f, o1 = 0.f;
#pragma unroll
    for (int w = 0; w < 3; w++) {
        int ll = l - 1 + w;
        if (ll >= 0 && ll < Lx) {
            float2 vf = __half22float2(*(const __half2*)(qkv + ((size_t)(b * Lx + ll)) * (3 * Hd) + 2 * Hd + n * HDd + lane * 2));
            float p = e[w] * inv;
            o0 += p * vf.x;
            o1 += p * vf.y;
        }
    }
    {
        const float* vp = rv + b * Hd + n * HDd;
        float p = e[3] * inv;
        o0 += p * vp[lane * 2];
        o1 += p * vp[lane * 2 + 1];
    }
    int c0 = n * HDd + lane * 2;
    *(__half2*)(out2 + (size_t)bl * Hd + c0) =
        __halves2half2(__float2half_rn(o0), __float2half_rn(o1));
}

// ---------------- star attention ----------------
__global__ __launch_bounds__(1024)
void star_attn_kernel(const float* __restrict__ sq, const __half* __restrict__ kv,
                      const float* __restrict__ rk, const float* __restrict__ rv,
                      const int* __restrict__ mask, float* __restrict__ out)
{
    __shared__ float qs[HDd];
    __shared__ float sc[Lx + 1];
    __shared__ float red[16 * HDd];

    int b = blockIdx.x / NHd;
    int n = blockIdx.x % NHd;
    int tid = threadIdx.x;

    if (tid < HDd) qs[tid] = sq[b * Hd + n * HDd + tid];
    __syncthreads();

    float lmax = -1e30f;
    for (int s = tid; s < Lx + 1; s += 1024) {
        float d = 0.f;
        if (s == 0) {
            const float* kp = rk + b * Hd + n * HDd;
#pragma unroll
            for (int i = 0; i < HDd; i++) d += qs[i] * kp[i];
        } else {
            const __half2* kp2 = (const __half2*)(kv + ((size_t)(b * Lx + s - 1)) * (2 * Hd) + n * HDd);
#pragma unroll
            for (int i = 0; i < HDd / 2; i++) {
                float2 f = __half22float2(kp2[i]);
                d += qs[2 * i] * f.x + qs[2 * i + 1] * f.y;
            }
        }
        d *= SCALE_ATT;
        if (s > 0 && mask[b * Lx + s - 1]) d = -1e30f;
        sc[s] = d;
        lmax = fmaxf(lmax, d);
    }
    float bmax = block_reduce_max<32>(lmax);

    float lsum = 0.f;
    for (int s = tid; s < Lx + 1; s += 1024) {
        float ev = expf(sc[s] - bmax);
        sc[s] = ev;
        lsum += ev;
    }
    float bsum = block_reduce_sum<32>(lsum);

    int gg = tid >> 6;
    int dd = tid & 63;
    float acc = 0.f;
    for (int s = gg; s < Lx + 1; s += 16) {
        float vv;
        if (s == 0) vv = rv[b * Hd + n * HDd + dd];
        else        vv = __half2float(kv[((size_t)(b * Lx + s - 1)) * (2 * Hd) + Hd + n * HDd + dd]);
        acc += sc[s] * vv;
    }
    red[gg * HDd + dd] = acc;
    __syncthreads();
    if (tid < HDd) {
        float r = 0.f;
#pragma unroll
        for (int g = 0; g < 16; g++) r += red[g * HDd + tid];
        out[b * Hd + n * HDd + tid] = r / bsum;
    }
}

// ---------------- gather ft ----------------
__global__ void gather_ft_kernel(const float* __restrict__ relay, const float* __restrict__ nodes,
                                 const int* __restrict__ positions, float* __restrict__ ft)
{
    int idx = blockIdx.x * blockDim.x + threadIdx.x;
    if (idx >= Bx * 2 * Hd) return;
    int b = idx / (2 * Hd);
    int i = idx % (2 * Hd);
    float v;
    if (i < Hd) v = relay[b * Hd + i];
    else        v = nodes[((size_t)b * Lx + positions[b]) * Hd + (i - Hd)];
    ft[idx] = v;
}

// ---------------- launch ----------------
extern "C" void kernel_launch(void* const* d_in, const int* in_sizes, int n_in,
                              void* d_out, int out_size)
{
    const int*   src       = (const int*)  d_in[0];
    const int*   positions = (const int*)  d_in[1];
    const float* emb       = (const float*)d_in[2];
    const float* pos_table = (const float*)d_in[3];
    const float* norm_g    = (const float*)d_in[4];
    const float* norm_b    = (const float*)d_in[5];
    const float* pw_w1     = (const float*)d_in[6];
    const float* pw_b1     = (const float*)d_in[7];
    const float* pw_w2     = (const float*)d_in[8];
    const float* pw_b2     = (const float*)d_in[9];
    const float* pw_g      = (const float*)d_in[10];
    const float* pw_bn     = (const float*)d_in[11];
    const float* ring_wq   = (const float*)d_in[12];
    const float* ring_bq   = (const float*)d_in[13];
    const float* ring_wk   = (const float*)d_in[14];
    const float* ring_bk   = (const float*)d_in[15];
    const float* ring_wv   = (const float*)d_in[16];
    const float* ring_bv   = (const float*)d_in[17];
    const float* ring_wo   = (const float*)d_in[18];
    const float* ring_bo   = (const float*)d_in[19];
    const float* star_wq   = (const float*)d_in[20];
    const float* star_bq   = (const float*)d_in[21];
    const float* star_wk   = (const float*)d_in[22];
    const float* star_bk   = (const float*)d_in[23];
    const float* star_wv   = (const float*)d_in[24];
    const float* star_bv   = (const float*)d_in[25];
    const float* star_wo   = (const float*)d_in[26];
    const float* star_bo   = (const float*)d_in[27];
    const float* head_w1   = (const float*)d_in[28];
    const float* head_b1   = (const float*)d_in[29];
    const float* head_w2   = (const float*)d_in[30];
    const float* head_b2   = (const float*)d_in[31];
    float* out = (float*)d_out;

    cudaFuncSetAttribute(gemm_tc2<0, 0>, cudaFuncAttributeMaxDynamicSharedMemorySize, SMEM_G);
    cudaFuncSetAttribute(gemm_tc2<0, 1>, cudaFuncAttributeMaxDynamicSharedMemorySize, SMEM_G);
    cudaFuncSetAttribute(gemm_tc2<1, 1>, cudaFuncAttributeMaxDynamicSharedMemorySize, SMEM_G);

    float *x, *ring, *ring2, *relay, *part, *rk, *rv, *sq, *srk, *srv;
    float *satt, *ft, *hid, *bqkv, *bskv;
    int* mask;
    __half *x2, *h2, *att2, *mid2, *qkv, *kv;
    __half *w1p, *w2p, *qkvp, *rop, *skvp;
    cudaGetSymbolAddress((void**)&x, g_x);
    cudaGetSymbolAddress((void**)&ring, g_ring);
    cudaGetSymbolAddress((void**)&ring2, g_ring2);
    cudaGetSymbolAddress((void**)&relay, g_relay);
    cudaGetSymbolAddress((void**)&part, g_part);
    cudaGetSymbolAddress((void**)&rk, g_rk);
    cudaGetSymbolAddress((void**)&rv, g_rv);
    cudaGetSymbolAddress((void**)&sq, g_sq);
    cudaGetSymbolAddress((void**)&srk, g_srk);
    cudaGetSymbolAddress((void**)&srv, g_srv);
    cudaGetSymbolAddress((void**)&satt, g_satt);
    cudaGetSymbolAddress((void**)&ft, g_ft);
    cudaGetSymbolAddress((void**)&hid, g_hid);
    cudaGetSymbolAddress((void**)&mask, g_mask);
    cudaGetSymbolAddress((void**)&x2, g_x2);
    cudaGetSymbolAddress((void**)&h2, g_h2);
    cudaGetSymbolAddress((void**)&att2, g_att2);
    cudaGetSymbolAddress((void**)&mid2, g_mid2);
    cudaGetSymbolAddress((void**)&qkv, g_qkv);
    cudaGetSymbolAddress((void**)&kv, g_kv);
    cudaGetSymbolAddress((void**)&w1p, g_w1p);
    cudaGetSymbolAddress((void**)&w2p, g_w2p);
    cudaGetSymbolAddress((void**)&qkvp, g_qkvp);
    cudaGetSymbolAddress((void**)&rop, g_rop);
    cudaGetSymbolAddress((void**)&skvp, g_skvp);
    cudaGetSymbolAddress((void**)&bqkv, g_bqkv);
    cudaGetSymbolAddress((void**)&bskv, g_bskv);

    const int M = ML;

    cvt_all<<<(S8 + 255) / 256, 256>>>(pw_w1, pw_w2, ring_wq, ring_wk, ring_wv, ring_wo,
                                       star_wk, star_wv, w1p, w2p, qkvp, rop, skvp);
    concat_bias<<<(NLAYERS * 5 * Hd + 255) / 256, 256>>>(ring_bq, ring_bk, ring_bv,
                                                          star_bk, star_bv, bqkv, bskv);
    embed_kernel<<<(ML * Hd + 255) / 256, 256>>>(src, emb, pos_table, x, x2, mask);

    bool relay_done = false;
    for (int i = 0; i < NLAYERS; i++) {
        const float* b1 = pw_b1 + (size_t)i * DI;
        const float* b2 = pw_b2 + (size_t)i * Hd;
        const float* pg = pw_g + (size_t)i * Hd;
        const float* pb = pw_bn + (size_t)i * Hd;
        const float* rbk = ring_bk + (size_t)i * Hd;
        const float* rbv = ring_bv + (size_t)i * Hd;
        const float* rbo = ring_bo + (size_t)i * Hd;
        const float* ng = norm_g + (size_t)i * Hd;
        const float* nb = norm_b + (size_t)i * Hd;
        const float* rwk = ring_wk + (size_t)i * Hd * Hd;
        const float* rwv = ring_wv + (size_t)i * Hd * Hd;
        const __half* w1i = w1p + (size_t)i * DI * Hd;
        const __half* w2i = w2p + (size_t)i * Hd * DI;
        const __half* qkvi = qkvp + (size_t)i * 3 * Hd * Hd;
        const __half* roi = rop + (size_t)i * Hd * Hd;
        const __half* skvi = skvp + (size_t)i * 2 * Hd * Hd;
        const float* bqkvi = bqkv + (size_t)i * 3 * Hd;
        const float* bskvi = bskv + (size_t)i * 2 * Hd;

        // PWFF
        gemm_p(1, 1, 0, x2, w1i, b1, nullptr, 0, mid2, nullptr, M, DI, Hd);   // launch 3 = profiled
        gemm_p(0, 0, 1, mid2, w2i, b2, ring, Hd, nullptr, ring2, M, Hd, DI);
        ln_kernel<1, 0, 1, 0><<<M / 8, 256>>>(ring, x, ring2, pg, pb, nullptr, h2, nullptr);

        if (!relay_done) {
            dim3 gp(6, 16, Bx);
            relay_part_kernel<<<gp, 128>>>(x2, part);
            dim3 gf(6, Bx);
            relay_fin_kernel<<<gf, 128>>>(part, relay);
            relay_done = true;
        }

        gemm_rel5<<<(5 * Hd * 32 + 255) / 256, 256>>>(relay,
            rwk, rbk, rwv, rbv,
            star_wq + (size_t)i * Hd * Hd, star_bq + (size_t)i * Hd,
            star_wk + (size_t)i * Hd * Hd, star_bk + (size_t)i * Hd,
            star_wv + (size_t)i * Hd * Hd, star_bv + (size_t)i * Hd,
            rk, rv, sq, srk, srv);

        // Ring attention
        gemm_p(0, 1, 0, h2, qkvi, bqkvi, nullptr, 0, qkv, nullptr, M, 3 * Hd, Hd);
        ring_attn_kernel<<<(M * NHd) / 8, 256>>>(qkv, rk, rv, att2);
        gemm_p(0, 0, 1, att2, roi, rbo, ring, Hd, nullptr, ring2, M, Hd, Hd);
        ln_kernel<0, 2, 2, 1><<<M / 8, 256>>>(ring, nullptr, ring2, ng, nb, x, x2, mask);

        // Star attention
        gemm_p(0, 1, 0, x2, skvi, bskvi, nullptr, 0, kv, nullptr, M, 2 * Hd, Hd);
        star_attn_kernel<<<Bx * NHd, 1024>>>(sq, kv, srk, srv, mask, satt);
        gemm_small8<<<(Hd * 32 + 255) / 256, 256>>>(satt, Hd,
            star_wo + (size_t)i * Hd * Hd, Hd, star_bo + (size_t)i * Hd,
            relay, Hd, Hd, Hd, 2);
    }

    // heads
    gather_ft_kernel<<<(Bx * 2 * Hd + 255) / 256, 256>>>(relay, x, positions, ft);
    gemm_small8<<<(3 * NHID * 32 + 255) / 256, 256>>>(ft, 2 * Hd, head_w1, 2 * Hd,
                                                      head_b1, hid, 3 * NHID,
                                                      3 * NHID, 2 * Hd, 1);
    head2_kernel<<<(3 * NOUT * 32 + 255) / 256, 256>>>(hid, head_w2, head_b2, out);
}